// round 1
// baseline (speedup 1.0000x reference)
#include <cuda_runtime.h>
#include <cuda_bf16.h>
#include <math.h>

// ---------------------------------------------------------------------------
// SwinTransformerLayer: B=32, H=W=56, C=192, WS=7, SHIFT=3, HEADS=6, HD=32
// N=49 tokens/window, 64 windows/image, 2048 windows total, M=100352 rows.
// ---------------------------------------------------------------------------

#define BATCH   32
#define HH      56
#define WW_     56
#define CCH     192
#define WS      7
#define SHIFT   3
#define HEADS   6
#define HD      32
#define NTOK    49
#define NWIN    64          // windows per image (8x8)
#define MROWS   (BATCH*HH*WW_)   // 100352
#define HIDDEN  768
#define QKSCALE 0.17677669529663687f

// ------------------------- scratch (device globals) ------------------------
__device__ float g_xw  [(size_t)MROWS * CCH];     // LN1 + shift + window partition
__device__ float g_qkv [(size_t)MROWS * 3 * CCH]; // qkv
__device__ float g_o   [(size_t)MROWS * CCH];     // attention output (window layout)
__device__ float g_xmid[(size_t)MROWS * CCH];     // x + attn branch (NHWC)
__device__ float g_y   [(size_t)MROWS * CCH];     // LN2 output (NHWC)
__device__ float g_h1  [(size_t)MROWS * HIDDEN];  // conv3x3 + gelu output

// ------------------------------- LayerNorm ---------------------------------
// window_mode=1: block m indexes (window,token); read rolled pixel from x,
// write to window layout. window_mode=0: identity layout.
__global__ void ln_kernel(const float* __restrict__ x,
                          const float* __restrict__ gamma,
                          const float* __restrict__ beta,
                          float* __restrict__ out,
                          int window_mode)
{
    int m = blockIdx.x;
    int c = threadIdx.x;   // 192 threads

    int src_p;
    if (window_mode) {
        int win = m / NTOK, tok = m % NTOK;
        int b  = win >> 6, wi = win & 63;
        int hs = (wi >> 3) * WS + tok / WS;
        int ws = (wi & 7)  * WS + tok % WS;
        int h = hs + SHIFT; if (h >= HH)  h -= HH;
        int w = ws + SHIFT; if (w >= WW_) w -= WW_;
        src_p = (b * HH + h) * WW_ + w;
    } else {
        src_p = m;
    }

    float v = x[(size_t)src_p * CCH + c];

    __shared__ float s1[256], s2[256];
    s1[c] = v; s2[c] = v * v;
    if (c < 64) { s1[c + 192] = 0.f; s2[c + 192] = 0.f; }
    __syncthreads();
    #pragma unroll
    for (int st = 128; st > 0; st >>= 1) {
        if (c < st) { s1[c] += s1[c + st]; s2[c] += s2[c + st]; }
        __syncthreads();
    }
    float mu  = s1[0] * (1.0f / CCH);
    float var = s2[0] * (1.0f / CCH) - mu * mu;
    float r = rsqrtf(var + 1e-3f);
    out[(size_t)m * CCH + c] = (v - mu) * r * gamma[c] + beta[c];
}

// ------------------------------- Attention ---------------------------------
// one block per (window, head), 128 threads
__global__ void attn_kernel(const float* __restrict__ qkv,
                            const float* __restrict__ table,  // [169, 6]
                            float* __restrict__ o)
{
    int blk = blockIdx.x;
    int win = blk / HEADS;
    int head = blk % HEADS;
    int tid = threadIdx.x;

    __shared__ float qs[NTOK * HD], ks[NTOK * HD], vs[NTOK * HD];
    __shared__ float S[NTOK * 50];

    for (int t = tid; t < NTOK * HD; t += 128) {
        int n = t >> 5, d = t & 31;
        const float* base = qkv + (size_t)(win * NTOK + n) * (3 * CCH) + head * HD + d;
        qs[t] = base[0] * QKSCALE;
        ks[t] = base[CCH];
        vs[t] = base[2 * CCH];
    }
    __syncthreads();

    int wi = win & 63;
    int wh = wi >> 3, wwn = wi & 7;

    for (int t = tid; t < NTOK * NTOK; t += 128) {
        int n = t / NTOK, mm = t % NTOK;
        float s = 0.f;
        #pragma unroll
        for (int d = 0; d < HD; d++) s += qs[n * HD + d] * ks[mm * HD + d];
        int rn = n / WS, cn = n % WS, rm = mm / WS, cm = mm % WS;
        int idx = (rn - rm + WS - 1) * (2 * WS - 1) + (cn - cm + WS - 1);
        s += table[idx * HEADS + head];
        // shifted-window mask: region labels on shifted-image coordinates
        int hn = wh * WS + rn, wn = wwn * WS + cn;
        int hm = wh * WS + rm, wm = wwn * WS + cm;
        int reg_n = (hn < 49 ? 0 : (hn < 53 ? 1 : 2)) * 3 + (wn < 49 ? 0 : (wn < 53 ? 1 : 2));
        int reg_m = (hm < 49 ? 0 : (hm < 53 ? 1 : 2)) * 3 + (wm < 49 ? 0 : (wm < 53 ? 1 : 2));
        if (reg_n != reg_m) s -= 100.0f;
        S[n * 50 + mm] = s;
    }
    __syncthreads();

    if (tid < NTOK) {
        float mx = -1e30f;
        #pragma unroll 7
        for (int m2 = 0; m2 < NTOK; m2++) mx = fmaxf(mx, S[tid * 50 + m2]);
        float sum = 0.f;
        #pragma unroll 7
        for (int m2 = 0; m2 < NTOK; m2++) {
            float e = __expf(S[tid * 50 + m2] - mx);
            S[tid * 50 + m2] = e; sum += e;
        }
        float inv = 1.0f / sum;
        #pragma unroll 7
        for (int m2 = 0; m2 < NTOK; m2++) S[tid * 50 + m2] *= inv;
    }
    __syncthreads();

    for (int t = tid; t < NTOK * HD; t += 128) {
        int n = t >> 5, d = t & 31;
        float acc = 0.f;
        #pragma unroll 7
        for (int m2 = 0; m2 < NTOK; m2++) acc += S[n * 50 + m2] * vs[m2 * HD + d];
        o[(size_t)(win * NTOK + n) * CCH + head * HD + d] = acc;
    }
}

// --------------------------------- GEMM ------------------------------------
// 64x64x16 tiled fp32 GEMM, 256 threads, 4x4 per thread.
// CONV3=1: A is implicit im2col of g_y (3x3 SAME, K=1728 tap-major).
// epi: 0 = +bias -> C
//      2 = +bias, window-reverse+roll remap, + addsrc -> C      (N==192)
//      3 = *scale+shift, exact GELU -> C
//      4 = *scale+shift, + addsrc -> C                           (N==192)
template<int CONV3>
__global__ void gemm_kernel(const float* __restrict__ A,
                            const float* __restrict__ B,
                            const float* __restrict__ bias,
                            float* __restrict__ C,
                            int M, int N, int K,
                            int epi,
                            const float* __restrict__ scale,
                            const float* __restrict__ shift,
                            const float* __restrict__ addsrc)
{
    __shared__ float As[16][68];
    __shared__ float Bs[16][64];

    int tid = threadIdx.x;
    int tx = tid & 15, ty = tid >> 4;
    int m0 = blockIdx.y * 64, n0 = blockIdx.x * 64;

    float acc[4][4] = {};

    int arow = tid >> 2, aquad = tid & 3;
    int brow = tid >> 4, bcol = (tid & 15) * 4;

    int a_m = m0 + arow;
    int ab = 0, ah = 0, aw = 0;
    if (CONV3) { ab = a_m / 3136; int r = a_m % 3136; ah = r / 56; aw = r % 56; }

    for (int k0 = 0; k0 < K; k0 += 16) {
        float4 av;
        if (!CONV3) {
            av = *reinterpret_cast<const float4*>(A + (size_t)a_m * K + k0 + aquad * 4);
        } else {
            int tap = k0 / CCH;                 // K tiles are tap-aligned (192 % 16 == 0)
            int ky = tap / 3 - 1, kx = tap % 3 - 1;
            int h2 = ah + ky, w2 = aw + kx;
            if (h2 >= 0 && h2 < HH && w2 >= 0 && w2 < WW_) {
                int c0 = (k0 % CCH) + aquad * 4;
                av = *reinterpret_cast<const float4*>(
                        A + ((size_t)(ab * HH + h2) * WW_ + w2) * CCH + c0);
            } else {
                av = make_float4(0.f, 0.f, 0.f, 0.f);
            }
        }
        As[aquad * 4 + 0][arow] = av.x;
        As[aquad * 4 + 1][arow] = av.y;
        As[aquad * 4 + 2][arow] = av.z;
        As[aquad * 4 + 3][arow] = av.w;

        *reinterpret_cast<float4*>(&Bs[brow][bcol]) =
            *reinterpret_cast<const float4*>(B + (size_t)(k0 + brow) * N + n0 + bcol);

        __syncthreads();
        #pragma unroll
        for (int kk = 0; kk < 16; kk++) {
            float a[4], b[4];
            #pragma unroll
            for (int i = 0; i < 4; i++) a[i] = As[kk][ty * 4 + i];
            #pragma unroll
            for (int j = 0; j < 4; j++) b[j] = Bs[kk][tx * 4 + j];
            #pragma unroll
            for (int i = 0; i < 4; i++)
                #pragma unroll
                for (int j = 0; j < 4; j++)
                    acc[i][j] += a[i] * b[j];
        }
        __syncthreads();
    }

    #pragma unroll
    for (int i = 0; i < 4; i++) {
        int m = m0 + ty * 4 + i;
        size_t outrow;
        if (epi == 2) {
            int win = m / NTOK, tok = m % NTOK;
            int b = win >> 6, wi = win & 63;
            int hs = (wi >> 3) * WS + tok / WS;
            int ws = (wi & 7)  * WS + tok % WS;
            int h = hs + SHIFT; if (h >= HH)  h -= HH;
            int w = ws + SHIFT; if (w >= WW_) w -= WW_;
            outrow = (size_t)(b * HH + h) * WW_ + w;
        } else {
            outrow = (size_t)m;
        }
        #pragma unroll
        for (int j = 0; j < 4; j++) {
            int n = n0 + tx * 4 + j;
            float v = acc[i][j];
            if (epi == 0) {
                C[(size_t)m * N + n] = v + bias[n];
            } else if (epi == 2) {
                size_t oidx = outrow * CCH + n;
                C[oidx] = v + bias[n] + addsrc[oidx];
            } else if (epi == 3) {
                v = v * scale[n] + shift[n];
                v = 0.5f * v * (1.0f + erff(v * 0.70710678118654752f));
                C[(size_t)m * N + n] = v;
            } else {  // epi == 4
                v = v * scale[n] + shift[n];
                size_t oidx = (size_t)m * CCH + n;
                C[oidx] = v + addsrc[oidx];
            }
        }
    }
}

// ------------------------------- launcher -----------------------------------
extern "C" void kernel_launch(void* const* d_in, const int* in_sizes, int n_in,
                              void* d_out, int out_size)
{
    const float* x         = (const float*)d_in[0];
    const float* ln1_g     = (const float*)d_in[1];
    const float* ln1_b     = (const float*)d_in[2];
    const float* w_qkv     = (const float*)d_in[3];
    const float* b_qkv     = (const float*)d_in[4];
    const float* bias_tbl  = (const float*)d_in[5];
    const float* w_proj    = (const float*)d_in[6];
    const float* b_proj    = (const float*)d_in[7];
    const float* ln2_g     = (const float*)d_in[8];
    const float* ln2_b     = (const float*)d_in[9];
    const float* w_ffn1    = (const float*)d_in[10];   // [3,3,192,768] -> [1728,768]
    const float* bn1_scale = (const float*)d_in[11];
    const float* bn1_shift = (const float*)d_in[12];
    const float* w_ffn2    = (const float*)d_in[13];   // [768,192]
    const float* bn2_scale = (const float*)d_in[14];
    const float* bn2_shift = (const float*)d_in[15];
    float* out = (float*)d_out;

    float *xw, *qkv, *o, *xmid, *y, *h1;
    cudaGetSymbolAddress((void**)&xw,   g_xw);
    cudaGetSymbolAddress((void**)&qkv,  g_qkv);
    cudaGetSymbolAddress((void**)&o,    g_o);
    cudaGetSymbolAddress((void**)&xmid, g_xmid);
    cudaGetSymbolAddress((void**)&y,    g_y);
    cudaGetSymbolAddress((void**)&h1,   g_h1);

    // 1. LN1 + roll(-3,-3) + window partition
    ln_kernel<<<MROWS, 192>>>(x, ln1_g, ln1_b, xw, 1);

    // 2. QKV GEMM [M,192]x[192,576]
    gemm_kernel<0><<<dim3(576 / 64, MROWS / 64), 256>>>(
        xw, w_qkv, b_qkv, qkv, MROWS, 576, CCH, 0, nullptr, nullptr, nullptr);

    // 3. windowed attention
    attn_kernel<<<(MROWS / NTOK) * HEADS, 128>>>(qkv, bias_tbl, o);

    // 4. proj GEMM + window reverse + roll(+3,+3) + shortcut
    gemm_kernel<0><<<dim3(CCH / 64, MROWS / 64), 256>>>(
        o, w_proj, b_proj, xmid, MROWS, CCH, CCH, 2, nullptr, nullptr, x);

    // 5. LN2
    ln_kernel<<<MROWS, 192>>>(xmid, ln2_g, ln2_b, y, 0);

    // 6. conv3x3 (implicit GEMM, K=1728) + BN affine + exact GELU
    gemm_kernel<1><<<dim3(HIDDEN / 64, MROWS / 64), 256>>>(
        y, w_ffn1, nullptr, h1, MROWS, HIDDEN, 9 * CCH, 3, bn1_scale, bn1_shift, nullptr);

    // 7. conv1x1 + BN affine + residual -> d_out
    gemm_kernel<0><<<dim3(CCH / 64, MROWS / 64), 256>>>(
        h1, w_ffn2, nullptr, out, MROWS, CCH, HIDDEN, 4, bn2_scale, bn2_shift, xmid);
}

// round 3
// speedup vs baseline: 1.7570x; 1.7570x over previous
#include <cuda_runtime.h>
#include <cuda_bf16.h>
#include <cstdint>
#include <math.h>

// ---------------------------------------------------------------------------
// SwinTransformerLayer on GB300 via baseline-PTX tensor cores (mma.sync bf16),
// fp32-accurate 3-term bf16 split: C = Ah*Bh + Al*Bh + Ah*Bl  (K tripled).
// ---------------------------------------------------------------------------

#define BATCH   32
#define HH      56
#define WW_     56
#define CCH     192
#define WS      7
#define SHIFT   3
#define HEADS   6
#define HD      32
#define NTOK    49
#define MROWS   (BATCH*HH*WW_)   // 100352
#define HIDDEN  768
#define QKSCALE 0.17677669529663687f

// GEMM tiling
#define TM      128
#define TN      64
#define TKB     32               // bf16 K per stage
#define STAGES  3
#define ROWB    80               // padded row bytes (40 bf16) — conflict-free ldmatrix
#define A_STG   (TM*ROWB)        // 10240
#define B_STG   (TN*ROWB)        // 5120

// ------------------------- scratch (device globals) ------------------------
__device__ __align__(16) __nv_bfloat16 g_xw_h [(size_t)MROWS * CCH];
__device__ __align__(16) __nv_bfloat16 g_xw_l [(size_t)MROWS * CCH];
__device__ __align__(16) float         g_qkv  [(size_t)MROWS * 3 * CCH];
__device__ __align__(16) __nv_bfloat16 g_o_h  [(size_t)MROWS * CCH];
__device__ __align__(16) __nv_bfloat16 g_o_l  [(size_t)MROWS * CCH];
__device__ __align__(16) float         g_xmid [(size_t)MROWS * CCH];
__device__ __align__(16) __nv_bfloat16 g_y_h  [(size_t)MROWS * CCH];
__device__ __align__(16) __nv_bfloat16 g_y_l  [(size_t)MROWS * CCH];
__device__ __align__(16) __nv_bfloat16 g_h1_h [(size_t)MROWS * HIDDEN];
__device__ __align__(16) __nv_bfloat16 g_h1_l [(size_t)MROWS * HIDDEN];
// split weights, [N, 3K] K-major bf16
__device__ __align__(16) __nv_bfloat16 g_wq [(size_t)576 * 576];
__device__ __align__(16) __nv_bfloat16 g_wp [(size_t)192 * 576];
__device__ __align__(16) __nv_bfloat16 g_w1 [(size_t)768 * 5184];
__device__ __align__(16) __nv_bfloat16 g_w2 [(size_t)192 * 2304];

// ------------------------------ PTX helpers --------------------------------
__device__ __forceinline__ void cp_async16(uint32_t dst, const void* src, bool full) {
    int sz = full ? 16 : 0;
    asm volatile("cp.async.cg.shared.global [%0], [%1], 16, %2;"
                 :: "r"(dst), "l"(src), "r"(sz) : "memory");
}
#define CP_COMMIT() asm volatile("cp.async.commit_group;" ::: "memory")
#define CP_WAIT(n)  asm volatile("cp.async.wait_group %0;" :: "n"(n) : "memory")

__device__ __forceinline__ void ldsm_x4(uint32_t addr, uint32_t r[4]) {
    asm volatile("ldmatrix.sync.aligned.m8n8.x4.shared.b16 {%0,%1,%2,%3}, [%4];"
                 : "=r"(r[0]), "=r"(r[1]), "=r"(r[2]), "=r"(r[3]) : "r"(addr));
}
__device__ __forceinline__ void mma16816(float c[4], const uint32_t a[4],
                                         uint32_t b0, uint32_t b1) {
    asm volatile("mma.sync.aligned.m16n8k16.row.col.f32.bf16.bf16.f32 "
                 "{%0,%1,%2,%3}, {%4,%5,%6,%7}, {%8,%9}, {%0,%1,%2,%3};"
                 : "+f"(c[0]), "+f"(c[1]), "+f"(c[2]), "+f"(c[3])
                 : "r"(a[0]), "r"(a[1]), "r"(a[2]), "r"(a[3]), "r"(b0), "r"(b1));
}

__device__ __forceinline__ void split_bf16(float v, __nv_bfloat16& hi, __nv_bfloat16& lo) {
    hi = __float2bfloat16(v);
    lo = __float2bfloat16(v - __bfloat162float(hi));
}

// ----------------------------- weight prep ---------------------------------
// W [K,N] fp32 -> D [N, 3K] bf16 K-major: seg0=Bh (pairs Ah), seg1=Bh (pairs Al),
// seg2=Bl (pairs Ah).
__global__ void prep_w(const float* __restrict__ W, __nv_bfloat16* __restrict__ D,
                       int K, int N)
{
    int i = blockIdx.x * 256 + threadIdx.x;
    if (i >= K * N) return;
    int k = i / N, n = i % N;
    __nv_bfloat16 hi, lo;
    split_bf16(W[i], hi, lo);
    size_t base = (size_t)n * 3 * K;
    D[base + k]         = hi;
    D[base + K + k]     = hi;
    D[base + 2 * K + k] = lo;
}

// ------------------------------- LayerNorm ---------------------------------
__global__ void ln_kernel(const float* __restrict__ x,
                          const float* __restrict__ gamma,
                          const float* __restrict__ beta,
                          __nv_bfloat16* __restrict__ oh,
                          __nv_bfloat16* __restrict__ ol,
                          int window_mode)
{
    int m = blockIdx.x;
    int c = threadIdx.x;   // 192

    int src_p;
    if (window_mode) {
        int win = m / NTOK, tok = m % NTOK;
        int b  = win >> 6, wi = win & 63;
        int hs = (wi >> 3) * WS + tok / WS;
        int ws = (wi & 7)  * WS + tok % WS;
        int h = hs + SHIFT; if (h >= HH)  h -= HH;
        int w = ws + SHIFT; if (w >= WW_) w -= WW_;
        src_p = (b * HH + h) * WW_ + w;
    } else src_p = m;

    float v = x[(size_t)src_p * CCH + c];

    __shared__ float s1[256], s2[256];
    s1[c] = v; s2[c] = v * v;
    if (c < 64) { s1[c + 192] = 0.f; s2[c + 192] = 0.f; }
    __syncthreads();
    #pragma unroll
    for (int st = 128; st > 0; st >>= 1) {
        if (c < st) { s1[c] += s1[c + st]; s2[c] += s2[c + st]; }
        __syncthreads();
    }
    float mu  = s1[0] * (1.0f / CCH);
    float var = s2[0] * (1.0f / CCH) - mu * mu;
    float r = rsqrtf(var + 1e-3f);
    float yv = (v - mu) * r * gamma[c] + beta[c];
    __nv_bfloat16 hi, lo; split_bf16(yv, hi, lo);
    oh[(size_t)m * CCH + c] = hi;
    ol[(size_t)m * CCH + c] = lo;
}

// ------------------------------- Attention ---------------------------------
__global__ void attn_kernel(const float* __restrict__ qkv,
                            const float* __restrict__ table,
                            __nv_bfloat16* __restrict__ oh,
                            __nv_bfloat16* __restrict__ ol)
{
    int blk = blockIdx.x;
    int win = blk / HEADS;
    int head = blk % HEADS;
    int tid = threadIdx.x;

    __shared__ float qs[NTOK * HD], ks[NTOK * HD], vs[NTOK * HD];
    __shared__ float S[NTOK * 50];

    for (int t = tid; t < NTOK * HD; t += 128) {
        int n = t >> 5, d = t & 31;
        const float* base = qkv + (size_t)(win * NTOK + n) * (3 * CCH) + head * HD + d;
        qs[t] = base[0] * QKSCALE;
        ks[t] = base[CCH];
        vs[t] = base[2 * CCH];
    }
    __syncthreads();

    int wi = win & 63;
    int wh = wi >> 3, wwn = wi & 7;

    for (int t = tid; t < NTOK * NTOK; t += 128) {
        int n = t / NTOK, mm = t % NTOK;
        float s = 0.f;
        #pragma unroll
        for (int d = 0; d < HD; d++) s += qs[n * HD + d] * ks[mm * HD + d];
        int rn = n / WS, cn = n % WS, rm = mm / WS, cm = mm % WS;
        int idx = (rn - rm + WS - 1) * (2 * WS - 1) + (cn - cm + WS - 1);
        s += table[idx * HEADS + head];
        int hn = wh * WS + rn, wn = wwn * WS + cn;
        int hm = wh * WS + rm, wm = wwn * WS + cm;
        int reg_n = (hn < 49 ? 0 : (hn < 53 ? 1 : 2)) * 3 + (wn < 49 ? 0 : (wn < 53 ? 1 : 2));
        int reg_m = (hm < 49 ? 0 : (hm < 53 ? 1 : 2)) * 3 + (wm < 49 ? 0 : (wm < 53 ? 1 : 2));
        if (reg_n != reg_m) s -= 100.0f;
        S[n * 50 + mm] = s;
    }
    __syncthreads();

    if (tid < NTOK) {
        float mx = -1e30f;
        for (int m2 = 0; m2 < NTOK; m2++) mx = fmaxf(mx, S[tid * 50 + m2]);
        float sum = 0.f;
        for (int m2 = 0; m2 < NTOK; m2++) {
            float e = __expf(S[tid * 50 + m2] - mx);
            S[tid * 50 + m2] = e; sum += e;
        }
        float inv = 1.0f / sum;
        for (int m2 = 0; m2 < NTOK; m2++) S[tid * 50 + m2] *= inv;
    }
    __syncthreads();

    for (int t = tid; t < NTOK * HD; t += 128) {
        int n = t >> 5, d = t & 31;
        float acc = 0.f;
        #pragma unroll 7
        for (int m2 = 0; m2 < NTOK; m2++) acc += S[n * 50 + m2] * vs[m2 * HD + d];
        size_t idx = (size_t)(win * NTOK + n) * CCH + head * HD + d;
        __nv_bfloat16 hi, lo; split_bf16(acc, hi, lo);
        oh[idx] = hi; ol[idx] = lo;
    }
}

// ---------------------------- HMMA GEMM ------------------------------------
// C[M,N] = A'[M,3K] x B'[3K,N], A'=[Ah|Al|Ah] bf16 (implicit), B' prebuilt [N,3K].
// 128x64 CTA tile, BK=32, 8 warps (4x2), warp tile 32x32, mma m16n8k16.
// CONV3: A rows are im2col pixels of a [M,192] NHWC tensor (3x3 SAME).
// epi: 0 = +bias -> Cf
//      2 = +bias, window-reverse+roll remap, +addsrc -> Cf
//      3 = *scale+shift, exact GELU -> (Ch, Cl) bf16 split
//      4 = *scale+shift, +addsrc -> Cf
template<int CONV3>
__global__ __launch_bounds__(256)
void gemm_tc(const __nv_bfloat16* __restrict__ Ah,
             const __nv_bfloat16* __restrict__ Al,
             const __nv_bfloat16* __restrict__ Bs,
             const float* __restrict__ bias,
             float* __restrict__ Cf,
             __nv_bfloat16* __restrict__ Ch,
             __nv_bfloat16* __restrict__ Cl,
             const float* __restrict__ scale,
             const float* __restrict__ shiftv,
             const float* __restrict__ addsrc,
             int N, int K1, int epi)
{
    __shared__ __align__(128) char smem[STAGES * (A_STG + B_STG)];
    uint32_t sA0 = (uint32_t)__cvta_generic_to_shared(smem);
    uint32_t sB0 = sA0 + STAGES * A_STG;

    int tid = threadIdx.x;
    int wid = tid >> 5, lid = tid & 31;
    int wr = wid >> 1, wc = wid & 1;
    int m0 = blockIdx.y * TM, n0 = blockIdx.x * TN;
    int K3 = 3 * K1;
    int nk = K3 / TKB;

    // per-thread load coordinates
    int arow0 = tid >> 2;          // A rows arow0 and arow0+64
    int aj = tid & 3;              // 16B chunk within 64B row payload
    int pb[2], ph[2], pw[2];
    size_t arowoff[2];
    #pragma unroll
    for (int p = 0; p < 2; p++) {
        int m = m0 + arow0 + p * 64;
        if (CONV3) { pb[p] = m / 3136; int r = m % 3136; ph[p] = r / 56; pw[p] = r % 56; }
        else arowoff[p] = (size_t)m * K1;
    }
    int brow = tid >> 2, bj = tid & 3;
    size_t browoff = (size_t)(n0 + brow) * K3;

    float acc[2][4][4];
    #pragma unroll
    for (int i = 0; i < 2; i++)
        #pragma unroll
        for (int j = 0; j < 4; j++)
            #pragma unroll
            for (int q = 0; q < 4; q++) acc[i][j][q] = 0.f;

    auto load_stage = [&](int kt) {
        int s = kt % STAGES;
        int k3 = kt * TKB;
        int seg = k3 / K1;
        int kk = k3 - seg * K1;
        const __nv_bfloat16* Asrc = (seg == 1) ? Al : Ah;
        #pragma unroll
        for (int p = 0; p < 2; p++) {
            uint32_t dst = sA0 + s * A_STG + (arow0 + p * 64) * ROWB + aj * 16;
            const __nv_bfloat16* src;
            bool ok = true;
            if (!CONV3) {
                src = Asrc + arowoff[p] + kk + aj * 8;
            } else {
                int tap = kk / CCH;
                int ky = tap / 3 - 1, kx = tap % 3 - 1;
                int h2 = ph[p] + ky, w2 = pw[p] + kx;
                ok = (h2 >= 0) && (h2 < HH) && (w2 >= 0) && (w2 < WW_);
                int h2c = ok ? h2 : 0, w2c = ok ? w2 : 0;
                int c0 = kk - tap * CCH;
                src = Asrc + ((size_t)(pb[p] * HH + h2c) * WW_ + w2c) * CCH + c0 + aj * 8;
            }
            cp_async16(dst, src, ok);
        }
        {
            uint32_t dst = sB0 + s * B_STG + brow * ROWB + bj * 16;
            cp_async16(dst, Bs + browoff + k3 + bj * 8, true);
        }
    };

    auto compute = [&](int s) {
        uint32_t aBase = sA0 + s * A_STG + (wr * 32 + (lid & 15)) * ROWB + (lid >> 4) * 16;
        uint32_t bBase = sB0 + s * B_STG
                       + (wc * 32 + (lid & 7) + ((lid >> 4) << 3)) * ROWB
                       + ((lid >> 3) & 1) * 16;
        #pragma unroll
        for (int ks = 0; ks < 2; ks++) {
            uint32_t a[2][4], b[2][4];
            #pragma unroll
            for (int mi = 0; mi < 2; mi++)
                ldsm_x4(aBase + mi * 16 * ROWB + ks * 32, a[mi]);
            #pragma unroll
            for (int bi = 0; bi < 2; bi++)
                ldsm_x4(bBase + bi * 16 * ROWB + ks * 32, b[bi]);
            #pragma unroll
            for (int mi = 0; mi < 2; mi++)
                #pragma unroll
                for (int ni = 0; ni < 4; ni++)
                    mma16816(acc[mi][ni], a[mi],
                             b[ni >> 1][(ni & 1) * 2], b[ni >> 1][(ni & 1) * 2 + 1]);
        }
    };

    #pragma unroll
    for (int p = 0; p < STAGES - 1; p++) { if (p < nk) load_stage(p); CP_COMMIT(); }

    for (int kt = 0; kt < nk; kt++) {
        if (kt + STAGES - 1 < nk) load_stage(kt + STAGES - 1);
        CP_COMMIT();
        CP_WAIT(STAGES - 1);
        __syncthreads();
        compute(kt % STAGES);
        __syncthreads();
    }

    // ------------------------------ epilogue -------------------------------
    int g = lid >> 2, t2 = (lid & 3) * 2;
    #pragma unroll
    for (int mi = 0; mi < 2; mi++) {
        #pragma unroll
        for (int rr = 0; rr < 2; rr++) {
            int m = m0 + wr * 32 + mi * 16 + g + rr * 8;
            size_t orow;
            if (epi == 2) {
                int win = m / NTOK, tok = m % NTOK;
                int b = win >> 6, wi2 = win & 63;
                int hs = (wi2 >> 3) * WS + tok / WS;
                int ws = (wi2 & 7)  * WS + tok % WS;
                int h = hs + SHIFT; if (h >= HH)  h -= HH;
                int w = ws + SHIFT; if (w >= WW_) w -= WW_;
                orow = (size_t)(b * HH + h) * WW_ + w;
            } else {
                orow = (size_t)m;
            }
            #pragma unroll
            for (int ni = 0; ni < 4; ni++) {
                int n = n0 + wc * 32 + ni * 8 + t2;
                float v0 = acc[mi][ni][rr * 2 + 0];
                float v1 = acc[mi][ni][rr * 2 + 1];
                if (epi == 0) {
                    float2 o = { v0 + bias[n], v1 + bias[n + 1] };
                    *reinterpret_cast<float2*>(Cf + (size_t)m * N + n) = o;
                } else if (epi == 2) {
                    size_t oi = orow * CCH + n;
                    float2 a4 = *reinterpret_cast<const float2*>(addsrc + oi);
                    float2 o = { v0 + bias[n] + a4.x, v1 + bias[n + 1] + a4.y };
                    *reinterpret_cast<float2*>(Cf + oi) = o;
                } else if (epi == 3) {
                    v0 = v0 * scale[n] + shiftv[n];
                    v1 = v1 * scale[n + 1] + shiftv[n + 1];
                    v0 = 0.5f * v0 * (1.0f + erff(v0 * 0.70710678118654752f));
                    v1 = 0.5f * v1 * (1.0f + erff(v1 * 0.70710678118654752f));
                    __nv_bfloat16 h0, l0, h1, l1;
                    split_bf16(v0, h0, l0);
                    split_bf16(v1, h1, l1);
                    __nv_bfloat162 hv; hv.x = h0; hv.y = h1;
                    __nv_bfloat162 lv; lv.x = l0; lv.y = l1;
                    *reinterpret_cast<__nv_bfloat162*>(Ch + (size_t)m * N + n) = hv;
                    *reinterpret_cast<__nv_bfloat162*>(Cl + (size_t)m * N + n) = lv;
                } else {  // epi == 4
                    size_t oi = (size_t)m * CCH + n;
                    float2 a4 = *reinterpret_cast<const float2*>(addsrc + oi);
                    float2 o = { v0 * scale[n] + shiftv[n] + a4.x,
                                 v1 * scale[n + 1] + shiftv[n + 1] + a4.y };
                    *reinterpret_cast<float2*>(Cf + oi) = o;
                }
            }
        }
    }
}

// ------------------------------- launcher -----------------------------------
extern "C" void kernel_launch(void* const* d_in, const int* in_sizes, int n_in,
                              void* d_out, int out_size)
{
    const float* x         = (const float*)d_in[0];
    const float* ln1_g     = (const float*)d_in[1];
    const float* ln1_b     = (const float*)d_in[2];
    const float* w_qkv     = (const float*)d_in[3];
    const float* b_qkv     = (const float*)d_in[4];
    const float* bias_tbl  = (const float*)d_in[5];
    const float* w_proj    = (const float*)d_in[6];
    const float* b_proj    = (const float*)d_in[7];
    const float* ln2_g     = (const float*)d_in[8];
    const float* ln2_b     = (const float*)d_in[9];
    const float* w_ffn1    = (const float*)d_in[10];
    const float* bn1_scale = (const float*)d_in[11];
    const float* bn1_shift = (const float*)d_in[12];
    const float* w_ffn2    = (const float*)d_in[13];
    const float* bn2_scale = (const float*)d_in[14];
    const float* bn2_shift = (const float*)d_in[15];
    float* out = (float*)d_out;

    __nv_bfloat16 *xw_h, *xw_l, *o_h, *o_l, *y_h, *y_l, *h1_h, *h1_l, *wq, *wp, *w1, *w2;
    float *qkv, *xmid;
    cudaGetSymbolAddress((void**)&xw_h, g_xw_h);  cudaGetSymbolAddress((void**)&xw_l, g_xw_l);
    cudaGetSymbolAddress((void**)&qkv,  g_qkv);
    cudaGetSymbolAddress((void**)&o_h,  g_o_h);   cudaGetSymbolAddress((void**)&o_l,  g_o_l);
    cudaGetSymbolAddress((void**)&xmid, g_xmid);
    cudaGetSymbolAddress((void**)&y_h,  g_y_h);   cudaGetSymbolAddress((void**)&y_l,  g_y_l);
    cudaGetSymbolAddress((void**)&h1_h, g_h1_h);  cudaGetSymbolAddress((void**)&h1_l, g_h1_l);
    cudaGetSymbolAddress((void**)&wq, g_wq); cudaGetSymbolAddress((void**)&wp, g_wp);
    cudaGetSymbolAddress((void**)&w1, g_w1); cudaGetSymbolAddress((void**)&w2, g_w2);

    // 0. weight splits, [N, 3K] K-major bf16
    prep_w<<<(192 * 576 + 255) / 256, 256>>>(w_qkv, wq, 192, 576);
    prep_w<<<(192 * 192 + 255) / 256, 256>>>(w_proj, wp, 192, 192);
    prep_w<<<(1728 * 768 + 255) / 256, 256>>>(w_ffn1, w1, 1728, 768);
    prep_w<<<(768 * 192 + 255) / 256, 256>>>(w_ffn2, w2, 768, 192);

    // 1. LN1 + roll + window partition -> bf16 split
    ln_kernel<<<MROWS, 192>>>(x, ln1_g, ln1_b, xw_h, xw_l, 1);

    // 2. QKV GEMM [M,192]x[192,576]
    gemm_tc<0><<<dim3(576 / TN, MROWS / TM), 256>>>(
        xw_h, xw_l, wq, b_qkv, qkv, nullptr, nullptr, nullptr, nullptr, nullptr,
        576, 192, 0);

    // 3. attention -> bf16 split
    attn_kernel<<<(MROWS / NTOK) * HEADS, 128>>>(qkv, bias_tbl, o_h, o_l);

    // 4. proj GEMM + window reverse + roll + shortcut
    gemm_tc<0><<<dim3(192 / TN, MROWS / TM), 256>>>(
        o_h, o_l, wp, b_proj, xmid, nullptr, nullptr, nullptr, nullptr, x,
        192, 192, 2);

    // 5. LN2 -> bf16 split
    ln_kernel<<<MROWS, 192>>>(xmid, ln2_g, ln2_b, y_h, y_l, 0);

    // 6. conv3x3 implicit GEMM + BN + GELU -> bf16 split
    gemm_tc<1><<<dim3(HIDDEN / TN, MROWS / TM), 256>>>(
        y_h, y_l, w1, nullptr, nullptr, h1_h, h1_l, bn1_scale, bn1_shift, nullptr,
        HIDDEN, 9 * CCH, 3);

    // 7. conv1x1 GEMM + BN + residual -> out
    gemm_tc<0><<<dim3(CCH / TN, MROWS / TM), 256>>>(
        h1_h, h1_l, w2, nullptr, out, nullptr, nullptr, bn2_scale, bn2_shift, xmid,
        CCH, HIDDEN, 4);
}

// round 4
// speedup vs baseline: 1.7888x; 1.0181x over previous
#include <cuda_runtime.h>
#include <cuda_bf16.h>
#include <cstdint>
#include <math.h>

// ---------------------------------------------------------------------------
// SwinTransformerLayer on GB300 via baseline-PTX tensor cores (mma.sync bf16),
// fp32-accurate 3-term bf16 split: C = Ah*Bh + Al*Bh + Ah*Bl  (K tripled).
// Round 4: TM=256 tiles, warp tile 64xWN, single-sync 3-stage cp.async pipe.
// ---------------------------------------------------------------------------

#define BATCH   32
#define HH      56
#define WW_     56
#define CCH     192
#define WS      7
#define SHIFT   3
#define HEADS   6
#define HD      32
#define NTOK    49
#define MROWS   (BATCH*HH*WW_)   // 100352
#define HIDDEN  768
#define QKSCALE 0.17677669529663687f

#define TM      256
#define TKB     32               // bf16 K per stage
#define STAGES  3
#define ROWB    80               // padded row bytes (40 bf16) — conflict-free ldmatrix
#define A_STG   (TM*ROWB)        // 20480

// ------------------------- scratch (device globals) ------------------------
__device__ __align__(16) __nv_bfloat16 g_xw_h [(size_t)MROWS * CCH];
__device__ __align__(16) __nv_bfloat16 g_xw_l [(size_t)MROWS * CCH];
__device__ __align__(16) float         g_qkv  [(size_t)MROWS * 3 * CCH];
__device__ __align__(16) __nv_bfloat16 g_o_h  [(size_t)MROWS * CCH];
__device__ __align__(16) __nv_bfloat16 g_o_l  [(size_t)MROWS * CCH];
__device__ __align__(16) float         g_xmid [(size_t)MROWS * CCH];
__device__ __align__(16) __nv_bfloat16 g_y_h  [(size_t)MROWS * CCH];
__device__ __align__(16) __nv_bfloat16 g_y_l  [(size_t)MROWS * CCH];
__device__ __align__(16) __nv_bfloat16 g_h1_h [(size_t)MROWS * HIDDEN];
__device__ __align__(16) __nv_bfloat16 g_h1_l [(size_t)MROWS * HIDDEN];
// split weights, [N, 3K] K-major bf16
__device__ __align__(16) __nv_bfloat16 g_wq [(size_t)576 * 576];
__device__ __align__(16) __nv_bfloat16 g_wp [(size_t)192 * 576];
__device__ __align__(16) __nv_bfloat16 g_w1 [(size_t)768 * 5184];
__device__ __align__(16) __nv_bfloat16 g_w2 [(size_t)192 * 2304];

// ------------------------------ PTX helpers --------------------------------
__device__ __forceinline__ void cp_async16(uint32_t dst, const void* src, bool full) {
    int sz = full ? 16 : 0;
    asm volatile("cp.async.cg.shared.global [%0], [%1], 16, %2;"
                 :: "r"(dst), "l"(src), "r"(sz) : "memory");
}
#define CP_COMMIT() asm volatile("cp.async.commit_group;" ::: "memory")
#define CP_WAIT(n)  asm volatile("cp.async.wait_group %0;" :: "n"(n) : "memory")

__device__ __forceinline__ void ldsm_x4(uint32_t addr, uint32_t r[4]) {
    asm volatile("ldmatrix.sync.aligned.m8n8.x4.shared.b16 {%0,%1,%2,%3}, [%4];"
                 : "=r"(r[0]), "=r"(r[1]), "=r"(r[2]), "=r"(r[3]) : "r"(addr));
}
__device__ __forceinline__ void mma16816(float c[4], const uint32_t a[4],
                                         uint32_t b0, uint32_t b1) {
    asm volatile("mma.sync.aligned.m16n8k16.row.col.f32.bf16.bf16.f32 "
                 "{%0,%1,%2,%3}, {%4,%5,%6,%7}, {%8,%9}, {%0,%1,%2,%3};"
                 : "+f"(c[0]), "+f"(c[1]), "+f"(c[2]), "+f"(c[3])
                 : "r"(a[0]), "r"(a[1]), "r"(a[2]), "r"(a[3]), "r"(b0), "r"(b1));
}

__device__ __forceinline__ void split_bf16(float v, __nv_bfloat16& hi, __nv_bfloat16& lo) {
    hi = __float2bfloat16(v);
    lo = __float2bfloat16(v - __bfloat162float(hi));
}

// ----------------------------- weight prep ---------------------------------
__global__ void prep_w(const float* __restrict__ W, __nv_bfloat16* __restrict__ D,
                       int K, int N)
{
    int i = blockIdx.x * 256 + threadIdx.x;
    if (i >= K * N) return;
    int k = i / N, n = i % N;
    __nv_bfloat16 hi, lo;
    split_bf16(W[i], hi, lo);
    size_t base = (size_t)n * 3 * K;
    D[base + k]         = hi;   // seg0: pairs Ah
    D[base + K + k]     = hi;   // seg1: pairs Al
    D[base + 2 * K + k] = lo;   // seg2: pairs Ah
}

// ------------------------------- LayerNorm ---------------------------------
__global__ void ln_kernel(const float* __restrict__ x,
                          const float* __restrict__ gamma,
                          const float* __restrict__ beta,
                          __nv_bfloat16* __restrict__ oh,
                          __nv_bfloat16* __restrict__ ol,
                          int window_mode)
{
    int m = blockIdx.x;
    int c = threadIdx.x;   // 192

    int src_p;
    if (window_mode) {
        int win = m / NTOK, tok = m % NTOK;
        int b  = win >> 6, wi = win & 63;
        int hs = (wi >> 3) * WS + tok / WS;
        int ws = (wi & 7)  * WS + tok % WS;
        int h = hs + SHIFT; if (h >= HH)  h -= HH;
        int w = ws + SHIFT; if (w >= WW_) w -= WW_;
        src_p = (b * HH + h) * WW_ + w;
    } else src_p = m;

    float v = x[(size_t)src_p * CCH + c];

    __shared__ float s1[256], s2[256];
    s1[c] = v; s2[c] = v * v;
    if (c < 64) { s1[c + 192] = 0.f; s2[c + 192] = 0.f; }
    __syncthreads();
    #pragma unroll
    for (int st = 128; st > 0; st >>= 1) {
        if (c < st) { s1[c] += s1[c + st]; s2[c] += s2[c + st]; }
        __syncthreads();
    }
    float mu  = s1[0] * (1.0f / CCH);
    float var = s2[0] * (1.0f / CCH) - mu * mu;
    float r = rsqrtf(var + 1e-3f);
    float yv = (v - mu) * r * gamma[c] + beta[c];
    __nv_bfloat16 hi, lo; split_bf16(yv, hi, lo);
    oh[(size_t)m * CCH + c] = hi;
    ol[(size_t)m * CCH + c] = lo;
}

// ------------------------------- Attention ---------------------------------
__global__ void attn_kernel(const float* __restrict__ qkv,
                            const float* __restrict__ table,
                            __nv_bfloat16* __restrict__ oh,
                            __nv_bfloat16* __restrict__ ol)
{
    int blk = blockIdx.x;
    int win = blk / HEADS;
    int head = blk % HEADS;
    int tid = threadIdx.x;

    __shared__ float qs[NTOK * HD], ks[NTOK * HD], vs[NTOK * HD];
    __shared__ float S[NTOK * 50];

    for (int t = tid; t < NTOK * HD; t += 128) {
        int n = t >> 5, d = t & 31;
        const float* base = qkv + (size_t)(win * NTOK + n) * (3 * CCH) + head * HD + d;
        qs[t] = base[0] * QKSCALE;
        ks[t] = base[CCH];
        vs[t] = base[2 * CCH];
    }
    __syncthreads();

    int wi = win & 63;
    int wh = wi >> 3, wwn = wi & 7;

    for (int t = tid; t < NTOK * NTOK; t += 128) {
        int n = t / NTOK, mm = t % NTOK;
        float s = 0.f;
        #pragma unroll
        for (int d = 0; d < HD; d++) s += qs[n * HD + d] * ks[mm * HD + d];
        int rn = n / WS, cn = n % WS, rm = mm / WS, cm = mm % WS;
        int idx = (rn - rm + WS - 1) * (2 * WS - 1) + (cn - cm + WS - 1);
        s += table[idx * HEADS + head];
        int hn = wh * WS + rn, wn = wwn * WS + cn;
        int hm = wh * WS + rm, wm = wwn * WS + cm;
        int reg_n = (hn < 49 ? 0 : (hn < 53 ? 1 : 2)) * 3 + (wn < 49 ? 0 : (wn < 53 ? 1 : 2));
        int reg_m = (hm < 49 ? 0 : (hm < 53 ? 1 : 2)) * 3 + (wm < 49 ? 0 : (wm < 53 ? 1 : 2));
        if (reg_n != reg_m) s -= 100.0f;
        S[n * 50 + mm] = s;
    }
    __syncthreads();

    if (tid < NTOK) {
        float mx = -1e30f;
        for (int m2 = 0; m2 < NTOK; m2++) mx = fmaxf(mx, S[tid * 50 + m2]);
        float sum = 0.f;
        for (int m2 = 0; m2 < NTOK; m2++) {
            float e = __expf(S[tid * 50 + m2] - mx);
            S[tid * 50 + m2] = e; sum += e;
        }
        float inv = 1.0f / sum;
        for (int m2 = 0; m2 < NTOK; m2++) S[tid * 50 + m2] *= inv;
    }
    __syncthreads();

    for (int t = tid; t < NTOK * HD; t += 128) {
        int n = t >> 5, d = t & 31;
        float acc = 0.f;
        #pragma unroll 7
        for (int m2 = 0; m2 < NTOK; m2++) acc += S[n * 50 + m2] * vs[m2 * HD + d];
        size_t idx = (size_t)(win * NTOK + n) * CCH + head * HD + d;
        __nv_bfloat16 hi, lo; split_bf16(acc, hi, lo);
        oh[idx] = hi; ol[idx] = lo;
    }
}

// ---------------------------- HMMA GEMM ------------------------------------
// C[M,N] = A'[M,3K] x B'[3K,N], A'=[Ah|Al|Ah] bf16 (implicit), B' prebuilt [N,3K].
// CTA tile 256 x (2*WN), BK=32, 8 warps in 4x2, warp tile 64xWN, mma m16n8k16.
// Single __syncthreads per K-stage; cp.async zero-fill for conv3x3 halo.
// epi: 0=+bias  2=+bias,remap,+addsrc  3=BN+GELU->bf16 split  4=BN,+addsrc
template<int CONV3, int WN>
__global__ __launch_bounds__(256)
void gemm_tc(const __nv_bfloat16* __restrict__ Ah,
             const __nv_bfloat16* __restrict__ Al,
             const __nv_bfloat16* __restrict__ Bs,
             const float* __restrict__ bias,
             float* __restrict__ Cf,
             __nv_bfloat16* __restrict__ Ch,
             __nv_bfloat16* __restrict__ Cl,
             const float* __restrict__ scale,
             const float* __restrict__ shiftv,
             const float* __restrict__ addsrc,
             int N, int K1, int epi)
{
    constexpr int TN   = 2 * WN;
    constexpr int NB   = WN / 16;        // B ldsm per ks
    constexpr int NI   = WN / 8;         // n-fragments per warp
    constexpr int B_STG = TN * ROWB;
    constexpr int BPASS = TN / 64;       // B load passes

    extern __shared__ char smem[];
    uint32_t sA0 = (uint32_t)__cvta_generic_to_shared(smem);
    uint32_t sB0 = sA0 + STAGES * A_STG;

    int tid = threadIdx.x;
    int wid = tid >> 5, lid = tid & 31;
    int wr = wid >> 1, wc = wid & 1;
    int m0 = blockIdx.y * TM, n0 = blockIdx.x * TN;
    int K3 = 3 * K1;
    int nk = K3 / TKB;

    // per-thread load coordinates
    int arow = tid >> 2;          // + p*64, p<4
    int aj = tid & 3;             // 16B chunk within 64B row payload
    int pb[4], ph[4], pw[4];
    size_t arowoff[4];
    #pragma unroll
    for (int p = 0; p < 4; p++) {
        int m = m0 + arow + p * 64;
        if (CONV3) { pb[p] = m / 3136; int r = m % 3136; ph[p] = r / 56; pw[p] = r % 56; }
        else arowoff[p] = (size_t)m * K1;
    }
    size_t browoff[BPASS];
    #pragma unroll
    for (int p = 0; p < BPASS; p++)
        browoff[p] = (size_t)(n0 + arow + p * 64) * K3;

    float acc[4][NI][4];
    #pragma unroll
    for (int i = 0; i < 4; i++)
        #pragma unroll
        for (int j = 0; j < NI; j++)
            #pragma unroll
            for (int q = 0; q < 4; q++) acc[i][j][q] = 0.f;

    auto load_stage = [&](int kt) {
        int s = kt % STAGES;
        int k3 = kt * TKB;
        int seg = k3 / K1;
        int kk = k3 - seg * K1;
        const __nv_bfloat16* Asrc = (seg == 1) ? Al : Ah;
        #pragma unroll
        for (int p = 0; p < 4; p++) {
            uint32_t dst = sA0 + s * A_STG + (arow + p * 64) * ROWB + aj * 16;
            const __nv_bfloat16* src;
            bool ok = true;
            if (!CONV3) {
                src = Asrc + arowoff[p] + kk + aj * 8;
            } else {
                int tap = kk / CCH;
                int ky = tap / 3 - 1, kx = tap % 3 - 1;
                int h2 = ph[p] + ky, w2 = pw[p] + kx;
                ok = (h2 >= 0) && (h2 < HH) && (w2 >= 0) && (w2 < WW_);
                int h2c = ok ? h2 : 0, w2c = ok ? w2 : 0;
                int c0 = kk - tap * CCH;
                src = Asrc + ((size_t)(pb[p] * HH + h2c) * WW_ + w2c) * CCH + c0 + aj * 8;
            }
            cp_async16(dst, src, ok);
        }
        #pragma unroll
        for (int p = 0; p < BPASS; p++) {
            uint32_t dst = sB0 + s * B_STG + (arow + p * 64) * ROWB + aj * 16;
            cp_async16(dst, Bs + browoff[p] + k3 + aj * 8, true);
        }
    };

    auto compute = [&](int s) {
        uint32_t aBase = sA0 + s * A_STG + (wr * 64 + (lid & 15)) * ROWB + (lid >> 4) * 16;
        uint32_t bBase = sB0 + s * B_STG
                       + (wc * WN + (lid & 7) + ((lid >> 4) << 3)) * ROWB
                       + ((lid >> 3) & 1) * 16;
        #pragma unroll
        for (int ks = 0; ks < 2; ks++) {
            uint32_t a[4][4], b[NB][4];
            #pragma unroll
            for (int mi = 0; mi < 4; mi++)
                ldsm_x4(aBase + mi * 16 * ROWB + ks * 32, a[mi]);
            #pragma unroll
            for (int bi = 0; bi < NB; bi++)
                ldsm_x4(bBase + bi * 16 * ROWB + ks * 32, b[bi]);
            #pragma unroll
            for (int mi = 0; mi < 4; mi++)
                #pragma unroll
                for (int ni = 0; ni < NI; ni++)
                    mma16816(acc[mi][ni], a[mi],
                             b[ni >> 1][(ni & 1) * 2], b[ni >> 1][(ni & 1) * 2 + 1]);
        }
    };

    #pragma unroll
    for (int p = 0; p < STAGES - 1; p++) { if (p < nk) load_stage(p); CP_COMMIT(); }

    for (int kt = 0; kt < nk; kt++) {
        CP_WAIT(STAGES - 2);
        __syncthreads();
        if (kt + STAGES - 1 < nk) load_stage(kt + STAGES - 1);
        CP_COMMIT();
        compute(kt % STAGES);
    }

    // ------------------------------ epilogue -------------------------------
    int g = lid >> 2, t2 = (lid & 3) * 2;
    #pragma unroll
    for (int mi = 0; mi < 4; mi++) {
        #pragma unroll
        for (int rr = 0; rr < 2; rr++) {
            int m = m0 + wr * 64 + mi * 16 + g + rr * 8;
            size_t orow;
            if (epi == 2) {
                int win = m / NTOK, tok = m % NTOK;
                int b = win >> 6, wi2 = win & 63;
                int hs = (wi2 >> 3) * WS + tok / WS;
                int ws = (wi2 & 7)  * WS + tok % WS;
                int h = hs + SHIFT; if (h >= HH)  h -= HH;
                int w = ws + SHIFT; if (w >= WW_) w -= WW_;
                orow = (size_t)(b * HH + h) * WW_ + w;
            } else {
                orow = (size_t)m;
            }
            #pragma unroll
            for (int ni = 0; ni < NI; ni++) {
                int n = n0 + wc * WN + ni * 8 + t2;
                float v0 = acc[mi][ni][rr * 2 + 0];
                float v1 = acc[mi][ni][rr * 2 + 1];
                if (epi == 0) {
                    float2 o = { v0 + bias[n], v1 + bias[n + 1] };
                    *reinterpret_cast<float2*>(Cf + (size_t)m * N + n) = o;
                } else if (epi == 2) {
                    size_t oi = orow * CCH + n;
                    float2 a4 = *reinterpret_cast<const float2*>(addsrc + oi);
                    float2 o = { v0 + bias[n] + a4.x, v1 + bias[n + 1] + a4.y };
                    *reinterpret_cast<float2*>(Cf + oi) = o;
                } else if (epi == 3) {
                    v0 = v0 * scale[n] + shiftv[n];
                    v1 = v1 * scale[n + 1] + shiftv[n + 1];
                    v0 = 0.5f * v0 * (1.0f + erff(v0 * 0.70710678118654752f));
                    v1 = 0.5f * v1 * (1.0f + erff(v1 * 0.70710678118654752f));
                    __nv_bfloat16 h0, l0, h1, l1;
                    split_bf16(v0, h0, l0);
                    split_bf16(v1, h1, l1);
                    __nv_bfloat162 hv; hv.x = h0; hv.y = h1;
                    __nv_bfloat162 lv; lv.x = l0; lv.y = l1;
                    *reinterpret_cast<__nv_bfloat162*>(Ch + (size_t)m * N + n) = hv;
                    *reinterpret_cast<__nv_bfloat162*>(Cl + (size_t)m * N + n) = lv;
                } else {  // epi == 4
                    size_t oi = (size_t)m * CCH + n;
                    float2 a4 = *reinterpret_cast<const float2*>(addsrc + oi);
                    float2 o = { v0 * scale[n] + shiftv[n] + a4.x,
                                 v1 * scale[n + 1] + shiftv[n + 1] + a4.y };
                    *reinterpret_cast<float2*>(Cf + oi) = o;
                }
            }
        }
    }
}

// ------------------------------- launcher -----------------------------------
extern "C" void kernel_launch(void* const* d_in, const int* in_sizes, int n_in,
                              void* d_out, int out_size)
{
    const float* x         = (const float*)d_in[0];
    const float* ln1_g     = (const float*)d_in[1];
    const float* ln1_b     = (const float*)d_in[2];
    const float* w_qkv     = (const float*)d_in[3];
    const float* b_qkv     = (const float*)d_in[4];
    const float* bias_tbl  = (const float*)d_in[5];
    const float* w_proj    = (const float*)d_in[6];
    const float* b_proj    = (const float*)d_in[7];
    const float* ln2_g     = (const float*)d_in[8];
    const float* ln2_b     = (const float*)d_in[9];
    const float* w_ffn1    = (const float*)d_in[10];
    const float* bn1_scale = (const float*)d_in[11];
    const float* bn1_shift = (const float*)d_in[12];
    const float* w_ffn2    = (const float*)d_in[13];
    const float* bn2_scale = (const float*)d_in[14];
    const float* bn2_shift = (const float*)d_in[15];
    float* out = (float*)d_out;

    __nv_bfloat16 *xw_h, *xw_l, *o_h, *o_l, *y_h, *y_l, *h1_h, *h1_l, *wq, *wp, *w1, *w2;
    float *qkv, *xmid;
    cudaGetSymbolAddress((void**)&xw_h, g_xw_h);  cudaGetSymbolAddress((void**)&xw_l, g_xw_l);
    cudaGetSymbolAddress((void**)&qkv,  g_qkv);
    cudaGetSymbolAddress((void**)&o_h,  g_o_h);   cudaGetSymbolAddress((void**)&o_l,  g_o_l);
    cudaGetSymbolAddress((void**)&xmid, g_xmid);
    cudaGetSymbolAddress((void**)&y_h,  g_y_h);   cudaGetSymbolAddress((void**)&y_l,  g_y_l);
    cudaGetSymbolAddress((void**)&h1_h, g_h1_h);  cudaGetSymbolAddress((void**)&h1_l, g_h1_l);
    cudaGetSymbolAddress((void**)&wq, g_wq); cudaGetSymbolAddress((void**)&wp, g_wp);
    cudaGetSymbolAddress((void**)&w1, g_w1); cudaGetSymbolAddress((void**)&w2, g_w2);

    constexpr int SM32 = STAGES * (A_STG + 64 * ROWB);    // 76800
    constexpr int SM64 = STAGES * (A_STG + 128 * ROWB);   // 92160
    cudaFuncSetAttribute(gemm_tc<0,32>, cudaFuncAttributeMaxDynamicSharedMemorySize, SM32);
    cudaFuncSetAttribute(gemm_tc<1,64>, cudaFuncAttributeMaxDynamicSharedMemorySize, SM64);

    // 0. weight splits, [N, 3K] K-major bf16
    prep_w<<<(192 * 576 + 255) / 256, 256>>>(w_qkv, wq, 192, 576);
    prep_w<<<(192 * 192 + 255) / 256, 256>>>(w_proj, wp, 192, 192);
    prep_w<<<(1728 * 768 + 255) / 256, 256>>>(w_ffn1, w1, 1728, 768);
    prep_w<<<(768 * 192 + 255) / 256, 256>>>(w_ffn2, w2, 768, 192);

    // 1. LN1 + roll + window partition -> bf16 split
    ln_kernel<<<MROWS, 192>>>(x, ln1_g, ln1_b, xw_h, xw_l, 1);

    // 2. QKV GEMM [M,192]x[192,576]
    gemm_tc<0,32><<<dim3(576 / 64, MROWS / TM), 256, SM32>>>(
        xw_h, xw_l, wq, b_qkv, qkv, nullptr, nullptr, nullptr, nullptr, nullptr,
        576, 192, 0);

    // 3. attention -> bf16 split
    attn_kernel<<<(MROWS / NTOK) * HEADS, 128>>>(qkv, bias_tbl, o_h, o_l);

    // 4. proj GEMM + window reverse + roll + shortcut
    gemm_tc<0,32><<<dim3(192 / 64, MROWS / TM), 256, SM32>>>(
        o_h, o_l, wp, b_proj, xmid, nullptr, nullptr, nullptr, nullptr, x,
        192, 192, 2);

    // 5. LN2 -> bf16 split
    ln_kernel<<<MROWS, 192>>>(xmid, ln2_g, ln2_b, y_h, y_l, 0);

    // 6. conv3x3 implicit GEMM + BN + GELU -> bf16 split
    gemm_tc<1,64><<<dim3(HIDDEN / 128, MROWS / TM), 256, SM64>>>(
        y_h, y_l, w1, nullptr, nullptr, h1_h, h1_l, bn1_scale, bn1_shift, nullptr,
        HIDDEN, 9 * CCH, 3);

    // 7. conv1x1 GEMM + BN + residual -> out
    gemm_tc<0,32><<<dim3(CCH / 64, MROWS / TM), 256, SM32>>>(
        h1_h, h1_l, w2, nullptr, out, nullptr, nullptr, bn2_scale, bn2_shift, xmid,
        CCH, HIDDEN, 4);
}

// round 5
// speedup vs baseline: 2.3530x; 1.3154x over previous
#include <cuda_runtime.h>
#include <cuda_bf16.h>
#include <cstdint>
#include <math.h>

// ---------------------------------------------------------------------------
// SwinTransformerLayer on GB300. mma.sync bf16 with fp32-accurate 3-term split
// (C = Ah*Bh + Al*Bh + Ah*Bl, K tripled). Round 5: conv3x3 via Winograd
// F(2x2,3x3) — 2.25x fewer tensor FLOPs on the dominant GEMM.
// ---------------------------------------------------------------------------

#define BATCH   32
#define HH      56
#define WW_     56
#define CCH     192
#define WS      7
#define SHIFT   3
#define HEADS   6
#define HD      32
#define NTOK    49
#define MROWS   (BATCH*HH*WW_)   // 100352
#define HIDDEN  768
#define QKSCALE 0.17677669529663687f
#define NTILE   25088            // 32 * 28 * 28 winograd tiles

#define TM      256
#define TKB     32               // bf16 K per stage
#define STAGES  3
#define ROWB    80               // padded row bytes (40 bf16) — conflict-free ldmatrix
#define A_STG   (TM*ROWB)        // 20480

// ------------------------- scratch (device globals) ------------------------
__device__ __align__(16) __nv_bfloat16 g_xw_h [(size_t)MROWS * CCH];
__device__ __align__(16) __nv_bfloat16 g_xw_l [(size_t)MROWS * CCH];
__device__ __align__(16) float         g_qkv  [(size_t)MROWS * 3 * CCH];
__device__ __align__(16) __nv_bfloat16 g_o_h  [(size_t)MROWS * CCH];
__device__ __align__(16) __nv_bfloat16 g_o_l  [(size_t)MROWS * CCH];
__device__ __align__(16) float         g_xmid [(size_t)MROWS * CCH];
__device__ __align__(16) float         g_y    [(size_t)MROWS * CCH];
__device__ __align__(16) __nv_bfloat16 g_h1_h [(size_t)MROWS * HIDDEN];
__device__ __align__(16) __nv_bfloat16 g_h1_l [(size_t)MROWS * HIDDEN];
// split weights, [N, 3K] K-major bf16
__device__ __align__(16) __nv_bfloat16 g_wq [(size_t)576 * 576];
__device__ __align__(16) __nv_bfloat16 g_wp [(size_t)192 * 576];
__device__ __align__(16) __nv_bfloat16 g_w2 [(size_t)192 * 2304];
// winograd
__device__ __align__(16) __nv_bfloat16 g_U  [(size_t)16 * HIDDEN * 576];   // [p][co][3K]
__device__ __align__(16) __nv_bfloat16 g_Vh [(size_t)16 * NTILE * CCH];
__device__ __align__(16) __nv_bfloat16 g_Vl [(size_t)16 * NTILE * CCH];
__device__ __align__(16) float         g_M  [(size_t)16 * NTILE * HIDDEN]; // fp32

// ------------------------------ PTX helpers --------------------------------
__device__ __forceinline__ void cp_async16(uint32_t dst, const void* src, bool full) {
    int sz = full ? 16 : 0;
    asm volatile("cp.async.cg.shared.global [%0], [%1], 16, %2;"
                 :: "r"(dst), "l"(src), "r"(sz) : "memory");
}
#define CP_COMMIT() asm volatile("cp.async.commit_group;" ::: "memory")
#define CP_WAIT(n)  asm volatile("cp.async.wait_group %0;" :: "n"(n) : "memory")

__device__ __forceinline__ void ldsm_x4(uint32_t addr, uint32_t r[4]) {
    asm volatile("ldmatrix.sync.aligned.m8n8.x4.shared.b16 {%0,%1,%2,%3}, [%4];"
                 : "=r"(r[0]), "=r"(r[1]), "=r"(r[2]), "=r"(r[3]) : "r"(addr));
}
__device__ __forceinline__ void mma16816(float c[4], const uint32_t a[4],
                                         uint32_t b0, uint32_t b1) {
    asm volatile("mma.sync.aligned.m16n8k16.row.col.f32.bf16.bf16.f32 "
                 "{%0,%1,%2,%3}, {%4,%5,%6,%7}, {%8,%9}, {%0,%1,%2,%3};"
                 : "+f"(c[0]), "+f"(c[1]), "+f"(c[2]), "+f"(c[3])
                 : "r"(a[0]), "r"(a[1]), "r"(a[2]), "r"(a[3]), "r"(b0), "r"(b1));
}

__device__ __forceinline__ void split_bf16(float v, __nv_bfloat16& hi, __nv_bfloat16& lo) {
    hi = __float2bfloat16(v);
    lo = __float2bfloat16(v - __bfloat162float(hi));
}

// ----------------------------- weight prep ---------------------------------
__global__ void prep_w(const float* __restrict__ W, __nv_bfloat16* __restrict__ D,
                       int K, int N)
{
    int i = blockIdx.x * 256 + threadIdx.x;
    if (i >= K * N) return;
    int k = i / N, n = i % N;
    __nv_bfloat16 hi, lo;
    split_bf16(W[i], hi, lo);
    size_t base = (size_t)n * 3 * K;
    D[base + k]         = hi;   // seg0: pairs Ah
    D[base + K + k]     = hi;   // seg1: pairs Al
    D[base + 2 * K + k] = lo;   // seg2: pairs Ah
}

// ----------------------- winograd weight transform --------------------------
// w_ffn1 [3][3][192][768] HWIO -> U[p][co][3K layout], p = 4*r + c
__global__ void wino_wt(const float* __restrict__ W, __nv_bfloat16* __restrict__ U)
{
    int i = blockIdx.x * 256 + threadIdx.x;
    if (i >= CCH * HIDDEN) return;
    int ci = i / HIDDEN, co = i % HIDDEN;

    float g[3][3];
    #pragma unroll
    for (int ky = 0; ky < 3; ky++)
        #pragma unroll
        for (int kx = 0; kx < 3; kx++)
            g[ky][kx] = W[((size_t)(ky * 3 + kx) * CCH + ci) * HIDDEN + co];

    float u[4][3];
    #pragma unroll
    for (int c = 0; c < 3; c++) {
        u[0][c] = g[0][c];
        u[1][c] = 0.5f * (g[0][c] + g[1][c] + g[2][c]);
        u[2][c] = 0.5f * (g[0][c] - g[1][c] + g[2][c]);
        u[3][c] = g[2][c];
    }
    #pragma unroll
    for (int r = 0; r < 4; r++) {
        float U4[4];
        U4[0] = u[r][0];
        U4[1] = 0.5f * (u[r][0] + u[r][1] + u[r][2]);
        U4[2] = 0.5f * (u[r][0] - u[r][1] + u[r][2]);
        U4[3] = u[r][2];
        #pragma unroll
        for (int c = 0; c < 4; c++) {
            int p = r * 4 + c;
            __nv_bfloat16 hi, lo;
            split_bf16(U4[c], hi, lo);
            size_t base = ((size_t)p * HIDDEN + co) * 576;
            U[base + ci]       = hi;
            U[base + 192 + ci] = hi;
            U[base + 384 + ci] = lo;
        }
    }
}

// ----------------------- winograd input transform ---------------------------
// y [B,56,56,192] fp32 -> V[p][tile][c] bf16 hi/lo.  tile = b*784 + ty*28 + tx
__global__ void wino_in(const float* __restrict__ y,
                        __nv_bfloat16* __restrict__ Vh,
                        __nv_bfloat16* __restrict__ Vl)
{
    int i = blockIdx.x * 256 + threadIdx.x;
    if (i >= NTILE * CCH) return;
    int tile = i / CCH, c = i % CCH;
    int b = tile / 784, r = tile % 784, ty = r / 28, tx = r % 28;

    float d[4][4];
    #pragma unroll
    for (int ii = 0; ii < 4; ii++) {
        int h = 2 * ty - 1 + ii;
        #pragma unroll
        for (int jj = 0; jj < 4; jj++) {
            int w = 2 * tx - 1 + jj;
            bool ok = (h >= 0) && (h < HH) && (w >= 0) && (w < WW_);
            d[ii][jj] = ok ? y[((size_t)(b * HH + h) * WW_ + w) * CCH + c] : 0.f;
        }
    }
    float t[4][4];
    #pragma unroll
    for (int jj = 0; jj < 4; jj++) {
        t[0][jj] = d[0][jj] - d[2][jj];
        t[1][jj] = d[1][jj] + d[2][jj];
        t[2][jj] = d[2][jj] - d[1][jj];
        t[3][jj] = d[1][jj] - d[3][jj];
    }
    #pragma unroll
    for (int ii = 0; ii < 4; ii++) {
        float V4[4];
        V4[0] = t[ii][0] - t[ii][2];
        V4[1] = t[ii][1] + t[ii][2];
        V4[2] = t[ii][2] - t[ii][1];
        V4[3] = t[ii][1] - t[ii][3];
        #pragma unroll
        for (int jj = 0; jj < 4; jj++) {
            int p = ii * 4 + jj;
            __nv_bfloat16 hi, lo;
            split_bf16(V4[jj], hi, lo);
            size_t idx = ((size_t)p * NTILE + tile) * CCH + c;
            Vh[idx] = hi; Vl[idx] = lo;
        }
    }
}

// ----------------------- winograd output transform --------------------------
// M[p][tile][co] fp32 -> Y 2x2 -> BN+GELU -> h1 hi/lo (pixel layout)
__global__ void wino_out(const float* __restrict__ M,
                         const float* __restrict__ scale,
                         const float* __restrict__ shiftv,
                         __nv_bfloat16* __restrict__ h1h,
                         __nv_bfloat16* __restrict__ h1l)
{
    int i = blockIdx.x * 256 + threadIdx.x;
    if (i >= NTILE * HIDDEN) return;
    int tile = i / HIDDEN, co = i % HIDDEN;
    int b = tile / 784, r = tile % 784, ty = r / 28, tx = r % 28;

    float m[4][4];
    #pragma unroll
    for (int p = 0; p < 16; p++)
        m[p >> 2][p & 3] = M[((size_t)p * NTILE + tile) * HIDDEN + co];

    float s[2][4];
    #pragma unroll
    for (int q = 0; q < 4; q++) {
        s[0][q] = m[0][q] + m[1][q] + m[2][q];
        s[1][q] = m[1][q] - m[2][q] - m[3][q];
    }
    float sc = scale[co], sh = shiftv[co];
    #pragma unroll
    for (int ii = 0; ii < 2; ii++) {
        float Y0 = s[ii][0] + s[ii][1] + s[ii][2];
        float Y1 = s[ii][1] - s[ii][2] - s[ii][3];
        #pragma unroll
        for (int jj = 0; jj < 2; jj++) {
            float v = (jj == 0 ? Y0 : Y1) * sc + sh;
            v = 0.5f * v * (1.0f + erff(v * 0.70710678118654752f));
            __nv_bfloat16 hi, lo;
            split_bf16(v, hi, lo);
            size_t px = (size_t)b * 3136 + (size_t)(2 * ty + ii) * 56 + (2 * tx + jj);
            h1h[px * HIDDEN + co] = hi;
            h1l[px * HIDDEN + co] = lo;
        }
    }
}

// ------------------------------- LayerNorm ---------------------------------
// out_f32 != null: write plain fp32; else write bf16 hi/lo split.
__global__ void ln_kernel(const float* __restrict__ x,
                          const float* __restrict__ gamma,
                          const float* __restrict__ beta,
                          __nv_bfloat16* __restrict__ oh,
                          __nv_bfloat16* __restrict__ ol,
                          float* __restrict__ out_f32,
                          int window_mode)
{
    int m = blockIdx.x;
    int c = threadIdx.x;   // 192

    int src_p;
    if (window_mode) {
        int win = m / NTOK, tok = m % NTOK;
        int b  = win >> 6, wi = win & 63;
        int hs = (wi >> 3) * WS + tok / WS;
        int ws = (wi & 7)  * WS + tok % WS;
        int h = hs + SHIFT; if (h >= HH)  h -= HH;
        int w = ws + SHIFT; if (w >= WW_) w -= WW_;
        src_p = (b * HH + h) * WW_ + w;
    } else src_p = m;

    float v = x[(size_t)src_p * CCH + c];

    __shared__ float s1[256], s2[256];
    s1[c] = v; s2[c] = v * v;
    if (c < 64) { s1[c + 192] = 0.f; s2[c + 192] = 0.f; }
    __syncthreads();
    #pragma unroll
    for (int st = 128; st > 0; st >>= 1) {
        if (c < st) { s1[c] += s1[c + st]; s2[c] += s2[c + st]; }
        __syncthreads();
    }
    float mu  = s1[0] * (1.0f / CCH);
    float var = s2[0] * (1.0f / CCH) - mu * mu;
    float r = rsqrtf(var + 1e-3f);
    float yv = (v - mu) * r * gamma[c] + beta[c];
    if (out_f32) {
        out_f32[(size_t)m * CCH + c] = yv;
    } else {
        __nv_bfloat16 hi, lo; split_bf16(yv, hi, lo);
        oh[(size_t)m * CCH + c] = hi;
        ol[(size_t)m * CCH + c] = lo;
    }
}

// ------------------------------- Attention ---------------------------------
__global__ void attn_kernel(const float* __restrict__ qkv,
                            const float* __restrict__ table,
                            __nv_bfloat16* __restrict__ oh,
                            __nv_bfloat16* __restrict__ ol)
{
    int blk = blockIdx.x;
    int win = blk / HEADS;
    int head = blk % HEADS;
    int tid = threadIdx.x;

    __shared__ float qs[NTOK * HD], ks[NTOK * HD], vs[NTOK * HD];
    __shared__ float S[NTOK * 50];

    for (int t = tid; t < NTOK * HD; t += 128) {
        int n = t >> 5, d = t & 31;
        const float* base = qkv + (size_t)(win * NTOK + n) * (3 * CCH) + head * HD + d;
        qs[t] = base[0] * QKSCALE;
        ks[t] = base[CCH];
        vs[t] = base[2 * CCH];
    }
    __syncthreads();

    int wi = win & 63;
    int wh = wi >> 3, wwn = wi & 7;

    for (int t = tid; t < NTOK * NTOK; t += 128) {
        int n = t / NTOK, mm = t % NTOK;
        float s = 0.f;
        #pragma unroll
        for (int d = 0; d < HD; d++) s += qs[n * HD + d] * ks[mm * HD + d];
        int rn = n / WS, cn = n % WS, rm = mm / WS, cm = mm % WS;
        int idx = (rn - rm + WS - 1) * (2 * WS - 1) + (cn - cm + WS - 1);
        s += table[idx * HEADS + head];
        int hn = wh * WS + rn, wn = wwn * WS + cn;
        int hm = wh * WS + rm, wm = wwn * WS + cm;
        int reg_n = (hn < 49 ? 0 : (hn < 53 ? 1 : 2)) * 3 + (wn < 49 ? 0 : (wn < 53 ? 1 : 2));
        int reg_m = (hm < 49 ? 0 : (hm < 53 ? 1 : 2)) * 3 + (wm < 49 ? 0 : (wm < 53 ? 1 : 2));
        if (reg_n != reg_m) s -= 100.0f;
        S[n * 50 + mm] = s;
    }
    __syncthreads();

    if (tid < NTOK) {
        float mx = -1e30f;
        for (int m2 = 0; m2 < NTOK; m2++) mx = fmaxf(mx, S[tid * 50 + m2]);
        float sum = 0.f;
        for (int m2 = 0; m2 < NTOK; m2++) {
            float e = __expf(S[tid * 50 + m2] - mx);
            S[tid * 50 + m2] = e; sum += e;
        }
        float inv = 1.0f / sum;
        for (int m2 = 0; m2 < NTOK; m2++) S[tid * 50 + m2] *= inv;
    }
    __syncthreads();

    for (int t = tid; t < NTOK * HD; t += 128) {
        int n = t >> 5, d = t & 31;
        float acc = 0.f;
        #pragma unroll 7
        for (int m2 = 0; m2 < NTOK; m2++) acc += S[n * 50 + m2] * vs[m2 * HD + d];
        size_t idx = (size_t)(win * NTOK + n) * CCH + head * HD + d;
        __nv_bfloat16 hi, lo; split_bf16(acc, hi, lo);
        oh[idx] = hi; ol[idx] = lo;
    }
}

// ---------------------------- HMMA GEMM ------------------------------------
// C[M,N] = A'[M,3K] x B'[3K,N], A'=[Ah|Al|Ah] bf16 (implicit), B' prebuilt [N,3K].
// CTA tile 256 x (2*WN), BK=32, 8 warps in 4x2, warp tile 64xWN, mma m16n8k16.
// Batched via blockIdx.z with element strides zsA/zsB/zsC.
// epi: 0=+bias  2=+bias,remap,+addsrc  4=BN,+addsrc  5=raw store
template<int WN>
__global__ __launch_bounds__(256)
void gemm_tc(const __nv_bfloat16* __restrict__ Ah,
             const __nv_bfloat16* __restrict__ Al,
             const __nv_bfloat16* __restrict__ Bs,
             const float* __restrict__ bias,
             float* __restrict__ Cf,
             const float* __restrict__ scale,
             const float* __restrict__ shiftv,
             const float* __restrict__ addsrc,
             int N, int K1, int epi,
             size_t zsA, size_t zsB, size_t zsC)
{
    constexpr int TN   = 2 * WN;
    constexpr int NB   = WN / 16;        // B ldsm per ks
    constexpr int NI   = WN / 8;         // n-fragments per warp
    constexpr int B_STG = TN * ROWB;
    constexpr int BPASS = TN / 64;       // B load passes

    Ah += blockIdx.z * zsA;
    Al += blockIdx.z * zsA;
    Bs += blockIdx.z * zsB;
    Cf += blockIdx.z * zsC;

    extern __shared__ char smem[];
    uint32_t sA0 = (uint32_t)__cvta_generic_to_shared(smem);
    uint32_t sB0 = sA0 + STAGES * A_STG;

    int tid = threadIdx.x;
    int wid = tid >> 5, lid = tid & 31;
    int wr = wid >> 1, wc = wid & 1;
    int m0 = blockIdx.y * TM, n0 = blockIdx.x * TN;
    int K3 = 3 * K1;
    int nk = K3 / TKB;

    int arow = tid >> 2;          // + p*64, p<4
    int aj = tid & 3;             // 16B chunk within 64B row payload
    size_t arowoff[4];
    #pragma unroll
    for (int p = 0; p < 4; p++) arowoff[p] = (size_t)(m0 + arow + p * 64) * K1;
    size_t browoff[BPASS];
    #pragma unroll
    for (int p = 0; p < BPASS; p++)
        browoff[p] = (size_t)(n0 + arow + p * 64) * K3;

    float acc[4][NI][4];
    #pragma unroll
    for (int i = 0; i < 4; i++)
        #pragma unroll
        for (int j = 0; j < NI; j++)
            #pragma unroll
            for (int q = 0; q < 4; q++) acc[i][j][q] = 0.f;

    auto load_stage = [&](int kt) {
        int s = kt % STAGES;
        int k3 = kt * TKB;
        int seg = k3 / K1;
        int kk = k3 - seg * K1;
        const __nv_bfloat16* Asrc = (seg == 1) ? Al : Ah;
        #pragma unroll
        for (int p = 0; p < 4; p++) {
            uint32_t dst = sA0 + s * A_STG + (arow + p * 64) * ROWB + aj * 16;
            cp_async16(dst, Asrc + arowoff[p] + kk + aj * 8, true);
        }
        #pragma unroll
        for (int p = 0; p < BPASS; p++) {
            uint32_t dst = sB0 + s * B_STG + (arow + p * 64) * ROWB + aj * 16;
            cp_async16(dst, Bs + browoff[p] + k3 + aj * 8, true);
        }
    };

    auto compute = [&](int s) {
        uint32_t aBase = sA0 + s * A_STG + (wr * 64 + (lid & 15)) * ROWB + (lid >> 4) * 16;
        uint32_t bBase = sB0 + s * B_STG
                       + (wc * WN + (lid & 7) + ((lid >> 4) << 3)) * ROWB
                       + ((lid >> 3) & 1) * 16;
        #pragma unroll
        for (int ks = 0; ks < 2; ks++) {
            uint32_t a[4][4], b[NB][4];
            #pragma unroll
            for (int mi = 0; mi < 4; mi++)
                ldsm_x4(aBase + mi * 16 * ROWB + ks * 32, a[mi]);
            #pragma unroll
            for (int bi = 0; bi < NB; bi++)
                ldsm_x4(bBase + bi * 16 * ROWB + ks * 32, b[bi]);
            #pragma unroll
            for (int mi = 0; mi < 4; mi++)
                #pragma unroll
                for (int ni = 0; ni < NI; ni++)
                    mma16816(acc[mi][ni], a[mi],
                             b[ni >> 1][(ni & 1) * 2], b[ni >> 1][(ni & 1) * 2 + 1]);
        }
    };

    #pragma unroll
    for (int p = 0; p < STAGES - 1; p++) { if (p < nk) load_stage(p); CP_COMMIT(); }

    for (int kt = 0; kt < nk; kt++) {
        CP_WAIT(STAGES - 2);
        __syncthreads();
        if (kt + STAGES - 1 < nk) load_stage(kt + STAGES - 1);
        CP_COMMIT();
        compute(kt % STAGES);
    }

    // ------------------------------ epilogue -------------------------------
    int g = lid >> 2, t2 = (lid & 3) * 2;
    #pragma unroll
    for (int mi = 0; mi < 4; mi++) {
        #pragma unroll
        for (int rr = 0; rr < 2; rr++) {
            int m = m0 + wr * 64 + mi * 16 + g + rr * 8;
            size_t orow;
            if (epi == 2) {
                int win = m / NTOK, tok = m % NTOK;
                int b = win >> 6, wi2 = win & 63;
                int hs = (wi2 >> 3) * WS + tok / WS;
                int ws = (wi2 & 7)  * WS + tok % WS;
                int h = hs + SHIFT; if (h >= HH)  h -= HH;
                int w = ws + SHIFT; if (w >= WW_) w -= WW_;
                orow = (size_t)(b * HH + h) * WW_ + w;
            } else {
                orow = (size_t)m;
            }
            #pragma unroll
            for (int ni = 0; ni < NI; ni++) {
                int n = n0 + wc * WN + ni * 8 + t2;
                float v0 = acc[mi][ni][rr * 2 + 0];
                float v1 = acc[mi][ni][rr * 2 + 1];
                if (epi == 0) {
                    float2 o = { v0 + bias[n], v1 + bias[n + 1] };
                    *reinterpret_cast<float2*>(Cf + (size_t)m * N + n) = o;
                } else if (epi == 2) {
                    size_t oi = orow * CCH + n;
                    float2 a4 = *reinterpret_cast<const float2*>(addsrc + oi);
                    float2 o = { v0 + bias[n] + a4.x, v1 + bias[n + 1] + a4.y };
                    *reinterpret_cast<float2*>(Cf + oi) = o;
                } else if (epi == 4) {
                    size_t oi = (size_t)m * CCH + n;
                    float2 a4 = *reinterpret_cast<const float2*>(addsrc + oi);
                    float2 o = { v0 * scale[n] + shiftv[n] + a4.x,
                                 v1 * scale[n + 1] + shiftv[n + 1] + a4.y };
                    *reinterpret_cast<float2*>(Cf + oi) = o;
                } else {  // epi == 5: raw
                    float2 o = { v0, v1 };
                    *reinterpret_cast<float2*>(Cf + (size_t)m * N + n) = o;
                }
            }
        }
    }
}

// ------------------------------- launcher -----------------------------------
extern "C" void kernel_launch(void* const* d_in, const int* in_sizes, int n_in,
                              void* d_out, int out_size)
{
    const float* x         = (const float*)d_in[0];
    const float* ln1_g     = (const float*)d_in[1];
    const float* ln1_b     = (const float*)d_in[2];
    const float* w_qkv     = (const float*)d_in[3];
    const float* b_qkv     = (const float*)d_in[4];
    const float* bias_tbl  = (const float*)d_in[5];
    const float* w_proj    = (const float*)d_in[6];
    const float* b_proj    = (const float*)d_in[7];
    const float* ln2_g     = (const float*)d_in[8];
    const float* ln2_b     = (const float*)d_in[9];
    const float* w_ffn1    = (const float*)d_in[10];
    const float* bn1_scale = (const float*)d_in[11];
    const float* bn1_shift = (const float*)d_in[12];
    const float* w_ffn2    = (const float*)d_in[13];
    const float* bn2_scale = (const float*)d_in[14];
    const float* bn2_shift = (const float*)d_in[15];
    float* out = (float*)d_out;

    __nv_bfloat16 *xw_h, *xw_l, *o_h, *o_l, *h1_h, *h1_l, *wq, *wp, *w2, *U, *Vh, *Vl;
    float *qkv, *xmid, *y, *Mbuf;
    cudaGetSymbolAddress((void**)&xw_h, g_xw_h);  cudaGetSymbolAddress((void**)&xw_l, g_xw_l);
    cudaGetSymbolAddress((void**)&qkv,  g_qkv);
    cudaGetSymbolAddress((void**)&o_h,  g_o_h);   cudaGetSymbolAddress((void**)&o_l,  g_o_l);
    cudaGetSymbolAddress((void**)&xmid, g_xmid);
    cudaGetSymbolAddress((void**)&y,    g_y);
    cudaGetSymbolAddress((void**)&h1_h, g_h1_h);  cudaGetSymbolAddress((void**)&h1_l, g_h1_l);
    cudaGetSymbolAddress((void**)&wq, g_wq); cudaGetSymbolAddress((void**)&wp, g_wp);
    cudaGetSymbolAddress((void**)&w2, g_w2);
    cudaGetSymbolAddress((void**)&U,  g_U);
    cudaGetSymbolAddress((void**)&Vh, g_Vh); cudaGetSymbolAddress((void**)&Vl, g_Vl);
    cudaGetSymbolAddress((void**)&Mbuf, g_M);

    constexpr int SM32 = STAGES * (A_STG + 64 * ROWB);    // 76800
    constexpr int SM64 = STAGES * (A_STG + 128 * ROWB);   // 92160
    cudaFuncSetAttribute(gemm_tc<32>, cudaFuncAttributeMaxDynamicSharedMemorySize, SM32);
    cudaFuncSetAttribute(gemm_tc<64>, cudaFuncAttributeMaxDynamicSharedMemorySize, SM64);

    // 0. weight preps
    prep_w<<<(192 * 576 + 255) / 256, 256>>>(w_qkv, wq, 192, 576);
    prep_w<<<(192 * 192 + 255) / 256, 256>>>(w_proj, wp, 192, 192);
    prep_w<<<(768 * 192 + 255) / 256, 256>>>(w_ffn2, w2, 768, 192);
    wino_wt<<<(CCH * HIDDEN + 255) / 256, 256>>>(w_ffn1, U);

    // 1. LN1 + roll + window partition -> bf16 split
    ln_kernel<<<MROWS, 192>>>(x, ln1_g, ln1_b, xw_h, xw_l, nullptr, 1);

    // 2. QKV GEMM [M,192]x[192,576]
    gemm_tc<32><<<dim3(576 / 64, MROWS / TM), 256, SM32>>>(
        xw_h, xw_l, wq, b_qkv, qkv, nullptr, nullptr, nullptr,
        576, 192, 0, 0, 0, 0);

    // 3. attention -> bf16 split
    attn_kernel<<<(MROWS / NTOK) * HEADS, 128>>>(qkv, bias_tbl, o_h, o_l);

    // 4. proj GEMM + window reverse + roll + shortcut
    gemm_tc<32><<<dim3(192 / 64, MROWS / TM), 256, SM32>>>(
        o_h, o_l, wp, b_proj, xmid, nullptr, nullptr, x,
        192, 192, 2, 0, 0, 0);

    // 5. LN2 -> fp32
    ln_kernel<<<MROWS, 192>>>(xmid, ln2_g, ln2_b, nullptr, nullptr, y, 0);

    // 6a. winograd input transform
    wino_in<<<(NTILE * CCH + 255) / 256, 256>>>(y, Vh, Vl);

    // 6b. 16 batched transform-domain GEMMs [25088,192]x[192,768] -> M
    gemm_tc<64><<<dim3(HIDDEN / 128, NTILE / TM, 16), 256, SM64>>>(
        Vh, Vl, U, nullptr, Mbuf, nullptr, nullptr, nullptr,
        HIDDEN, 192, 5,
        (size_t)NTILE * CCH, (size_t)HIDDEN * 576, (size_t)NTILE * HIDDEN);

    // 6c. winograd output transform + BN + GELU -> h1 hi/lo
    wino_out<<<(NTILE * HIDDEN + 255) / 256, 256>>>(Mbuf, bn1_scale, bn1_shift, h1_h, h1_l);

    // 7. conv1x1 GEMM + BN + residual -> out
    gemm_tc<32><<<dim3(CCH / 64, MROWS / TM), 256, SM32>>>(
        h1_h, h1_l, w2, nullptr, out, bn2_scale, bn2_shift, xmid,
        CCH, HIDDEN, 4, 0, 0, 0);
}

// round 6
// speedup vs baseline: 2.9384x; 1.2488x over previous
#include <cuda_runtime.h>
#include <cuda_bf16.h>
#include <cstdint>
#include <math.h>

// ---------------------------------------------------------------------------
// SwinTransformerLayer on GB300. mma.sync bf16 with fp32-accurate 3-term split
// (C = Ah*Bh + Al*Bh + Ah*Bl, K tripled). Round 6: conv3x3 via Winograd
// F(4x4,3x3) (36 planes, 4x fewer multiplies than direct), warp-per-row LN.
// ---------------------------------------------------------------------------

#define BATCH   32
#define HH      56
#define WW_     56
#define CCH     192
#define WS      7
#define SHIFT   3
#define HEADS   6
#define HD      32
#define NTOK    49
#define MROWS   (BATCH*HH*WW_)   // 100352
#define HIDDEN  768
#define QKSCALE 0.17677669529663687f
#define NT4     6272             // 32 * 14 * 14 winograd F(4,3) tiles
#define NTP     6400             // padded to multiple of 256

#define TM      256
#define TKB     32               // bf16 K per stage
#define STAGES  3
#define ROWB    80               // padded row bytes (40 bf16) — conflict-free ldmatrix
#define A_STG   (TM*ROWB)        // 20480

// ------------------------- scratch (device globals) ------------------------
__device__ __align__(16) __nv_bfloat16 g_xw_h [(size_t)MROWS * CCH];
__device__ __align__(16) __nv_bfloat16 g_xw_l [(size_t)MROWS * CCH];
__device__ __align__(16) float         g_qkv  [(size_t)MROWS * 3 * CCH];
__device__ __align__(16) __nv_bfloat16 g_o_h  [(size_t)MROWS * CCH];
__device__ __align__(16) __nv_bfloat16 g_o_l  [(size_t)MROWS * CCH];
__device__ __align__(16) float         g_xmid [(size_t)MROWS * CCH];
__device__ __align__(16) float         g_y    [(size_t)MROWS * CCH];
__device__ __align__(16) __nv_bfloat16 g_h1_h [(size_t)MROWS * HIDDEN];
__device__ __align__(16) __nv_bfloat16 g_h1_l [(size_t)MROWS * HIDDEN];
// split weights, [N, 3K] K-major bf16
__device__ __align__(16) __nv_bfloat16 g_wq [(size_t)576 * 576];
__device__ __align__(16) __nv_bfloat16 g_wp [(size_t)192 * 576];
__device__ __align__(16) __nv_bfloat16 g_w2 [(size_t)192 * 2304];
// winograd F(4,3): 36 planes
__device__ __align__(16) __nv_bfloat16 g_U  [(size_t)36 * HIDDEN * 576];   // [p][co][3K]
__device__ __align__(16) __nv_bfloat16 g_Vh [(size_t)36 * NTP * CCH];
__device__ __align__(16) __nv_bfloat16 g_Vl [(size_t)36 * NTP * CCH];
__device__ __align__(16) float         g_M  [(size_t)36 * NTP * HIDDEN];   // fp32

// ------------------------------ PTX helpers --------------------------------
__device__ __forceinline__ void cp_async16(uint32_t dst, const void* src, bool full) {
    int sz = full ? 16 : 0;
    asm volatile("cp.async.cg.shared.global [%0], [%1], 16, %2;"
                 :: "r"(dst), "l"(src), "r"(sz) : "memory");
}
#define CP_COMMIT() asm volatile("cp.async.commit_group;" ::: "memory")
#define CP_WAIT(n)  asm volatile("cp.async.wait_group %0;" :: "n"(n) : "memory")

__device__ __forceinline__ void ldsm_x4(uint32_t addr, uint32_t r[4]) {
    asm volatile("ldmatrix.sync.aligned.m8n8.x4.shared.b16 {%0,%1,%2,%3}, [%4];"
                 : "=r"(r[0]), "=r"(r[1]), "=r"(r[2]), "=r"(r[3]) : "r"(addr));
}
__device__ __forceinline__ void mma16816(float c[4], const uint32_t a[4],
                                         uint32_t b0, uint32_t b1) {
    asm volatile("mma.sync.aligned.m16n8k16.row.col.f32.bf16.bf16.f32 "
                 "{%0,%1,%2,%3}, {%4,%5,%6,%7}, {%8,%9}, {%0,%1,%2,%3};"
                 : "+f"(c[0]), "+f"(c[1]), "+f"(c[2]), "+f"(c[3])
                 : "r"(a[0]), "r"(a[1]), "r"(a[2]), "r"(a[3]), "r"(b0), "r"(b1));
}

__device__ __forceinline__ void split_bf16(float v, __nv_bfloat16& hi, __nv_bfloat16& lo) {
    hi = __float2bfloat16(v);
    lo = __float2bfloat16(v - __bfloat162float(hi));
}

// ----------------------------- weight prep ---------------------------------
__global__ void prep_w(const float* __restrict__ W, __nv_bfloat16* __restrict__ D,
                       int K, int N)
{
    int i = blockIdx.x * 256 + threadIdx.x;
    if (i >= K * N) return;
    int k = i / N, n = i % N;
    __nv_bfloat16 hi, lo;
    split_bf16(W[i], hi, lo);
    size_t base = (size_t)n * 3 * K;
    D[base + k]         = hi;   // seg0: pairs Ah
    D[base + K + k]     = hi;   // seg1: pairs Al
    D[base + 2 * K + k] = lo;   // seg2: pairs Ah
}

// ----------------------- winograd weight transform --------------------------
// w_ffn1 [3][3][192][768] HWIO -> U[p][co][3K], p = 6*r + c.  U6 = G g G^T.
// G = [1/4,0,0; -1/6,-1/6,-1/6; -1/6,1/6,-1/6; 1/24,1/12,1/6; 1/24,-1/12,1/6; 0,0,1]
__global__ void wino_wt(const float* __restrict__ W, __nv_bfloat16* __restrict__ U)
{
    int i = blockIdx.x * 256 + threadIdx.x;
    if (i >= CCH * HIDDEN) return;
    int ci = i / HIDDEN, co = i % HIDDEN;

    float g[3][3];
    #pragma unroll
    for (int ky = 0; ky < 3; ky++)
        #pragma unroll
        for (int kx = 0; kx < 3; kx++)
            g[ky][kx] = W[((size_t)(ky * 3 + kx) * CCH + ci) * HIDDEN + co];

    float u[6][3];
    #pragma unroll
    for (int c = 0; c < 3; c++) {
        float g0 = g[0][c], g1 = g[1][c], g2 = g[2][c];
        u[0][c] = 0.25f * g0;
        u[1][c] = -(g0 + g1 + g2) * (1.0f / 6.0f);
        u[2][c] = (-g0 + g1 - g2) * (1.0f / 6.0f);
        u[3][c] = g0 * (1.0f / 24.0f) + g1 * (1.0f / 12.0f) + g2 * (1.0f / 6.0f);
        u[4][c] = g0 * (1.0f / 24.0f) - g1 * (1.0f / 12.0f) + g2 * (1.0f / 6.0f);
        u[5][c] = g2;
    }
    #pragma unroll
    for (int r = 0; r < 6; r++) {
        float a0 = u[r][0], a1 = u[r][1], a2 = u[r][2];
        float U6[6];
        U6[0] = 0.25f * a0;
        U6[1] = -(a0 + a1 + a2) * (1.0f / 6.0f);
        U6[2] = (-a0 + a1 - a2) * (1.0f / 6.0f);
        U6[3] = a0 * (1.0f / 24.0f) + a1 * (1.0f / 12.0f) + a2 * (1.0f / 6.0f);
        U6[4] = a0 * (1.0f / 24.0f) - a1 * (1.0f / 12.0f) + a2 * (1.0f / 6.0f);
        U6[5] = a2;
        #pragma unroll
        for (int c = 0; c < 6; c++) {
            int p = r * 6 + c;
            __nv_bfloat16 hi, lo;
            split_bf16(U6[c], hi, lo);
            size_t base = ((size_t)p * HIDDEN + co) * 576;
            U[base + ci]       = hi;
            U[base + 192 + ci] = hi;
            U[base + 384 + ci] = lo;
        }
    }
}

// ----------------------- winograd input transform ---------------------------
// y [B,56,56,192] fp32 -> V[p][tile][c] bf16 hi/lo.  tile = b*196 + ty*14 + tx
// B^T rows: [4,0,-5,0,1,0; 0,-4,-4,1,1,0; 0,4,-4,-1,1,0; 0,-2,-1,2,1,0;
//            0,2,-1,-2,1,0; 0,4,0,-5,0,1]
__device__ __forceinline__ void bt6(const float d[6], float t[6]) {
    t[0] = 4.f * d[0] - 5.f * d[2] + d[4];
    t[1] = -4.f * d[1] - 4.f * d[2] + d[3] + d[4];
    t[2] = 4.f * d[1] - 4.f * d[2] - d[3] + d[4];
    t[3] = -2.f * d[1] - d[2] + 2.f * d[3] + d[4];
    t[4] = 2.f * d[1] - d[2] - 2.f * d[3] + d[4];
    t[5] = 4.f * d[1] - 5.f * d[3] + d[5];
}

__global__ __launch_bounds__(256)
void wino_in(const float* __restrict__ y,
             __nv_bfloat16* __restrict__ Vh,
             __nv_bfloat16* __restrict__ Vl)
{
    int i = blockIdx.x * 256 + threadIdx.x;
    if (i >= NT4 * CCH) return;
    int tile = i / CCH, c = i % CCH;
    int b = tile / 196, r = tile % 196, ty = r / 14, tx = r % 14;

    float d[6][6];
    #pragma unroll
    for (int ii = 0; ii < 6; ii++) {
        int h = 4 * ty - 1 + ii;
        #pragma unroll
        for (int jj = 0; jj < 6; jj++) {
            int w = 4 * tx - 1 + jj;
            bool ok = (h >= 0) && (h < HH) && (w >= 0) && (w < WW_);
            d[ii][jj] = ok ? y[((size_t)(b * HH + h) * WW_ + w) * CCH + c] : 0.f;
        }
    }
    float t[6][6];
    // columns: t = B^T d
    #pragma unroll
    for (int jj = 0; jj < 6; jj++) {
        float col[6], tc[6];
        #pragma unroll
        for (int ii = 0; ii < 6; ii++) col[ii] = d[ii][jj];
        bt6(col, tc);
        #pragma unroll
        for (int ii = 0; ii < 6; ii++) t[ii][jj] = tc[ii];
    }
    // rows: V = t B
    #pragma unroll
    for (int ii = 0; ii < 6; ii++) {
        float V6[6];
        bt6(t[ii], V6);
        #pragma unroll
        for (int jj = 0; jj < 6; jj++) {
            int p = ii * 6 + jj;
            __nv_bfloat16 hi, lo;
            split_bf16(V6[jj], hi, lo);
            size_t idx = ((size_t)p * NTP + tile) * CCH + c;
            Vh[idx] = hi; Vl[idx] = lo;
        }
    }
}

// ----------------------- winograd output transform --------------------------
// M[p][tile][co] fp32 -> Y 4x4 -> BN+GELU -> h1 hi/lo (pixel layout)
// A^T = [1,1,1,1,1,0; 0,1,-1,2,-2,0; 0,1,1,4,4,0; 0,1,-1,8,-8,1]
__device__ __forceinline__ void at6(const float m[6], float s[4]) {
    s[0] = m[0] + m[1] + m[2] + m[3] + m[4];
    s[1] = m[1] - m[2] + 2.f * m[3] - 2.f * m[4];
    s[2] = m[1] + m[2] + 4.f * m[3] + 4.f * m[4];
    s[3] = m[1] - m[2] + 8.f * m[3] - 8.f * m[4] + m[5];
}

__global__ __launch_bounds__(256)
void wino_out(const float* __restrict__ M,
              const float* __restrict__ scale,
              const float* __restrict__ shiftv,
              __nv_bfloat16* __restrict__ h1h,
              __nv_bfloat16* __restrict__ h1l)
{
    int i = blockIdx.x * 256 + threadIdx.x;
    if (i >= NT4 * HIDDEN) return;
    int tile = i / HIDDEN, co = i % HIDDEN;
    int b = tile / 196, r = tile % 196, ty = r / 14, tx = r % 14;

    float m[6][6];
    #pragma unroll
    for (int p = 0; p < 36; p++)
        m[p / 6][p % 6] = M[((size_t)p * NTP + tile) * HIDDEN + co];

    float s[4][6];
    // columns: s = A^T m
    #pragma unroll
    for (int jj = 0; jj < 6; jj++) {
        float col[6], sc4[4];
        #pragma unroll
        for (int ii = 0; ii < 6; ii++) col[ii] = m[ii][jj];
        at6(col, sc4);
        #pragma unroll
        for (int ii = 0; ii < 4; ii++) s[ii][jj] = sc4[ii];
    }
    float sc = scale[co], sh = shiftv[co];
    #pragma unroll
    for (int ii = 0; ii < 4; ii++) {
        float Y4[4];
        at6(s[ii], Y4);
        #pragma unroll
        for (int jj = 0; jj < 4; jj++) {
            float v = Y4[jj] * sc + sh;
            v = 0.5f * v * (1.0f + erff(v * 0.70710678118654752f));
            __nv_bfloat16 hi, lo;
            split_bf16(v, hi, lo);
            size_t px = (size_t)b * 3136 + (size_t)(4 * ty + ii) * 56 + (4 * tx + jj);
            h1h[px * HIDDEN + co] = hi;
            h1l[px * HIDDEN + co] = lo;
        }
    }
}

// ------------------------------- LayerNorm ---------------------------------
// warp per row, 8 rows/CTA.  out_f32!=null: fp32 out; else bf16 hi/lo split.
__global__ __launch_bounds__(256)
void ln_kernel(const float* __restrict__ x,
               const float* __restrict__ gamma,
               const float* __restrict__ beta,
               __nv_bfloat16* __restrict__ oh,
               __nv_bfloat16* __restrict__ ol,
               float* __restrict__ out_f32,
               int window_mode)
{
    int m = blockIdx.x * 8 + (threadIdx.x >> 5);
    int lane = threadIdx.x & 31;

    int src_p;
    if (window_mode) {
        int win = m / NTOK, tok = m % NTOK;
        int b  = win >> 6, wi = win & 63;
        int hs = (wi >> 3) * WS + tok / WS;
        int ws = (wi & 7)  * WS + tok % WS;
        int h = hs + SHIFT; if (h >= HH)  h -= HH;
        int w = ws + SHIFT; if (w >= WW_) w -= WW_;
        src_p = (b * HH + h) * WW_ + w;
    } else src_p = m;

    const float* src = x + (size_t)src_p * CCH;
    float v[6];
    float s1 = 0.f, s2 = 0.f;
    #pragma unroll
    for (int q = 0; q < 6; q++) {
        v[q] = src[lane + 32 * q];
        s1 += v[q]; s2 += v[q] * v[q];
    }
    #pragma unroll
    for (int o = 16; o > 0; o >>= 1) {
        s1 += __shfl_xor_sync(0xFFFFFFFF, s1, o);
        s2 += __shfl_xor_sync(0xFFFFFFFF, s2, o);
    }
    float mu  = s1 * (1.0f / CCH);
    float var = s2 * (1.0f / CCH) - mu * mu;
    float rs = rsqrtf(var + 1e-3f);

    #pragma unroll
    for (int q = 0; q < 6; q++) {
        int c = lane + 32 * q;
        float yv = (v[q] - mu) * rs * gamma[c] + beta[c];
        if (out_f32) {
            out_f32[(size_t)m * CCH + c] = yv;
        } else {
            __nv_bfloat16 hi, lo; split_bf16(yv, hi, lo);
            oh[(size_t)m * CCH + c] = hi;
            ol[(size_t)m * CCH + c] = lo;
        }
    }
}

// ------------------------------- Attention ---------------------------------
__global__ void attn_kernel(const float* __restrict__ qkv,
                            const float* __restrict__ table,
                            __nv_bfloat16* __restrict__ oh,
                            __nv_bfloat16* __restrict__ ol)
{
    int blk = blockIdx.x;
    int win = blk / HEADS;
    int head = blk % HEADS;
    int tid = threadIdx.x;

    __shared__ float qs[NTOK * HD], ks[NTOK * HD], vs[NTOK * HD];
    __shared__ float S[NTOK * 50];

    for (int t = tid; t < NTOK * HD; t += 128) {
        int n = t >> 5, d = t & 31;
        const float* base = qkv + (size_t)(win * NTOK + n) * (3 * CCH) + head * HD + d;
        qs[t] = base[0] * QKSCALE;
        ks[t] = base[CCH];
        vs[t] = base[2 * CCH];
    }
    __syncthreads();

    int wi = win & 63;
    int wh = wi >> 3, wwn = wi & 7;

    for (int t = tid; t < NTOK * NTOK; t += 128) {
        int n = t / NTOK, mm = t % NTOK;
        float s = 0.f;
        #pragma unroll
        for (int d = 0; d < HD; d++) s += qs[n * HD + d] * ks[mm * HD + d];
        int rn = n / WS, cn = n % WS, rm = mm / WS, cm = mm % WS;
        int idx = (rn - rm + WS - 1) * (2 * WS - 1) + (cn - cm + WS - 1);
        s += table[idx * HEADS + head];
        int hn = wh * WS + rn, wn = wwn * WS + cn;
        int hm = wh * WS + rm, wm = wwn * WS + cm;
        int reg_n = (hn < 49 ? 0 : (hn < 53 ? 1 : 2)) * 3 + (wn < 49 ? 0 : (wn < 53 ? 1 : 2));
        int reg_m = (hm < 49 ? 0 : (hm < 53 ? 1 : 2)) * 3 + (wm < 49 ? 0 : (wm < 53 ? 1 : 2));
        if (reg_n != reg_m) s -= 100.0f;
        S[n * 50 + mm] = s;
    }
    __syncthreads();

    if (tid < NTOK) {
        float mx = -1e30f;
        for (int m2 = 0; m2 < NTOK; m2++) mx = fmaxf(mx, S[tid * 50 + m2]);
        float sum = 0.f;
        for (int m2 = 0; m2 < NTOK; m2++) {
            float e = __expf(S[tid * 50 + m2] - mx);
            S[tid * 50 + m2] = e; sum += e;
        }
        float inv = 1.0f / sum;
        for (int m2 = 0; m2 < NTOK; m2++) S[tid * 50 + m2] *= inv;
    }
    __syncthreads();

    for (int t = tid; t < NTOK * HD; t += 128) {
        int n = t >> 5, d = t & 31;
        float acc = 0.f;
        #pragma unroll 7
        for (int m2 = 0; m2 < NTOK; m2++) acc += S[n * 50 + m2] * vs[m2 * HD + d];
        size_t idx = (size_t)(win * NTOK + n) * CCH + head * HD + d;
        __nv_bfloat16 hi, lo; split_bf16(acc, hi, lo);
        oh[idx] = hi; ol[idx] = lo;
    }
}

// ---------------------------- HMMA GEMM ------------------------------------
// C[M,N] = A'[M,3K] x B'[3K,N], A'=[Ah|Al|Ah] bf16 (implicit), B' prebuilt [N,3K].
// CTA tile 256 x (2*WN), BK=32, 8 warps in 4x2, warp tile 64xWN, mma m16n8k16.
// Batched via blockIdx.z with element strides zsA/zsB/zsC.
// epi: 0=+bias  2=+bias,remap,+addsrc  4=BN,+addsrc  5=raw store
template<int WN>
__global__ __launch_bounds__(256)
void gemm_tc(const __nv_bfloat16* __restrict__ Ah,
             const __nv_bfloat16* __restrict__ Al,
             const __nv_bfloat16* __restrict__ Bs,
             const float* __restrict__ bias,
             float* __restrict__ Cf,
             const float* __restrict__ scale,
             const float* __restrict__ shiftv,
             const float* __restrict__ addsrc,
             int N, int K1, int epi,
             size_t zsA, size_t zsB, size_t zsC)
{
    constexpr int TN   = 2 * WN;
    constexpr int NB   = WN / 16;        // B ldsm per ks
    constexpr int NI   = WN / 8;         // n-fragments per warp
    constexpr int B_STG = TN * ROWB;
    constexpr int BPASS = TN / 64;       // B load passes

    Ah += blockIdx.z * zsA;
    Al += blockIdx.z * zsA;
    Bs += blockIdx.z * zsB;
    Cf += blockIdx.z * zsC;

    extern __shared__ char smem[];
    uint32_t sA0 = (uint32_t)__cvta_generic_to_shared(smem);
    uint32_t sB0 = sA0 + STAGES * A_STG;

    int tid = threadIdx.x;
    int wid = tid >> 5, lid = tid & 31;
    int wr = wid >> 1, wc = wid & 1;
    int m0 = blockIdx.y * TM, n0 = blockIdx.x * TN;
    int K3 = 3 * K1;
    int nk = K3 / TKB;

    int arow = tid >> 2;          // + p*64, p<4
    int aj = tid & 3;             // 16B chunk within 64B row payload
    size_t arowoff[4];
    #pragma unroll
    for (int p = 0; p < 4; p++) arowoff[p] = (size_t)(m0 + arow + p * 64) * K1;
    size_t browoff[BPASS];
    #pragma unroll
    for (int p = 0; p < BPASS; p++)
        browoff[p] = (size_t)(n0 + arow + p * 64) * K3;

    float acc[4][NI][4];
    #pragma unroll
    for (int i = 0; i < 4; i++)
        #pragma unroll
        for (int j = 0; j < NI; j++)
            #pragma unroll
            for (int q = 0; q < 4; q++) acc[i][j][q] = 0.f;

    auto load_stage = [&](int kt) {
        int s = kt % STAGES;
        int k3 = kt * TKB;
        int seg = k3 / K1;
        int kk = k3 - seg * K1;
        const __nv_bfloat16* Asrc = (seg == 1) ? Al : Ah;
        #pragma unroll
        for (int p = 0; p < 4; p++) {
            uint32_t dst = sA0 + s * A_STG + (arow + p * 64) * ROWB + aj * 16;
            cp_async16(dst, Asrc + arowoff[p] + kk + aj * 8, true);
        }
        #pragma unroll
        for (int p = 0; p < BPASS; p++) {
            uint32_t dst = sB0 + s * B_STG + (arow + p * 64) * ROWB + aj * 16;
            cp_async16(dst, Bs + browoff[p] + k3 + aj * 8, true);
        }
    };

    auto compute = [&](int s) {
        uint32_t aBase = sA0 + s * A_STG + (wr * 64 + (lid & 15)) * ROWB + (lid >> 4) * 16;
        uint32_t bBase = sB0 + s * B_STG
                       + (wc * WN + (lid & 7) + ((lid >> 4) << 3)) * ROWB
                       + ((lid >> 3) & 1) * 16;
        #pragma unroll
        for (int ks = 0; ks < 2; ks++) {
            uint32_t a[4][4], b[NB][4];
            #pragma unroll
            for (int mi = 0; mi < 4; mi++)
                ldsm_x4(aBase + mi * 16 * ROWB + ks * 32, a[mi]);
            #pragma unroll
            for (int bi = 0; bi < NB; bi++)
                ldsm_x4(bBase + bi * 16 * ROWB + ks * 32, b[bi]);
            #pragma unroll
            for (int mi = 0; mi < 4; mi++)
                #pragma unroll
                for (int ni = 0; ni < NI; ni++)
                    mma16816(acc[mi][ni], a[mi],
                             b[ni >> 1][(ni & 1) * 2], b[ni >> 1][(ni & 1) * 2 + 1]);
        }
    };

    #pragma unroll
    for (int p = 0; p < STAGES - 1; p++) { if (p < nk) load_stage(p); CP_COMMIT(); }

    for (int kt = 0; kt < nk; kt++) {
        CP_WAIT(STAGES - 2);
        __syncthreads();
        if (kt + STAGES - 1 < nk) load_stage(kt + STAGES - 1);
        CP_COMMIT();
        compute(kt % STAGES);
    }

    // ------------------------------ epilogue -------------------------------
    int g = lid >> 2, t2 = (lid & 3) * 2;
    #pragma unroll
    for (int mi = 0; mi < 4; mi++) {
        #pragma unroll
        for (int rr = 0; rr < 2; rr++) {
            int m = m0 + wr * 64 + mi * 16 + g + rr * 8;
            size_t orow;
            if (epi == 2) {
                int win = m / NTOK, tok = m % NTOK;
                int b = win >> 6, wi2 = win & 63;
                int hs = (wi2 >> 3) * WS + tok / WS;
                int ws = (wi2 & 7)  * WS + tok % WS;
                int h = hs + SHIFT; if (h >= HH)  h -= HH;
                int w = ws + SHIFT; if (w >= WW_) w -= WW_;
                orow = (size_t)(b * HH + h) * WW_ + w;
            } else {
                orow = (size_t)m;
            }
            #pragma unroll
            for (int ni = 0; ni < NI; ni++) {
                int n = n0 + wc * WN + ni * 8 + t2;
                float v0 = acc[mi][ni][rr * 2 + 0];
                float v1 = acc[mi][ni][rr * 2 + 1];
                if (epi == 0) {
                    float2 o = { v0 + bias[n], v1 + bias[n + 1] };
                    *reinterpret_cast<float2*>(Cf + (size_t)m * N + n) = o;
                } else if (epi == 2) {
                    size_t oi = orow * CCH + n;
                    float2 a4 = *reinterpret_cast<const float2*>(addsrc + oi);
                    float2 o = { v0 + bias[n] + a4.x, v1 + bias[n + 1] + a4.y };
                    *reinterpret_cast<float2*>(Cf + oi) = o;
                } else if (epi == 4) {
                    size_t oi = (size_t)m * CCH + n;
                    float2 a4 = *reinterpret_cast<const float2*>(addsrc + oi);
                    float2 o = { v0 * scale[n] + shiftv[n] + a4.x,
                                 v1 * scale[n + 1] + shiftv[n + 1] + a4.y };
                    *reinterpret_cast<float2*>(Cf + oi) = o;
                } else {  // epi == 5: raw
                    float2 o = { v0, v1 };
                    *reinterpret_cast<float2*>(Cf + (size_t)m * N + n) = o;
                }
            }
        }
    }
}

// ------------------------------- launcher -----------------------------------
extern "C" void kernel_launch(void* const* d_in, const int* in_sizes, int n_in,
                              void* d_out, int out_size)
{
    const float* x         = (const float*)d_in[0];
    const float* ln1_g     = (const float*)d_in[1];
    const float* ln1_b     = (const float*)d_in[2];
    const float* w_qkv     = (const float*)d_in[3];
    const float* b_qkv     = (const float*)d_in[4];
    const float* bias_tbl  = (const float*)d_in[5];
    const float* w_proj    = (const float*)d_in[6];
    const float* b_proj    = (const float*)d_in[7];
    const float* ln2_g     = (const float*)d_in[8];
    const float* ln2_b     = (const float*)d_in[9];
    const float* w_ffn1    = (const float*)d_in[10];
    const float* bn1_scale = (const float*)d_in[11];
    const float* bn1_shift = (const float*)d_in[12];
    const float* w_ffn2    = (const float*)d_in[13];
    const float* bn2_scale = (const float*)d_in[14];
    const float* bn2_shift = (const float*)d_in[15];
    float* out = (float*)d_out;

    __nv_bfloat16 *xw_h, *xw_l, *o_h, *o_l, *h1_h, *h1_l, *wq, *wp, *w2, *U, *Vh, *Vl;
    float *qkv, *xmid, *y, *Mbuf;
    cudaGetSymbolAddress((void**)&xw_h, g_xw_h);  cudaGetSymbolAddress((void**)&xw_l, g_xw_l);
    cudaGetSymbolAddress((void**)&qkv,  g_qkv);
    cudaGetSymbolAddress((void**)&o_h,  g_o_h);   cudaGetSymbolAddress((void**)&o_l,  g_o_l);
    cudaGetSymbolAddress((void**)&xmid, g_xmid);
    cudaGetSymbolAddress((void**)&y,    g_y);
    cudaGetSymbolAddress((void**)&h1_h, g_h1_h);  cudaGetSymbolAddress((void**)&h1_l, g_h1_l);
    cudaGetSymbolAddress((void**)&wq, g_wq); cudaGetSymbolAddress((void**)&wp, g_wp);
    cudaGetSymbolAddress((void**)&w2, g_w2);
    cudaGetSymbolAddress((void**)&U,  g_U);
    cudaGetSymbolAddress((void**)&Vh, g_Vh); cudaGetSymbolAddress((void**)&Vl, g_Vl);
    cudaGetSymbolAddress((void**)&Mbuf, g_M);

    constexpr int SM32 = STAGES * (A_STG + 64 * ROWB);    // 76800
    constexpr int SM64 = STAGES * (A_STG + 128 * ROWB);   // 92160
    cudaFuncSetAttribute(gemm_tc<32>, cudaFuncAttributeMaxDynamicSharedMemorySize, SM32);
    cudaFuncSetAttribute(gemm_tc<64>, cudaFuncAttributeMaxDynamicSharedMemorySize, SM64);

    // 0. weight preps
    prep_w<<<(192 * 576 + 255) / 256, 256>>>(w_qkv, wq, 192, 576);
    prep_w<<<(192 * 192 + 255) / 256, 256>>>(w_proj, wp, 192, 192);
    prep_w<<<(768 * 192 + 255) / 256, 256>>>(w_ffn2, w2, 768, 192);
    wino_wt<<<(CCH * HIDDEN + 255) / 256, 256>>>(w_ffn1, U);

    // 1. LN1 + roll + window partition -> bf16 split
    ln_kernel<<<MROWS / 8, 256>>>(x, ln1_g, ln1_b, xw_h, xw_l, nullptr, 1);

    // 2. QKV GEMM [M,192]x[192,576]
    gemm_tc<32><<<dim3(576 / 64, MROWS / TM), 256, SM32>>>(
        xw_h, xw_l, wq, b_qkv, qkv, nullptr, nullptr, nullptr,
        576, 192, 0, 0, 0, 0);

    // 3. attention -> bf16 split
    attn_kernel<<<(MROWS / NTOK) * HEADS, 128>>>(qkv, bias_tbl, o_h, o_l);

    // 4. proj GEMM + window reverse + roll + shortcut
    gemm_tc<32><<<dim3(192 / 64, MROWS / TM), 256, SM32>>>(
        o_h, o_l, wp, b_proj, xmid, nullptr, nullptr, x,
        192, 192, 2, 0, 0, 0);

    // 5. LN2 -> fp32
    ln_kernel<<<MROWS / 8, 256>>>(xmid, ln2_g, ln2_b, nullptr, nullptr, y, 0);

    // 6a. winograd F(4,3) input transform
    wino_in<<<(NT4 * CCH + 255) / 256, 256>>>(y, Vh, Vl);

    // 6b. 36 batched transform-domain GEMMs [6400,192]x[192,768] -> M
    gemm_tc<64><<<dim3(HIDDEN / 128, NTP / TM, 36), 256, SM64>>>(
        Vh, Vl, U, nullptr, Mbuf, nullptr, nullptr, nullptr,
        HIDDEN, 192, 5,
        (size_t)NTP * CCH, (size_t)HIDDEN * 576, (size_t)NTP * HIDDEN);

    // 6c. winograd output transform + BN + GELU -> h1 hi/lo
    wino_out<<<(NT4 * HIDDEN + 255) / 256, 256>>>(Mbuf, bn1_scale, bn1_shift, h1_h, h1_l);

    // 7. conv1x1 GEMM + BN + residual -> out
    gemm_tc<32><<<dim3(CCH / 64, MROWS / TM), 256, SM32>>>(
        h1_h, h1_l, w2, nullptr, out, bn2_scale, bn2_shift, xmid,
        CCH, HIDDEN, 4, 0, 0, 0);
}

// round 7
// speedup vs baseline: 3.3793x; 1.1501x over previous
#include <cuda_runtime.h>
#include <cuda_bf16.h>
#include <cstdint>
#include <math.h>

// ---------------------------------------------------------------------------
// SwinTransformerLayer on GB300. mma.sync bf16 with fp32-accurate 3-term split
// (C = Ah*Bh + Al*Bh + Ah*Bl, K tripled). Winograd F(4x4,3x3) conv3x3.
// Round 7: coalesced wino_wt, warp-parallel softmax, occupancy probe,
// launch order chosen so ncu (-s 5) profiles the proj GEMM.
// ---------------------------------------------------------------------------

#define BATCH   32
#define HH      56
#define WW_     56
#define CCH     192
#define WS      7
#define SHIFT   3
#define HEADS   6
#define HD      32
#define NTOK    49
#define MROWS   (BATCH*HH*WW_)   // 100352
#define HIDDEN  768
#define QKSCALE 0.17677669529663687f
#define NT4     6272             // 32 * 14 * 14 winograd F(4,3) tiles
#define NTP     6400             // padded to multiple of 256

#define TM      256
#define TKB     32               // bf16 K per stage
#define STAGES  3
#define ROWB    80               // padded row bytes (40 bf16) — conflict-free ldmatrix
#define A_STG   (TM*ROWB)        // 20480

// ------------------------- scratch (device globals) ------------------------
__device__ __align__(16) __nv_bfloat16 g_xw_h [(size_t)MROWS * CCH];
__device__ __align__(16) __nv_bfloat16 g_xw_l [(size_t)MROWS * CCH];
__device__ __align__(16) float         g_qkv  [(size_t)MROWS * 3 * CCH];
__device__ __align__(16) __nv_bfloat16 g_o_h  [(size_t)MROWS * CCH];
__device__ __align__(16) __nv_bfloat16 g_o_l  [(size_t)MROWS * CCH];
__device__ __align__(16) float         g_xmid [(size_t)MROWS * CCH];
__device__ __align__(16) float         g_y    [(size_t)MROWS * CCH];
__device__ __align__(16) __nv_bfloat16 g_h1_h [(size_t)MROWS * HIDDEN];
__device__ __align__(16) __nv_bfloat16 g_h1_l [(size_t)MROWS * HIDDEN];
// split weights, [N, 3K] K-major bf16
__device__ __align__(16) __nv_bfloat16 g_wq [(size_t)576 * 576];
__device__ __align__(16) __nv_bfloat16 g_wp [(size_t)192 * 576];
__device__ __align__(16) __nv_bfloat16 g_w2 [(size_t)192 * 2304];
// winograd F(4,3): 36 planes
__device__ __align__(16) __nv_bfloat16 g_U  [(size_t)36 * HIDDEN * 576];   // [p][co][3K]
__device__ __align__(16) __nv_bfloat16 g_Vh [(size_t)36 * NTP * CCH];
__device__ __align__(16) __nv_bfloat16 g_Vl [(size_t)36 * NTP * CCH];
__device__ __align__(16) float         g_M  [(size_t)36 * NTP * HIDDEN];   // fp32

// ------------------------------ PTX helpers --------------------------------
__device__ __forceinline__ void cp_async16(uint32_t dst, const void* src, bool full) {
    int sz = full ? 16 : 0;
    asm volatile("cp.async.cg.shared.global [%0], [%1], 16, %2;"
                 :: "r"(dst), "l"(src), "r"(sz) : "memory");
}
#define CP_COMMIT() asm volatile("cp.async.commit_group;" ::: "memory")
#define CP_WAIT(n)  asm volatile("cp.async.wait_group %0;" :: "n"(n) : "memory")

__device__ __forceinline__ void ldsm_x4(uint32_t addr, uint32_t r[4]) {
    asm volatile("ldmatrix.sync.aligned.m8n8.x4.shared.b16 {%0,%1,%2,%3}, [%4];"
                 : "=r"(r[0]), "=r"(r[1]), "=r"(r[2]), "=r"(r[3]) : "r"(addr));
}
__device__ __forceinline__ void mma16816(float c[4], const uint32_t a[4],
                                         uint32_t b0, uint32_t b1) {
    asm volatile("mma.sync.aligned.m16n8k16.row.col.f32.bf16.bf16.f32 "
                 "{%0,%1,%2,%3}, {%4,%5,%6,%7}, {%8,%9}, {%0,%1,%2,%3};"
                 : "+f"(c[0]), "+f"(c[1]), "+f"(c[2]), "+f"(c[3])
                 : "r"(a[0]), "r"(a[1]), "r"(a[2]), "r"(a[3]), "r"(b0), "r"(b1));
}

__device__ __forceinline__ void split_bf16(float v, __nv_bfloat16& hi, __nv_bfloat16& lo) {
    hi = __float2bfloat16(v);
    lo = __float2bfloat16(v - __bfloat162float(hi));
}

// ----------------------------- weight prep ---------------------------------
__global__ void prep_w(const float* __restrict__ W, __nv_bfloat16* __restrict__ D,
                       int K, int N)
{
    int i = blockIdx.x * 256 + threadIdx.x;
    if (i >= K * N) return;
    int k = i / N, n = i % N;
    __nv_bfloat16 hi, lo;
    split_bf16(W[i], hi, lo);
    size_t base = (size_t)n * 3 * K;
    D[base + k]         = hi;   // seg0: pairs Ah
    D[base + K + k]     = hi;   // seg1: pairs Al
    D[base + 2 * K + k] = lo;   // seg2: pairs Ah
}

// ----------------------- winograd weight transform --------------------------
// w_ffn1 [3][3][192][768] HWIO -> U[p][co][3K], p = 6*r + c.  U6 = G g G^T.
// ci is the fastest index so the bf16 writes coalesce across lanes.
__global__ void wino_wt(const float* __restrict__ W, __nv_bfloat16* __restrict__ U)
{
    int i = blockIdx.x * 256 + threadIdx.x;
    if (i >= CCH * HIDDEN) return;
    int ci = i % CCH, co = i / CCH;

    float g[3][3];
    #pragma unroll
    for (int ky = 0; ky < 3; ky++)
        #pragma unroll
        for (int kx = 0; kx < 3; kx++)
            g[ky][kx] = W[((size_t)(ky * 3 + kx) * CCH + ci) * HIDDEN + co];

    float u[6][3];
    #pragma unroll
    for (int c = 0; c < 3; c++) {
        float g0 = g[0][c], g1 = g[1][c], g2 = g[2][c];
        u[0][c] = 0.25f * g0;
        u[1][c] = -(g0 + g1 + g2) * (1.0f / 6.0f);
        u[2][c] = (-g0 + g1 - g2) * (1.0f / 6.0f);
        u[3][c] = g0 * (1.0f / 24.0f) + g1 * (1.0f / 12.0f) + g2 * (1.0f / 6.0f);
        u[4][c] = g0 * (1.0f / 24.0f) - g1 * (1.0f / 12.0f) + g2 * (1.0f / 6.0f);
        u[5][c] = g2;
    }
    #pragma unroll
    for (int r = 0; r < 6; r++) {
        float a0 = u[r][0], a1 = u[r][1], a2 = u[r][2];
        float U6[6];
        U6[0] = 0.25f * a0;
        U6[1] = -(a0 + a1 + a2) * (1.0f / 6.0f);
        U6[2] = (-a0 + a1 - a2) * (1.0f / 6.0f);
        U6[3] = a0 * (1.0f / 24.0f) + a1 * (1.0f / 12.0f) + a2 * (1.0f / 6.0f);
        U6[4] = a0 * (1.0f / 24.0f) - a1 * (1.0f / 12.0f) + a2 * (1.0f / 6.0f);
        U6[5] = a2;
        #pragma unroll
        for (int c = 0; c < 6; c++) {
            int p = r * 6 + c;
            __nv_bfloat16 hi, lo;
            split_bf16(U6[c], hi, lo);
            size_t base = ((size_t)p * HIDDEN + co) * 576;
            U[base + ci]       = hi;
            U[base + 192 + ci] = hi;
            U[base + 384 + ci] = lo;
        }
    }
}

// ----------------------- winograd input transform ---------------------------
__device__ __forceinline__ void bt6(const float d[6], float t[6]) {
    t[0] = 4.f * d[0] - 5.f * d[2] + d[4];
    t[1] = -4.f * d[1] - 4.f * d[2] + d[3] + d[4];
    t[2] = 4.f * d[1] - 4.f * d[2] - d[3] + d[4];
    t[3] = -2.f * d[1] - d[2] + 2.f * d[3] + d[4];
    t[4] = 2.f * d[1] - d[2] - 2.f * d[3] + d[4];
    t[5] = 4.f * d[1] - 5.f * d[3] + d[5];
}

__global__ __launch_bounds__(256)
void wino_in(const float* __restrict__ y,
             __nv_bfloat16* __restrict__ Vh,
             __nv_bfloat16* __restrict__ Vl)
{
    int i = blockIdx.x * 256 + threadIdx.x;
    if (i >= NT4 * CCH) return;
    int tile = i / CCH, c = i % CCH;
    int b = tile / 196, r = tile % 196, ty = r / 14, tx = r % 14;

    float d[6][6];
    #pragma unroll
    for (int ii = 0; ii < 6; ii++) {
        int h = 4 * ty - 1 + ii;
        #pragma unroll
        for (int jj = 0; jj < 6; jj++) {
            int w = 4 * tx - 1 + jj;
            bool ok = (h >= 0) && (h < HH) && (w >= 0) && (w < WW_);
            d[ii][jj] = ok ? y[((size_t)(b * HH + h) * WW_ + w) * CCH + c] : 0.f;
        }
    }
    float t[6][6];
    #pragma unroll
    for (int jj = 0; jj < 6; jj++) {
        float col[6], tc[6];
        #pragma unroll
        for (int ii = 0; ii < 6; ii++) col[ii] = d[ii][jj];
        bt6(col, tc);
        #pragma unroll
        for (int ii = 0; ii < 6; ii++) t[ii][jj] = tc[ii];
    }
    #pragma unroll
    for (int ii = 0; ii < 6; ii++) {
        float V6[6];
        bt6(t[ii], V6);
        #pragma unroll
        for (int jj = 0; jj < 6; jj++) {
            int p = ii * 6 + jj;
            __nv_bfloat16 hi, lo;
            split_bf16(V6[jj], hi, lo);
            size_t idx = ((size_t)p * NTP + tile) * CCH + c;
            Vh[idx] = hi; Vl[idx] = lo;
        }
    }
}

// ----------------------- winograd output transform --------------------------
__device__ __forceinline__ void at6(const float m[6], float s[4]) {
    s[0] = m[0] + m[1] + m[2] + m[3] + m[4];
    s[1] = m[1] - m[2] + 2.f * m[3] - 2.f * m[4];
    s[2] = m[1] + m[2] + 4.f * m[3] + 4.f * m[4];
    s[3] = m[1] - m[2] + 8.f * m[3] - 8.f * m[4] + m[5];
}

__global__ __launch_bounds__(256)
void wino_out(const float* __restrict__ M,
              const float* __restrict__ scale,
              const float* __restrict__ shiftv,
              __nv_bfloat16* __restrict__ h1h,
              __nv_bfloat16* __restrict__ h1l)
{
    int i = blockIdx.x * 256 + threadIdx.x;
    if (i >= NT4 * HIDDEN) return;
    int tile = i / HIDDEN, co = i % HIDDEN;
    int b = tile / 196, r = tile % 196, ty = r / 14, tx = r % 14;

    float m[6][6];
    #pragma unroll
    for (int p = 0; p < 36; p++)
        m[p / 6][p % 6] = M[((size_t)p * NTP + tile) * HIDDEN + co];

    float s[4][6];
    #pragma unroll
    for (int jj = 0; jj < 6; jj++) {
        float col[6], sc4[4];
        #pragma unroll
        for (int ii = 0; ii < 6; ii++) col[ii] = m[ii][jj];
        at6(col, sc4);
        #pragma unroll
        for (int ii = 0; ii < 4; ii++) s[ii][jj] = sc4[ii];
    }
    float sc = scale[co], sh = shiftv[co];
    #pragma unroll
    for (int ii = 0; ii < 4; ii++) {
        float Y4[4];
        at6(s[ii], Y4);
        #pragma unroll
        for (int jj = 0; jj < 4; jj++) {
            float v = Y4[jj] * sc + sh;
            v = 0.5f * v * (1.0f + erff(v * 0.70710678118654752f));
            __nv_bfloat16 hi, lo;
            split_bf16(v, hi, lo);
            size_t px = (size_t)b * 3136 + (size_t)(4 * ty + ii) * 56 + (4 * tx + jj);
            h1h[px * HIDDEN + co] = hi;
            h1l[px * HIDDEN + co] = lo;
        }
    }
}

// ------------------------------- LayerNorm ---------------------------------
__global__ __launch_bounds__(256)
void ln_kernel(const float* __restrict__ x,
               const float* __restrict__ gamma,
               const float* __restrict__ beta,
               __nv_bfloat16* __restrict__ oh,
               __nv_bfloat16* __restrict__ ol,
               float* __restrict__ out_f32,
               int window_mode)
{
    int m = blockIdx.x * 8 + (threadIdx.x >> 5);
    int lane = threadIdx.x & 31;

    int src_p;
    if (window_mode) {
        int win = m / NTOK, tok = m % NTOK;
        int b  = win >> 6, wi = win & 63;
        int hs = (wi >> 3) * WS + tok / WS;
        int ws = (wi & 7)  * WS + tok % WS;
        int h = hs + SHIFT; if (h >= HH)  h -= HH;
        int w = ws + SHIFT; if (w >= WW_) w -= WW_;
        src_p = (b * HH + h) * WW_ + w;
    } else src_p = m;

    const float* src = x + (size_t)src_p * CCH;
    float v[6];
    float s1 = 0.f, s2 = 0.f;
    #pragma unroll
    for (int q = 0; q < 6; q++) {
        v[q] = src[lane + 32 * q];
        s1 += v[q]; s2 += v[q] * v[q];
    }
    #pragma unroll
    for (int o = 16; o > 0; o >>= 1) {
        s1 += __shfl_xor_sync(0xFFFFFFFF, s1, o);
        s2 += __shfl_xor_sync(0xFFFFFFFF, s2, o);
    }
    float mu  = s1 * (1.0f / CCH);
    float var = s2 * (1.0f / CCH) - mu * mu;
    float rs = rsqrtf(var + 1e-3f);

    #pragma unroll
    for (int q = 0; q < 6; q++) {
        int c = lane + 32 * q;
        float yv = (v[q] - mu) * rs * gamma[c] + beta[c];
        if (out_f32) {
            out_f32[(size_t)m * CCH + c] = yv;
        } else {
            __nv_bfloat16 hi, lo; split_bf16(yv, hi, lo);
            oh[(size_t)m * CCH + c] = hi;
            ol[(size_t)m * CCH + c] = lo;
        }
    }
}

// ------------------------------- Attention ---------------------------------
__global__ void attn_kernel(const float* __restrict__ qkv,
                            const float* __restrict__ table,
                            __nv_bfloat16* __restrict__ oh,
                            __nv_bfloat16* __restrict__ ol)
{
    int blk = blockIdx.x;
    int win = blk / HEADS;
    int head = blk % HEADS;
    int tid = threadIdx.x;

    __shared__ float qs[NTOK * HD], ks[NTOK * HD], vs[NTOK * HD];
    __shared__ float S[NTOK * 50];

    for (int t = tid; t < NTOK * HD; t += 128) {
        int n = t >> 5, d = t & 31;
        const float* base = qkv + (size_t)(win * NTOK + n) * (3 * CCH) + head * HD + d;
        qs[t] = base[0] * QKSCALE;
        ks[t] = base[CCH];
        vs[t] = base[2 * CCH];
    }
    __syncthreads();

    int wi = win & 63;
    int wh = wi >> 3, wwn = wi & 7;

    for (int t = tid; t < NTOK * NTOK; t += 128) {
        int n = t / NTOK, mm = t % NTOK;
        float s = 0.f;
        #pragma unroll
        for (int d = 0; d < HD; d++) s += qs[n * HD + d] * ks[mm * HD + d];
        int rn = n / WS, cn = n % WS, rm = mm / WS, cm = mm % WS;
        int idx = (rn - rm + WS - 1) * (2 * WS - 1) + (cn - cm + WS - 1);
        s += table[idx * HEADS + head];
        int hn = wh * WS + rn, wn = wwn * WS + cn;
        int hm = wh * WS + rm, wm = wwn * WS + cm;
        int reg_n = (hn < 49 ? 0 : (hn < 53 ? 1 : 2)) * 3 + (wn < 49 ? 0 : (wn < 53 ? 1 : 2));
        int reg_m = (hm < 49 ? 0 : (hm < 53 ? 1 : 2)) * 3 + (wm < 49 ? 0 : (wm < 53 ? 1 : 2));
        if (reg_n != reg_m) s -= 100.0f;
        S[n * 50 + mm] = s;
    }
    __syncthreads();

    // warp-per-row softmax (4 warps, shuffle reductions)
    {
        int w4 = tid >> 5, lane = tid & 31;
        for (int row = w4; row < NTOK; row += 4) {
            float* Sr = S + row * 50;
            float mx = -1e30f;
            for (int c = lane; c < NTOK; c += 32) mx = fmaxf(mx, Sr[c]);
            #pragma unroll
            for (int o = 16; o > 0; o >>= 1)
                mx = fmaxf(mx, __shfl_xor_sync(0xFFFFFFFF, mx, o));
            float sum = 0.f;
            for (int c = lane; c < NTOK; c += 32) {
                float e = __expf(Sr[c] - mx);
                Sr[c] = e; sum += e;
            }
            #pragma unroll
            for (int o = 16; o > 0; o >>= 1)
                sum += __shfl_xor_sync(0xFFFFFFFF, sum, o);
            float inv = 1.0f / sum;
            for (int c = lane; c < NTOK; c += 32) Sr[c] *= inv;
        }
    }
    __syncthreads();

    for (int t = tid; t < NTOK * HD; t += 128) {
        int n = t >> 5, d = t & 31;
        float acc = 0.f;
        #pragma unroll 7
        for (int m2 = 0; m2 < NTOK; m2++) acc += S[n * 50 + m2] * vs[m2 * HD + d];
        size_t idx = (size_t)(win * NTOK + n) * CCH + head * HD + d;
        __nv_bfloat16 hi, lo; split_bf16(acc, hi, lo);
        oh[idx] = hi; ol[idx] = lo;
    }
}

// ---------------------------- HMMA GEMM ------------------------------------
// C[M,N] = A'[M,3K] x B'[3K,N], A'=[Ah|Al|Ah] bf16 (implicit), B' prebuilt [N,3K].
// CTA tile 256 x (2*WN), BK=32, 8 warps in 4x2, warp tile 64xWN, mma m16n8k16.
// Batched via blockIdx.z with element strides zsA/zsB/zsC.
// epi: 0=+bias  2=+bias,remap,+addsrc  4=BN,+addsrc  5=raw store
template<int WN, int MINCTA>
__global__ __launch_bounds__(256, MINCTA)
void gemm_tc(const __nv_bfloat16* __restrict__ Ah,
             const __nv_bfloat16* __restrict__ Al,
             const __nv_bfloat16* __restrict__ Bs,
             const float* __restrict__ bias,
             float* __restrict__ Cf,
             const float* __restrict__ scale,
             const float* __restrict__ shiftv,
             const float* __restrict__ addsrc,
             int N, int K1, int epi,
             size_t zsA, size_t zsB, size_t zsC)
{
    constexpr int TN   = 2 * WN;
    constexpr int NB   = WN / 16;        // B ldsm per ks
    constexpr int NI   = WN / 8;         // n-fragments per warp
    constexpr int B_STG = TN * ROWB;
    constexpr int BPASS = TN / 64;       // B load passes

    Ah += blockIdx.z * zsA;
    Al += blockIdx.z * zsA;
    Bs += blockIdx.z * zsB;
    Cf += blockIdx.z * zsC;

    extern __shared__ char smem[];
    uint32_t sA0 = (uint32_t)__cvta_generic_to_shared(smem);
    uint32_t sB0 = sA0 + STAGES * A_STG;

    int tid = threadIdx.x;
    int wid = tid >> 5, lid = tid & 31;
    int wr = wid >> 1, wc = wid & 1;
    int m0 = blockIdx.y * TM, n0 = blockIdx.x * TN;
    int K3 = 3 * K1;
    int nk = K3 / TKB;

    int arow = tid >> 2;          // + p*64, p<4
    int aj = tid & 3;             // 16B chunk within 64B row payload
    size_t arowoff[4];
    #pragma unroll
    for (int p = 0; p < 4; p++) arowoff[p] = (size_t)(m0 + arow + p * 64) * K1;
    size_t browoff[BPASS];
    #pragma unroll
    for (int p = 0; p < BPASS; p++)
        browoff[p] = (size_t)(n0 + arow + p * 64) * K3;

    float acc[4][NI][4];
    #pragma unroll
    for (int i = 0; i < 4; i++)
        #pragma unroll
        for (int j = 0; j < NI; j++)
            #pragma unroll
            for (int q = 0; q < 4; q++) acc[i][j][q] = 0.f;

    auto load_stage = [&](int kt) {
        int s = kt % STAGES;
        int k3 = kt * TKB;
        int seg = k3 / K1;
        int kk = k3 - seg * K1;
        const __nv_bfloat16* Asrc = (seg == 1) ? Al : Ah;
        #pragma unroll
        for (int p = 0; p < 4; p++) {
            uint32_t dst = sA0 + s * A_STG + (arow + p * 64) * ROWB + aj * 16;
            cp_async16(dst, Asrc + arowoff[p] + kk + aj * 8, true);
        }
        #pragma unroll
        for (int p = 0; p < BPASS; p++) {
            uint32_t dst = sB0 + s * B_STG + (arow + p * 64) * ROWB + aj * 16;
            cp_async16(dst, Bs + browoff[p] + k3 + aj * 8, true);
        }
    };

    auto compute = [&](int s) {
        uint32_t aBase = sA0 + s * A_STG + (wr * 64 + (lid & 15)) * ROWB + (lid >> 4) * 16;
        uint32_t bBase = sB0 + s * B_STG
                       + (wc * WN + (lid & 7) + ((lid >> 4) << 3)) * ROWB
                       + ((lid >> 3) & 1) * 16;
        #pragma unroll
        for (int ks = 0; ks < 2; ks++) {
            uint32_t a[4][4], b[NB][4];
            #pragma unroll
            for (int mi = 0; mi < 4; mi++)
                ldsm_x4(aBase + mi * 16 * ROWB + ks * 32, a[mi]);
            #pragma unroll
            for (int bi = 0; bi < NB; bi++)
                ldsm_x4(bBase + bi * 16 * ROWB + ks * 32, b[bi]);
            #pragma unroll
            for (int mi = 0; mi < 4; mi++)
                #pragma unroll
                for (int ni = 0; ni < NI; ni++)
                    mma16816(acc[mi][ni], a[mi],
                             b[ni >> 1][(ni & 1) * 2], b[ni >> 1][(ni & 1) * 2 + 1]);
        }
    };

    #pragma unroll
    for (int p = 0; p < STAGES - 1; p++) { if (p < nk) load_stage(p); CP_COMMIT(); }

    for (int kt = 0; kt < nk; kt++) {
        CP_WAIT(STAGES - 2);
        __syncthreads();
        if (kt + STAGES - 1 < nk) load_stage(kt + STAGES - 1);
        CP_COMMIT();
        compute(kt % STAGES);
    }

    // ------------------------------ epilogue -------------------------------
    int g = lid >> 2, t2 = (lid & 3) * 2;
    #pragma unroll
    for (int mi = 0; mi < 4; mi++) {
        #pragma unroll
        for (int rr = 0; rr < 2; rr++) {
            int m = m0 + wr * 64 + mi * 16 + g + rr * 8;
            size_t orow;
            if (epi == 2) {
                int win = m / NTOK, tok = m % NTOK;
                int b = win >> 6, wi2 = win & 63;
                int hs = (wi2 >> 3) * WS + tok / WS;
                int ws = (wi2 & 7)  * WS + tok % WS;
                int h = hs + SHIFT; if (h >= HH)  h -= HH;
                int w = ws + SHIFT; if (w >= WW_) w -= WW_;
                orow = (size_t)(b * HH + h) * WW_ + w;
            } else {
                orow = (size_t)m;
            }
            #pragma unroll
            for (int ni = 0; ni < NI; ni++) {
                int n = n0 + wc * WN + ni * 8 + t2;
                float v0 = acc[mi][ni][rr * 2 + 0];
                float v1 = acc[mi][ni][rr * 2 + 1];
                if (epi == 0) {
                    float2 o = { v0 + bias[n], v1 + bias[n + 1] };
                    *reinterpret_cast<float2*>(Cf + (size_t)m * N + n) = o;
                } else if (epi == 2) {
                    size_t oi = orow * CCH + n;
                    float2 a4 = *reinterpret_cast<const float2*>(addsrc + oi);
                    float2 o = { v0 + bias[n] + a4.x, v1 + bias[n + 1] + a4.y };
                    *reinterpret_cast<float2*>(Cf + oi) = o;
                } else if (epi == 4) {
                    size_t oi = (size_t)m * CCH + n;
                    float2 a4 = *reinterpret_cast<const float2*>(addsrc + oi);
                    float2 o = { v0 * scale[n] + shiftv[n] + a4.x,
                                 v1 * scale[n + 1] + shiftv[n + 1] + a4.y };
                    *reinterpret_cast<float2*>(Cf + oi) = o;
                } else {  // epi == 5: raw
                    float2 o = { v0, v1 };
                    *reinterpret_cast<float2*>(Cf + (size_t)m * N + n) = o;
                }
            }
        }
    }
}

// ------------------------------- launcher -----------------------------------
extern "C" void kernel_launch(void* const* d_in, const int* in_sizes, int n_in,
                              void* d_out, int out_size)
{
    const float* x         = (const float*)d_in[0];
    const float* ln1_g     = (const float*)d_in[1];
    const float* ln1_b     = (const float*)d_in[2];
    const float* w_qkv     = (const float*)d_in[3];
    const float* b_qkv     = (const float*)d_in[4];
    const float* bias_tbl  = (const float*)d_in[5];
    const float* w_proj    = (const float*)d_in[6];
    const float* b_proj    = (const float*)d_in[7];
    const float* ln2_g     = (const float*)d_in[8];
    const float* ln2_b     = (const float*)d_in[9];
    const float* w_ffn1    = (const float*)d_in[10];
    const float* bn1_scale = (const float*)d_in[11];
    const float* bn1_shift = (const float*)d_in[12];
    const float* w_ffn2    = (const float*)d_in[13];
    const float* bn2_scale = (const float*)d_in[14];
    const float* bn2_shift = (const float*)d_in[15];
    float* out = (float*)d_out;

    __nv_bfloat16 *xw_h, *xw_l, *o_h, *o_l, *h1_h, *h1_l, *wq, *wp, *w2, *U, *Vh, *Vl;
    float *qkv, *xmid, *y, *Mbuf;
    cudaGetSymbolAddress((void**)&xw_h, g_xw_h);  cudaGetSymbolAddress((void**)&xw_l, g_xw_l);
    cudaGetSymbolAddress((void**)&qkv,  g_qkv);
    cudaGetSymbolAddress((void**)&o_h,  g_o_h);   cudaGetSymbolAddress((void**)&o_l,  g_o_l);
    cudaGetSymbolAddress((void**)&xmid, g_xmid);
    cudaGetSymbolAddress((void**)&y,    g_y);
    cudaGetSymbolAddress((void**)&h1_h, g_h1_h);  cudaGetSymbolAddress((void**)&h1_l, g_h1_l);
    cudaGetSymbolAddress((void**)&wq, g_wq); cudaGetSymbolAddress((void**)&wp, g_wp);
    cudaGetSymbolAddress((void**)&w2, g_w2);
    cudaGetSymbolAddress((void**)&U,  g_U);
    cudaGetSymbolAddress((void**)&Vh, g_Vh); cudaGetSymbolAddress((void**)&Vl, g_Vl);
    cudaGetSymbolAddress((void**)&Mbuf, g_M);

    constexpr int SM32 = STAGES * (A_STG + 64 * ROWB);    // 76800
    constexpr int SM64 = STAGES * (A_STG + 128 * ROWB);   // 92160
    cudaFuncSetAttribute((const void*)gemm_tc<32,2>, cudaFuncAttributeMaxDynamicSharedMemorySize, SM32);
    cudaFuncSetAttribute((const void*)gemm_tc<64,1>, cudaFuncAttributeMaxDynamicSharedMemorySize, SM64);

    // launch order puts the proj GEMM at index 5 for ncu (-s 5 -c 1)
    // 0. LN1 + roll + window partition -> bf16 split
    ln_kernel<<<MROWS / 8, 256>>>(x, ln1_g, ln1_b, xw_h, xw_l, nullptr, 1);

    // 1. qkv weight split
    prep_w<<<(192 * 576 + 255) / 256, 256>>>(w_qkv, wq, 192, 576);

    // 2. QKV GEMM [M,192]x[192,576]
    gemm_tc<32,2><<<dim3(576 / 64, MROWS / TM), 256, SM32>>>(
        xw_h, xw_l, wq, b_qkv, qkv, nullptr, nullptr, nullptr,
        576, 192, 0, 0, 0, 0);

    // 3. proj weight split
    prep_w<<<(192 * 192 + 255) / 256, 256>>>(w_proj, wp, 192, 192);

    // 4. attention -> bf16 split
    attn_kernel<<<(MROWS / NTOK) * HEADS, 128>>>(qkv, bias_tbl, o_h, o_l);

    // 5. proj GEMM + window reverse + roll + shortcut   <-- ncu profiles this
    gemm_tc<32,2><<<dim3(192 / 64, MROWS / TM), 256, SM32>>>(
        o_h, o_l, wp, b_proj, xmid, nullptr, nullptr, x,
        192, 192, 2, 0, 0, 0);

    // 6. LN2 -> fp32
    ln_kernel<<<MROWS / 8, 256>>>(xmid, ln2_g, ln2_b, nullptr, nullptr, y, 0);

    // 7. winograd weight transform
    wino_wt<<<(CCH * HIDDEN + 255) / 256, 256>>>(w_ffn1, U);

    // 8. winograd F(4,3) input transform
    wino_in<<<(NT4 * CCH + 255) / 256, 256>>>(y, Vh, Vl);

    // 9. 36 batched transform-domain GEMMs [6400,192]x[192,768] -> M
    gemm_tc<64,1><<<dim3(HIDDEN / 128, NTP / TM, 36), 256, SM64>>>(
        Vh, Vl, U, nullptr, Mbuf, nullptr, nullptr, nullptr,
        HIDDEN, 192, 5,
        (size_t)NTP * CCH, (size_t)HIDDEN * 576, (size_t)NTP * HIDDEN);

    // 10. winograd output transform + BN + GELU -> h1 hi/lo
    wino_out<<<(NT4 * HIDDEN + 255) / 256, 256>>>(Mbuf, bn1_scale, bn1_shift, h1_h, h1_l);

    // 11. conv1x1 weight split
    prep_w<<<(768 * 192 + 255) / 256, 256>>>(w_ffn2, w2, 768, 192);

    // 12. conv1x1 GEMM + BN + residual -> out
    gemm_tc<32,2><<<dim3(CCH / 64, MROWS / TM), 256, SM32>>>(
        h1_h, h1_l, w2, nullptr, out, bn2_scale, bn2_shift, xmid,
        CCH, HIDDEN, 4, 0, 0, 0);
}

// round 8
// speedup vs baseline: 3.7263x; 1.1027x over previous
#include <cuda_runtime.h>
#include <cuda_bf16.h>
#include <cuda_fp16.h>
#include <cstdint>
#include <math.h>

// ---------------------------------------------------------------------------
// SwinTransformerLayer on GB300, mma.sync tensor cores.
// - QKV / proj / conv1x1 GEMMs: fp16 2-term weight split  (A fp16, B=[Bh;Bl],
//   K doubled; computes Ah*B exactly, error = (A-Ah)*B ~ 2^-12)
// - conv3x3: Winograd F(4x4,3x3), transform-domain GEMMs in bf16 3-term split
//   (C = Ah*Bh + Al*Bh + Ah*Bl, K tripled; error ~2^-18 pre-amplification)
// Round 8: fp16 2-term on small GEMMs + 2 CTA/SM on the winograd GEMM.
// ---------------------------------------------------------------------------

#define BATCH   32
#define HH      56
#define WW_     56
#define CCH     192
#define WS      7
#define SHIFT   3
#define HEADS   6
#define HD      32
#define NTOK    49
#define MROWS   (BATCH*HH*WW_)   // 100352
#define HIDDEN  768
#define QKSCALE 0.17677669529663687f
#define NT4     6272             // 32 * 14 * 14 winograd F(4,3) tiles
#define NTP     6400             // padded to multiple of 256

#define TM      256
#define TKB     32               // K elements per stage
#define STAGES  3
#define ROWB    80               // padded row bytes (40 elems) — conflict-free ldmatrix
#define A_STG   (TM*ROWB)        // 20480

// ------------------------- scratch (device globals) ------------------------
__device__ __align__(16) __half        g_xw16 [(size_t)MROWS * CCH];
__device__ __align__(16) float         g_qkv  [(size_t)MROWS * 3 * CCH];
__device__ __align__(16) __half        g_o16  [(size_t)MROWS * CCH];
__device__ __align__(16) float         g_xmid [(size_t)MROWS * CCH];
__device__ __align__(16) float         g_y    [(size_t)MROWS * CCH];
__device__ __align__(16) __half        g_h116 [(size_t)MROWS * HIDDEN];
// fp16 2-term weights, [N, 2K]
__device__ __align__(16) __half        g_wq16 [(size_t)576 * 384];
__device__ __align__(16) __half        g_wp16 [(size_t)192 * 384];
__device__ __align__(16) __half        g_w216 [(size_t)192 * 1536];
// winograd F(4,3): 36 planes, bf16 3-term
__device__ __align__(16) __nv_bfloat16 g_U  [(size_t)36 * HIDDEN * 576];   // [p][co][3K]
__device__ __align__(16) __nv_bfloat16 g_Vh [(size_t)36 * NTP * CCH];
__device__ __align__(16) __nv_bfloat16 g_Vl [(size_t)36 * NTP * CCH];
__device__ __align__(16) float         g_M  [(size_t)36 * NTP * HIDDEN];   // fp32

// ------------------------------ PTX helpers --------------------------------
__device__ __forceinline__ void cp_async16(uint32_t dst, const void* src, bool full) {
    int sz = full ? 16 : 0;
    asm volatile("cp.async.cg.shared.global [%0], [%1], 16, %2;"
                 :: "r"(dst), "l"(src), "r"(sz) : "memory");
}
#define CP_COMMIT() asm volatile("cp.async.commit_group;" ::: "memory")
#define CP_WAIT(n)  asm volatile("cp.async.wait_group %0;" :: "n"(n) : "memory")

__device__ __forceinline__ void ldsm_x4(uint32_t addr, uint32_t r[4]) {
    asm volatile("ldmatrix.sync.aligned.m8n8.x4.shared.b16 {%0,%1,%2,%3}, [%4];"
                 : "=r"(r[0]), "=r"(r[1]), "=r"(r[2]), "=r"(r[3]) : "r"(addr));
}
template<typename T>
__device__ __forceinline__ void mma_any(float c[4], const uint32_t a[4],
                                        uint32_t b0, uint32_t b1);
template<>
__device__ __forceinline__ void mma_any<__nv_bfloat16>(float c[4], const uint32_t a[4],
                                                       uint32_t b0, uint32_t b1) {
    asm volatile("mma.sync.aligned.m16n8k16.row.col.f32.bf16.bf16.f32 "
                 "{%0,%1,%2,%3}, {%4,%5,%6,%7}, {%8,%9}, {%0,%1,%2,%3};"
                 : "+f"(c[0]), "+f"(c[1]), "+f"(c[2]), "+f"(c[3])
                 : "r"(a[0]), "r"(a[1]), "r"(a[2]), "r"(a[3]), "r"(b0), "r"(b1));
}
template<>
__device__ __forceinline__ void mma_any<__half>(float c[4], const uint32_t a[4],
                                                uint32_t b0, uint32_t b1) {
    asm volatile("mma.sync.aligned.m16n8k16.row.col.f32.f16.f16.f32 "
                 "{%0,%1,%2,%3}, {%4,%5,%6,%7}, {%8,%9}, {%0,%1,%2,%3};"
                 : "+f"(c[0]), "+f"(c[1]), "+f"(c[2]), "+f"(c[3])
                 : "r"(a[0]), "r"(a[1]), "r"(a[2]), "r"(a[3]), "r"(b0), "r"(b1));
}

__device__ __forceinline__ void split_bf16(float v, __nv_bfloat16& hi, __nv_bfloat16& lo) {
    hi = __float2bfloat16(v);
    lo = __float2bfloat16(v - __bfloat162float(hi));
}

// ----------------------------- weight prep ---------------------------------
// fp16 2-term: W [K,N] fp32 -> D [N, 2K] fp16: seg0 = Bh, seg1 = Bl.
__global__ void prep_w16(const float* __restrict__ W, __half* __restrict__ D,
                         int K, int N)
{
    int i = blockIdx.x * 256 + threadIdx.x;
    if (i >= K * N) return;
    int k = i / N, n = i % N;
    float w = W[i];
    __half hi = __float2half(w);
    __half lo = __float2half(w - __half2float(hi));
    size_t base = (size_t)n * 2 * K;
    D[base + k]     = hi;
    D[base + K + k] = lo;
}

// ----------------------- winograd weight transform --------------------------
// w_ffn1 [3][3][192][768] HWIO -> U[p][co][3K], p = 6*r + c.  U6 = G g G^T.
__global__ void wino_wt(const float* __restrict__ W, __nv_bfloat16* __restrict__ U)
{
    int i = blockIdx.x * 256 + threadIdx.x;
    if (i >= CCH * HIDDEN) return;
    int ci = i % CCH, co = i / CCH;

    float g[3][3];
    #pragma unroll
    for (int ky = 0; ky < 3; ky++)
        #pragma unroll
        for (int kx = 0; kx < 3; kx++)
            g[ky][kx] = W[((size_t)(ky * 3 + kx) * CCH + ci) * HIDDEN + co];

    float u[6][3];
    #pragma unroll
    for (int c = 0; c < 3; c++) {
        float g0 = g[0][c], g1 = g[1][c], g2 = g[2][c];
        u[0][c] = 0.25f * g0;
        u[1][c] = -(g0 + g1 + g2) * (1.0f / 6.0f);
        u[2][c] = (-g0 + g1 - g2) * (1.0f / 6.0f);
        u[3][c] = g0 * (1.0f / 24.0f) + g1 * (1.0f / 12.0f) + g2 * (1.0f / 6.0f);
        u[4][c] = g0 * (1.0f / 24.0f) - g1 * (1.0f / 12.0f) + g2 * (1.0f / 6.0f);
        u[5][c] = g2;
    }
    #pragma unroll
    for (int r = 0; r < 6; r++) {
        float a0 = u[r][0], a1 = u[r][1], a2 = u[r][2];
        float U6[6];
        U6[0] = 0.25f * a0;
        U6[1] = -(a0 + a1 + a2) * (1.0f / 6.0f);
        U6[2] = (-a0 + a1 - a2) * (1.0f / 6.0f);
        U6[3] = a0 * (1.0f / 24.0f) + a1 * (1.0f / 12.0f) + a2 * (1.0f / 6.0f);
        U6[4] = a0 * (1.0f / 24.0f) - a1 * (1.0f / 12.0f) + a2 * (1.0f / 6.0f);
        U6[5] = a2;
        #pragma unroll
        for (int c = 0; c < 6; c++) {
            int p = r * 6 + c;
            __nv_bfloat16 hi, lo;
            split_bf16(U6[c], hi, lo);
            size_t base = ((size_t)p * HIDDEN + co) * 576;
            U[base + ci]       = hi;
            U[base + 192 + ci] = hi;
            U[base + 384 + ci] = lo;
        }
    }
}

// ----------------------- winograd input transform ---------------------------
__device__ __forceinline__ void bt6(const float d[6], float t[6]) {
    t[0] = 4.f * d[0] - 5.f * d[2] + d[4];
    t[1] = -4.f * d[1] - 4.f * d[2] + d[3] + d[4];
    t[2] = 4.f * d[1] - 4.f * d[2] - d[3] + d[4];
    t[3] = -2.f * d[1] - d[2] + 2.f * d[3] + d[4];
    t[4] = 2.f * d[1] - d[2] - 2.f * d[3] + d[4];
    t[5] = 4.f * d[1] - 5.f * d[3] + d[5];
}

__global__ __launch_bounds__(256)
void wino_in(const float* __restrict__ y,
             __nv_bfloat16* __restrict__ Vh,
             __nv_bfloat16* __restrict__ Vl)
{
    int i = blockIdx.x * 256 + threadIdx.x;
    if (i >= NT4 * CCH) return;
    int tile = i / CCH, c = i % CCH;
    int b = tile / 196, r = tile % 196, ty = r / 14, tx = r % 14;

    float d[6][6];
    #pragma unroll
    for (int ii = 0; ii < 6; ii++) {
        int h = 4 * ty - 1 + ii;
        #pragma unroll
        for (int jj = 0; jj < 6; jj++) {
            int w = 4 * tx - 1 + jj;
            bool ok = (h >= 0) && (h < HH) && (w >= 0) && (w < WW_);
            d[ii][jj] = ok ? y[((size_t)(b * HH + h) * WW_ + w) * CCH + c] : 0.f;
        }
    }
    float t[6][6];
    #pragma unroll
    for (int jj = 0; jj < 6; jj++) {
        float col[6], tc[6];
        #pragma unroll
        for (int ii = 0; ii < 6; ii++) col[ii] = d[ii][jj];
        bt6(col, tc);
        #pragma unroll
        for (int ii = 0; ii < 6; ii++) t[ii][jj] = tc[ii];
    }
    #pragma unroll
    for (int ii = 0; ii < 6; ii++) {
        float V6[6];
        bt6(t[ii], V6);
        #pragma unroll
        for (int jj = 0; jj < 6; jj++) {
            int p = ii * 6 + jj;
            __nv_bfloat16 hi, lo;
            split_bf16(V6[jj], hi, lo);
            size_t idx = ((size_t)p * NTP + tile) * CCH + c;
            Vh[idx] = hi; Vl[idx] = lo;
        }
    }
}

// ----------------------- winograd output transform --------------------------
__device__ __forceinline__ void at6(const float m[6], float s[4]) {
    s[0] = m[0] + m[1] + m[2] + m[3] + m[4];
    s[1] = m[1] - m[2] + 2.f * m[3] - 2.f * m[4];
    s[2] = m[1] + m[2] + 4.f * m[3] + 4.f * m[4];
    s[3] = m[1] - m[2] + 8.f * m[3] - 8.f * m[4] + m[5];
}

__global__ __launch_bounds__(256)
void wino_out(const float* __restrict__ M,
              const float* __restrict__ scale,
              const float* __restrict__ shiftv,
              __half* __restrict__ h116)
{
    int i = blockIdx.x * 256 + threadIdx.x;
    if (i >= NT4 * HIDDEN) return;
    int tile = i / HIDDEN, co = i % HIDDEN;
    int b = tile / 196, r = tile % 196, ty = r / 14, tx = r % 14;

    float m[6][6];
    #pragma unroll
    for (int p = 0; p < 36; p++)
        m[p / 6][p % 6] = M[((size_t)p * NTP + tile) * HIDDEN + co];

    float s[4][6];
    #pragma unroll
    for (int jj = 0; jj < 6; jj++) {
        float col[6], sc4[4];
        #pragma unroll
        for (int ii = 0; ii < 6; ii++) col[ii] = m[ii][jj];
        at6(col, sc4);
        #pragma unroll
        for (int ii = 0; ii < 4; ii++) s[ii][jj] = sc4[ii];
    }
    float sc = scale[co], sh = shiftv[co];
    #pragma unroll
    for (int ii = 0; ii < 4; ii++) {
        float Y4[4];
        at6(s[ii], Y4);
        #pragma unroll
        for (int jj = 0; jj < 4; jj++) {
            float v = Y4[jj] * sc + sh;
            v = 0.5f * v * (1.0f + erff(v * 0.70710678118654752f));
            size_t px = (size_t)b * 3136 + (size_t)(4 * ty + ii) * 56 + (4 * tx + jj);
            h116[px * HIDDEN + co] = __float2half(v);
        }
    }
}

// ------------------------------- LayerNorm ---------------------------------
// warp per row, 8 rows/CTA.  out_f32!=null: fp32 out; else single fp16 out.
__global__ __launch_bounds__(256)
void ln_kernel(const float* __restrict__ x,
               const float* __restrict__ gamma,
               const float* __restrict__ beta,
               __half* __restrict__ out16,
               float* __restrict__ out_f32,
               int window_mode)
{
    int m = blockIdx.x * 8 + (threadIdx.x >> 5);
    int lane = threadIdx.x & 31;

    int src_p;
    if (window_mode) {
        int win = m / NTOK, tok = m % NTOK;
        int b  = win >> 6, wi = win & 63;
        int hs = (wi >> 3) * WS + tok / WS;
        int ws = (wi & 7)  * WS + tok % WS;
        int h = hs + SHIFT; if (h >= HH)  h -= HH;
        int w = ws + SHIFT; if (w >= WW_) w -= WW_;
        src_p = (b * HH + h) * WW_ + w;
    } else src_p = m;

    const float* src = x + (size_t)src_p * CCH;
    float v[6];
    float s1 = 0.f, s2 = 0.f;
    #pragma unroll
    for (int q = 0; q < 6; q++) {
        v[q] = src[lane + 32 * q];
        s1 += v[q]; s2 += v[q] * v[q];
    }
    #pragma unroll
    for (int o = 16; o > 0; o >>= 1) {
        s1 += __shfl_xor_sync(0xFFFFFFFF, s1, o);
        s2 += __shfl_xor_sync(0xFFFFFFFF, s2, o);
    }
    float mu  = s1 * (1.0f / CCH);
    float var = s2 * (1.0f / CCH) - mu * mu;
    float rs = rsqrtf(var + 1e-3f);

    #pragma unroll
    for (int q = 0; q < 6; q++) {
        int c = lane + 32 * q;
        float yv = (v[q] - mu) * rs * gamma[c] + beta[c];
        if (out_f32) out_f32[(size_t)m * CCH + c] = yv;
        else         out16[(size_t)m * CCH + c] = __float2half(yv);
    }
}

// ------------------------------- Attention ---------------------------------
__global__ void attn_kernel(const float* __restrict__ qkv,
                            const float* __restrict__ table,
                            __half* __restrict__ o16)
{
    int blk = blockIdx.x;
    int win = blk / HEADS;
    int head = blk % HEADS;
    int tid = threadIdx.x;

    __shared__ float qs[NTOK * HD], ks[NTOK * HD], vs[NTOK * HD];
    __shared__ float S[NTOK * 50];

    for (int t = tid; t < NTOK * HD; t += 128) {
        int n = t >> 5, d = t & 31;
        const float* base = qkv + (size_t)(win * NTOK + n) * (3 * CCH) + head * HD + d;
        qs[t] = base[0] * QKSCALE;
        ks[t] = base[CCH];
        vs[t] = base[2 * CCH];
    }
    __syncthreads();

    int wi = win & 63;
    int wh = wi >> 3, wwn = wi & 7;

    for (int t = tid; t < NTOK * NTOK; t += 128) {
        int n = t / NTOK, mm = t % NTOK;
        float s = 0.f;
        #pragma unroll
        for (int d = 0; d < HD; d++) s += qs[n * HD + d] * ks[mm * HD + d];
        int rn = n / WS, cn = n % WS, rm = mm / WS, cm = mm % WS;
        int idx = (rn - rm + WS - 1) * (2 * WS - 1) + (cn - cm + WS - 1);
        s += table[idx * HEADS + head];
        int hn = wh * WS + rn, wn = wwn * WS + cn;
        int hm = wh * WS + rm, wm = wwn * WS + cm;
        int reg_n = (hn < 49 ? 0 : (hn < 53 ? 1 : 2)) * 3 + (wn < 49 ? 0 : (wn < 53 ? 1 : 2));
        int reg_m = (hm < 49 ? 0 : (hm < 53 ? 1 : 2)) * 3 + (wm < 49 ? 0 : (wm < 53 ? 1 : 2));
        if (reg_n != reg_m) s -= 100.0f;
        S[n * 50 + mm] = s;
    }
    __syncthreads();

    // warp-per-row softmax
    {
        int w4 = tid >> 5, lane = tid & 31;
        for (int row = w4; row < NTOK; row += 4) {
            float* Sr = S + row * 50;
            float mx = -1e30f;
            for (int c = lane; c < NTOK; c += 32) mx = fmaxf(mx, Sr[c]);
            #pragma unroll
            for (int o = 16; o > 0; o >>= 1)
                mx = fmaxf(mx, __shfl_xor_sync(0xFFFFFFFF, mx, o));
            float sum = 0.f;
            for (int c = lane; c < NTOK; c += 32) {
                float e = __expf(Sr[c] - mx);
                Sr[c] = e; sum += e;
            }
            #pragma unroll
            for (int o = 16; o > 0; o >>= 1)
                sum += __shfl_xor_sync(0xFFFFFFFF, sum, o);
            float inv = 1.0f / sum;
            for (int c = lane; c < NTOK; c += 32) Sr[c] *= inv;
        }
    }
    __syncthreads();

    for (int t = tid; t < NTOK * HD; t += 128) {
        int n = t >> 5, d = t & 31;
        float acc = 0.f;
        #pragma unroll 7
        for (int m2 = 0; m2 < NTOK; m2++) acc += S[n * 50 + m2] * vs[m2 * HD + d];
        size_t idx = (size_t)(win * NTOK + n) * CCH + head * HD + d;
        o16[idx] = __float2half(acc);
    }
}

// ---------------------------- HMMA GEMM ------------------------------------
// SPLIT=3 (bf16): C = A'[M,3K] x B'[3K,N], A' = [Ah|Al|Ah] (Al separate buffer).
// SPLIT=2 (fp16): C = Ah[M,K] x (Bh+Bl) via B'=[Bh;Bl], A repeated over segs.
// CTA tile 256 x (2*WN), BK=32, 8 warps in 4x2, warp tile 64xWN, mma m16n8k16.
// Batched via blockIdx.z with element strides zsA/zsB/zsC.
// epi: 0=+bias  2=+bias,remap,+addsrc  4=BN,+addsrc  5=raw store
template<int WN, int MINCTA, int SPLIT, typename T>
__global__ __launch_bounds__(256, MINCTA)
void gemm_tc(const T* __restrict__ Ah,
             const T* __restrict__ Al,
             const T* __restrict__ Bs,
             const float* __restrict__ bias,
             float* __restrict__ Cf,
             const float* __restrict__ scale,
             const float* __restrict__ shiftv,
             const float* __restrict__ addsrc,
             int N, int K1, int epi,
             size_t zsA, size_t zsB, size_t zsC)
{
    constexpr int TN   = 2 * WN;
    constexpr int NB   = WN / 16;        // B ldsm per ks
    constexpr int NI   = WN / 8;         // n-fragments per warp
    constexpr int B_STG = TN * ROWB;
    constexpr int BPASS = TN / 64;       // B load passes

    Ah += blockIdx.z * zsA;
    Al += blockIdx.z * zsA;
    Bs += blockIdx.z * zsB;
    Cf += blockIdx.z * zsC;

    extern __shared__ char smem[];
    uint32_t sA0 = (uint32_t)__cvta_generic_to_shared(smem);
    uint32_t sB0 = sA0 + STAGES * A_STG;

    int tid = threadIdx.x;
    int wid = tid >> 5, lid = tid & 31;
    int wr = wid >> 1, wc = wid & 1;
    int m0 = blockIdx.y * TM, n0 = blockIdx.x * TN;
    int KS = SPLIT * K1;
    int nk = KS / TKB;

    int arow = tid >> 2;          // + p*64, p<4
    int aj = tid & 3;             // 16B chunk within 64B row payload
    size_t arowoff[4];
    #pragma unroll
    for (int p = 0; p < 4; p++) arowoff[p] = (size_t)(m0 + arow + p * 64) * K1;
    size_t browoff[BPASS];
    #pragma unroll
    for (int p = 0; p < BPASS; p++)
        browoff[p] = (size_t)(n0 + arow + p * 64) * KS;

    float acc[4][NI][4];
    #pragma unroll
    for (int i = 0; i < 4; i++)
        #pragma unroll
        for (int j = 0; j < NI; j++)
            #pragma unroll
            for (int q = 0; q < 4; q++) acc[i][j][q] = 0.f;

    auto load_stage = [&](int kt) {
        int s = kt % STAGES;
        int k3 = kt * TKB;
        int seg = k3 / K1;
        int kk = k3 - seg * K1;
        const T* Asrc = (SPLIT == 3 && seg == 1) ? Al : Ah;
        #pragma unroll
        for (int p = 0; p < 4; p++) {
            uint32_t dst = sA0 + s * A_STG + (arow + p * 64) * ROWB + aj * 16;
            cp_async16(dst, Asrc + arowoff[p] + kk + aj * 8, true);
        }
        #pragma unroll
        for (int p = 0; p < BPASS; p++) {
            uint32_t dst = sB0 + s * B_STG + (arow + p * 64) * ROWB + aj * 16;
            cp_async16(dst, Bs + browoff[p] + k3 + aj * 8, true);
        }
    };

    auto compute = [&](int s) {
        uint32_t aBase = sA0 + s * A_STG + (wr * 64 + (lid & 15)) * ROWB + (lid >> 4) * 16;
        uint32_t bBase = sB0 + s * B_STG
                       + (wc * WN + (lid & 7) + ((lid >> 4) << 3)) * ROWB
                       + ((lid >> 3) & 1) * 16;
        #pragma unroll
        for (int ks = 0; ks < 2; ks++) {
            uint32_t a[4][4], b[NB][4];
            #pragma unroll
            for (int mi = 0; mi < 4; mi++)
                ldsm_x4(aBase + mi * 16 * ROWB + ks * 32, a[mi]);
            #pragma unroll
            for (int bi = 0; bi < NB; bi++)
                ldsm_x4(bBase + bi * 16 * ROWB + ks * 32, b[bi]);
            #pragma unroll
            for (int mi = 0; mi < 4; mi++)
                #pragma unroll
                for (int ni = 0; ni < NI; ni++)
                    mma_any<T>(acc[mi][ni], a[mi],
                               b[ni >> 1][(ni & 1) * 2], b[ni >> 1][(ni & 1) * 2 + 1]);
        }
    };

    #pragma unroll
    for (int p = 0; p < STAGES - 1; p++) { if (p < nk) load_stage(p); CP_COMMIT(); }

    for (int kt = 0; kt < nk; kt++) {
        CP_WAIT(STAGES - 2);
        __syncthreads();
        if (kt + STAGES - 1 < nk) load_stage(kt + STAGES - 1);
        CP_COMMIT();
        compute(kt % STAGES);
    }

    // ------------------------------ epilogue -------------------------------
    int g = lid >> 2, t2 = (lid & 3) * 2;
    #pragma unroll
    for (int mi = 0; mi < 4; mi++) {
        #pragma unroll
        for (int rr = 0; rr < 2; rr++) {
            int m = m0 + wr * 64 + mi * 16 + g + rr * 8;
            size_t orow;
            if (epi == 2) {
                int win = m / NTOK, tok = m % NTOK;
                int b = win >> 6, wi2 = win & 63;
                int hs = (wi2 >> 3) * WS + tok / WS;
                int ws = (wi2 & 7)  * WS + tok % WS;
                int h = hs + SHIFT; if (h >= HH)  h -= HH;
                int w = ws + SHIFT; if (w >= WW_) w -= WW_;
                orow = (size_t)(b * HH + h) * WW_ + w;
            } else {
                orow = (size_t)m;
            }
            #pragma unroll
            for (int ni = 0; ni < NI; ni++) {
                int n = n0 + wc * WN + ni * 8 + t2;
                float v0 = acc[mi][ni][rr * 2 + 0];
                float v1 = acc[mi][ni][rr * 2 + 1];
                if (epi == 0) {
                    float2 o = { v0 + bias[n], v1 + bias[n + 1] };
                    *reinterpret_cast<float2*>(Cf + (size_t)m * N + n) = o;
                } else if (epi == 2) {
                    size_t oi = orow * CCH + n;
                    float2 a4 = *reinterpret_cast<const float2*>(addsrc + oi);
                    float2 o = { v0 + bias[n] + a4.x, v1 + bias[n + 1] + a4.y };
                    *reinterpret_cast<float2*>(Cf + oi) = o;
                } else if (epi == 4) {
                    size_t oi = (size_t)m * CCH + n;
                    float2 a4 = *reinterpret_cast<const float2*>(addsrc + oi);
                    float2 o = { v0 * scale[n] + shiftv[n] + a4.x,
                                 v1 * scale[n + 1] + shiftv[n + 1] + a4.y };
                    *reinterpret_cast<float2*>(Cf + oi) = o;
                } else {  // epi == 5: raw
                    float2 o = { v0, v1 };
                    *reinterpret_cast<float2*>(Cf + (size_t)m * N + n) = o;
                }
            }
        }
    }
}

// ------------------------------- launcher -----------------------------------
extern "C" void kernel_launch(void* const* d_in, const int* in_sizes, int n_in,
                              void* d_out, int out_size)
{
    const float* x         = (const float*)d_in[0];
    const float* ln1_g     = (const float*)d_in[1];
    const float* ln1_b     = (const float*)d_in[2];
    const float* w_qkv     = (const float*)d_in[3];
    const float* b_qkv     = (const float*)d_in[4];
    const float* bias_tbl  = (const float*)d_in[5];
    const float* w_proj    = (const float*)d_in[6];
    const float* b_proj    = (const float*)d_in[7];
    const float* ln2_g     = (const float*)d_in[8];
    const float* ln2_b     = (const float*)d_in[9];
    const float* w_ffn1    = (const float*)d_in[10];
    const float* bn1_scale = (const float*)d_in[11];
    const float* bn1_shift = (const float*)d_in[12];
    const float* w_ffn2    = (const float*)d_in[13];
    const float* bn2_scale = (const float*)d_in[14];
    const float* bn2_shift = (const float*)d_in[15];
    float* out = (float*)d_out;

    __half *xw16, *o16, *h116, *wq16, *wp16, *w216;
    __nv_bfloat16 *U, *Vh, *Vl;
    float *qkv, *xmid, *y, *Mbuf;
    cudaGetSymbolAddress((void**)&xw16, g_xw16);
    cudaGetSymbolAddress((void**)&qkv,  g_qkv);
    cudaGetSymbolAddress((void**)&o16,  g_o16);
    cudaGetSymbolAddress((void**)&xmid, g_xmid);
    cudaGetSymbolAddress((void**)&y,    g_y);
    cudaGetSymbolAddress((void**)&h116, g_h116);
    cudaGetSymbolAddress((void**)&wq16, g_wq16);
    cudaGetSymbolAddress((void**)&wp16, g_wp16);
    cudaGetSymbolAddress((void**)&w216, g_w216);
    cudaGetSymbolAddress((void**)&U,  g_U);
    cudaGetSymbolAddress((void**)&Vh, g_Vh); cudaGetSymbolAddress((void**)&Vl, g_Vl);
    cudaGetSymbolAddress((void**)&Mbuf, g_M);

    constexpr int SM32 = STAGES * (A_STG + 64 * ROWB);    // 76800
    cudaFuncSetAttribute((const void*)gemm_tc<32,2,2,__half>,
                         cudaFuncAttributeMaxDynamicSharedMemorySize, SM32);
    cudaFuncSetAttribute((const void*)gemm_tc<32,2,3,__nv_bfloat16>,
                         cudaFuncAttributeMaxDynamicSharedMemorySize, SM32);

    // 0-3: weight preps
    prep_w16<<<(192 * 576 + 255) / 256, 256>>>(w_qkv, wq16, 192, 576);
    prep_w16<<<(192 * 192 + 255) / 256, 256>>>(w_proj, wp16, 192, 192);
    prep_w16<<<(768 * 192 + 255) / 256, 256>>>(w_ffn2, w216, 768, 192);
    wino_wt<<<(CCH * HIDDEN + 255) / 256, 256>>>(w_ffn1, U);

    // 4. LN1 + roll + window partition -> fp16
    ln_kernel<<<MROWS / 8, 256>>>(x, ln1_g, ln1_b, xw16, nullptr, 1);

    // 5. QKV GEMM [M,192]x[192,576] fp16 2-term   <-- ncu (-s 5 -c 1)
    gemm_tc<32,2,2,__half><<<dim3(576 / 64, MROWS / TM), 256, SM32>>>(
        xw16, xw16, wq16, b_qkv, qkv, nullptr, nullptr, nullptr,
        576, 192, 0, 0, 0, 0);

    // 6. attention -> fp16
    attn_kernel<<<(MROWS / NTOK) * HEADS, 128>>>(qkv, bias_tbl, o16);

    // 7. proj GEMM + window reverse + roll + shortcut
    gemm_tc<32,2,2,__half><<<dim3(192 / 64, MROWS / TM), 256, SM32>>>(
        o16, o16, wp16, b_proj, xmid, nullptr, nullptr, x,
        192, 192, 2, 0, 0, 0);

    // 8. LN2 -> fp32
    ln_kernel<<<MROWS / 8, 256>>>(xmid, ln2_g, ln2_b, nullptr, y, 0);

    // 9. winograd F(4,3) input transform
    wino_in<<<(NT4 * CCH + 255) / 256, 256>>>(y, Vh, Vl);

    // 10. 36 batched transform-domain GEMMs [6400,192]x[192,768] -> M (bf16 3-term)
    gemm_tc<32,2,3,__nv_bfloat16><<<dim3(HIDDEN / 64, NTP / TM, 36), 256, SM32>>>(
        Vh, Vl, U, nullptr, Mbuf, nullptr, nullptr, nullptr,
        HIDDEN, 192, 5,
        (size_t)NTP * CCH, (size_t)HIDDEN * 576, (size_t)NTP * HIDDEN);

    // 11. winograd output transform + BN + GELU -> h1 fp16
    wino_out<<<(NT4 * HIDDEN + 255) / 256, 256>>>(Mbuf, bn1_scale, bn1_shift, h116);

    // 12. conv1x1 GEMM + BN + residual -> out (fp16 2-term)
    gemm_tc<32,2,2,__half><<<dim3(CCH / 64, MROWS / TM), 256, SM32>>>(
        h116, h116, w216, nullptr, out, bn2_scale, bn2_shift, xmid,
        CCH, 768, 4, 0, 0, 0);
}

// round 9
// speedup vs baseline: 3.7870x; 1.0163x over previous
#include <cuda_runtime.h>
#include <cuda_bf16.h>
#include <cuda_fp16.h>
#include <cstdint>
#include <math.h>

// ---------------------------------------------------------------------------
// SwinTransformerLayer on GB300, mma.sync tensor cores.
// - QKV / proj GEMMs: plain fp16 (error diluted by residual shortcut)
// - conv1x1 GEMM: fp16 2-term weight split (B=[Bh;Bl], K doubled)
// - conv3x3: Winograd F(4x4,3x3), transform GEMMs in bf16 3-term split
// Round 9: 1-term fp16 qkv/proj, fp16 qkv activations, 4-stage pipeline.
// ---------------------------------------------------------------------------

#define BATCH   32
#define HH      56
#define WW_     56
#define CCH     192
#define WS      7
#define SHIFT   3
#define HEADS   6
#define HD      32
#define NTOK    49
#define MROWS   (BATCH*HH*WW_)   // 100352
#define HIDDEN  768
#define QKSCALE 0.17677669529663687f
#define NT4     6272             // 32 * 14 * 14 winograd F(4,3) tiles
#define NTP     6400             // padded to multiple of 256

#define TM      256
#define TKB     32               // K elements per stage
#define STAGES  4
#define ROWB    80               // padded row bytes (40 elems) — conflict-free ldmatrix
#define A_STG   (TM*ROWB)        // 20480

// ------------------------- scratch (device globals) ------------------------
__device__ __align__(16) __half        g_xw16 [(size_t)MROWS * CCH];
__device__ __align__(16) __half        g_qkv16[(size_t)MROWS * 3 * CCH];
__device__ __align__(16) __half        g_o16  [(size_t)MROWS * CCH];
__device__ __align__(16) float         g_xmid [(size_t)MROWS * CCH];
__device__ __align__(16) float         g_y    [(size_t)MROWS * CCH];
__device__ __align__(16) __half        g_h116 [(size_t)MROWS * HIDDEN];
// fp16 weights: qkv/proj 1-term [N,K]; conv1x1 2-term [N,2K]
__device__ __align__(16) __half        g_wq16 [(size_t)576 * 192];
__device__ __align__(16) __half        g_wp16 [(size_t)192 * 192];
__device__ __align__(16) __half        g_w216 [(size_t)192 * 1536];
// winograd F(4,3): 36 planes, bf16 3-term
__device__ __align__(16) __nv_bfloat16 g_U  [(size_t)36 * HIDDEN * 576];   // [p][co][3K]
__device__ __align__(16) __nv_bfloat16 g_Vh [(size_t)36 * NTP * CCH];
__device__ __align__(16) __nv_bfloat16 g_Vl [(size_t)36 * NTP * CCH];
__device__ __align__(16) float         g_M  [(size_t)36 * NTP * HIDDEN];   // fp32

// ------------------------------ PTX helpers --------------------------------
__device__ __forceinline__ void cp_async16(uint32_t dst, const void* src, bool full) {
    int sz = full ? 16 : 0;
    asm volatile("cp.async.cg.shared.global [%0], [%1], 16, %2;"
                 :: "r"(dst), "l"(src), "r"(sz) : "memory");
}
#define CP_COMMIT() asm volatile("cp.async.commit_group;" ::: "memory")
#define CP_WAIT(n)  asm volatile("cp.async.wait_group %0;" :: "n"(n) : "memory")

__device__ __forceinline__ void ldsm_x4(uint32_t addr, uint32_t r[4]) {
    asm volatile("ldmatrix.sync.aligned.m8n8.x4.shared.b16 {%0,%1,%2,%3}, [%4];"
                 : "=r"(r[0]), "=r"(r[1]), "=r"(r[2]), "=r"(r[3]) : "r"(addr));
}
template<typename T>
__device__ __forceinline__ void mma_any(float c[4], const uint32_t a[4],
                                        uint32_t b0, uint32_t b1);
template<>
__device__ __forceinline__ void mma_any<__nv_bfloat16>(float c[4], const uint32_t a[4],
                                                       uint32_t b0, uint32_t b1) {
    asm volatile("mma.sync.aligned.m16n8k16.row.col.f32.bf16.bf16.f32 "
                 "{%0,%1,%2,%3}, {%4,%5,%6,%7}, {%8,%9}, {%0,%1,%2,%3};"
                 : "+f"(c[0]), "+f"(c[1]), "+f"(c[2]), "+f"(c[3])
                 : "r"(a[0]), "r"(a[1]), "r"(a[2]), "r"(a[3]), "r"(b0), "r"(b1));
}
template<>
__device__ __forceinline__ void mma_any<__half>(float c[4], const uint32_t a[4],
                                                uint32_t b0, uint32_t b1) {
    asm volatile("mma.sync.aligned.m16n8k16.row.col.f32.f16.f16.f32 "
                 "{%0,%1,%2,%3}, {%4,%5,%6,%7}, {%8,%9}, {%0,%1,%2,%3};"
                 : "+f"(c[0]), "+f"(c[1]), "+f"(c[2]), "+f"(c[3])
                 : "r"(a[0]), "r"(a[1]), "r"(a[2]), "r"(a[3]), "r"(b0), "r"(b1));
}

__device__ __forceinline__ void split_bf16(float v, __nv_bfloat16& hi, __nv_bfloat16& lo) {
    hi = __float2bfloat16(v);
    lo = __float2bfloat16(v - __bfloat162float(hi));
}

// ----------------------------- weight prep ---------------------------------
// TERMS=1: W [K,N] fp32 -> D [N,K] fp16 (plain).
// TERMS=2: W [K,N] fp32 -> D [N,2K] fp16: seg0 = Bh, seg1 = Bl.
template<int TERMS>
__global__ void prep_w16(const float* __restrict__ W, __half* __restrict__ D,
                         int K, int N)
{
    int i = blockIdx.x * 256 + threadIdx.x;
    if (i >= K * N) return;
    int k = i / N, n = i % N;
    float w = W[i];
    __half hi = __float2half(w);
    if (TERMS == 1) {
        D[(size_t)n * K + k] = hi;
    } else {
        __half lo = __float2half(w - __half2float(hi));
        size_t base = (size_t)n * 2 * K;
        D[base + k]     = hi;
        D[base + K + k] = lo;
    }
}

// ----------------------- winograd weight transform --------------------------
__global__ void wino_wt(const float* __restrict__ W, __nv_bfloat16* __restrict__ U)
{
    int i = blockIdx.x * 256 + threadIdx.x;
    if (i >= CCH * HIDDEN) return;
    int ci = i % CCH, co = i / CCH;

    float g[3][3];
    #pragma unroll
    for (int ky = 0; ky < 3; ky++)
        #pragma unroll
        for (int kx = 0; kx < 3; kx++)
            g[ky][kx] = W[((size_t)(ky * 3 + kx) * CCH + ci) * HIDDEN + co];

    float u[6][3];
    #pragma unroll
    for (int c = 0; c < 3; c++) {
        float g0 = g[0][c], g1 = g[1][c], g2 = g[2][c];
        u[0][c] = 0.25f * g0;
        u[1][c] = -(g0 + g1 + g2) * (1.0f / 6.0f);
        u[2][c] = (-g0 + g1 - g2) * (1.0f / 6.0f);
        u[3][c] = g0 * (1.0f / 24.0f) + g1 * (1.0f / 12.0f) + g2 * (1.0f / 6.0f);
        u[4][c] = g0 * (1.0f / 24.0f) - g1 * (1.0f / 12.0f) + g2 * (1.0f / 6.0f);
        u[5][c] = g2;
    }
    #pragma unroll
    for (int r = 0; r < 6; r++) {
        float a0 = u[r][0], a1 = u[r][1], a2 = u[r][2];
        float U6[6];
        U6[0] = 0.25f * a0;
        U6[1] = -(a0 + a1 + a2) * (1.0f / 6.0f);
        U6[2] = (-a0 + a1 - a2) * (1.0f / 6.0f);
        U6[3] = a0 * (1.0f / 24.0f) + a1 * (1.0f / 12.0f) + a2 * (1.0f / 6.0f);
        U6[4] = a0 * (1.0f / 24.0f) - a1 * (1.0f / 12.0f) + a2 * (1.0f / 6.0f);
        U6[5] = a2;
        #pragma unroll
        for (int c = 0; c < 6; c++) {
            int p = r * 6 + c;
            __nv_bfloat16 hi, lo;
            split_bf16(U6[c], hi, lo);
            size_t base = ((size_t)p * HIDDEN + co) * 576;
            U[base + ci]       = hi;
            U[base + 192 + ci] = hi;
            U[base + 384 + ci] = lo;
        }
    }
}

// ----------------------- winograd input transform ---------------------------
__device__ __forceinline__ void bt6(const float d[6], float t[6]) {
    t[0] = 4.f * d[0] - 5.f * d[2] + d[4];
    t[1] = -4.f * d[1] - 4.f * d[2] + d[3] + d[4];
    t[2] = 4.f * d[1] - 4.f * d[2] - d[3] + d[4];
    t[3] = -2.f * d[1] - d[2] + 2.f * d[3] + d[4];
    t[4] = 2.f * d[1] - d[2] - 2.f * d[3] + d[4];
    t[5] = 4.f * d[1] - 5.f * d[3] + d[5];
}

__global__ __launch_bounds__(256)
void wino_in(const float* __restrict__ y,
             __nv_bfloat16* __restrict__ Vh,
             __nv_bfloat16* __restrict__ Vl)
{
    int i = blockIdx.x * 256 + threadIdx.x;
    if (i >= NT4 * CCH) return;
    int tile = i / CCH, c = i % CCH;
    int b = tile / 196, r = tile % 196, ty = r / 14, tx = r % 14;

    float d[6][6];
    #pragma unroll
    for (int ii = 0; ii < 6; ii++) {
        int h = 4 * ty - 1 + ii;
        #pragma unroll
        for (int jj = 0; jj < 6; jj++) {
            int w = 4 * tx - 1 + jj;
            bool ok = (h >= 0) && (h < HH) && (w >= 0) && (w < WW_);
            d[ii][jj] = ok ? y[((size_t)(b * HH + h) * WW_ + w) * CCH + c] : 0.f;
        }
    }
    float t[6][6];
    #pragma unroll
    for (int jj = 0; jj < 6; jj++) {
        float col[6], tc[6];
        #pragma unroll
        for (int ii = 0; ii < 6; ii++) col[ii] = d[ii][jj];
        bt6(col, tc);
        #pragma unroll
        for (int ii = 0; ii < 6; ii++) t[ii][jj] = tc[ii];
    }
    #pragma unroll
    for (int ii = 0; ii < 6; ii++) {
        float V6[6];
        bt6(t[ii], V6);
        #pragma unroll
        for (int jj = 0; jj < 6; jj++) {
            int p = ii * 6 + jj;
            __nv_bfloat16 hi, lo;
            split_bf16(V6[jj], hi, lo);
            size_t idx = ((size_t)p * NTP + tile) * CCH + c;
            Vh[idx] = hi; Vl[idx] = lo;
        }
    }
}

// ----------------------- winograd output transform --------------------------
__device__ __forceinline__ void at6(const float m[6], float s[4]) {
    s[0] = m[0] + m[1] + m[2] + m[3] + m[4];
    s[1] = m[1] - m[2] + 2.f * m[3] - 2.f * m[4];
    s[2] = m[1] + m[2] + 4.f * m[3] + 4.f * m[4];
    s[3] = m[1] - m[2] + 8.f * m[3] - 8.f * m[4] + m[5];
}

__global__ __launch_bounds__(256)
void wino_out(const float* __restrict__ M,
              const float* __restrict__ scale,
              const float* __restrict__ shiftv,
              __half* __restrict__ h116)
{
    int i = blockIdx.x * 256 + threadIdx.x;
    if (i >= NT4 * HIDDEN) return;
    int tile = i / HIDDEN, co = i % HIDDEN;
    int b = tile / 196, r = tile % 196, ty = r / 14, tx = r % 14;

    float m[6][6];
    #pragma unroll
    for (int p = 0; p < 36; p++)
        m[p / 6][p % 6] = M[((size_t)p * NTP + tile) * HIDDEN + co];

    float s[4][6];
    #pragma unroll
    for (int jj = 0; jj < 6; jj++) {
        float col[6], sc4[4];
        #pragma unroll
        for (int ii = 0; ii < 6; ii++) col[ii] = m[ii][jj];
        at6(col, sc4);
        #pragma unroll
        for (int ii = 0; ii < 4; ii++) s[ii][jj] = sc4[ii];
    }
    float sc = scale[co], sh = shiftv[co];
    #pragma unroll
    for (int ii = 0; ii < 4; ii++) {
        float Y4[4];
        at6(s[ii], Y4);
        #pragma unroll
        for (int jj = 0; jj < 4; jj++) {
            float v = Y4[jj] * sc + sh;
            v = 0.5f * v * (1.0f + erff(v * 0.70710678118654752f));
            size_t px = (size_t)b * 3136 + (size_t)(4 * ty + ii) * 56 + (4 * tx + jj);
            h116[px * HIDDEN + co] = __float2half(v);
        }
    }
}

// ------------------------------- LayerNorm ---------------------------------
__global__ __launch_bounds__(256)
void ln_kernel(const float* __restrict__ x,
               const float* __restrict__ gamma,
               const float* __restrict__ beta,
               __half* __restrict__ out16,
               float* __restrict__ out_f32,
               int window_mode)
{
    int m = blockIdx.x * 8 + (threadIdx.x >> 5);
    int lane = threadIdx.x & 31;

    int src_p;
    if (window_mode) {
        int win = m / NTOK, tok = m % NTOK;
        int b  = win >> 6, wi = win & 63;
        int hs = (wi >> 3) * WS + tok / WS;
        int ws = (wi & 7)  * WS + tok % WS;
        int h = hs + SHIFT; if (h >= HH)  h -= HH;
        int w = ws + SHIFT; if (w >= WW_) w -= WW_;
        src_p = (b * HH + h) * WW_ + w;
    } else src_p = m;

    const float* src = x + (size_t)src_p * CCH;
    float v[6];
    float s1 = 0.f, s2 = 0.f;
    #pragma unroll
    for (int q = 0; q < 6; q++) {
        v[q] = src[lane + 32 * q];
        s1 += v[q]; s2 += v[q] * v[q];
    }
    #pragma unroll
    for (int o = 16; o > 0; o >>= 1) {
        s1 += __shfl_xor_sync(0xFFFFFFFF, s1, o);
        s2 += __shfl_xor_sync(0xFFFFFFFF, s2, o);
    }
    float mu  = s1 * (1.0f / CCH);
    float var = s2 * (1.0f / CCH) - mu * mu;
    float rs = rsqrtf(var + 1e-3f);

    #pragma unroll
    for (int q = 0; q < 6; q++) {
        int c = lane + 32 * q;
        float yv = (v[q] - mu) * rs * gamma[c] + beta[c];
        if (out_f32) out_f32[(size_t)m * CCH + c] = yv;
        else         out16[(size_t)m * CCH + c] = __float2half(yv);
    }
}

// ------------------------------- Attention ---------------------------------
__global__ void attn_kernel(const __half* __restrict__ qkv,
                            const float* __restrict__ table,
                            __half* __restrict__ o16)
{
    int blk = blockIdx.x;
    int win = blk / HEADS;
    int head = blk % HEADS;
    int tid = threadIdx.x;

    __shared__ float qs[NTOK * HD], ks[NTOK * HD], vs[NTOK * HD];
    __shared__ float S[NTOK * 50];

    for (int t = tid; t < NTOK * HD; t += 128) {
        int n = t >> 5, d = t & 31;
        const __half* base = qkv + (size_t)(win * NTOK + n) * (3 * CCH) + head * HD + d;
        qs[t] = __half2float(base[0]) * QKSCALE;
        ks[t] = __half2float(base[CCH]);
        vs[t] = __half2float(base[2 * CCH]);
    }
    __syncthreads();

    int wi = win & 63;
    int wh = wi >> 3, wwn = wi & 7;

    for (int t = tid; t < NTOK * NTOK; t += 128) {
        int n = t / NTOK, mm = t % NTOK;
        float s = 0.f;
        #pragma unroll
        for (int d = 0; d < HD; d++) s += qs[n * HD + d] * ks[mm * HD + d];
        int rn = n / WS, cn = n % WS, rm = mm / WS, cm = mm % WS;
        int idx = (rn - rm + WS - 1) * (2 * WS - 1) + (cn - cm + WS - 1);
        s += table[idx * HEADS + head];
        int hn = wh * WS + rn, wn = wwn * WS + cn;
        int hm = wh * WS + rm, wm = wwn * WS + cm;
        int reg_n = (hn < 49 ? 0 : (hn < 53 ? 1 : 2)) * 3 + (wn < 49 ? 0 : (wn < 53 ? 1 : 2));
        int reg_m = (hm < 49 ? 0 : (hm < 53 ? 1 : 2)) * 3 + (wm < 49 ? 0 : (wm < 53 ? 1 : 2));
        if (reg_n != reg_m) s -= 100.0f;
        S[n * 50 + mm] = s;
    }
    __syncthreads();

    // warp-per-row softmax
    {
        int w4 = tid >> 5, lane = tid & 31;
        for (int row = w4; row < NTOK; row += 4) {
            float* Sr = S + row * 50;
            float mx = -1e30f;
            for (int c = lane; c < NTOK; c += 32) mx = fmaxf(mx, Sr[c]);
            #pragma unroll
            for (int o = 16; o > 0; o >>= 1)
                mx = fmaxf(mx, __shfl_xor_sync(0xFFFFFFFF, mx, o));
            float sum = 0.f;
            for (int c = lane; c < NTOK; c += 32) {
                float e = __expf(Sr[c] - mx);
                Sr[c] = e; sum += e;
            }
            #pragma unroll
            for (int o = 16; o > 0; o >>= 1)
                sum += __shfl_xor_sync(0xFFFFFFFF, sum, o);
            float inv = 1.0f / sum;
            for (int c = lane; c < NTOK; c += 32) Sr[c] *= inv;
        }
    }
    __syncthreads();

    for (int t = tid; t < NTOK * HD; t += 128) {
        int n = t >> 5, d = t & 31;
        float acc = 0.f;
        #pragma unroll 7
        for (int m2 = 0; m2 < NTOK; m2++) acc += S[n * 50 + m2] * vs[m2 * HD + d];
        size_t idx = (size_t)(win * NTOK + n) * CCH + head * HD + d;
        o16[idx] = __float2half(acc);
    }
}

// ---------------------------- HMMA GEMM ------------------------------------
// SPLIT=1 (fp16): C = A[M,K] x B[K,N] plain.
// SPLIT=2 (fp16): C = A[M,K] x (Bh+Bl) via B'=[Bh;Bl], A repeated over segs.
// SPLIT=3 (bf16): C = A'[M,3K] x B'[3K,N], A' = [Ah|Al|Ah].
// CTA tile 256 x (2*WN), BK=32, 8 warps in 4x2, warp tile 64xWN, mma m16n8k16.
// epi: 2=+bias,remap,+addsrc->f32  4=BN,+addsrc->f32  5=raw->f32  6=+bias->f16
template<int WN, int MINCTA, int SPLIT, typename T>
__global__ __launch_bounds__(256, MINCTA)
void gemm_tc(const T* __restrict__ Ah,
             const T* __restrict__ Al,
             const T* __restrict__ Bs,
             const float* __restrict__ bias,
             float* __restrict__ Cf,
             __half* __restrict__ C16,
             const float* __restrict__ scale,
             const float* __restrict__ shiftv,
             const float* __restrict__ addsrc,
             int N, int K1, int epi,
             size_t zsA, size_t zsB, size_t zsC)
{
    constexpr int TN   = 2 * WN;
    constexpr int NB   = WN / 16;        // B ldsm per ks
    constexpr int NI   = WN / 8;         // n-fragments per warp
    constexpr int B_STG = TN * ROWB;
    constexpr int BPASS = TN / 64;       // B load passes

    Ah += blockIdx.z * zsA;
    Al += blockIdx.z * zsA;
    Bs += blockIdx.z * zsB;
    Cf += blockIdx.z * zsC;

    extern __shared__ char smem[];
    uint32_t sA0 = (uint32_t)__cvta_generic_to_shared(smem);
    uint32_t sB0 = sA0 + STAGES * A_STG;

    int tid = threadIdx.x;
    int wid = tid >> 5, lid = tid & 31;
    int wr = wid >> 1, wc = wid & 1;
    int m0 = blockIdx.y * TM, n0 = blockIdx.x * TN;
    int KS = SPLIT * K1;
    int nk = KS / TKB;

    int arow = tid >> 2;          // + p*64, p<4
    int aj = tid & 3;             // 16B chunk within 64B row payload
    size_t arowoff[4];
    #pragma unroll
    for (int p = 0; p < 4; p++) arowoff[p] = (size_t)(m0 + arow + p * 64) * K1;
    size_t browoff[BPASS];
    #pragma unroll
    for (int p = 0; p < BPASS; p++)
        browoff[p] = (size_t)(n0 + arow + p * 64) * KS;

    float acc[4][NI][4];
    #pragma unroll
    for (int i = 0; i < 4; i++)
        #pragma unroll
        for (int j = 0; j < NI; j++)
            #pragma unroll
            for (int q = 0; q < 4; q++) acc[i][j][q] = 0.f;

    auto load_stage = [&](int kt) {
        int s = kt % STAGES;
        int k3 = kt * TKB;
        int seg = k3 / K1;
        int kk = k3 - seg * K1;
        const T* Asrc = (SPLIT == 3 && seg == 1) ? Al : Ah;
        #pragma unroll
        for (int p = 0; p < 4; p++) {
            uint32_t dst = sA0 + s * A_STG + (arow + p * 64) * ROWB + aj * 16;
            cp_async16(dst, Asrc + arowoff[p] + kk + aj * 8, true);
        }
        #pragma unroll
        for (int p = 0; p < BPASS; p++) {
            uint32_t dst = sB0 + s * B_STG + (arow + p * 64) * ROWB + aj * 16;
            cp_async16(dst, Bs + browoff[p] + k3 + aj * 8, true);
        }
    };

    auto compute = [&](int s) {
        uint32_t aBase = sA0 + s * A_STG + (wr * 64 + (lid & 15)) * ROWB + (lid >> 4) * 16;
        uint32_t bBase = sB0 + s * B_STG
                       + (wc * WN + (lid & 7) + ((lid >> 4) << 3)) * ROWB
                       + ((lid >> 3) & 1) * 16;
        #pragma unroll
        for (int ks = 0; ks < 2; ks++) {
            uint32_t a[4][4], b[NB][4];
            #pragma unroll
            for (int mi = 0; mi < 4; mi++)
                ldsm_x4(aBase + mi * 16 * ROWB + ks * 32, a[mi]);
            #pragma unroll
            for (int bi = 0; bi < NB; bi++)
                ldsm_x4(bBase + bi * 16 * ROWB + ks * 32, b[bi]);
            #pragma unroll
            for (int mi = 0; mi < 4; mi++)
                #pragma unroll
                for (int ni = 0; ni < NI; ni++)
                    mma_any<T>(acc[mi][ni], a[mi],
                               b[ni >> 1][(ni & 1) * 2], b[ni >> 1][(ni & 1) * 2 + 1]);
        }
    };

    #pragma unroll
    for (int p = 0; p < STAGES - 1; p++) { if (p < nk) load_stage(p); CP_COMMIT(); }

    for (int kt = 0; kt < nk; kt++) {
        CP_WAIT(STAGES - 2);
        __syncthreads();
        if (kt + STAGES - 1 < nk) load_stage(kt + STAGES - 1);
        CP_COMMIT();
        compute(kt % STAGES);
    }

    // ------------------------------ epilogue -------------------------------
    int g = lid >> 2, t2 = (lid & 3) * 2;
    #pragma unroll
    for (int mi = 0; mi < 4; mi++) {
        #pragma unroll
        for (int rr = 0; rr < 2; rr++) {
            int m = m0 + wr * 64 + mi * 16 + g + rr * 8;
            size_t orow;
            if (epi == 2) {
                int win = m / NTOK, tok = m % NTOK;
                int b = win >> 6, wi2 = win & 63;
                int hs = (wi2 >> 3) * WS + tok / WS;
                int ws = (wi2 & 7)  * WS + tok % WS;
                int h = hs + SHIFT; if (h >= HH)  h -= HH;
                int w = ws + SHIFT; if (w >= WW_) w -= WW_;
                orow = (size_t)(b * HH + h) * WW_ + w;
            } else {
                orow = (size_t)m;
            }
            #pragma unroll
            for (int ni = 0; ni < NI; ni++) {
                int n = n0 + wc * WN + ni * 8 + t2;
                float v0 = acc[mi][ni][rr * 2 + 0];
                float v1 = acc[mi][ni][rr * 2 + 1];
                if (epi == 6) {
                    __half2 o;
                    o.x = __float2half(v0 + bias[n]);
                    o.y = __float2half(v1 + bias[n + 1]);
                    *reinterpret_cast<__half2*>(C16 + (size_t)m * N + n) = o;
                } else if (epi == 2) {
                    size_t oi = orow * CCH + n;
                    float2 a4 = *reinterpret_cast<const float2*>(addsrc + oi);
                    float2 o = { v0 + bias[n] + a4.x, v1 + bias[n + 1] + a4.y };
                    *reinterpret_cast<float2*>(Cf + oi) = o;
                } else if (epi == 4) {
                    size_t oi = (size_t)m * CCH + n;
                    float2 a4 = *reinterpret_cast<const float2*>(addsrc + oi);
                    float2 o = { v0 * scale[n] + shiftv[n] + a4.x,
                                 v1 * scale[n + 1] + shiftv[n + 1] + a4.y };
                    *reinterpret_cast<float2*>(Cf + oi) = o;
                } else {  // epi == 5: raw
                    float2 o = { v0, v1 };
                    *reinterpret_cast<float2*>(Cf + (size_t)m * N + n) = o;
                }
            }
        }
    }
}

// ------------------------------- launcher -----------------------------------
extern "C" void kernel_launch(void* const* d_in, const int* in_sizes, int n_in,
                              void* d_out, int out_size)
{
    const float* x         = (const float*)d_in[0];
    const float* ln1_g     = (const float*)d_in[1];
    const float* ln1_b     = (const float*)d_in[2];
    const float* w_qkv     = (const float*)d_in[3];
    const float* b_qkv     = (const float*)d_in[4];
    const float* bias_tbl  = (const float*)d_in[5];
    const float* w_proj    = (const float*)d_in[6];
    const float* b_proj    = (const float*)d_in[7];
    const float* ln2_g     = (const float*)d_in[8];
    const float* ln2_b     = (const float*)d_in[9];
    const float* w_ffn1    = (const float*)d_in[10];
    const float* bn1_scale = (const float*)d_in[11];
    const float* bn1_shift = (const float*)d_in[12];
    const float* w_ffn2    = (const float*)d_in[13];
    const float* bn2_scale = (const float*)d_in[14];
    const float* bn2_shift = (const float*)d_in[15];
    float* out = (float*)d_out;

    __half *xw16, *qkv16, *o16, *h116, *wq16, *wp16, *w216;
    __nv_bfloat16 *U, *Vh, *Vl;
    float *xmid, *y, *Mbuf;
    cudaGetSymbolAddress((void**)&xw16,  g_xw16);
    cudaGetSymbolAddress((void**)&qkv16, g_qkv16);
    cudaGetSymbolAddress((void**)&o16,   g_o16);
    cudaGetSymbolAddress((void**)&xmid,  g_xmid);
    cudaGetSymbolAddress((void**)&y,     g_y);
    cudaGetSymbolAddress((void**)&h116,  g_h116);
    cudaGetSymbolAddress((void**)&wq16,  g_wq16);
    cudaGetSymbolAddress((void**)&wp16,  g_wp16);
    cudaGetSymbolAddress((void**)&w216,  g_w216);
    cudaGetSymbolAddress((void**)&U,  g_U);
    cudaGetSymbolAddress((void**)&Vh, g_Vh); cudaGetSymbolAddress((void**)&Vl, g_Vl);
    cudaGetSymbolAddress((void**)&Mbuf, g_M);

    constexpr int SMSZ = STAGES * (A_STG + 64 * ROWB);   // 102400
    cudaFuncSetAttribute((const void*)gemm_tc<32,2,1,__half>,
                         cudaFuncAttributeMaxDynamicSharedMemorySize, SMSZ);
    cudaFuncSetAttribute((const void*)gemm_tc<32,2,2,__half>,
                         cudaFuncAttributeMaxDynamicSharedMemorySize, SMSZ);
    cudaFuncSetAttribute((const void*)gemm_tc<32,2,3,__nv_bfloat16>,
                         cudaFuncAttributeMaxDynamicSharedMemorySize, SMSZ);

    // weight preps
    prep_w16<1><<<(192 * 576 + 255) / 256, 256>>>(w_qkv, wq16, 192, 576);
    prep_w16<1><<<(192 * 192 + 255) / 256, 256>>>(w_proj, wp16, 192, 192);
    prep_w16<2><<<(768 * 192 + 255) / 256, 256>>>(w_ffn2, w216, 768, 192);
    wino_wt<<<(CCH * HIDDEN + 255) / 256, 256>>>(w_ffn1, U);

    // LN1 + roll + window partition -> fp16
    ln_kernel<<<MROWS / 8, 256>>>(x, ln1_g, ln1_b, xw16, nullptr, 1);

    // QKV GEMM [M,192]x[192,576] fp16 1-term -> fp16
    gemm_tc<32,2,1,__half><<<dim3(576 / 64, MROWS / TM), 256, SMSZ>>>(
        xw16, xw16, wq16, b_qkv, nullptr, qkv16, nullptr, nullptr, nullptr,
        576, 192, 6, 0, 0, 0);

    // attention -> fp16
    attn_kernel<<<(MROWS / NTOK) * HEADS, 128>>>(qkv16, bias_tbl, o16);

    // proj GEMM + window reverse + roll + shortcut (fp16 1-term)
    gemm_tc<32,2,1,__half><<<dim3(192 / 64, MROWS / TM), 256, SMSZ>>>(
        o16, o16, wp16, b_proj, xmid, nullptr, nullptr, nullptr, x,
        192, 192, 2, 0, 0, 0);

    // LN2 -> fp32
    ln_kernel<<<MROWS / 8, 256>>>(xmid, ln2_g, ln2_b, nullptr, y, 0);

    // winograd F(4,3) input transform
    wino_in<<<(NT4 * CCH + 255) / 256, 256>>>(y, Vh, Vl);

    // 36 batched transform-domain GEMMs [6400,192]x[192,768] -> M (bf16 3-term)
    gemm_tc<32,2,3,__nv_bfloat16><<<dim3(HIDDEN / 64, NTP / TM, 36), 256, SMSZ>>>(
        Vh, Vl, U, nullptr, Mbuf, nullptr, nullptr, nullptr, nullptr,
        HIDDEN, 192, 5,
        (size_t)NTP * CCH, (size_t)HIDDEN * 576, (size_t)NTP * HIDDEN);

    // winograd output transform + BN + GELU -> h1 fp16
    wino_out<<<(NT4 * HIDDEN + 255) / 256, 256>>>(Mbuf, bn1_scale, bn1_shift, h116);

    // conv1x1 GEMM + BN + residual -> out (fp16 2-term)
    gemm_tc<32,2,2,__half><<<dim3(CCH / 64, MROWS / TM), 256, SMSZ>>>(
        h116, h116, w216, nullptr, out, nullptr, bn2_scale, bn2_shift, xmid,
        CCH, 768, 4, 0, 0, 0);
}

// round 10
// speedup vs baseline: 3.9161x; 1.0341x over previous
#include <cuda_runtime.h>
#include <cuda_bf16.h>
#include <cuda_fp16.h>
#include <cstdint>
#include <math.h>

// ---------------------------------------------------------------------------
// SwinTransformerLayer on GB300, mma.sync tensor cores.
// - QKV / proj / conv1x1 GEMMs: plain fp16 (errors diluted by residual adds;
//   empirically ~1e-4 per rounding source, quadrature)
// - conv3x3: Winograd F(4x4,3x3), transform GEMMs in bf16 3-term split
//   (C = Ah*Bh + Al*Bh + Ah*Bl, K tripled)
// Round 10: conv1x1 1-term, STAGES=3, LN2 fused into winograd input transform.
// ---------------------------------------------------------------------------

#define BATCH   32
#define HH      56
#define WW_     56
#define CCH     192
#define WS      7
#define SHIFT   3
#define HEADS   6
#define HD      32
#define NTOK    49
#define MROWS   (BATCH*HH*WW_)   // 100352
#define HIDDEN  768
#define QKSCALE 0.17677669529663687f
#define NT4     6272             // 32 * 14 * 14 winograd F(4,3) tiles
#define NTP     6400             // padded to multiple of 256

#define TM      256
#define TKB     32               // K elements per stage
#define STAGES  3
#define ROWB    80               // padded row bytes (40 elems) — conflict-free ldmatrix
#define A_STG   (TM*ROWB)        // 20480

// ------------------------- scratch (device globals) ------------------------
__device__ __align__(16) __half        g_xw16 [(size_t)MROWS * CCH];
__device__ __align__(16) __half        g_qkv16[(size_t)MROWS * 3 * CCH];
__device__ __align__(16) __half        g_o16  [(size_t)MROWS * CCH];
__device__ __align__(16) float         g_xmid [(size_t)MROWS * CCH];
__device__ __align__(16) float         g_mu   [(size_t)MROWS];
__device__ __align__(16) float         g_rs   [(size_t)MROWS];
__device__ __align__(16) __half        g_h116 [(size_t)MROWS * HIDDEN];
// fp16 1-term weights, [N,K]
__device__ __align__(16) __half        g_wq16 [(size_t)576 * 192];
__device__ __align__(16) __half        g_wp16 [(size_t)192 * 192];
__device__ __align__(16) __half        g_w216 [(size_t)192 * 768];
// winograd F(4,3): 36 planes, bf16 3-term
__device__ __align__(16) __nv_bfloat16 g_U  [(size_t)36 * HIDDEN * 576];   // [p][co][3K]
__device__ __align__(16) __nv_bfloat16 g_Vh [(size_t)36 * NTP * CCH];
__device__ __align__(16) __nv_bfloat16 g_Vl [(size_t)36 * NTP * CCH];
__device__ __align__(16) float         g_M  [(size_t)36 * NTP * HIDDEN];   // fp32

// ------------------------------ PTX helpers --------------------------------
__device__ __forceinline__ void cp_async16(uint32_t dst, const void* src, bool full) {
    int sz = full ? 16 : 0;
    asm volatile("cp.async.cg.shared.global [%0], [%1], 16, %2;"
                 :: "r"(dst), "l"(src), "r"(sz) : "memory");
}
#define CP_COMMIT() asm volatile("cp.async.commit_group;" ::: "memory")
#define CP_WAIT(n)  asm volatile("cp.async.wait_group %0;" :: "n"(n) : "memory")

__device__ __forceinline__ void ldsm_x4(uint32_t addr, uint32_t r[4]) {
    asm volatile("ldmatrix.sync.aligned.m8n8.x4.shared.b16 {%0,%1,%2,%3}, [%4];"
                 : "=r"(r[0]), "=r"(r[1]), "=r"(r[2]), "=r"(r[3]) : "r"(addr));
}
template<typename T>
__device__ __forceinline__ void mma_any(float c[4], const uint32_t a[4],
                                        uint32_t b0, uint32_t b1);
template<>
__device__ __forceinline__ void mma_any<__nv_bfloat16>(float c[4], const uint32_t a[4],
                                                       uint32_t b0, uint32_t b1) {
    asm volatile("mma.sync.aligned.m16n8k16.row.col.f32.bf16.bf16.f32 "
                 "{%0,%1,%2,%3}, {%4,%5,%6,%7}, {%8,%9}, {%0,%1,%2,%3};"
                 : "+f"(c[0]), "+f"(c[1]), "+f"(c[2]), "+f"(c[3])
                 : "r"(a[0]), "r"(a[1]), "r"(a[2]), "r"(a[3]), "r"(b0), "r"(b1));
}
template<>
__device__ __forceinline__ void mma_any<__half>(float c[4], const uint32_t a[4],
                                                uint32_t b0, uint32_t b1) {
    asm volatile("mma.sync.aligned.m16n8k16.row.col.f32.f16.f16.f32 "
                 "{%0,%1,%2,%3}, {%4,%5,%6,%7}, {%8,%9}, {%0,%1,%2,%3};"
                 : "+f"(c[0]), "+f"(c[1]), "+f"(c[2]), "+f"(c[3])
                 : "r"(a[0]), "r"(a[1]), "r"(a[2]), "r"(a[3]), "r"(b0), "r"(b1));
}

__device__ __forceinline__ void split_bf16(float v, __nv_bfloat16& hi, __nv_bfloat16& lo) {
    hi = __float2bfloat16(v);
    lo = __float2bfloat16(v - __bfloat162float(hi));
}

// ----------------------------- weight prep ---------------------------------
// W [K,N] fp32 -> D [N,K] fp16 (plain 1-term).
__global__ void prep_w16(const float* __restrict__ W, __half* __restrict__ D,
                         int K, int N)
{
    int i = blockIdx.x * 256 + threadIdx.x;
    if (i >= K * N) return;
    int k = i / N, n = i % N;
    D[(size_t)n * K + k] = __float2half(W[i]);
}

// ----------------------- winograd weight transform --------------------------
__global__ void wino_wt(const float* __restrict__ W, __nv_bfloat16* __restrict__ U)
{
    int i = blockIdx.x * 256 + threadIdx.x;
    if (i >= CCH * HIDDEN) return;
    int ci = i % CCH, co = i / CCH;

    float g[3][3];
    #pragma unroll
    for (int ky = 0; ky < 3; ky++)
        #pragma unroll
        for (int kx = 0; kx < 3; kx++)
            g[ky][kx] = W[((size_t)(ky * 3 + kx) * CCH + ci) * HIDDEN + co];

    float u[6][3];
    #pragma unroll
    for (int c = 0; c < 3; c++) {
        float g0 = g[0][c], g1 = g[1][c], g2 = g[2][c];
        u[0][c] = 0.25f * g0;
        u[1][c] = -(g0 + g1 + g2) * (1.0f / 6.0f);
        u[2][c] = (-g0 + g1 - g2) * (1.0f / 6.0f);
        u[3][c] = g0 * (1.0f / 24.0f) + g1 * (1.0f / 12.0f) + g2 * (1.0f / 6.0f);
        u[4][c] = g0 * (1.0f / 24.0f) - g1 * (1.0f / 12.0f) + g2 * (1.0f / 6.0f);
        u[5][c] = g2;
    }
    #pragma unroll
    for (int r = 0; r < 6; r++) {
        float a0 = u[r][0], a1 = u[r][1], a2 = u[r][2];
        float U6[6];
        U6[0] = 0.25f * a0;
        U6[1] = -(a0 + a1 + a2) * (1.0f / 6.0f);
        U6[2] = (-a0 + a1 - a2) * (1.0f / 6.0f);
        U6[3] = a0 * (1.0f / 24.0f) + a1 * (1.0f / 12.0f) + a2 * (1.0f / 6.0f);
        U6[4] = a0 * (1.0f / 24.0f) - a1 * (1.0f / 12.0f) + a2 * (1.0f / 6.0f);
        U6[5] = a2;
        #pragma unroll
        for (int c = 0; c < 6; c++) {
            int p = r * 6 + c;
            __nv_bfloat16 hi, lo;
            split_bf16(U6[c], hi, lo);
            size_t base = ((size_t)p * HIDDEN + co) * 576;
            U[base + ci]       = hi;
            U[base + 192 + ci] = hi;
            U[base + 384 + ci] = lo;
        }
    }
}

// ------------------------ LN row statistics (for LN2) -----------------------
__global__ __launch_bounds__(256)
void ln_stats(const float* __restrict__ x, float* __restrict__ mu_o,
              float* __restrict__ rs_o)
{
    int m = blockIdx.x * 8 + (threadIdx.x >> 5);
    int lane = threadIdx.x & 31;
    const float* src = x + (size_t)m * CCH;
    float s1 = 0.f, s2 = 0.f;
    #pragma unroll
    for (int q = 0; q < 6; q++) {
        float v = src[lane + 32 * q];
        s1 += v; s2 += v * v;
    }
    #pragma unroll
    for (int o = 16; o > 0; o >>= 1) {
        s1 += __shfl_xor_sync(0xFFFFFFFF, s1, o);
        s2 += __shfl_xor_sync(0xFFFFFFFF, s2, o);
    }
    if (lane == 0) {
        float mu  = s1 * (1.0f / CCH);
        float var = s2 * (1.0f / CCH) - mu * mu;
        mu_o[m] = mu;
        rs_o[m] = rsqrtf(var + 1e-3f);
    }
}

// ----------------- winograd input transform (LN2 fused) ---------------------
__device__ __forceinline__ void bt6(const float d[6], float t[6]) {
    t[0] = 4.f * d[0] - 5.f * d[2] + d[4];
    t[1] = -4.f * d[1] - 4.f * d[2] + d[3] + d[4];
    t[2] = 4.f * d[1] - 4.f * d[2] - d[3] + d[4];
    t[3] = -2.f * d[1] - d[2] + 2.f * d[3] + d[4];
    t[4] = 2.f * d[1] - d[2] - 2.f * d[3] + d[4];
    t[5] = 4.f * d[1] - 5.f * d[3] + d[5];
}

__global__ __launch_bounds__(256)
void wino_in(const float* __restrict__ x,
             const float* __restrict__ mu,
             const float* __restrict__ rs,
             const float* __restrict__ gamma,
             const float* __restrict__ beta,
             __nv_bfloat16* __restrict__ Vh,
             __nv_bfloat16* __restrict__ Vl)
{
    int i = blockIdx.x * 256 + threadIdx.x;
    if (i >= NT4 * CCH) return;
    int tile = i / CCH, c = i % CCH;
    int b = tile / 196, r = tile % 196, ty = r / 14, tx = r % 14;
    float gm = gamma[c], bt = beta[c];

    float d[6][6];
    #pragma unroll
    for (int ii = 0; ii < 6; ii++) {
        int h = 4 * ty - 1 + ii;
        #pragma unroll
        for (int jj = 0; jj < 6; jj++) {
            int w = 4 * tx - 1 + jj;
            bool ok = (h >= 0) && (h < HH) && (w >= 0) && (w < WW_);
            if (ok) {
                size_t row = (size_t)(b * HH + h) * WW_ + w;
                d[ii][jj] = (x[row * CCH + c] - mu[row]) * rs[row] * gm + bt;
            } else d[ii][jj] = 0.f;
        }
    }
    float t[6][6];
    #pragma unroll
    for (int jj = 0; jj < 6; jj++) {
        float col[6], tc[6];
        #pragma unroll
        for (int ii = 0; ii < 6; ii++) col[ii] = d[ii][jj];
        bt6(col, tc);
        #pragma unroll
        for (int ii = 0; ii < 6; ii++) t[ii][jj] = tc[ii];
    }
    #pragma unroll
    for (int ii = 0; ii < 6; ii++) {
        float V6[6];
        bt6(t[ii], V6);
        #pragma unroll
        for (int jj = 0; jj < 6; jj++) {
            int p = ii * 6 + jj;
            __nv_bfloat16 hi, lo;
            split_bf16(V6[jj], hi, lo);
            size_t idx = ((size_t)p * NTP + tile) * CCH + c;
            Vh[idx] = hi; Vl[idx] = lo;
        }
    }
}

// ----------------------- winograd output transform --------------------------
__device__ __forceinline__ void at6(const float m[6], float s[4]) {
    s[0] = m[0] + m[1] + m[2] + m[3] + m[4];
    s[1] = m[1] - m[2] + 2.f * m[3] - 2.f * m[4];
    s[2] = m[1] + m[2] + 4.f * m[3] + 4.f * m[4];
    s[3] = m[1] - m[2] + 8.f * m[3] - 8.f * m[4] + m[5];
}

__global__ __launch_bounds__(256)
void wino_out(const float* __restrict__ M,
              const float* __restrict__ scale,
              const float* __restrict__ shiftv,
              __half* __restrict__ h116)
{
    int i = blockIdx.x * 256 + threadIdx.x;
    if (i >= NT4 * HIDDEN) return;
    int tile = i / HIDDEN, co = i % HIDDEN;
    int b = tile / 196, r = tile % 196, ty = r / 14, tx = r % 14;

    float m[6][6];
    #pragma unroll
    for (int p = 0; p < 36; p++)
        m[p / 6][p % 6] = M[((size_t)p * NTP + tile) * HIDDEN + co];

    float s[4][6];
    #pragma unroll
    for (int jj = 0; jj < 6; jj++) {
        float col[6], sc4[4];
        #pragma unroll
        for (int ii = 0; ii < 6; ii++) col[ii] = m[ii][jj];
        at6(col, sc4);
        #pragma unroll
        for (int ii = 0; ii < 4; ii++) s[ii][jj] = sc4[ii];
    }
    float sc = scale[co], sh = shiftv[co];
    #pragma unroll
    for (int ii = 0; ii < 4; ii++) {
        float Y4[4];
        at6(s[ii], Y4);
        #pragma unroll
        for (int jj = 0; jj < 4; jj++) {
            float v = Y4[jj] * sc + sh;
            v = 0.5f * v * (1.0f + erff(v * 0.70710678118654752f));
            size_t px = (size_t)b * 3136 + (size_t)(4 * ty + ii) * 56 + (4 * tx + jj);
            h116[px * HIDDEN + co] = __float2half(v);
        }
    }
}

// ------------------------------- LayerNorm (LN1) ----------------------------
__global__ __launch_bounds__(256)
void ln_kernel(const float* __restrict__ x,
               const float* __restrict__ gamma,
               const float* __restrict__ beta,
               __half* __restrict__ out16)
{
    int m = blockIdx.x * 8 + (threadIdx.x >> 5);
    int lane = threadIdx.x & 31;

    // window mode: read rolled pixel, write window layout
    int win = m / NTOK, tok = m % NTOK;
    int b  = win >> 6, wi = win & 63;
    int hs = (wi >> 3) * WS + tok / WS;
    int ws = (wi & 7)  * WS + tok % WS;
    int h = hs + SHIFT; if (h >= HH)  h -= HH;
    int w = ws + SHIFT; if (w >= WW_) w -= WW_;
    int src_p = (b * HH + h) * WW_ + w;

    const float* src = x + (size_t)src_p * CCH;
    float v[6];
    float s1 = 0.f, s2 = 0.f;
    #pragma unroll
    for (int q = 0; q < 6; q++) {
        v[q] = src[lane + 32 * q];
        s1 += v[q]; s2 += v[q] * v[q];
    }
    #pragma unroll
    for (int o = 16; o > 0; o >>= 1) {
        s1 += __shfl_xor_sync(0xFFFFFFFF, s1, o);
        s2 += __shfl_xor_sync(0xFFFFFFFF, s2, o);
    }
    float mu  = s1 * (1.0f / CCH);
    float var = s2 * (1.0f / CCH) - mu * mu;
    float rsg = rsqrtf(var + 1e-3f);

    #pragma unroll
    for (int q = 0; q < 6; q++) {
        int c = lane + 32 * q;
        float yv = (v[q] - mu) * rsg * gamma[c] + beta[c];
        out16[(size_t)m * CCH + c] = __float2half(yv);
    }
}

// ------------------------------- Attention ---------------------------------
__global__ void attn_kernel(const __half* __restrict__ qkv,
                            const float* __restrict__ table,
                            __half* __restrict__ o16)
{
    int blk = blockIdx.x;
    int win = blk / HEADS;
    int head = blk % HEADS;
    int tid = threadIdx.x;

    __shared__ float qs[NTOK * HD], ks[NTOK * HD], vs[NTOK * HD];
    __shared__ float S[NTOK * 50];

    for (int t = tid; t < NTOK * HD; t += 128) {
        int n = t >> 5, d = t & 31;
        const __half* base = qkv + (size_t)(win * NTOK + n) * (3 * CCH) + head * HD + d;
        qs[t] = __half2float(base[0]) * QKSCALE;
        ks[t] = __half2float(base[CCH]);
        vs[t] = __half2float(base[2 * CCH]);
    }
    __syncthreads();

    int wi = win & 63;
    int wh = wi >> 3, wwn = wi & 7;

    for (int t = tid; t < NTOK * NTOK; t += 128) {
        int n = t / NTOK, mm = t % NTOK;
        float s = 0.f;
        #pragma unroll
        for (int d = 0; d < HD; d++) s += qs[n * HD + d] * ks[mm * HD + d];
        int rn = n / WS, cn = n % WS, rm = mm / WS, cm = mm % WS;
        int idx = (rn - rm + WS - 1) * (2 * WS - 1) + (cn - cm + WS - 1);
        s += table[idx * HEADS + head];
        int hn = wh * WS + rn, wn = wwn * WS + cn;
        int hm = wh * WS + rm, wm = wwn * WS + cm;
        int reg_n = (hn < 49 ? 0 : (hn < 53 ? 1 : 2)) * 3 + (wn < 49 ? 0 : (wn < 53 ? 1 : 2));
        int reg_m = (hm < 49 ? 0 : (hm < 53 ? 1 : 2)) * 3 + (wm < 49 ? 0 : (wm < 53 ? 1 : 2));
        if (reg_n != reg_m) s -= 100.0f;
        S[n * 50 + mm] = s;
    }
    __syncthreads();

    // warp-per-row softmax
    {
        int w4 = tid >> 5, lane = tid & 31;
        for (int row = w4; row < NTOK; row += 4) {
            float* Sr = S + row * 50;
            float mx = -1e30f;
            for (int c = lane; c < NTOK; c += 32) mx = fmaxf(mx, Sr[c]);
            #pragma unroll
            for (int o = 16; o > 0; o >>= 1)
                mx = fmaxf(mx, __shfl_xor_sync(0xFFFFFFFF, mx, o));
            float sum = 0.f;
            for (int c = lane; c < NTOK; c += 32) {
                float e = __expf(Sr[c] - mx);
                Sr[c] = e; sum += e;
            }
            #pragma unroll
            for (int o = 16; o > 0; o >>= 1)
                sum += __shfl_xor_sync(0xFFFFFFFF, sum, o);
            float inv = 1.0f / sum;
            for (int c = lane; c < NTOK; c += 32) Sr[c] *= inv;
        }
    }
    __syncthreads();

    for (int t = tid; t < NTOK * HD; t += 128) {
        int n = t >> 5, d = t & 31;
        float acc = 0.f;
        #pragma unroll 7
        for (int m2 = 0; m2 < NTOK; m2++) acc += S[n * 50 + m2] * vs[m2 * HD + d];
        size_t idx = (size_t)(win * NTOK + n) * CCH + head * HD + d;
        o16[idx] = __float2half(acc);
    }
}

// ---------------------------- HMMA GEMM ------------------------------------
// SPLIT=1 (fp16): C = A[M,K] x B[K,N] plain.
// SPLIT=3 (bf16): C = A'[M,3K] x B'[3K,N], A' = [Ah|Al|Ah].
// CTA tile 256 x (2*WN), BK=32, 8 warps in 4x2, warp tile 64xWN, mma m16n8k16.
// epi: 2=+bias,remap,+addsrc->f32  4=BN,+addsrc->f32  5=raw->f32  6=+bias->f16
template<int WN, int MINCTA, int SPLIT, typename T>
__global__ __launch_bounds__(256, MINCTA)
void gemm_tc(const T* __restrict__ Ah,
             const T* __restrict__ Al,
             const T* __restrict__ Bs,
             const float* __restrict__ bias,
             float* __restrict__ Cf,
             __half* __restrict__ C16,
             const float* __restrict__ scale,
             const float* __restrict__ shiftv,
             const float* __restrict__ addsrc,
             int N, int K1, int epi,
             size_t zsA, size_t zsB, size_t zsC)
{
    constexpr int TN   = 2 * WN;
    constexpr int NB   = WN / 16;        // B ldsm per ks
    constexpr int NI   = WN / 8;         // n-fragments per warp
    constexpr int B_STG = TN * ROWB;
    constexpr int BPASS = TN / 64;       // B load passes

    Ah += blockIdx.z * zsA;
    Al += blockIdx.z * zsA;
    Bs += blockIdx.z * zsB;
    Cf += blockIdx.z * zsC;

    extern __shared__ char smem[];
    uint32_t sA0 = (uint32_t)__cvta_generic_to_shared(smem);
    uint32_t sB0 = sA0 + STAGES * A_STG;

    int tid = threadIdx.x;
    int wid = tid >> 5, lid = tid & 31;
    int wr = wid >> 1, wc = wid & 1;
    int m0 = blockIdx.y * TM, n0 = blockIdx.x * TN;
    int KS = SPLIT * K1;
    int nk = KS / TKB;

    int arow = tid >> 2;          // + p*64, p<4
    int aj = tid & 3;             // 16B chunk within 64B row payload
    size_t arowoff[4];
    #pragma unroll
    for (int p = 0; p < 4; p++) arowoff[p] = (size_t)(m0 + arow + p * 64) * K1;
    size_t browoff[BPASS];
    #pragma unroll
    for (int p = 0; p < BPASS; p++)
        browoff[p] = (size_t)(n0 + arow + p * 64) * KS;

    float acc[4][NI][4];
    #pragma unroll
    for (int i = 0; i < 4; i++)
        #pragma unroll
        for (int j = 0; j < NI; j++)
            #pragma unroll
            for (int q = 0; q < 4; q++) acc[i][j][q] = 0.f;

    auto load_stage = [&](int kt) {
        int s = kt % STAGES;
        int k3 = kt * TKB;
        int seg = k3 / K1;
        int kk = k3 - seg * K1;
        const T* Asrc = (SPLIT == 3 && seg == 1) ? Al : Ah;
        #pragma unroll
        for (int p = 0; p < 4; p++) {
            uint32_t dst = sA0 + s * A_STG + (arow + p * 64) * ROWB + aj * 16;
            cp_async16(dst, Asrc + arowoff[p] + kk + aj * 8, true);
        }
        #pragma unroll
        for (int p = 0; p < BPASS; p++) {
            uint32_t dst = sB0 + s * B_STG + (arow + p * 64) * ROWB + aj * 16;
            cp_async16(dst, Bs + browoff[p] + k3 + aj * 8, true);
        }
    };

    auto compute = [&](int s) {
        uint32_t aBase = sA0 + s * A_STG + (wr * 64 + (lid & 15)) * ROWB + (lid >> 4) * 16;
        uint32_t bBase = sB0 + s * B_STG
                       + (wc * WN + (lid & 7) + ((lid >> 4) << 3)) * ROWB
                       + ((lid >> 3) & 1) * 16;
        #pragma unroll
        for (int ks = 0; ks < 2; ks++) {
            uint32_t a[4][4], b[NB][4];
            #pragma unroll
            for (int mi = 0; mi < 4; mi++)
                ldsm_x4(aBase + mi * 16 * ROWB + ks * 32, a[mi]);
            #pragma unroll
            for (int bi = 0; bi < NB; bi++)
                ldsm_x4(bBase + bi * 16 * ROWB + ks * 32, b[bi]);
            #pragma unroll
            for (int mi = 0; mi < 4; mi++)
                #pragma unroll
                for (int ni = 0; ni < NI; ni++)
                    mma_any<T>(acc[mi][ni], a[mi],
                               b[ni >> 1][(ni & 1) * 2], b[ni >> 1][(ni & 1) * 2 + 1]);
        }
    };

    #pragma unroll
    for (int p = 0; p < STAGES - 1; p++) { if (p < nk) load_stage(p); CP_COMMIT(); }

    for (int kt = 0; kt < nk; kt++) {
        CP_WAIT(STAGES - 2);
        __syncthreads();
        if (kt + STAGES - 1 < nk) load_stage(kt + STAGES - 1);
        CP_COMMIT();
        compute(kt % STAGES);
    }

    // ------------------------------ epilogue -------------------------------
    int g = lid >> 2, t2 = (lid & 3) * 2;
    #pragma unroll
    for (int mi = 0; mi < 4; mi++) {
        #pragma unroll
        for (int rr = 0; rr < 2; rr++) {
            int m = m0 + wr * 64 + mi * 16 + g + rr * 8;
            size_t orow;
            if (epi == 2) {
                int win = m / NTOK, tok = m % NTOK;
                int b = win >> 6, wi2 = win & 63;
                int hs = (wi2 >> 3) * WS + tok / WS;
                int ws = (wi2 & 7)  * WS + tok % WS;
                int h = hs + SHIFT; if (h >= HH)  h -= HH;
                int w = ws + SHIFT; if (w >= WW_) w -= WW_;
                orow = (size_t)(b * HH + h) * WW_ + w;
            } else {
                orow = (size_t)m;
            }
            #pragma unroll
            for (int ni = 0; ni < NI; ni++) {
                int n = n0 + wc * WN + ni * 8 + t2;
                float v0 = acc[mi][ni][rr * 2 + 0];
                float v1 = acc[mi][ni][rr * 2 + 1];
                if (epi == 6) {
                    __half2 o;
                    o.x = __float2half(v0 + bias[n]);
                    o.y = __float2half(v1 + bias[n + 1]);
                    *reinterpret_cast<__half2*>(C16 + (size_t)m * N + n) = o;
                } else if (epi == 2) {
                    size_t oi = orow * CCH + n;
                    float2 a4 = *reinterpret_cast<const float2*>(addsrc + oi);
                    float2 o = { v0 + bias[n] + a4.x, v1 + bias[n + 1] + a4.y };
                    *reinterpret_cast<float2*>(Cf + oi) = o;
                } else if (epi == 4) {
                    size_t oi = (size_t)m * CCH + n;
                    float2 a4 = *reinterpret_cast<const float2*>(addsrc + oi);
                    float2 o = { v0 * scale[n] + shiftv[n] + a4.x,
                                 v1 * scale[n + 1] + shiftv[n + 1] + a4.y };
                    *reinterpret_cast<float2*>(Cf + oi) = o;
                } else {  // epi == 5: raw
                    float2 o = { v0, v1 };
                    *reinterpret_cast<float2*>(Cf + (size_t)m * N + n) = o;
                }
            }
        }
    }
}

// ------------------------------- launcher -----------------------------------
extern "C" void kernel_launch(void* const* d_in, const int* in_sizes, int n_in,
                              void* d_out, int out_size)
{
    const float* x         = (const float*)d_in[0];
    const float* ln1_g     = (const float*)d_in[1];
    const float* ln1_b     = (const float*)d_in[2];
    const float* w_qkv     = (const float*)d_in[3];
    const float* b_qkv     = (const float*)d_in[4];
    const float* bias_tbl  = (const float*)d_in[5];
    const float* w_proj    = (const float*)d_in[6];
    const float* b_proj    = (const float*)d_in[7];
    const float* ln2_g     = (const float*)d_in[8];
    const float* ln2_b     = (const float*)d_in[9];
    const float* w_ffn1    = (const float*)d_in[10];
    const float* bn1_scale = (const float*)d_in[11];
    const float* bn1_shift = (const float*)d_in[12];
    const float* w_ffn2    = (const float*)d_in[13];
    const float* bn2_scale = (const float*)d_in[14];
    const float* bn2_shift = (const float*)d_in[15];
    float* out = (float*)d_out;

    __half *xw16, *qkv16, *o16, *h116, *wq16, *wp16, *w216;
    __nv_bfloat16 *U, *Vh, *Vl;
    float *xmid, *mu, *rs, *Mbuf;
    cudaGetSymbolAddress((void**)&xw16,  g_xw16);
    cudaGetSymbolAddress((void**)&qkv16, g_qkv16);
    cudaGetSymbolAddress((void**)&o16,   g_o16);
    cudaGetSymbolAddress((void**)&xmid,  g_xmid);
    cudaGetSymbolAddress((void**)&mu,    g_mu);
    cudaGetSymbolAddress((void**)&rs,    g_rs);
    cudaGetSymbolAddress((void**)&h116,  g_h116);
    cudaGetSymbolAddress((void**)&wq16,  g_wq16);
    cudaGetSymbolAddress((void**)&wp16,  g_wp16);
    cudaGetSymbolAddress((void**)&w216,  g_w216);
    cudaGetSymbolAddress((void**)&U,  g_U);
    cudaGetSymbolAddress((void**)&Vh, g_Vh); cudaGetSymbolAddress((void**)&Vl, g_Vl);
    cudaGetSymbolAddress((void**)&Mbuf, g_M);

    constexpr int SMSZ = STAGES * (A_STG + 64 * ROWB);   // 76800
    cudaFuncSetAttribute((const void*)gemm_tc<32,2,1,__half>,
                         cudaFuncAttributeMaxDynamicSharedMemorySize, SMSZ);
    cudaFuncSetAttribute((const void*)gemm_tc<32,2,3,__nv_bfloat16>,
                         cudaFuncAttributeMaxDynamicSharedMemorySize, SMSZ);

    // weight preps
    prep_w16<<<(192 * 576 + 255) / 256, 256>>>(w_qkv, wq16, 192, 576);
    prep_w16<<<(192 * 192 + 255) / 256, 256>>>(w_proj, wp16, 192, 192);
    prep_w16<<<(768 * 192 + 255) / 256, 256>>>(w_ffn2, w216, 768, 192);
    wino_wt<<<(CCH * HIDDEN + 255) / 256, 256>>>(w_ffn1, U);

    // LN1 + roll + window partition -> fp16
    ln_kernel<<<MROWS / 8, 256>>>(x, ln1_g, ln1_b, xw16);

    // QKV GEMM [M,192]x[192,576] fp16 -> fp16
    gemm_tc<32,2,1,__half><<<dim3(576 / 64, MROWS / TM), 256, SMSZ>>>(
        xw16, xw16, wq16, b_qkv, nullptr, qkv16, nullptr, nullptr, nullptr,
        576, 192, 6, 0, 0, 0);

    // attention -> fp16
    attn_kernel<<<(MROWS / NTOK) * HEADS, 128>>>(qkv16, bias_tbl, o16);

    // proj GEMM + window reverse + roll + shortcut (fp16)
    gemm_tc<32,2,1,__half><<<dim3(192 / 64, MROWS / TM), 256, SMSZ>>>(
        o16, o16, wp16, b_proj, xmid, nullptr, nullptr, nullptr, x,
        192, 192, 2, 0, 0, 0);

    // LN2 row stats
    ln_stats<<<MROWS / 8, 256>>>(xmid, mu, rs);

    // winograd F(4,3) input transform with fused LN2
    wino_in<<<(NT4 * CCH + 255) / 256, 256>>>(xmid, mu, rs, ln2_g, ln2_b, Vh, Vl);

    // 36 batched transform-domain GEMMs [6400,192]x[192,768] -> M (bf16 3-term)
    gemm_tc<32,2,3,__nv_bfloat16><<<dim3(HIDDEN / 64, NTP / TM, 36), 256, SMSZ>>>(
        Vh, Vl, U, nullptr, Mbuf, nullptr, nullptr, nullptr, nullptr,
        HIDDEN, 192, 5,
        (size_t)NTP * CCH, (size_t)HIDDEN * 576, (size_t)NTP * HIDDEN);

    // winograd output transform + BN + GELU -> h1 fp16
    wino_out<<<(NT4 * HIDDEN + 255) / 256, 256>>>(Mbuf, bn1_scale, bn1_shift, h116);

    // conv1x1 GEMM + BN + residual -> out (fp16 1-term)
    gemm_tc<32,2,1,__half><<<dim3(CCH / 64, MROWS / TM), 256, SMSZ>>>(
        h116, h116, w216, nullptr, out, nullptr, bn2_scale, bn2_shift, xmid,
        CCH, 768, 4, 0, 0, 0);
}

// round 12
// speedup vs baseline: 3.9463x; 1.0077x over previous
#include <cuda_runtime.h>
#include <cuda_bf16.h>
#include <cuda_fp16.h>
#include <cstdint>
#include <math.h>

// ---------------------------------------------------------------------------
// SwinTransformerLayer on GB300, mma.sync tensor cores.
// - QKV / proj / conv1x1 GEMMs: plain fp16 (residual-diluted error ~1e-4 each)
// - conv3x3: Winograd F(4x4,3x3); transform GEMMs bf16 3-term split
//   (C = Ah*Bh + Al*Bh + Ah*Bl, K tripled), fp32 M.  [R11 showed 16-bit
//   anywhere in the winograd chain is amplified ~6-10x by A^T cancellation.]
// - Residual trunk xmid stored fp16 (direct-noise source, ~1.5e-4, no
//   transform amplification).
// Round 12: revert winograd to R10 precision + fp16 trunk.
// ---------------------------------------------------------------------------

#define BATCH   32
#define HH      56
#define WW_     56
#define CCH     192
#define WS      7
#define SHIFT   3
#define HEADS   6
#define HD      32
#define NTOK    49
#define MROWS   (BATCH*HH*WW_)   // 100352
#define HIDDEN  768
#define QKSCALE 0.17677669529663687f
#define NT4     6272             // 32 * 14 * 14 winograd F(4,3) tiles
#define NTP     6400             // padded to multiple of 256

#define TM      256
#define TKB     32               // K elements per stage
#define STAGES  3
#define ROWB    80               // padded row bytes (40 elems) — conflict-free ldmatrix
#define A_STG   (TM*ROWB)        // 20480

// ------------------------- scratch (device globals) ------------------------
__device__ __align__(16) __half        g_xw16 [(size_t)MROWS * CCH];
__device__ __align__(16) __half        g_qkv16[(size_t)MROWS * 3 * CCH];
__device__ __align__(16) __half        g_o16  [(size_t)MROWS * CCH];
__device__ __align__(16) __half        g_xmid [(size_t)MROWS * CCH];   // fp16 trunk
__device__ __align__(16) float         g_mu   [(size_t)MROWS];
__device__ __align__(16) float         g_rs   [(size_t)MROWS];
__device__ __align__(16) __half        g_h116 [(size_t)MROWS * HIDDEN];
// fp16 1-term weights, [N,K]
__device__ __align__(16) __half        g_wq16 [(size_t)576 * 192];
__device__ __align__(16) __half        g_wp16 [(size_t)192 * 192];
__device__ __align__(16) __half        g_w216 [(size_t)192 * 768];
// winograd F(4,3): 36 planes, bf16 3-term
__device__ __align__(16) __nv_bfloat16 g_U  [(size_t)36 * HIDDEN * 576];   // [p][co][3K]
__device__ __align__(16) __nv_bfloat16 g_Vh [(size_t)36 * NTP * CCH];
__device__ __align__(16) __nv_bfloat16 g_Vl [(size_t)36 * NTP * CCH];
__device__ __align__(16) float         g_M  [(size_t)36 * NTP * HIDDEN];   // fp32

// ------------------------------ PTX helpers --------------------------------
__device__ __forceinline__ void cp_async16(uint32_t dst, const void* src, bool full) {
    int sz = full ? 16 : 0;
    asm volatile("cp.async.cg.shared.global [%0], [%1], 16, %2;"
                 :: "r"(dst), "l"(src), "r"(sz) : "memory");
}
#define CP_COMMIT() asm volatile("cp.async.commit_group;" ::: "memory")
#define CP_WAIT(n)  asm volatile("cp.async.wait_group %0;" :: "n"(n) : "memory")

__device__ __forceinline__ void ldsm_x4(uint32_t addr, uint32_t r[4]) {
    asm volatile("ldmatrix.sync.aligned.m8n8.x4.shared.b16 {%0,%1,%2,%3}, [%4];"
                 : "=r"(r[0]), "=r"(r[1]), "=r"(r[2]), "=r"(r[3]) : "r"(addr));
}
template<typename T>
__device__ __forceinline__ void mma_any(float c[4], const uint32_t a[4],
                                        uint32_t b0, uint32_t b1);
template<>
__device__ __forceinline__ void mma_any<__nv_bfloat16>(float c[4], const uint32_t a[4],
                                                       uint32_t b0, uint32_t b1) {
    asm volatile("mma.sync.aligned.m16n8k16.row.col.f32.bf16.bf16.f32 "
                 "{%0,%1,%2,%3}, {%4,%5,%6,%7}, {%8,%9}, {%0,%1,%2,%3};"
                 : "+f"(c[0]), "+f"(c[1]), "+f"(c[2]), "+f"(c[3])
                 : "r"(a[0]), "r"(a[1]), "r"(a[2]), "r"(a[3]), "r"(b0), "r"(b1));
}
template<>
__device__ __forceinline__ void mma_any<__half>(float c[4], const uint32_t a[4],
                                                uint32_t b0, uint32_t b1) {
    asm volatile("mma.sync.aligned.m16n8k16.row.col.f32.f16.f16.f32 "
                 "{%0,%1,%2,%3}, {%4,%5,%6,%7}, {%8,%9}, {%0,%1,%2,%3};"
                 : "+f"(c[0]), "+f"(c[1]), "+f"(c[2]), "+f"(c[3])
                 : "r"(a[0]), "r"(a[1]), "r"(a[2]), "r"(a[3]), "r"(b0), "r"(b1));
}

__device__ __forceinline__ void split_bf16(float v, __nv_bfloat16& hi, __nv_bfloat16& lo) {
    hi = __float2bfloat16(v);
    lo = __float2bfloat16(v - __bfloat162float(hi));
}

// ----------------------------- weight prep ---------------------------------
// W [K,N] fp32 -> D [N,K] fp16 (plain 1-term).
__global__ void prep_w16(const float* __restrict__ W, __half* __restrict__ D,
                         int K, int N)
{
    int i = blockIdx.x * 256 + threadIdx.x;
    if (i >= K * N) return;
    int k = i / N, n = i % N;
    D[(size_t)n * K + k] = __float2half(W[i]);
}

// ----------------------- winograd weight transform --------------------------
// w_ffn1 [3][3][192][768] HWIO -> U[p][co][3K] bf16 3-term, p = 6*r + c.
__global__ void wino_wt(const float* __restrict__ W, __nv_bfloat16* __restrict__ U)
{
    int i = blockIdx.x * 256 + threadIdx.x;
    if (i >= CCH * HIDDEN) return;
    int ci = i % CCH, co = i / CCH;

    float g[3][3];
    #pragma unroll
    for (int ky = 0; ky < 3; ky++)
        #pragma unroll
        for (int kx = 0; kx < 3; kx++)
            g[ky][kx] = W[((size_t)(ky * 3 + kx) * CCH + ci) * HIDDEN + co];

    float u[6][3];
    #pragma unroll
    for (int c = 0; c < 3; c++) {
        float g0 = g[0][c], g1 = g[1][c], g2 = g[2][c];
        u[0][c] = 0.25f * g0;
        u[1][c] = -(g0 + g1 + g2) * (1.0f / 6.0f);
        u[2][c] = (-g0 + g1 - g2) * (1.0f / 6.0f);
        u[3][c] = g0 * (1.0f / 24.0f) + g1 * (1.0f / 12.0f) + g2 * (1.0f / 6.0f);
        u[4][c] = g0 * (1.0f / 24.0f) - g1 * (1.0f / 12.0f) + g2 * (1.0f / 6.0f);
        u[5][c] = g2;
    }
    #pragma unroll
    for (int r = 0; r < 6; r++) {
        float a0 = u[r][0], a1 = u[r][1], a2 = u[r][2];
        float U6[6];
        U6[0] = 0.25f * a0;
        U6[1] = -(a0 + a1 + a2) * (1.0f / 6.0f);
        U6[2] = (-a0 + a1 - a2) * (1.0f / 6.0f);
        U6[3] = a0 * (1.0f / 24.0f) + a1 * (1.0f / 12.0f) + a2 * (1.0f / 6.0f);
        U6[4] = a0 * (1.0f / 24.0f) - a1 * (1.0f / 12.0f) + a2 * (1.0f / 6.0f);
        U6[5] = a2;
        #pragma unroll
        for (int c = 0; c < 6; c++) {
            int p = r * 6 + c;
            __nv_bfloat16 hi, lo;
            split_bf16(U6[c], hi, lo);
            size_t base = ((size_t)p * HIDDEN + co) * 576;
            U[base + ci]       = hi;
            U[base + 192 + ci] = hi;
            U[base + 384 + ci] = lo;
        }
    }
}

// ------------------------ LN row statistics (for LN2) -----------------------
__global__ __launch_bounds__(256)
void ln_stats(const __half* __restrict__ x, float* __restrict__ mu_o,
              float* __restrict__ rs_o)
{
    int m = blockIdx.x * 8 + (threadIdx.x >> 5);
    int lane = threadIdx.x & 31;
    const __half2* src = reinterpret_cast<const __half2*>(x + (size_t)m * CCH);
    float s1 = 0.f, s2 = 0.f;
    #pragma unroll
    for (int q = 0; q < 3; q++) {
        float2 v = __half22float2(src[lane + 32 * q]);
        s1 += v.x + v.y; s2 += v.x * v.x + v.y * v.y;
    }
    #pragma unroll
    for (int o = 16; o > 0; o >>= 1) {
        s1 += __shfl_xor_sync(0xFFFFFFFF, s1, o);
        s2 += __shfl_xor_sync(0xFFFFFFFF, s2, o);
    }
    if (lane == 0) {
        float mu  = s1 * (1.0f / CCH);
        float var = s2 * (1.0f / CCH) - mu * mu;
        mu_o[m] = mu;
        rs_o[m] = rsqrtf(var + 1e-3f);
    }
}

// ----------------- winograd input transform (LN2 fused) ---------------------
__device__ __forceinline__ void bt6(const float d[6], float t[6]) {
    t[0] = 4.f * d[0] - 5.f * d[2] + d[4];
    t[1] = -4.f * d[1] - 4.f * d[2] + d[3] + d[4];
    t[2] = 4.f * d[1] - 4.f * d[2] - d[3] + d[4];
    t[3] = -2.f * d[1] - d[2] + 2.f * d[3] + d[4];
    t[4] = 2.f * d[1] - d[2] - 2.f * d[3] + d[4];
    t[5] = 4.f * d[1] - 5.f * d[3] + d[5];
}

__global__ __launch_bounds__(256)
void wino_in(const __half* __restrict__ x,
             const float* __restrict__ mu,
             const float* __restrict__ rs,
             const float* __restrict__ gamma,
             const float* __restrict__ beta,
             __nv_bfloat16* __restrict__ Vh,
             __nv_bfloat16* __restrict__ Vl)
{
    int i = blockIdx.x * 256 + threadIdx.x;
    if (i >= NT4 * CCH) return;
    int tile = i / CCH, c = i % CCH;
    int b = tile / 196, r = tile % 196, ty = r / 14, tx = r % 14;
    float gm = gamma[c], bt = beta[c];

    float d[6][6];
    #pragma unroll
    for (int ii = 0; ii < 6; ii++) {
        int h = 4 * ty - 1 + ii;
        #pragma unroll
        for (int jj = 0; jj < 6; jj++) {
            int w = 4 * tx - 1 + jj;
            bool ok = (h >= 0) && (h < HH) && (w >= 0) && (w < WW_);
            if (ok) {
                size_t row = (size_t)(b * HH + h) * WW_ + w;
                d[ii][jj] = (__half2float(x[row * CCH + c]) - mu[row]) * rs[row] * gm + bt;
            } else d[ii][jj] = 0.f;
        }
    }
    float t[6][6];
    #pragma unroll
    for (int jj = 0; jj < 6; jj++) {
        float col[6], tc[6];
        #pragma unroll
        for (int ii = 0; ii < 6; ii++) col[ii] = d[ii][jj];
        bt6(col, tc);
        #pragma unroll
        for (int ii = 0; ii < 6; ii++) t[ii][jj] = tc[ii];
    }
    #pragma unroll
    for (int ii = 0; ii < 6; ii++) {
        float V6[6];
        bt6(t[ii], V6);
        #pragma unroll
        for (int jj = 0; jj < 6; jj++) {
            int p = ii * 6 + jj;
            __nv_bfloat16 hi, lo;
            split_bf16(V6[jj], hi, lo);
            size_t idx = ((size_t)p * NTP + tile) * CCH + c;
            Vh[idx] = hi; Vl[idx] = lo;
        }
    }
}

// ----------------------- winograd output transform --------------------------
__device__ __forceinline__ void at6(const float m[6], float s[4]) {
    s[0] = m[0] + m[1] + m[2] + m[3] + m[4];
    s[1] = m[1] - m[2] + 2.f * m[3] - 2.f * m[4];
    s[2] = m[1] + m[2] + 4.f * m[3] + 4.f * m[4];
    s[3] = m[1] - m[2] + 8.f * m[3] - 8.f * m[4] + m[5];
}

__global__ __launch_bounds__(256)
void wino_out(const float* __restrict__ M,
              const float* __restrict__ scale,
              const float* __restrict__ shiftv,
              __half* __restrict__ h116)
{
    int i = blockIdx.x * 256 + threadIdx.x;
    if (i >= NT4 * HIDDEN) return;
    int tile = i / HIDDEN, co = i % HIDDEN;
    int b = tile / 196, r = tile % 196, ty = r / 14, tx = r % 14;

    float m[6][6];
    #pragma unroll
    for (int p = 0; p < 36; p++)
        m[p / 6][p % 6] = M[((size_t)p * NTP + tile) * HIDDEN + co];

    float s[4][6];
    #pragma unroll
    for (int jj = 0; jj < 6; jj++) {
        float col[6], sc4[4];
        #pragma unroll
        for (int ii = 0; ii < 6; ii++) col[ii] = m[ii][jj];
        at6(col, sc4);
        #pragma unroll
        for (int ii = 0; ii < 4; ii++) s[ii][jj] = sc4[ii];
    }
    float sc = scale[co], sh = shiftv[co];
    #pragma unroll
    for (int ii = 0; ii < 4; ii++) {
        float Y4[4];
        at6(s[ii], Y4);
        #pragma unroll
        for (int jj = 0; jj < 4; jj++) {
            float v = Y4[jj] * sc + sh;
            v = 0.5f * v * (1.0f + erff(v * 0.70710678118654752f));
            size_t px = (size_t)b * 3136 + (size_t)(4 * ty + ii) * 56 + (4 * tx + jj);
            h116[px * HIDDEN + co] = __float2half(v);
        }
    }
}

// ------------------------------- LayerNorm (LN1) ----------------------------
__global__ __launch_bounds__(256)
void ln_kernel(const float* __restrict__ x,
               const float* __restrict__ gamma,
               const float* __restrict__ beta,
               __half* __restrict__ out16)
{
    int m = blockIdx.x * 8 + (threadIdx.x >> 5);
    int lane = threadIdx.x & 31;

    int win = m / NTOK, tok = m % NTOK;
    int b  = win >> 6, wi = win & 63;
    int hs = (wi >> 3) * WS + tok / WS;
    int ws = (wi & 7)  * WS + tok % WS;
    int h = hs + SHIFT; if (h >= HH)  h -= HH;
    int w = ws + SHIFT; if (w >= WW_) w -= WW_;
    int src_p = (b * HH + h) * WW_ + w;

    const float* src = x + (size_t)src_p * CCH;
    float v[6];
    float s1 = 0.f, s2 = 0.f;
    #pragma unroll
    for (int q = 0; q < 6; q++) {
        v[q] = src[lane + 32 * q];
        s1 += v[q]; s2 += v[q] * v[q];
    }
    #pragma unroll
    for (int o = 16; o > 0; o >>= 1) {
        s1 += __shfl_xor_sync(0xFFFFFFFF, s1, o);
        s2 += __shfl_xor_sync(0xFFFFFFFF, s2, o);
    }
    float mu  = s1 * (1.0f / CCH);
    float var = s2 * (1.0f / CCH) - mu * mu;
    float rsg = rsqrtf(var + 1e-3f);

    #pragma unroll
    for (int q = 0; q < 6; q++) {
        int c = lane + 32 * q;
        float yv = (v[q] - mu) * rsg * gamma[c] + beta[c];
        out16[(size_t)m * CCH + c] = __float2half(yv);
    }
}

// ------------------------------- Attention ---------------------------------
__global__ void attn_kernel(const __half* __restrict__ qkv,
                            const float* __restrict__ table,
                            __half* __restrict__ o16)
{
    int blk = blockIdx.x;
    int win = blk / HEADS;
    int head = blk % HEADS;
    int tid = threadIdx.x;

    __shared__ float qs[NTOK * HD], ks[NTOK * HD], vs[NTOK * HD];
    __shared__ float S[NTOK * 50];

    for (int t = tid; t < NTOK * HD; t += 128) {
        int n = t >> 5, d = t & 31;
        const __half* base = qkv + (size_t)(win * NTOK + n) * (3 * CCH) + head * HD + d;
        qs[t] = __half2float(base[0]) * QKSCALE;
        ks[t] = __half2float(base[CCH]);
        vs[t] = __half2float(base[2 * CCH]);
    }
    __syncthreads();

    int wi = win & 63;
    int wh = wi >> 3, wwn = wi & 7;

    for (int t = tid; t < NTOK * NTOK; t += 128) {
        int n = t / NTOK, mm = t % NTOK;
        float s = 0.f;
        #pragma unroll
        for (int d = 0; d < HD; d++) s += qs[n * HD + d] * ks[mm * HD + d];
        int rn = n / WS, cn = n % WS, rm = mm / WS, cm = mm % WS;
        int idx = (rn - rm + WS - 1) * (2 * WS - 1) + (cn - cm + WS - 1);
        s += table[idx * HEADS + head];
        int hn = wh * WS + rn, wn = wwn * WS + cn;
        int hm = wh * WS + rm, wm = wwn * WS + cm;
        int reg_n = (hn < 49 ? 0 : (hn < 53 ? 1 : 2)) * 3 + (wn < 49 ? 0 : (wn < 53 ? 1 : 2));
        int reg_m = (hm < 49 ? 0 : (hm < 53 ? 1 : 2)) * 3 + (wm < 49 ? 0 : (wm < 53 ? 1 : 2));
        if (reg_n != reg_m) s -= 100.0f;
        S[n * 50 + mm] = s;
    }
    __syncthreads();

    // warp-per-row softmax
    {
        int w4 = tid >> 5, lane = tid & 31;
        for (int row = w4; row < NTOK; row += 4) {
            float* Sr = S + row * 50;
            float mx = -1e30f;
            for (int c = lane; c < NTOK; c += 32) mx = fmaxf(mx, Sr[c]);
            #pragma unroll
            for (int o = 16; o > 0; o >>= 1)
                mx = fmaxf(mx, __shfl_xor_sync(0xFFFFFFFF, mx, o));
            float sum = 0.f;
            for (int c = lane; c < NTOK; c += 32) {
                float e = __expf(Sr[c] - mx);
                Sr[c] = e; sum += e;
            }
            #pragma unroll
            for (int o = 16; o > 0; o >>= 1)
                sum += __shfl_xor_sync(0xFFFFFFFF, sum, o);
            float inv = 1.0f / sum;
            for (int c = lane; c < NTOK; c += 32) Sr[c] *= inv;
        }
    }
    __syncthreads();

    for (int t = tid; t < NTOK * HD; t += 128) {
        int n = t >> 5, d = t & 31;
        float acc = 0.f;
        #pragma unroll 7
        for (int m2 = 0; m2 < NTOK; m2++) acc += S[n * 50 + m2] * vs[m2 * HD + d];
        size_t idx = (size_t)(win * NTOK + n) * CCH + head * HD + d;
        o16[idx] = __float2half(acc);
    }
}

// ---------------------------- HMMA GEMM ------------------------------------
// SPLIT=1 (fp16): C = A[M,K] x B[K,N] plain.
// SPLIT=3 (bf16): C = A'[M,3K] x B'[3K,N], A' = [Ah|Al|Ah].
// CTA tile 256 x (2*WN), BK=32, 8 warps in 4x2, warp tile 64xWN, mma m16n8k16.
// epi: 2=+bias,remap,+addF(f32) -> f16
//      4=BN,+addH(f16) -> f32
//      5=raw -> f32
//      6=+bias -> f16
template<int WN, int MINCTA, int SPLIT, typename T>
__global__ __launch_bounds__(256, MINCTA)
void gemm_tc(const T* __restrict__ Ah,
             const T* __restrict__ Al,
             const T* __restrict__ Bs,
             const float* __restrict__ bias,
             float* __restrict__ Cf,
             __half* __restrict__ C16,
             const float* __restrict__ scale,
             const float* __restrict__ shiftv,
             const float* __restrict__ addF,
             const __half* __restrict__ addH,
             int N, int K1, int epi,
             size_t zsA, size_t zsB, size_t zsC)
{
    constexpr int TN   = 2 * WN;
    constexpr int NB   = WN / 16;        // B ldsm per ks
    constexpr int NI   = WN / 8;         // n-fragments per warp
    constexpr int B_STG = TN * ROWB;
    constexpr int BPASS = TN / 64;       // B load passes

    Ah += blockIdx.z * zsA;
    Al += blockIdx.z * zsA;
    Bs += blockIdx.z * zsB;
    if (Cf) Cf += blockIdx.z * zsC;

    extern __shared__ char smem[];
    uint32_t sA0 = (uint32_t)__cvta_generic_to_shared(smem);
    uint32_t sB0 = sA0 + STAGES * A_STG;

    int tid = threadIdx.x;
    int wid = tid >> 5, lid = tid & 31;
    int wr = wid >> 1, wc = wid & 1;
    int m0 = blockIdx.y * TM, n0 = blockIdx.x * TN;
    int KS = SPLIT * K1;
    int nk = KS / TKB;

    int arow = tid >> 2;          // + p*64, p<4
    int aj = tid & 3;             // 16B chunk within 64B row payload
    size_t arowoff[4];
    #pragma unroll
    for (int p = 0; p < 4; p++) arowoff[p] = (size_t)(m0 + arow + p * 64) * K1;
    size_t browoff[BPASS];
    #pragma unroll
    for (int p = 0; p < BPASS; p++)
        browoff[p] = (size_t)(n0 + arow + p * 64) * KS;

    float acc[4][NI][4];
    #pragma unroll
    for (int i = 0; i < 4; i++)
        #pragma unroll
        for (int j = 0; j < NI; j++)
            #pragma unroll
            for (int q = 0; q < 4; q++) acc[i][j][q] = 0.f;

    auto load_stage = [&](int kt) {
        int s = kt % STAGES;
        int k3 = kt * TKB;
        int seg = k3 / K1;
        int kk = k3 - seg * K1;
        const T* Asrc = (SPLIT == 3 && seg == 1) ? Al : Ah;
        #pragma unroll
        for (int p = 0; p < 4; p++) {
            uint32_t dst = sA0 + s * A_STG + (arow + p * 64) * ROWB + aj * 16;
            cp_async16(dst, Asrc + arowoff[p] + kk + aj * 8, true);
        }
        #pragma unroll
        for (int p = 0; p < BPASS; p++) {
            uint32_t dst = sB0 + s * B_STG + (arow + p * 64) * ROWB + aj * 16;
            cp_async16(dst, Bs + browoff[p] + k3 + aj * 8, true);
        }
    };

    auto compute = [&](int s) {
        uint32_t aBase = sA0 + s * A_STG + (wr * 64 + (lid & 15)) * ROWB + (lid >> 4) * 16;
        uint32_t bBase = sB0 + s * B_STG
                       + (wc * WN + (lid & 7) + ((lid >> 4) << 3)) * ROWB
                       + ((lid >> 3) & 1) * 16;
        #pragma unroll
        for (int ks = 0; ks < 2; ks++) {
            uint32_t a[4][4], b[NB][4];
            #pragma unroll
            for (int mi = 0; mi < 4; mi++)
                ldsm_x4(aBase + mi * 16 * ROWB + ks * 32, a[mi]);
            #pragma unroll
            for (int bi = 0; bi < NB; bi++)
                ldsm_x4(bBase + bi * 16 * ROWB + ks * 32, b[bi]);
            #pragma unroll
            for (int mi = 0; mi < 4; mi++)
                #pragma unroll
                for (int ni = 0; ni < NI; ni++)
                    mma_any<T>(acc[mi][ni], a[mi],
                               b[ni >> 1][(ni & 1) * 2], b[ni >> 1][(ni & 1) * 2 + 1]);
        }
    };

    #pragma unroll
    for (int p = 0; p < STAGES - 1; p++) { if (p < nk) load_stage(p); CP_COMMIT(); }

    for (int kt = 0; kt < nk; kt++) {
        CP_WAIT(STAGES - 2);
        __syncthreads();
        if (kt + STAGES - 1 < nk) load_stage(kt + STAGES - 1);
        CP_COMMIT();
        compute(kt % STAGES);
    }

    // ------------------------------ epilogue -------------------------------
    int g = lid >> 2, t2 = (lid & 3) * 2;
    #pragma unroll
    for (int mi = 0; mi < 4; mi++) {
        #pragma unroll
        for (int rr = 0; rr < 2; rr++) {
            int m = m0 + wr * 64 + mi * 16 + g + rr * 8;
            size_t orow;
            if (epi == 2) {
                int win = m / NTOK, tok = m % NTOK;
                int b = win >> 6, wi2 = win & 63;
                int hs = (wi2 >> 3) * WS + tok / WS;
                int ws = (wi2 & 7)  * WS + tok % WS;
                int h = hs + SHIFT; if (h >= HH)  h -= HH;
                int w = ws + SHIFT; if (w >= WW_) w -= WW_;
                orow = (size_t)(b * HH + h) * WW_ + w;
            } else {
                orow = (size_t)m;
            }
            #pragma unroll
            for (int ni = 0; ni < NI; ni++) {
                int n = n0 + wc * WN + ni * 8 + t2;
                float v0 = acc[mi][ni][rr * 2 + 0];
                float v1 = acc[mi][ni][rr * 2 + 1];
                if (epi == 6) {
                    __half2 o;
                    o.x = __float2half(v0 + bias[n]);
                    o.y = __float2half(v1 + bias[n + 1]);
                    *reinterpret_cast<__half2*>(C16 + (size_t)m * N + n) = o;
                } else if (epi == 2) {
                    size_t oi = orow * CCH + n;
                    float2 a4 = *reinterpret_cast<const float2*>(addF + oi);
                    __half2 o;
                    o.x = __float2half(v0 + bias[n] + a4.x);
                    o.y = __float2half(v1 + bias[n + 1] + a4.y);
                    *reinterpret_cast<__half2*>(C16 + oi) = o;
                } else if (epi == 4) {
                    size_t oi = (size_t)m * CCH + n;
                    float2 a4 = __half22float2(
                        *reinterpret_cast<const __half2*>(addH + oi));
                    float2 o = { v0 * scale[n] + shiftv[n] + a4.x,
                                 v1 * scale[n + 1] + shiftv[n + 1] + a4.y };
                    *reinterpret_cast<float2*>(Cf + oi) = o;
                } else {  // epi == 5: raw fp32
                    float2 o = { v0, v1 };
                    *reinterpret_cast<float2*>(Cf + (size_t)m * N + n) = o;
                }
            }
        }
    }
}

// ------------------------------- launcher -----------------------------------
extern "C" void kernel_launch(void* const* d_in, const int* in_sizes, int n_in,
                              void* d_out, int out_size)
{
    const float* x         = (const float*)d_in[0];
    const float* ln1_g     = (const float*)d_in[1];
    const float* ln1_b     = (const float*)d_in[2];
    const float* w_qkv     = (const float*)d_in[3];
    const float* b_qkv     = (const float*)d_in[4];
    const float* bias_tbl  = (const float*)d_in[5];
    const float* w_proj    = (const float*)d_in[6];
    const float* b_proj    = (const float*)d_in[7];
    const float* ln2_g     = (const float*)d_in[8];
    const float* ln2_b     = (const float*)d_in[9];
    const float* w_ffn1    = (const float*)d_in[10];
    const float* bn1_scale = (const float*)d_in[11];
    const float* bn1_shift = (const float*)d_in[12];
    const float* w_ffn2    = (const float*)d_in[13];
    const float* bn2_scale = (const float*)d_in[14];
    const float* bn2_shift = (const float*)d_in[15];
    float* out = (float*)d_out;

    __half *xw16, *qkv16, *o16, *xmid16, *h116, *wq16, *wp16, *w216;
    __nv_bfloat16 *U, *Vh, *Vl;
    float *mu, *rs, *Mbuf;
    cudaGetSymbolAddress((void**)&xw16,   g_xw16);
    cudaGetSymbolAddress((void**)&qkv16,  g_qkv16);
    cudaGetSymbolAddress((void**)&o16,    g_o16);
    cudaGetSymbolAddress((void**)&xmid16, g_xmid);
    cudaGetSymbolAddress((void**)&mu,     g_mu);
    cudaGetSymbolAddress((void**)&rs,     g_rs);
    cudaGetSymbolAddress((void**)&h116,   g_h116);
    cudaGetSymbolAddress((void**)&wq16,   g_wq16);
    cudaGetSymbolAddress((void**)&wp16,   g_wp16);
    cudaGetSymbolAddress((void**)&w216,   g_w216);
    cudaGetSymbolAddress((void**)&U,  g_U);
    cudaGetSymbolAddress((void**)&Vh, g_Vh); cudaGetSymbolAddress((void**)&Vl, g_Vl);
    cudaGetSymbolAddress((void**)&Mbuf, g_M);

    constexpr int SMSZ = STAGES * (A_STG + 64 * ROWB);   // 76800
    cudaFuncSetAttribute((const void*)gemm_tc<32,2,1,__half>,
                         cudaFuncAttributeMaxDynamicSharedMemorySize, SMSZ);
    cudaFuncSetAttribute((const void*)gemm_tc<32,2,3,__nv_bfloat16>,
                         cudaFuncAttributeMaxDynamicSharedMemorySize, SMSZ);

    // weight preps
    prep_w16<<<(192 * 576 + 255) / 256, 256>>>(w_qkv, wq16, 192, 576);
    prep_w16<<<(192 * 192 + 255) / 256, 256>>>(w_proj, wp16, 192, 192);
    prep_w16<<<(768 * 192 + 255) / 256, 256>>>(w_ffn2, w216, 768, 192);
    wino_wt<<<(CCH * HIDDEN + 255) / 256, 256>>>(w_ffn1, U);

    // LN1 + roll + window partition -> fp16
    ln_kernel<<<MROWS / 8, 256>>>(x, ln1_g, ln1_b, xw16);

    // QKV GEMM [M,192]x[192,576] fp16 -> fp16
    gemm_tc<32,2,1,__half><<<dim3(576 / 64, MROWS / TM), 256, SMSZ>>>(
        xw16, xw16, wq16, b_qkv, nullptr, qkv16, nullptr, nullptr, nullptr, nullptr,
        576, 192, 6, 0, 0, 0);

    // attention -> fp16
    attn_kernel<<<(MROWS / NTOK) * HEADS, 128>>>(qkv16, bias_tbl, o16);

    // proj GEMM + window reverse + roll + shortcut(x fp32) -> fp16 trunk
    gemm_tc<32,2,1,__half><<<dim3(192 / 64, MROWS / TM), 256, SMSZ>>>(
        o16, o16, wp16, b_proj, nullptr, xmid16, nullptr, nullptr, x, nullptr,
        192, 192, 2, 0, 0, 0);

    // LN2 row stats (fp16 trunk)
    ln_stats<<<MROWS / 8, 256>>>(xmid16, mu, rs);

    // winograd F(4,3) input transform with fused LN2 -> bf16 hi/lo
    wino_in<<<(NT4 * CCH + 255) / 256, 256>>>(xmid16, mu, rs, ln2_g, ln2_b, Vh, Vl);

    // 36 batched transform-domain GEMMs [6400,192]x[192,768] -> fp32 M (bf16 3-term)
    gemm_tc<32,2,3,__nv_bfloat16><<<dim3(HIDDEN / 64, NTP / TM, 36), 256, SMSZ>>>(
        Vh, Vl, U, nullptr, Mbuf, nullptr, nullptr, nullptr, nullptr, nullptr,
        HIDDEN, 192, 5,
        (size_t)NTP * CCH, (size_t)HIDDEN * 576, (size_t)NTP * HIDDEN);

    // winograd output transform + BN + GELU -> h1 fp16
    wino_out<<<(NT4 * HIDDEN + 255) / 256, 256>>>(Mbuf, bn1_scale, bn1_shift, h116);

    // conv1x1 GEMM + BN + residual(fp16 trunk) -> out fp32
    gemm_tc<32,2,1,__half><<<dim3(CCH / 64, MROWS / TM), 256, SMSZ>>>(
        h116, h116, w216, nullptr, out, nullptr, bn2_scale, bn2_shift, nullptr, xmid16,
        CCH, 768, 4, 0, 0, 0);
}

// round 13
// speedup vs baseline: 5.1604x; 1.3077x over previous
#include <cuda_runtime.h>
#include <cuda_bf16.h>
#include <cuda_fp16.h>
#include <cstdint>
#include <math.h>

// ---------------------------------------------------------------------------
// SwinTransformerLayer on GB300, mma.sync tensor cores.
// - QKV / proj / conv1x1 GEMMs: plain fp16 (residual-diluted error ~1e-4 each)
// - conv3x3: Winograd F(4x4,3x3); transform GEMMs bf16 3-term split, fp32 M
//   (16-bit anywhere in the winograd chain is amplified ~6-10x by A^T
//    cancellation — locked per R11).
// - fp16 residual trunk.
// Round 13: attention QK smem bank-conflict fix (stride 32 -> 33).
// ---------------------------------------------------------------------------

#define BATCH   32
#define HH      56
#define WW_     56
#define CCH     192
#define WS      7
#define SHIFT   3
#define HEADS   6
#define HD      32
#define NTOK    49
#define MROWS   (BATCH*HH*WW_)   // 100352
#define HIDDEN  768
#define QKSCALE 0.17677669529663687f
#define NT4     6272             // 32 * 14 * 14 winograd F(4,3) tiles
#define NTP     6400             // padded to multiple of 256

#define TM      256
#define TKB     32               // K elements per stage
#define STAGES  3
#define ROWB    80               // padded row bytes (40 elems) — conflict-free ldmatrix
#define A_STG   (TM*ROWB)        // 20480

// ------------------------- scratch (device globals) ------------------------
__device__ __align__(16) __half        g_xw16 [(size_t)MROWS * CCH];
__device__ __align__(16) __half        g_qkv16[(size_t)MROWS * 3 * CCH];
__device__ __align__(16) __half        g_o16  [(size_t)MROWS * CCH];
__device__ __align__(16) __half        g_xmid [(size_t)MROWS * CCH];   // fp16 trunk
__device__ __align__(16) float         g_mu   [(size_t)MROWS];
__device__ __align__(16) float         g_rs   [(size_t)MROWS];
__device__ __align__(16) __half        g_h116 [(size_t)MROWS * HIDDEN];
// fp16 1-term weights, [N,K]
__device__ __align__(16) __half        g_wq16 [(size_t)576 * 192];
__device__ __align__(16) __half        g_wp16 [(size_t)192 * 192];
__device__ __align__(16) __half        g_w216 [(size_t)192 * 768];
// winograd F(4,3): 36 planes, bf16 3-term
__device__ __align__(16) __nv_bfloat16 g_U  [(size_t)36 * HIDDEN * 576];   // [p][co][3K]
__device__ __align__(16) __nv_bfloat16 g_Vh [(size_t)36 * NTP * CCH];
__device__ __align__(16) __nv_bfloat16 g_Vl [(size_t)36 * NTP * CCH];
__device__ __align__(16) float         g_M  [(size_t)36 * NTP * HIDDEN];   // fp32

// ------------------------------ PTX helpers --------------------------------
__device__ __forceinline__ void cp_async16(uint32_t dst, const void* src, bool full) {
    int sz = full ? 16 : 0;
    asm volatile("cp.async.cg.shared.global [%0], [%1], 16, %2;"
                 :: "r"(dst), "l"(src), "r"(sz) : "memory");
}
#define CP_COMMIT() asm volatile("cp.async.commit_group;" ::: "memory")
#define CP_WAIT(n)  asm volatile("cp.async.wait_group %0;" :: "n"(n) : "memory")

__device__ __forceinline__ void ldsm_x4(uint32_t addr, uint32_t r[4]) {
    asm volatile("ldmatrix.sync.aligned.m8n8.x4.shared.b16 {%0,%1,%2,%3}, [%4];"
                 : "=r"(r[0]), "=r"(r[1]), "=r"(r[2]), "=r"(r[3]) : "r"(addr));
}
template<typename T>
__device__ __forceinline__ void mma_any(float c[4], const uint32_t a[4],
                                        uint32_t b0, uint32_t b1);
template<>
__device__ __forceinline__ void mma_any<__nv_bfloat16>(float c[4], const uint32_t a[4],
                                                       uint32_t b0, uint32_t b1) {
    asm volatile("mma.sync.aligned.m16n8k16.row.col.f32.bf16.bf16.f32 "
                 "{%0,%1,%2,%3}, {%4,%5,%6,%7}, {%8,%9}, {%0,%1,%2,%3};"
                 : "+f"(c[0]), "+f"(c[1]), "+f"(c[2]), "+f"(c[3])
                 : "r"(a[0]), "r"(a[1]), "r"(a[2]), "r"(a[3]), "r"(b0), "r"(b1));
}
template<>
__device__ __forceinline__ void mma_any<__half>(float c[4], const uint32_t a[4],
                                                uint32_t b0, uint32_t b1) {
    asm volatile("mma.sync.aligned.m16n8k16.row.col.f32.f16.f16.f32 "
                 "{%0,%1,%2,%3}, {%4,%5,%6,%7}, {%8,%9}, {%0,%1,%2,%3};"
                 : "+f"(c[0]), "+f"(c[1]), "+f"(c[2]), "+f"(c[3])
                 : "r"(a[0]), "r"(a[1]), "r"(a[2]), "r"(a[3]), "r"(b0), "r"(b1));
}

__device__ __forceinline__ void split_bf16(float v, __nv_bfloat16& hi, __nv_bfloat16& lo) {
    hi = __float2bfloat16(v);
    lo = __float2bfloat16(v - __bfloat162float(hi));
}

// ----------------------------- weight prep ---------------------------------
__global__ void prep_w16(const float* __restrict__ W, __half* __restrict__ D,
                         int K, int N)
{
    int i = blockIdx.x * 256 + threadIdx.x;
    if (i >= K * N) return;
    int k = i / N, n = i % N;
    D[(size_t)n * K + k] = __float2half(W[i]);
}

// ----------------------- winograd weight transform --------------------------
__global__ void wino_wt(const float* __restrict__ W, __nv_bfloat16* __restrict__ U)
{
    int i = blockIdx.x * 256 + threadIdx.x;
    if (i >= CCH * HIDDEN) return;
    int ci = i % CCH, co = i / CCH;

    float g[3][3];
    #pragma unroll
    for (int ky = 0; ky < 3; ky++)
        #pragma unroll
        for (int kx = 0; kx < 3; kx++)
            g[ky][kx] = W[((size_t)(ky * 3 + kx) * CCH + ci) * HIDDEN + co];

    float u[6][3];
    #pragma unroll
    for (int c = 0; c < 3; c++) {
        float g0 = g[0][c], g1 = g[1][c], g2 = g[2][c];
        u[0][c] = 0.25f * g0;
        u[1][c] = -(g0 + g1 + g2) * (1.0f / 6.0f);
        u[2][c] = (-g0 + g1 - g2) * (1.0f / 6.0f);
        u[3][c] = g0 * (1.0f / 24.0f) + g1 * (1.0f / 12.0f) + g2 * (1.0f / 6.0f);
        u[4][c] = g0 * (1.0f / 24.0f) - g1 * (1.0f / 12.0f) + g2 * (1.0f / 6.0f);
        u[5][c] = g2;
    }
    #pragma unroll
    for (int r = 0; r < 6; r++) {
        float a0 = u[r][0], a1 = u[r][1], a2 = u[r][2];
        float U6[6];
        U6[0] = 0.25f * a0;
        U6[1] = -(a0 + a1 + a2) * (1.0f / 6.0f);
        U6[2] = (-a0 + a1 - a2) * (1.0f / 6.0f);
        U6[3] = a0 * (1.0f / 24.0f) + a1 * (1.0f / 12.0f) + a2 * (1.0f / 6.0f);
        U6[4] = a0 * (1.0f / 24.0f) - a1 * (1.0f / 12.0f) + a2 * (1.0f / 6.0f);
        U6[5] = a2;
        #pragma unroll
        for (int c = 0; c < 6; c++) {
            int p = r * 6 + c;
            __nv_bfloat16 hi, lo;
            split_bf16(U6[c], hi, lo);
            size_t base = ((size_t)p * HIDDEN + co) * 576;
            U[base + ci]       = hi;
            U[base + 192 + ci] = hi;
            U[base + 384 + ci] = lo;
        }
    }
}

// ------------------------ LN row statistics (for LN2) -----------------------
__global__ __launch_bounds__(256)
void ln_stats(const __half* __restrict__ x, float* __restrict__ mu_o,
              float* __restrict__ rs_o)
{
    int m = blockIdx.x * 8 + (threadIdx.x >> 5);
    int lane = threadIdx.x & 31;
    const __half2* src = reinterpret_cast<const __half2*>(x + (size_t)m * CCH);
    float s1 = 0.f, s2 = 0.f;
    #pragma unroll
    for (int q = 0; q < 3; q++) {
        float2 v = __half22float2(src[lane + 32 * q]);
        s1 += v.x + v.y; s2 += v.x * v.x + v.y * v.y;
    }
    #pragma unroll
    for (int o = 16; o > 0; o >>= 1) {
        s1 += __shfl_xor_sync(0xFFFFFFFF, s1, o);
        s2 += __shfl_xor_sync(0xFFFFFFFF, s2, o);
    }
    if (lane == 0) {
        float mu  = s1 * (1.0f / CCH);
        float var = s2 * (1.0f / CCH) - mu * mu;
        mu_o[m] = mu;
        rs_o[m] = rsqrtf(var + 1e-3f);
    }
}

// ----------------- winograd input transform (LN2 fused) ---------------------
__device__ __forceinline__ void bt6(const float d[6], float t[6]) {
    t[0] = 4.f * d[0] - 5.f * d[2] + d[4];
    t[1] = -4.f * d[1] - 4.f * d[2] + d[3] + d[4];
    t[2] = 4.f * d[1] - 4.f * d[2] - d[3] + d[4];
    t[3] = -2.f * d[1] - d[2] + 2.f * d[3] + d[4];
    t[4] = 2.f * d[1] - d[2] - 2.f * d[3] + d[4];
    t[5] = 4.f * d[1] - 5.f * d[3] + d[5];
}

__global__ __launch_bounds__(256)
void wino_in(const __half* __restrict__ x,
             const float* __restrict__ mu,
             const float* __restrict__ rs,
             const float* __restrict__ gamma,
             const float* __restrict__ beta,
             __nv_bfloat16* __restrict__ Vh,
             __nv_bfloat16* __restrict__ Vl)
{
    int i = blockIdx.x * 256 + threadIdx.x;
    if (i >= NT4 * CCH) return;
    int tile = i / CCH, c = i % CCH;
    int b = tile / 196, r = tile % 196, ty = r / 14, tx = r % 14;
    float gm = gamma[c], bt = beta[c];

    float d[6][6];
    #pragma unroll
    for (int ii = 0; ii < 6; ii++) {
        int h = 4 * ty - 1 + ii;
        #pragma unroll
        for (int jj = 0; jj < 6; jj++) {
            int w = 4 * tx - 1 + jj;
            bool ok = (h >= 0) && (h < HH) && (w >= 0) && (w < WW_);
            if (ok) {
                size_t row = (size_t)(b * HH + h) * WW_ + w;
                d[ii][jj] = (__half2float(x[row * CCH + c]) - mu[row]) * rs[row] * gm + bt;
            } else d[ii][jj] = 0.f;
        }
    }
    float t[6][6];
    #pragma unroll
    for (int jj = 0; jj < 6; jj++) {
        float col[6], tc[6];
        #pragma unroll
        for (int ii = 0; ii < 6; ii++) col[ii] = d[ii][jj];
        bt6(col, tc);
        #pragma unroll
        for (int ii = 0; ii < 6; ii++) t[ii][jj] = tc[ii];
    }
    #pragma unroll
    for (int ii = 0; ii < 6; ii++) {
        float V6[6];
        bt6(t[ii], V6);
        #pragma unroll
        for (int jj = 0; jj < 6; jj++) {
            int p = ii * 6 + jj;
            __nv_bfloat16 hi, lo;
            split_bf16(V6[jj], hi, lo);
            size_t idx = ((size_t)p * NTP + tile) * CCH + c;
            Vh[idx] = hi; Vl[idx] = lo;
        }
    }
}

// ----------------------- winograd output transform --------------------------
__device__ __forceinline__ void at6(const float m[6], float s[4]) {
    s[0] = m[0] + m[1] + m[2] + m[3] + m[4];
    s[1] = m[1] - m[2] + 2.f * m[3] - 2.f * m[4];
    s[2] = m[1] + m[2] + 4.f * m[3] + 4.f * m[4];
    s[3] = m[1] - m[2] + 8.f * m[3] - 8.f * m[4] + m[5];
}

__global__ __launch_bounds__(256)
void wino_out(const float* __restrict__ M,
              const float* __restrict__ scale,
              const float* __restrict__ shiftv,
              __half* __restrict__ h116)
{
    int i = blockIdx.x * 256 + threadIdx.x;
    if (i >= NT4 * HIDDEN) return;
    int tile = i / HIDDEN, co = i % HIDDEN;
    int b = tile / 196, r = tile % 196, ty = r / 14, tx = r % 14;

    float m[6][6];
    #pragma unroll
    for (int p = 0; p < 36; p++)
        m[p / 6][p % 6] = M[((size_t)p * NTP + tile) * HIDDEN + co];

    float s[4][6];
    #pragma unroll
    for (int jj = 0; jj < 6; jj++) {
        float col[6], sc4[4];
        #pragma unroll
        for (int ii = 0; ii < 6; ii++) col[ii] = m[ii][jj];
        at6(col, sc4);
        #pragma unroll
        for (int ii = 0; ii < 4; ii++) s[ii][jj] = sc4[ii];
    }
    float sc = scale[co], sh = shiftv[co];
    #pragma unroll
    for (int ii = 0; ii < 4; ii++) {
        float Y4[4];
        at6(s[ii], Y4);
        #pragma unroll
        for (int jj = 0; jj < 4; jj++) {
            float v = Y4[jj] * sc + sh;
            v = 0.5f * v * (1.0f + erff(v * 0.70710678118654752f));
            size_t px = (size_t)b * 3136 + (size_t)(4 * ty + ii) * 56 + (4 * tx + jj);
            h116[px * HIDDEN + co] = __float2half(v);
        }
    }
}

// ------------------------------- LayerNorm (LN1) ----------------------------
__global__ __launch_bounds__(256)
void ln_kernel(const float* __restrict__ x,
               const float* __restrict__ gamma,
               const float* __restrict__ beta,
               __half* __restrict__ out16)
{
    int m = blockIdx.x * 8 + (threadIdx.x >> 5);
    int lane = threadIdx.x & 31;

    int win = m / NTOK, tok = m % NTOK;
    int b  = win >> 6, wi = win & 63;
    int hs = (wi >> 3) * WS + tok / WS;
    int ws = (wi & 7)  * WS + tok % WS;
    int h = hs + SHIFT; if (h >= HH)  h -= HH;
    int w = ws + SHIFT; if (w >= WW_) w -= WW_;
    int src_p = (b * HH + h) * WW_ + w;

    const float* src = x + (size_t)src_p * CCH;
    float v[6];
    float s1 = 0.f, s2 = 0.f;
    #pragma unroll
    for (int q = 0; q < 6; q++) {
        v[q] = src[lane + 32 * q];
        s1 += v[q]; s2 += v[q] * v[q];
    }
    #pragma unroll
    for (int o = 16; o > 0; o >>= 1) {
        s1 += __shfl_xor_sync(0xFFFFFFFF, s1, o);
        s2 += __shfl_xor_sync(0xFFFFFFFF, s2, o);
    }
    float mu  = s1 * (1.0f / CCH);
    float var = s2 * (1.0f / CCH) - mu * mu;
    float rsg = rsqrtf(var + 1e-3f);

    #pragma unroll
    for (int q = 0; q < 6; q++) {
        int c = lane + 32 * q;
        float yv = (v[q] - mu) * rsg * gamma[c] + beta[c];
        out16[(size_t)m * CCH + c] = __float2half(yv);
    }
}

// ------------------------------- Attention ---------------------------------
// qs/ks padded to stride 33 floats: in the QK loop lanes read ks rows at
// lane-varying row index, so a 32-float stride puts every lane in the SAME
// bank (32-way conflict). 33 -> all distinct banks.
#define QKP 33
__global__ void attn_kernel(const __half* __restrict__ qkv,
                            const float* __restrict__ table,
                            __half* __restrict__ o16)
{
    int blk = blockIdx.x;
    int win = blk / HEADS;
    int head = blk % HEADS;
    int tid = threadIdx.x;

    __shared__ float qs[NTOK * QKP], ks[NTOK * QKP], vs[NTOK * HD];
    __shared__ float S[NTOK * 50];

    for (int t = tid; t < NTOK * HD; t += 128) {
        int n = t >> 5, d = t & 31;
        const __half* base = qkv + (size_t)(win * NTOK + n) * (3 * CCH) + head * HD + d;
        qs[n * QKP + d] = __half2float(base[0]) * QKSCALE;
        ks[n * QKP + d] = __half2float(base[CCH]);
        vs[t] = __half2float(base[2 * CCH]);
    }
    __syncthreads();

    int wi = win & 63;
    int wh = wi >> 3, wwn = wi & 7;

    for (int t = tid; t < NTOK * NTOK; t += 128) {
        int n = t / NTOK, mm = t % NTOK;
        float s = 0.f;
        #pragma unroll
        for (int d = 0; d < HD; d++) s += qs[n * QKP + d] * ks[mm * QKP + d];
        int rn = n / WS, cn = n % WS, rm = mm / WS, cm = mm % WS;
        int idx = (rn - rm + WS - 1) * (2 * WS - 1) + (cn - cm + WS - 1);
        s += table[idx * HEADS + head];
        int hn = wh * WS + rn, wn = wwn * WS + cn;
        int hm = wh * WS + rm, wm = wwn * WS + cm;
        int reg_n = (hn < 49 ? 0 : (hn < 53 ? 1 : 2)) * 3 + (wn < 49 ? 0 : (wn < 53 ? 1 : 2));
        int reg_m = (hm < 49 ? 0 : (hm < 53 ? 1 : 2)) * 3 + (wm < 49 ? 0 : (wm < 53 ? 1 : 2));
        if (reg_n != reg_m) s -= 100.0f;
        S[n * 50 + mm] = s;
    }
    __syncthreads();

    // warp-per-row softmax
    {
        int w4 = tid >> 5, lane = tid & 31;
        for (int row = w4; row < NTOK; row += 4) {
            float* Sr = S + row * 50;
            float mx = -1e30f;
            for (int c = lane; c < NTOK; c += 32) mx = fmaxf(mx, Sr[c]);
            #pragma unroll
            for (int o = 16; o > 0; o >>= 1)
                mx = fmaxf(mx, __shfl_xor_sync(0xFFFFFFFF, mx, o));
            float sum = 0.f;
            for (int c = lane; c < NTOK; c += 32) {
                float e = __expf(Sr[c] - mx);
                Sr[c] = e; sum += e;
            }
            #pragma unroll
            for (int o = 16; o > 0; o >>= 1)
                sum += __shfl_xor_sync(0xFFFFFFFF, sum, o);
            float inv = 1.0f / sum;
            for (int c = lane; c < NTOK; c += 32) Sr[c] *= inv;
        }
    }
    __syncthreads();

    for (int t = tid; t < NTOK * HD; t += 128) {
        int n = t >> 5, d = t & 31;
        float acc = 0.f;
        #pragma unroll 7
        for (int m2 = 0; m2 < NTOK; m2++) acc += S[n * 50 + m2] * vs[m2 * HD + d];
        size_t idx = (size_t)(win * NTOK + n) * CCH + head * HD + d;
        o16[idx] = __float2half(acc);
    }
}

// ---------------------------- HMMA GEMM ------------------------------------
// SPLIT=1 (fp16): C = A[M,K] x B[K,N] plain.
// SPLIT=3 (bf16): C = A'[M,3K] x B'[3K,N], A' = [Ah|Al|Ah].
// epi: 2=+bias,remap,+addF(f32) -> f16   4=BN,+addH(f16) -> f32
//      5=raw -> f32                       6=+bias -> f16
template<int WN, int MINCTA, int SPLIT, typename T>
__global__ __launch_bounds__(256, MINCTA)
void gemm_tc(const T* __restrict__ Ah,
             const T* __restrict__ Al,
             const T* __restrict__ Bs,
             const float* __restrict__ bias,
             float* __restrict__ Cf,
             __half* __restrict__ C16,
             const float* __restrict__ scale,
             const float* __restrict__ shiftv,
             const float* __restrict__ addF,
             const __half* __restrict__ addH,
             int N, int K1, int epi,
             size_t zsA, size_t zsB, size_t zsC)
{
    constexpr int TN   = 2 * WN;
    constexpr int NB   = WN / 16;
    constexpr int NI   = WN / 8;
    constexpr int B_STG = TN * ROWB;
    constexpr int BPASS = TN / 64;

    Ah += blockIdx.z * zsA;
    Al += blockIdx.z * zsA;
    Bs += blockIdx.z * zsB;
    if (Cf) Cf += blockIdx.z * zsC;

    extern __shared__ char smem[];
    uint32_t sA0 = (uint32_t)__cvta_generic_to_shared(smem);
    uint32_t sB0 = sA0 + STAGES * A_STG;

    int tid = threadIdx.x;
    int wid = tid >> 5, lid = tid & 31;
    int wr = wid >> 1, wc = wid & 1;
    int m0 = blockIdx.y * TM, n0 = blockIdx.x * TN;
    int KS = SPLIT * K1;
    int nk = KS / TKB;

    int arow = tid >> 2;
    int aj = tid & 3;
    size_t arowoff[4];
    #pragma unroll
    for (int p = 0; p < 4; p++) arowoff[p] = (size_t)(m0 + arow + p * 64) * K1;
    size_t browoff[BPASS];
    #pragma unroll
    for (int p = 0; p < BPASS; p++)
        browoff[p] = (size_t)(n0 + arow + p * 64) * KS;

    float acc[4][NI][4];
    #pragma unroll
    for (int i = 0; i < 4; i++)
        #pragma unroll
        for (int j = 0; j < NI; j++)
            #pragma unroll
            for (int q = 0; q < 4; q++) acc[i][j][q] = 0.f;

    auto load_stage = [&](int kt) {
        int s = kt % STAGES;
        int k3 = kt * TKB;
        int seg = k3 / K1;
        int kk = k3 - seg * K1;
        const T* Asrc = (SPLIT == 3 && seg == 1) ? Al : Ah;
        #pragma unroll
        for (int p = 0; p < 4; p++) {
            uint32_t dst = sA0 + s * A_STG + (arow + p * 64) * ROWB + aj * 16;
            cp_async16(dst, Asrc + arowoff[p] + kk + aj * 8, true);
        }
        #pragma unroll
        for (int p = 0; p < BPASS; p++) {
            uint32_t dst = sB0 + s * B_STG + (arow + p * 64) * ROWB + aj * 16;
            cp_async16(dst, Bs + browoff[p] + k3 + aj * 8, true);
        }
    };

    auto compute = [&](int s) {
        uint32_t aBase = sA0 + s * A_STG + (wr * 64 + (lid & 15)) * ROWB + (lid >> 4) * 16;
        uint32_t bBase = sB0 + s * B_STG
                       + (wc * WN + (lid & 7) + ((lid >> 4) << 3)) * ROWB
                       + ((lid >> 3) & 1) * 16;
        #pragma unroll
        for (int ks = 0; ks < 2; ks++) {
            uint32_t a[4][4], b[NB][4];
            #pragma unroll
            for (int mi = 0; mi < 4; mi++)
                ldsm_x4(aBase + mi * 16 * ROWB + ks * 32, a[mi]);
            #pragma unroll
            for (int bi = 0; bi < NB; bi++)
                ldsm_x4(bBase + bi * 16 * ROWB + ks * 32, b[bi]);
            #pragma unroll
            for (int mi = 0; mi < 4; mi++)
                #pragma unroll
                for (int ni = 0; ni < NI; ni++)
                    mma_any<T>(acc[mi][ni], a[mi],
                               b[ni >> 1][(ni & 1) * 2], b[ni >> 1][(ni & 1) * 2 + 1]);
        }
    };

    #pragma unroll
    for (int p = 0; p < STAGES - 1; p++) { if (p < nk) load_stage(p); CP_COMMIT(); }

    for (int kt = 0; kt < nk; kt++) {
        CP_WAIT(STAGES - 2);
        __syncthreads();
        if (kt + STAGES - 1 < nk) load_stage(kt + STAGES - 1);
        CP_COMMIT();
        compute(kt % STAGES);
    }

    // ------------------------------ epilogue -------------------------------
    int g = lid >> 2, t2 = (lid & 3) * 2;
    #pragma unroll
    for (int mi = 0; mi < 4; mi++) {
        #pragma unroll
        for (int rr = 0; rr < 2; rr++) {
            int m = m0 + wr * 64 + mi * 16 + g + rr * 8;
            size_t orow;
            if (epi == 2) {
                int win = m / NTOK, tok = m % NTOK;
                int b = win >> 6, wi2 = win & 63;
                int hs = (wi2 >> 3) * WS + tok / WS;
                int ws = (wi2 & 7)  * WS + tok % WS;
                int h = hs + SHIFT; if (h >= HH)  h -= HH;
                int w = ws + SHIFT; if (w >= WW_) w -= WW_;
                orow = (size_t)(b * HH + h) * WW_ + w;
            } else {
                orow = (size_t)m;
            }
            #pragma unroll
            for (int ni = 0; ni < NI; ni++) {
                int n = n0 + wc * WN + ni * 8 + t2;
                float v0 = acc[mi][ni][rr * 2 + 0];
                float v1 = acc[mi][ni][rr * 2 + 1];
                if (epi == 6) {
                    __half2 o;
                    o.x = __float2half(v0 + bias[n]);
                    o.y = __float2half(v1 + bias[n + 1]);
                    *reinterpret_cast<__half2*>(C16 + (size_t)m * N + n) = o;
                } else if (epi == 2) {
                    size_t oi = orow * CCH + n;
                    float2 a4 = *reinterpret_cast<const float2*>(addF + oi);
                    __half2 o;
                    o.x = __float2half(v0 + bias[n] + a4.x);
                    o.y = __float2half(v1 + bias[n + 1] + a4.y);
                    *reinterpret_cast<__half2*>(C16 + oi) = o;
                } else if (epi == 4) {
                    size_t oi = (size_t)m * CCH + n;
                    float2 a4 = __half22float2(
                        *reinterpret_cast<const __half2*>(addH + oi));
                    float2 o = { v0 * scale[n] + shiftv[n] + a4.x,
                                 v1 * scale[n + 1] + shiftv[n + 1] + a4.y };
                    *reinterpret_cast<float2*>(Cf + oi) = o;
                } else {  // epi == 5: raw fp32
                    float2 o = { v0, v1 };
                    *reinterpret_cast<float2*>(Cf + (size_t)m * N + n) = o;
                }
            }
        }
    }
}

// ------------------------------- launcher -----------------------------------
extern "C" void kernel_launch(void* const* d_in, const int* in_sizes, int n_in,
                              void* d_out, int out_size)
{
    const float* x         = (const float*)d_in[0];
    const float* ln1_g     = (const float*)d_in[1];
    const float* ln1_b     = (const float*)d_in[2];
    const float* w_qkv     = (const float*)d_in[3];
    const float* b_qkv     = (const float*)d_in[4];
    const float* bias_tbl  = (const float*)d_in[5];
    const float* w_proj    = (const float*)d_in[6];
    const float* b_proj    = (const float*)d_in[7];
    const float* ln2_g     = (const float*)d_in[8];
    const float* ln2_b     = (const float*)d_in[9];
    const float* w_ffn1    = (const float*)d_in[10];
    const float* bn1_scale = (const float*)d_in[11];
    const float* bn1_shift = (const float*)d_in[12];
    const float* w_ffn2    = (const float*)d_in[13];
    const float* bn2_scale = (const float*)d_in[14];
    const float* bn2_shift = (const float*)d_in[15];
    float* out = (float*)d_out;

    __half *xw16, *qkv16, *o16, *xmid16, *h116, *wq16, *wp16, *w216;
    __nv_bfloat16 *U, *Vh, *Vl;
    float *mu, *rs, *Mbuf;
    cudaGetSymbolAddress((void**)&xw16,   g_xw16);
    cudaGetSymbolAddress((void**)&qkv16,  g_qkv16);
    cudaGetSymbolAddress((void**)&o16,    g_o16);
    cudaGetSymbolAddress((void**)&xmid16, g_xmid);
    cudaGetSymbolAddress((void**)&mu,     g_mu);
    cudaGetSymbolAddress((void**)&rs,     g_rs);
    cudaGetSymbolAddress((void**)&h116,   g_h116);
    cudaGetSymbolAddress((void**)&wq16,   g_wq16);
    cudaGetSymbolAddress((void**)&wp16,   g_wp16);
    cudaGetSymbolAddress((void**)&w216,   g_w216);
    cudaGetSymbolAddress((void**)&U,  g_U);
    cudaGetSymbolAddress((void**)&Vh, g_Vh); cudaGetSymbolAddress((void**)&Vl, g_Vl);
    cudaGetSymbolAddress((void**)&Mbuf, g_M);

    constexpr int SMSZ = STAGES * (A_STG + 64 * ROWB);   // 76800
    cudaFuncSetAttribute((const void*)gemm_tc<32,2,1,__half>,
                         cudaFuncAttributeMaxDynamicSharedMemorySize, SMSZ);
    cudaFuncSetAttribute((const void*)gemm_tc<32,2,3,__nv_bfloat16>,
                         cudaFuncAttributeMaxDynamicSharedMemorySize, SMSZ);

    // weight preps
    prep_w16<<<(192 * 576 + 255) / 256, 256>>>(w_qkv, wq16, 192, 576);
    prep_w16<<<(192 * 192 + 255) / 256, 256>>>(w_proj, wp16, 192, 192);
    prep_w16<<<(768 * 192 + 255) / 256, 256>>>(w_ffn2, w216, 768, 192);
    wino_wt<<<(CCH * HIDDEN + 255) / 256, 256>>>(w_ffn1, U);

    // LN1 + roll + window partition -> fp16
    ln_kernel<<<MROWS / 8, 256>>>(x, ln1_g, ln1_b, xw16);

    // QKV GEMM [M,192]x[192,576] fp16 -> fp16
    gemm_tc<32,2,1,__half><<<dim3(576 / 64, MROWS / TM), 256, SMSZ>>>(
        xw16, xw16, wq16, b_qkv, nullptr, qkv16, nullptr, nullptr, nullptr, nullptr,
        576, 192, 6, 0, 0, 0);

    // attention -> fp16
    attn_kernel<<<(MROWS / NTOK) * HEADS, 128>>>(qkv16, bias_tbl, o16);

    // proj GEMM + window reverse + roll + shortcut(x fp32) -> fp16 trunk
    gemm_tc<32,2,1,__half><<<dim3(192 / 64, MROWS / TM), 256, SMSZ>>>(
        o16, o16, wp16, b_proj, nullptr, xmid16, nullptr, nullptr, x, nullptr,
        192, 192, 2, 0, 0, 0);

    // LN2 row stats (fp16 trunk)
    ln_stats<<<MROWS / 8, 256>>>(xmid16, mu, rs);

    // winograd F(4,3) input transform with fused LN2 -> bf16 hi/lo
    wino_in<<<(NT4 * CCH + 255) / 256, 256>>>(xmid16, mu, rs, ln2_g, ln2_b, Vh, Vl);

    // 36 batched transform-domain GEMMs [6400,192]x[192,768] -> fp32 M (bf16 3-term)
    gemm_tc<32,2,3,__nv_bfloat16><<<dim3(HIDDEN / 64, NTP / TM, 36), 256, SMSZ>>>(
        Vh, Vl, U, nullptr, Mbuf, nullptr, nullptr, nullptr, nullptr, nullptr,
        HIDDEN, 192, 5,
        (size_t)NTP * CCH, (size_t)HIDDEN * 576, (size_t)NTP * HIDDEN);

    // winograd output transform + BN + GELU -> h1 fp16
    wino_out<<<(NT4 * HIDDEN + 255) / 256, 256>>>(Mbuf, bn1_scale, bn1_shift, h116);

    // conv1x1 GEMM + BN + residual(fp16 trunk) -> out fp32
    gemm_tc<32,2,1,__half><<<dim3(CCH / 64, MROWS / TM), 256, SMSZ>>>(
        h116, h116, w216, nullptr, out, nullptr, bn2_scale, bn2_shift, nullptr, xmid16,
        CCH, 768, 4, 0, 0, 0);
}

// round 14
// speedup vs baseline: 5.2430x; 1.0160x over previous
#include <cuda_runtime.h>
#include <cuda_bf16.h>
#include <cuda_fp16.h>
#include <cstdint>
#include <math.h>

// ---------------------------------------------------------------------------
// SwinTransformerLayer on GB300, mma.sync tensor cores.
// - QKV / proj / conv1x1 GEMMs: plain fp16 (residual-diluted error ~1e-4 each)
// - conv3x3: Winograd F(4x4,3x3); transform GEMMs bf16 3-term split, fp32 M
//   (16-bit anywhere in the winograd chain amplified ~6-10x — locked, R11).
// - fp16 residual trunk; attention QK smem padded (stride 33) — R13.
// Round 14: per-kernel pipeline depth (STAGES=4 for long-K GEMMs).
// ---------------------------------------------------------------------------

#define BATCH   32
#define HH      56
#define WW_     56
#define CCH     192
#define WS      7
#define SHIFT   3
#define HEADS   6
#define HD      32
#define NTOK    49
#define MROWS   (BATCH*HH*WW_)   // 100352
#define HIDDEN  768
#define QKSCALE 0.17677669529663687f
#define NT4     6272             // 32 * 14 * 14 winograd F(4,3) tiles
#define NTP     6400             // padded to multiple of 256

#define TM      256
#define TKB     32               // K elements per stage
#define ROWB    80               // padded row bytes (40 elems) — conflict-free ldmatrix
#define A_STG   (TM*ROWB)        // 20480

// ------------------------- scratch (device globals) ------------------------
__device__ __align__(16) __half        g_xw16 [(size_t)MROWS * CCH];
__device__ __align__(16) __half        g_qkv16[(size_t)MROWS * 3 * CCH];
__device__ __align__(16) __half        g_o16  [(size_t)MROWS * CCH];
__device__ __align__(16) __half        g_xmid [(size_t)MROWS * CCH];   // fp16 trunk
__device__ __align__(16) float         g_mu   [(size_t)MROWS];
__device__ __align__(16) float         g_rs   [(size_t)MROWS];
__device__ __align__(16) __half        g_h116 [(size_t)MROWS * HIDDEN];
// fp16 1-term weights, [N,K]
__device__ __align__(16) __half        g_wq16 [(size_t)576 * 192];
__device__ __align__(16) __half        g_wp16 [(size_t)192 * 192];
__device__ __align__(16) __half        g_w216 [(size_t)192 * 768];
// winograd F(4,3): 36 planes, bf16 3-term
__device__ __align__(16) __nv_bfloat16 g_U  [(size_t)36 * HIDDEN * 576];   // [p][co][3K]
__device__ __align__(16) __nv_bfloat16 g_Vh [(size_t)36 * NTP * CCH];
__device__ __align__(16) __nv_bfloat16 g_Vl [(size_t)36 * NTP * CCH];
__device__ __align__(16) float         g_M  [(size_t)36 * NTP * HIDDEN];   // fp32

// ------------------------------ PTX helpers --------------------------------
__device__ __forceinline__ void cp_async16(uint32_t dst, const void* src, bool full) {
    int sz = full ? 16 : 0;
    asm volatile("cp.async.cg.shared.global [%0], [%1], 16, %2;"
                 :: "r"(dst), "l"(src), "r"(sz) : "memory");
}
#define CP_COMMIT() asm volatile("cp.async.commit_group;" ::: "memory")
#define CP_WAIT(n)  asm volatile("cp.async.wait_group %0;" :: "n"(n) : "memory")

__device__ __forceinline__ void ldsm_x4(uint32_t addr, uint32_t r[4]) {
    asm volatile("ldmatrix.sync.aligned.m8n8.x4.shared.b16 {%0,%1,%2,%3}, [%4];"
                 : "=r"(r[0]), "=r"(r[1]), "=r"(r[2]), "=r"(r[3]) : "r"(addr));
}
template<typename T>
__device__ __forceinline__ void mma_any(float c[4], const uint32_t a[4],
                                        uint32_t b0, uint32_t b1);
template<>
__device__ __forceinline__ void mma_any<__nv_bfloat16>(float c[4], const uint32_t a[4],
                                                       uint32_t b0, uint32_t b1) {
    asm volatile("mma.sync.aligned.m16n8k16.row.col.f32.bf16.bf16.f32 "
                 "{%0,%1,%2,%3}, {%4,%5,%6,%7}, {%8,%9}, {%0,%1,%2,%3};"
                 : "+f"(c[0]), "+f"(c[1]), "+f"(c[2]), "+f"(c[3])
                 : "r"(a[0]), "r"(a[1]), "r"(a[2]), "r"(a[3]), "r"(b0), "r"(b1));
}
template<>
__device__ __forceinline__ void mma_any<__half>(float c[4], const uint32_t a[4],
                                                uint32_t b0, uint32_t b1) {
    asm volatile("mma.sync.aligned.m16n8k16.row.col.f32.f16.f16.f32 "
                 "{%0,%1,%2,%3}, {%4,%5,%6,%7}, {%8,%9}, {%0,%1,%2,%3};"
                 : "+f"(c[0]), "+f"(c[1]), "+f"(c[2]), "+f"(c[3])
                 : "r"(a[0]), "r"(a[1]), "r"(a[2]), "r"(a[3]), "r"(b0), "r"(b1));
}

__device__ __forceinline__ void split_bf16(float v, __nv_bfloat16& hi, __nv_bfloat16& lo) {
    hi = __float2bfloat16(v);
    lo = __float2bfloat16(v - __bfloat162float(hi));
}

// ----------------------------- weight prep ---------------------------------
__global__ void prep_w16(const float* __restrict__ W, __half* __restrict__ D,
                         int K, int N)
{
    int i = blockIdx.x * 256 + threadIdx.x;
    if (i >= K * N) return;
    int k = i / N, n = i % N;
    D[(size_t)n * K + k] = __float2half(W[i]);
}

// ----------------------- winograd weight transform --------------------------
__global__ void wino_wt(const float* __restrict__ W, __nv_bfloat16* __restrict__ U)
{
    int i = blockIdx.x * 256 + threadIdx.x;
    if (i >= CCH * HIDDEN) return;
    int ci = i % CCH, co = i / CCH;

    float g[3][3];
    #pragma unroll
    for (int ky = 0; ky < 3; ky++)
        #pragma unroll
        for (int kx = 0; kx < 3; kx++)
            g[ky][kx] = W[((size_t)(ky * 3 + kx) * CCH + ci) * HIDDEN + co];

    float u[6][3];
    #pragma unroll
    for (int c = 0; c < 3; c++) {
        float g0 = g[0][c], g1 = g[1][c], g2 = g[2][c];
        u[0][c] = 0.25f * g0;
        u[1][c] = -(g0 + g1 + g2) * (1.0f / 6.0f);
        u[2][c] = (-g0 + g1 - g2) * (1.0f / 6.0f);
        u[3][c] = g0 * (1.0f / 24.0f) + g1 * (1.0f / 12.0f) + g2 * (1.0f / 6.0f);
        u[4][c] = g0 * (1.0f / 24.0f) - g1 * (1.0f / 12.0f) + g2 * (1.0f / 6.0f);
        u[5][c] = g2;
    }
    #pragma unroll
    for (int r = 0; r < 6; r++) {
        float a0 = u[r][0], a1 = u[r][1], a2 = u[r][2];
        float U6[6];
        U6[0] = 0.25f * a0;
        U6[1] = -(a0 + a1 + a2) * (1.0f / 6.0f);
        U6[2] = (-a0 + a1 - a2) * (1.0f / 6.0f);
        U6[3] = a0 * (1.0f / 24.0f) + a1 * (1.0f / 12.0f) + a2 * (1.0f / 6.0f);
        U6[4] = a0 * (1.0f / 24.0f) - a1 * (1.0f / 12.0f) + a2 * (1.0f / 6.0f);
        U6[5] = a2;
        #pragma unroll
        for (int c = 0; c < 6; c++) {
            int p = r * 6 + c;
            __nv_bfloat16 hi, lo;
            split_bf16(U6[c], hi, lo);
            size_t base = ((size_t)p * HIDDEN + co) * 576;
            U[base + ci]       = hi;
            U[base + 192 + ci] = hi;
            U[base + 384 + ci] = lo;
        }
    }
}

// ------------------------ LN row statistics (for LN2) -----------------------
__global__ __launch_bounds__(256)
void ln_stats(const __half* __restrict__ x, float* __restrict__ mu_o,
              float* __restrict__ rs_o)
{
    int m = blockIdx.x * 8 + (threadIdx.x >> 5);
    int lane = threadIdx.x & 31;
    const __half2* src = reinterpret_cast<const __half2*>(x + (size_t)m * CCH);
    float s1 = 0.f, s2 = 0.f;
    #pragma unroll
    for (int q = 0; q < 3; q++) {
        float2 v = __half22float2(src[lane + 32 * q]);
        s1 += v.x + v.y; s2 += v.x * v.x + v.y * v.y;
    }
    #pragma unroll
    for (int o = 16; o > 0; o >>= 1) {
        s1 += __shfl_xor_sync(0xFFFFFFFF, s1, o);
        s2 += __shfl_xor_sync(0xFFFFFFFF, s2, o);
    }
    if (lane == 0) {
        float mu  = s1 * (1.0f / CCH);
        float var = s2 * (1.0f / CCH) - mu * mu;
        mu_o[m] = mu;
        rs_o[m] = rsqrtf(var + 1e-3f);
    }
}

// ----------------- winograd input transform (LN2 fused) ---------------------
__device__ __forceinline__ void bt6(const float d[6], float t[6]) {
    t[0] = 4.f * d[0] - 5.f * d[2] + d[4];
    t[1] = -4.f * d[1] - 4.f * d[2] + d[3] + d[4];
    t[2] = 4.f * d[1] - 4.f * d[2] - d[3] + d[4];
    t[3] = -2.f * d[1] - d[2] + 2.f * d[3] + d[4];
    t[4] = 2.f * d[1] - d[2] - 2.f * d[3] + d[4];
    t[5] = 4.f * d[1] - 5.f * d[3] + d[5];
}

__global__ __launch_bounds__(256)
void wino_in(const __half* __restrict__ x,
             const float* __restrict__ mu,
             const float* __restrict__ rs,
             const float* __restrict__ gamma,
             const float* __restrict__ beta,
             __nv_bfloat16* __restrict__ Vh,
             __nv_bfloat16* __restrict__ Vl)
{
    int i = blockIdx.x * 256 + threadIdx.x;
    if (i >= NT4 * CCH) return;
    int tile = i / CCH, c = i % CCH;
    int b = tile / 196, r = tile % 196, ty = r / 14, tx = r % 14;
    float gm = gamma[c], bt = beta[c];

    float d[6][6];
    #pragma unroll
    for (int ii = 0; ii < 6; ii++) {
        int h = 4 * ty - 1 + ii;
        #pragma unroll
        for (int jj = 0; jj < 6; jj++) {
            int w = 4 * tx - 1 + jj;
            bool ok = (h >= 0) && (h < HH) && (w >= 0) && (w < WW_);
            if (ok) {
                size_t row = (size_t)(b * HH + h) * WW_ + w;
                d[ii][jj] = (__half2float(x[row * CCH + c]) - mu[row]) * rs[row] * gm + bt;
            } else d[ii][jj] = 0.f;
        }
    }
    float t[6][6];
    #pragma unroll
    for (int jj = 0; jj < 6; jj++) {
        float col[6], tc[6];
        #pragma unroll
        for (int ii = 0; ii < 6; ii++) col[ii] = d[ii][jj];
        bt6(col, tc);
        #pragma unroll
        for (int ii = 0; ii < 6; ii++) t[ii][jj] = tc[ii];
    }
    #pragma unroll
    for (int ii = 0; ii < 6; ii++) {
        float V6[6];
        bt6(t[ii], V6);
        #pragma unroll
        for (int jj = 0; jj < 6; jj++) {
            int p = ii * 6 + jj;
            __nv_bfloat16 hi, lo;
            split_bf16(V6[jj], hi, lo);
            size_t idx = ((size_t)p * NTP + tile) * CCH + c;
            Vh[idx] = hi; Vl[idx] = lo;
        }
    }
}

// ----------------------- winograd output transform --------------------------
__device__ __forceinline__ void at6(const float m[6], float s[4]) {
    s[0] = m[0] + m[1] + m[2] + m[3] + m[4];
    s[1] = m[1] - m[2] + 2.f * m[3] - 2.f * m[4];
    s[2] = m[1] + m[2] + 4.f * m[3] + 4.f * m[4];
    s[3] = m[1] - m[2] + 8.f * m[3] - 8.f * m[4] + m[5];
}

__global__ __launch_bounds__(256)
void wino_out(const float* __restrict__ M,
              const float* __restrict__ scale,
              const float* __restrict__ shiftv,
              __half* __restrict__ h116)
{
    int i = blockIdx.x * 256 + threadIdx.x;
    if (i >= NT4 * HIDDEN) return;
    int tile = i / HIDDEN, co = i % HIDDEN;
    int b = tile / 196, r = tile % 196, ty = r / 14, tx = r % 14;

    float m[6][6];
    #pragma unroll
    for (int p = 0; p < 36; p++)
        m[p / 6][p % 6] = M[((size_t)p * NTP + tile) * HIDDEN + co];

    float s[4][6];
    #pragma unroll
    for (int jj = 0; jj < 6; jj++) {
        float col[6], sc4[4];
        #pragma unroll
        for (int ii = 0; ii < 6; ii++) col[ii] = m[ii][jj];
        at6(col, sc4);
        #pragma unroll
        for (int ii = 0; ii < 4; ii++) s[ii][jj] = sc4[ii];
    }
    float sc = scale[co], sh = shiftv[co];
    #pragma unroll
    for (int ii = 0; ii < 4; ii++) {
        float Y4[4];
        at6(s[ii], Y4);
        #pragma unroll
        for (int jj = 0; jj < 4; jj++) {
            float v = Y4[jj] * sc + sh;
            v = 0.5f * v * (1.0f + erff(v * 0.70710678118654752f));
            size_t px = (size_t)b * 3136 + (size_t)(4 * ty + ii) * 56 + (4 * tx + jj);
            h116[px * HIDDEN + co] = __float2half(v);
        }
    }
}

// ------------------------------- LayerNorm (LN1) ----------------------------
__global__ __launch_bounds__(256)
void ln_kernel(const float* __restrict__ x,
               const float* __restrict__ gamma,
               const float* __restrict__ beta,
               __half* __restrict__ out16)
{
    int m = blockIdx.x * 8 + (threadIdx.x >> 5);
    int lane = threadIdx.x & 31;

    int win = m / NTOK, tok = m % NTOK;
    int b  = win >> 6, wi = win & 63;
    int hs = (wi >> 3) * WS + tok / WS;
    int ws = (wi & 7)  * WS + tok % WS;
    int h = hs + SHIFT; if (h >= HH)  h -= HH;
    int w = ws + SHIFT; if (w >= WW_) w -= WW_;
    int src_p = (b * HH + h) * WW_ + w;

    const float* src = x + (size_t)src_p * CCH;
    float v[6];
    float s1 = 0.f, s2 = 0.f;
    #pragma unroll
    for (int q = 0; q < 6; q++) {
        v[q] = src[lane + 32 * q];
        s1 += v[q]; s2 += v[q] * v[q];
    }
    #pragma unroll
    for (int o = 16; o > 0; o >>= 1) {
        s1 += __shfl_xor_sync(0xFFFFFFFF, s1, o);
        s2 += __shfl_xor_sync(0xFFFFFFFF, s2, o);
    }
    float mu  = s1 * (1.0f / CCH);
    float var = s2 * (1.0f / CCH) - mu * mu;
    float rsg = rsqrtf(var + 1e-3f);

    #pragma unroll
    for (int q = 0; q < 6; q++) {
        int c = lane + 32 * q;
        float yv = (v[q] - mu) * rsg * gamma[c] + beta[c];
        out16[(size_t)m * CCH + c] = __float2half(yv);
    }
}

// ------------------------------- Attention ---------------------------------
#define QKP 33
__global__ void attn_kernel(const __half* __restrict__ qkv,
                            const float* __restrict__ table,
                            __half* __restrict__ o16)
{
    int blk = blockIdx.x;
    int win = blk / HEADS;
    int head = blk % HEADS;
    int tid = threadIdx.x;

    __shared__ float qs[NTOK * QKP], ks[NTOK * QKP], vs[NTOK * HD];
    __shared__ float S[NTOK * 50];

    for (int t = tid; t < NTOK * HD; t += 128) {
        int n = t >> 5, d = t & 31;
        const __half* base = qkv + (size_t)(win * NTOK + n) * (3 * CCH) + head * HD + d;
        qs[n * QKP + d] = __half2float(base[0]) * QKSCALE;
        ks[n * QKP + d] = __half2float(base[CCH]);
        vs[t] = __half2float(base[2 * CCH]);
    }
    __syncthreads();

    int wi = win & 63;
    int wh = wi >> 3, wwn = wi & 7;

    for (int t = tid; t < NTOK * NTOK; t += 128) {
        int n = t / NTOK, mm = t % NTOK;
        float s = 0.f;
        #pragma unroll
        for (int d = 0; d < HD; d++) s += qs[n * QKP + d] * ks[mm * QKP + d];
        int rn = n / WS, cn = n % WS, rm = mm / WS, cm = mm % WS;
        int idx = (rn - rm + WS - 1) * (2 * WS - 1) + (cn - cm + WS - 1);
        s += table[idx * HEADS + head];
        int hn = wh * WS + rn, wn = wwn * WS + cn;
        int hm = wh * WS + rm, wm = wwn * WS + cm;
        int reg_n = (hn < 49 ? 0 : (hn < 53 ? 1 : 2)) * 3 + (wn < 49 ? 0 : (wn < 53 ? 1 : 2));
        int reg_m = (hm < 49 ? 0 : (hm < 53 ? 1 : 2)) * 3 + (wm < 49 ? 0 : (wm < 53 ? 1 : 2));
        if (reg_n != reg_m) s -= 100.0f;
        S[n * 50 + mm] = s;
    }
    __syncthreads();

    // warp-per-row softmax
    {
        int w4 = tid >> 5, lane = tid & 31;
        for (int row = w4; row < NTOK; row += 4) {
            float* Sr = S + row * 50;
            float mx = -1e30f;
            for (int c = lane; c < NTOK; c += 32) mx = fmaxf(mx, Sr[c]);
            #pragma unroll
            for (int o = 16; o > 0; o >>= 1)
                mx = fmaxf(mx, __shfl_xor_sync(0xFFFFFFFF, mx, o));
            float sum = 0.f;
            for (int c = lane; c < NTOK; c += 32) {
                float e = __expf(Sr[c] - mx);
                Sr[c] = e; sum += e;
            }
            #pragma unroll
            for (int o = 16; o > 0; o >>= 1)
                sum += __shfl_xor_sync(0xFFFFFFFF, sum, o);
            float inv = 1.0f / sum;
            for (int c = lane; c < NTOK; c += 32) Sr[c] *= inv;
        }
    }
    __syncthreads();

    for (int t = tid; t < NTOK * HD; t += 128) {
        int n = t >> 5, d = t & 31;
        float acc = 0.f;
        #pragma unroll 7
        for (int m2 = 0; m2 < NTOK; m2++) acc += S[n * 50 + m2] * vs[m2 * HD + d];
        size_t idx = (size_t)(win * NTOK + n) * CCH + head * HD + d;
        o16[idx] = __float2half(acc);
    }
}

// ---------------------------- HMMA GEMM ------------------------------------
// SPLIT=1 (fp16): C = A[M,K] x B[K,N] plain.
// SPLIT=3 (bf16): C = A'[M,3K] x B'[3K,N], A' = [Ah|Al|Ah].
// STG: pipeline depth (3 for short-K, 4 for long-K).
// epi: 2=+bias,remap,+addF(f32) -> f16   4=BN,+addH(f16) -> f32
//      5=raw -> f32                       6=+bias -> f16
template<int WN, int MINCTA, int SPLIT, int STG, typename T>
__global__ __launch_bounds__(256, MINCTA)
void gemm_tc(const T* __restrict__ Ah,
             const T* __restrict__ Al,
             const T* __restrict__ Bs,
             const float* __restrict__ bias,
             float* __restrict__ Cf,
             __half* __restrict__ C16,
             const float* __restrict__ scale,
             const float* __restrict__ shiftv,
             const float* __restrict__ addF,
             const __half* __restrict__ addH,
             int N, int K1, int epi,
             size_t zsA, size_t zsB, size_t zsC)
{
    constexpr int TN   = 2 * WN;
    constexpr int NB   = WN / 16;
    constexpr int NI   = WN / 8;
    constexpr int B_STG = TN * ROWB;
    constexpr int BPASS = TN / 64;

    Ah += blockIdx.z * zsA;
    Al += blockIdx.z * zsA;
    Bs += blockIdx.z * zsB;
    if (Cf) Cf += blockIdx.z * zsC;

    extern __shared__ char smem[];
    uint32_t sA0 = (uint32_t)__cvta_generic_to_shared(smem);
    uint32_t sB0 = sA0 + STG * A_STG;

    int tid = threadIdx.x;
    int wid = tid >> 5, lid = tid & 31;
    int wr = wid >> 1, wc = wid & 1;
    int m0 = blockIdx.y * TM, n0 = blockIdx.x * TN;
    int KS = SPLIT * K1;
    int nk = KS / TKB;

    int arow = tid >> 2;
    int aj = tid & 3;
    size_t arowoff[4];
    #pragma unroll
    for (int p = 0; p < 4; p++) arowoff[p] = (size_t)(m0 + arow + p * 64) * K1;
    size_t browoff[BPASS];
    #pragma unroll
    for (int p = 0; p < BPASS; p++)
        browoff[p] = (size_t)(n0 + arow + p * 64) * KS;

    float acc[4][NI][4];
    #pragma unroll
    for (int i = 0; i < 4; i++)
        #pragma unroll
        for (int j = 0; j < NI; j++)
            #pragma unroll
            for (int q = 0; q < 4; q++) acc[i][j][q] = 0.f;

    auto load_stage = [&](int kt) {
        int s = kt % STG;
        int k3 = kt * TKB;
        int seg = k3 / K1;
        int kk = k3 - seg * K1;
        const T* Asrc = (SPLIT == 3 && seg == 1) ? Al : Ah;
        #pragma unroll
        for (int p = 0; p < 4; p++) {
            uint32_t dst = sA0 + s * A_STG + (arow + p * 64) * ROWB + aj * 16;
            cp_async16(dst, Asrc + arowoff[p] + kk + aj * 8, true);
        }
        #pragma unroll
        for (int p = 0; p < BPASS; p++) {
            uint32_t dst = sB0 + s * B_STG + (arow + p * 64) * ROWB + aj * 16;
            cp_async16(dst, Bs + browoff[p] + k3 + aj * 8, true);
        }
    };

    auto compute = [&](int s) {
        uint32_t aBase = sA0 + s * A_STG + (wr * 64 + (lid & 15)) * ROWB + (lid >> 4) * 16;
        uint32_t bBase = sB0 + s * B_STG
                       + (wc * WN + (lid & 7) + ((lid >> 4) << 3)) * ROWB
                       + ((lid >> 3) & 1) * 16;
        #pragma unroll
        for (int ks = 0; ks < 2; ks++) {
            uint32_t a[4][4], b[NB][4];
            #pragma unroll
            for (int mi = 0; mi < 4; mi++)
                ldsm_x4(aBase + mi * 16 * ROWB + ks * 32, a[mi]);
            #pragma unroll
            for (int bi = 0; bi < NB; bi++)
                ldsm_x4(bBase + bi * 16 * ROWB + ks * 32, b[bi]);
            #pragma unroll
            for (int mi = 0; mi < 4; mi++)
                #pragma unroll
                for (int ni = 0; ni < NI; ni++)
                    mma_any<T>(acc[mi][ni], a[mi],
                               b[ni >> 1][(ni & 1) * 2], b[ni >> 1][(ni & 1) * 2 + 1]);
        }
    };

    #pragma unroll
    for (int p = 0; p < STG - 1; p++) { if (p < nk) load_stage(p); CP_COMMIT(); }

    for (int kt = 0; kt < nk; kt++) {
        CP_WAIT(STG - 2);
        __syncthreads();
        if (kt + STG - 1 < nk) load_stage(kt + STG - 1);
        CP_COMMIT();
        compute(kt % STG);
    }

    // ------------------------------ epilogue -------------------------------
    int g = lid >> 2, t2 = (lid & 3) * 2;
    #pragma unroll
    for (int mi = 0; mi < 4; mi++) {
        #pragma unroll
        for (int rr = 0; rr < 2; rr++) {
            int m = m0 + wr * 64 + mi * 16 + g + rr * 8;
            size_t orow;
            if (epi == 2) {
                int win = m / NTOK, tok = m % NTOK;
                int b = win >> 6, wi2 = win & 63;
                int hs = (wi2 >> 3) * WS + tok / WS;
                int ws = (wi2 & 7)  * WS + tok % WS;
                int h = hs + SHIFT; if (h >= HH)  h -= HH;
                int w = ws + SHIFT; if (w >= WW_) w -= WW_;
                orow = (size_t)(b * HH + h) * WW_ + w;
            } else {
                orow = (size_t)m;
            }
            #pragma unroll
            for (int ni = 0; ni < NI; ni++) {
                int n = n0 + wc * WN + ni * 8 + t2;
                float v0 = acc[mi][ni][rr * 2 + 0];
                float v1 = acc[mi][ni][rr * 2 + 1];
                if (epi == 6) {
                    __half2 o;
                    o.x = __float2half(v0 + bias[n]);
                    o.y = __float2half(v1 + bias[n + 1]);
                    *reinterpret_cast<__half2*>(C16 + (size_t)m * N + n) = o;
                } else if (epi == 2) {
                    size_t oi = orow * CCH + n;
                    float2 a4 = *reinterpret_cast<const float2*>(addF + oi);
                    __half2 o;
                    o.x = __float2half(v0 + bias[n] + a4.x);
                    o.y = __float2half(v1 + bias[n + 1] + a4.y);
                    *reinterpret_cast<__half2*>(C16 + oi) = o;
                } else if (epi == 4) {
                    size_t oi = (size_t)m * CCH + n;
                    float2 a4 = __half22float2(
                        *reinterpret_cast<const __half2*>(addH + oi));
                    float2 o = { v0 * scale[n] + shiftv[n] + a4.x,
                                 v1 * scale[n + 1] + shiftv[n + 1] + a4.y };
                    *reinterpret_cast<float2*>(Cf + oi) = o;
                } else {  // epi == 5: raw fp32
                    float2 o = { v0, v1 };
                    *reinterpret_cast<float2*>(Cf + (size_t)m * N + n) = o;
                }
            }
        }
    }
}

// ------------------------------- launcher -----------------------------------
extern "C" void kernel_launch(void* const* d_in, const int* in_sizes, int n_in,
                              void* d_out, int out_size)
{
    const float* x         = (const float*)d_in[0];
    const float* ln1_g     = (const float*)d_in[1];
    const float* ln1_b     = (const float*)d_in[2];
    const float* w_qkv     = (const float*)d_in[3];
    const float* b_qkv     = (const float*)d_in[4];
    const float* bias_tbl  = (const float*)d_in[5];
    const float* w_proj    = (const float*)d_in[6];
    const float* b_proj    = (const float*)d_in[7];
    const float* ln2_g     = (const float*)d_in[8];
    const float* ln2_b     = (const float*)d_in[9];
    const float* w_ffn1    = (const float*)d_in[10];
    const float* bn1_scale = (const float*)d_in[11];
    const float* bn1_shift = (const float*)d_in[12];
    const float* w_ffn2    = (const float*)d_in[13];
    const float* bn2_scale = (const float*)d_in[14];
    const float* bn2_shift = (const float*)d_in[15];
    float* out = (float*)d_out;

    __half *xw16, *qkv16, *o16, *xmid16, *h116, *wq16, *wp16, *w216;
    __nv_bfloat16 *U, *Vh, *Vl;
    float *mu, *rs, *Mbuf;
    cudaGetSymbolAddress((void**)&xw16,   g_xw16);
    cudaGetSymbolAddress((void**)&qkv16,  g_qkv16);
    cudaGetSymbolAddress((void**)&o16,    g_o16);
    cudaGetSymbolAddress((void**)&xmid16, g_xmid);
    cudaGetSymbolAddress((void**)&mu,     g_mu);
    cudaGetSymbolAddress((void**)&rs,     g_rs);
    cudaGetSymbolAddress((void**)&h116,   g_h116);
    cudaGetSymbolAddress((void**)&wq16,   g_wq16);
    cudaGetSymbolAddress((void**)&wp16,   g_wp16);
    cudaGetSymbolAddress((void**)&w216,   g_w216);
    cudaGetSymbolAddress((void**)&U,  g_U);
    cudaGetSymbolAddress((void**)&Vh, g_Vh); cudaGetSymbolAddress((void**)&Vl, g_Vl);
    cudaGetSymbolAddress((void**)&Mbuf, g_M);

    constexpr int SM3 = 3 * (A_STG + 64 * ROWB);   // 76800
    constexpr int SM4 = 4 * (A_STG + 64 * ROWB);   // 102400
    cudaFuncSetAttribute((const void*)gemm_tc<32,2,1,3,__half>,
                         cudaFuncAttributeMaxDynamicSharedMemorySize, SM3);
    cudaFuncSetAttribute((const void*)gemm_tc<32,2,1,4,__half>,
                         cudaFuncAttributeMaxDynamicSharedMemorySize, SM4);
    cudaFuncSetAttribute((const void*)gemm_tc<32,2,3,4,__nv_bfloat16>,
                         cudaFuncAttributeMaxDynamicSharedMemorySize, SM4);

    // weight preps
    prep_w16<<<(192 * 576 + 255) / 256, 256>>>(w_qkv, wq16, 192, 576);
    prep_w16<<<(192 * 192 + 255) / 256, 256>>>(w_proj, wp16, 192, 192);
    prep_w16<<<(768 * 192 + 255) / 256, 256>>>(w_ffn2, w216, 768, 192);
    wino_wt<<<(CCH * HIDDEN + 255) / 256, 256>>>(w_ffn1, U);

    // LN1 + roll + window partition -> fp16
    ln_kernel<<<MROWS / 8, 256>>>(x, ln1_g, ln1_b, xw16);

    // QKV GEMM [M,192]x[192,576] fp16 -> fp16  (short K: STAGES=3)
    gemm_tc<32,2,1,3,__half><<<dim3(576 / 64, MROWS / TM), 256, SM3>>>(
        xw16, xw16, wq16, b_qkv, nullptr, qkv16, nullptr, nullptr, nullptr, nullptr,
        576, 192, 6, 0, 0, 0);

    // attention -> fp16
    attn_kernel<<<(MROWS / NTOK) * HEADS, 128>>>(qkv16, bias_tbl, o16);

    // proj GEMM + window reverse + roll + shortcut(x fp32) -> fp16 trunk (STAGES=3)
    gemm_tc<32,2,1,3,__half><<<dim3(192 / 64, MROWS / TM), 256, SM3>>>(
        o16, o16, wp16, b_proj, nullptr, xmid16, nullptr, nullptr, x, nullptr,
        192, 192, 2, 0, 0, 0);

    // LN2 row stats (fp16 trunk)
    ln_stats<<<MROWS / 8, 256>>>(xmid16, mu, rs);

    // winograd F(4,3) input transform with fused LN2 -> bf16 hi/lo
    wino_in<<<(NT4 * CCH + 255) / 256, 256>>>(xmid16, mu, rs, ln2_g, ln2_b, Vh, Vl);

    // 36 batched transform GEMMs [6400,192]x[192,768] -> fp32 M (nk=18: STAGES=4)
    gemm_tc<32,2,3,4,__nv_bfloat16><<<dim3(HIDDEN / 64, NTP / TM, 36), 256, SM4>>>(
        Vh, Vl, U, nullptr, Mbuf, nullptr, nullptr, nullptr, nullptr, nullptr,
        HIDDEN, 192, 5,
        (size_t)NTP * CCH, (size_t)HIDDEN * 576, (size_t)NTP * HIDDEN);

    // winograd output transform + BN + GELU -> h1 fp16
    wino_out<<<(NT4 * HIDDEN + 255) / 256, 256>>>(Mbuf, bn1_scale, bn1_shift, h116);

    // conv1x1 GEMM + BN + residual(fp16 trunk) -> out fp32 (nk=24: STAGES=4)
    gemm_tc<32,2,1,4,__half><<<dim3(CCH / 64, MROWS / TM), 256, SM4>>>(
        h116, h116, w216, nullptr, out, nullptr, bn2_scale, bn2_shift, nullptr, xmid16,
        CCH, 768, 4, 0, 0, 0);
}

// round 15
// speedup vs baseline: 5.7428x; 1.0953x over previous
#include <cuda_runtime.h>
#include <cuda_bf16.h>
#include <cuda_fp16.h>
#include <cstdint>
#include <math.h>

// ---------------------------------------------------------------------------
// SwinTransformerLayer on GB300, mma.sync tensor cores.
// - QKV / proj / conv1x1 GEMMs: plain fp16 (residual-diluted error ~1e-4 each)
// - conv3x3: Winograd F(4x4,3x3); transform GEMMs bf16 3-term split, fp32 M
//   (16-bit anywhere in the winograd chain amplified ~6-10x — locked, R11).
// - fp16 residual trunk; attention QK smem padded — R13.
// Round 15: attention q/k/v kept as __half2 in smem (halves crossbar bytes).
// ---------------------------------------------------------------------------

#define BATCH   32
#define HH      56
#define WW_     56
#define CCH     192
#define WS      7
#define SHIFT   3
#define HEADS   6
#define HD      32
#define NTOK    49
#define MROWS   (BATCH*HH*WW_)   // 100352
#define HIDDEN  768
#define QKSCALE 0.17677669529663687f
#define NT4     6272             // 32 * 14 * 14 winograd F(4,3) tiles
#define NTP     6400             // padded to multiple of 256

#define TM      256
#define TKB     32               // K elements per stage
#define ROWB    80               // padded row bytes (40 elems) — conflict-free ldmatrix
#define A_STG   (TM*ROWB)        // 20480

// ------------------------- scratch (device globals) ------------------------
__device__ __align__(16) __half        g_xw16 [(size_t)MROWS * CCH];
__device__ __align__(16) __half        g_qkv16[(size_t)MROWS * 3 * CCH];
__device__ __align__(16) __half        g_o16  [(size_t)MROWS * CCH];
__device__ __align__(16) __half        g_xmid [(size_t)MROWS * CCH];   // fp16 trunk
__device__ __align__(16) float         g_mu   [(size_t)MROWS];
__device__ __align__(16) float         g_rs   [(size_t)MROWS];
__device__ __align__(16) __half        g_h116 [(size_t)MROWS * HIDDEN];
// fp16 1-term weights, [N,K]
__device__ __align__(16) __half        g_wq16 [(size_t)576 * 192];
__device__ __align__(16) __half        g_wp16 [(size_t)192 * 192];
__device__ __align__(16) __half        g_w216 [(size_t)192 * 768];
// winograd F(4,3): 36 planes, bf16 3-term
__device__ __align__(16) __nv_bfloat16 g_U  [(size_t)36 * HIDDEN * 576];   // [p][co][3K]
__device__ __align__(16) __nv_bfloat16 g_Vh [(size_t)36 * NTP * CCH];
__device__ __align__(16) __nv_bfloat16 g_Vl [(size_t)36 * NTP * CCH];
__device__ __align__(16) float         g_M  [(size_t)36 * NTP * HIDDEN];   // fp32

// ------------------------------ PTX helpers --------------------------------
__device__ __forceinline__ void cp_async16(uint32_t dst, const void* src, bool full) {
    int sz = full ? 16 : 0;
    asm volatile("cp.async.cg.shared.global [%0], [%1], 16, %2;"
                 :: "r"(dst), "l"(src), "r"(sz) : "memory");
}
#define CP_COMMIT() asm volatile("cp.async.commit_group;" ::: "memory")
#define CP_WAIT(n)  asm volatile("cp.async.wait_group %0;" :: "n"(n) : "memory")

__device__ __forceinline__ void ldsm_x4(uint32_t addr, uint32_t r[4]) {
    asm volatile("ldmatrix.sync.aligned.m8n8.x4.shared.b16 {%0,%1,%2,%3}, [%4];"
                 : "=r"(r[0]), "=r"(r[1]), "=r"(r[2]), "=r"(r[3]) : "r"(addr));
}
template<typename T>
__device__ __forceinline__ void mma_any(float c[4], const uint32_t a[4],
                                        uint32_t b0, uint32_t b1);
template<>
__device__ __forceinline__ void mma_any<__nv_bfloat16>(float c[4], const uint32_t a[4],
                                                       uint32_t b0, uint32_t b1) {
    asm volatile("mma.sync.aligned.m16n8k16.row.col.f32.bf16.bf16.f32 "
                 "{%0,%1,%2,%3}, {%4,%5,%6,%7}, {%8,%9}, {%0,%1,%2,%3};"
                 : "+f"(c[0]), "+f"(c[1]), "+f"(c[2]), "+f"(c[3])
                 : "r"(a[0]), "r"(a[1]), "r"(a[2]), "r"(a[3]), "r"(b0), "r"(b1));
}
template<>
__device__ __forceinline__ void mma_any<__half>(float c[4], const uint32_t a[4],
                                                uint32_t b0, uint32_t b1) {
    asm volatile("mma.sync.aligned.m16n8k16.row.col.f32.f16.f16.f32 "
                 "{%0,%1,%2,%3}, {%4,%5,%6,%7}, {%8,%9}, {%0,%1,%2,%3};"
                 : "+f"(c[0]), "+f"(c[1]), "+f"(c[2]), "+f"(c[3])
                 : "r"(a[0]), "r"(a[1]), "r"(a[2]), "r"(a[3]), "r"(b0), "r"(b1));
}

__device__ __forceinline__ void split_bf16(float v, __nv_bfloat16& hi, __nv_bfloat16& lo) {
    hi = __float2bfloat16(v);
    lo = __float2bfloat16(v - __bfloat162float(hi));
}

// ----------------------------- weight prep ---------------------------------
__global__ void prep_w16(const float* __restrict__ W, __half* __restrict__ D,
                         int K, int N)
{
    int i = blockIdx.x * 256 + threadIdx.x;
    if (i >= K * N) return;
    int k = i / N, n = i % N;
    D[(size_t)n * K + k] = __float2half(W[i]);
}

// ----------------------- winograd weight transform --------------------------
__global__ void wino_wt(const float* __restrict__ W, __nv_bfloat16* __restrict__ U)
{
    int i = blockIdx.x * 256 + threadIdx.x;
    if (i >= CCH * HIDDEN) return;
    int ci = i % CCH, co = i / CCH;

    float g[3][3];
    #pragma unroll
    for (int ky = 0; ky < 3; ky++)
        #pragma unroll
        for (int kx = 0; kx < 3; kx++)
            g[ky][kx] = W[((size_t)(ky * 3 + kx) * CCH + ci) * HIDDEN + co];

    float u[6][3];
    #pragma unroll
    for (int c = 0; c < 3; c++) {
        float g0 = g[0][c], g1 = g[1][c], g2 = g[2][c];
        u[0][c] = 0.25f * g0;
        u[1][c] = -(g0 + g1 + g2) * (1.0f / 6.0f);
        u[2][c] = (-g0 + g1 - g2) * (1.0f / 6.0f);
        u[3][c] = g0 * (1.0f / 24.0f) + g1 * (1.0f / 12.0f) + g2 * (1.0f / 6.0f);
        u[4][c] = g0 * (1.0f / 24.0f) - g1 * (1.0f / 12.0f) + g2 * (1.0f / 6.0f);
        u[5][c] = g2;
    }
    #pragma unroll
    for (int r = 0; r < 6; r++) {
        float a0 = u[r][0], a1 = u[r][1], a2 = u[r][2];
        float U6[6];
        U6[0] = 0.25f * a0;
        U6[1] = -(a0 + a1 + a2) * (1.0f / 6.0f);
        U6[2] = (-a0 + a1 - a2) * (1.0f / 6.0f);
        U6[3] = a0 * (1.0f / 24.0f) + a1 * (1.0f / 12.0f) + a2 * (1.0f / 6.0f);
        U6[4] = a0 * (1.0f / 24.0f) - a1 * (1.0f / 12.0f) + a2 * (1.0f / 6.0f);
        U6[5] = a2;
        #pragma unroll
        for (int c = 0; c < 6; c++) {
            int p = r * 6 + c;
            __nv_bfloat16 hi, lo;
            split_bf16(U6[c], hi, lo);
            size_t base = ((size_t)p * HIDDEN + co) * 576;
            U[base + ci]       = hi;
            U[base + 192 + ci] = hi;
            U[base + 384 + ci] = lo;
        }
    }
}

// ------------------------ LN row statistics (for LN2) -----------------------
__global__ __launch_bounds__(256)
void ln_stats(const __half* __restrict__ x, float* __restrict__ mu_o,
              float* __restrict__ rs_o)
{
    int m = blockIdx.x * 8 + (threadIdx.x >> 5);
    int lane = threadIdx.x & 31;
    const __half2* src = reinterpret_cast<const __half2*>(x + (size_t)m * CCH);
    float s1 = 0.f, s2 = 0.f;
    #pragma unroll
    for (int q = 0; q < 3; q++) {
        float2 v = __half22float2(src[lane + 32 * q]);
        s1 += v.x + v.y; s2 += v.x * v.x + v.y * v.y;
    }
    #pragma unroll
    for (int o = 16; o > 0; o >>= 1) {
        s1 += __shfl_xor_sync(0xFFFFFFFF, s1, o);
        s2 += __shfl_xor_sync(0xFFFFFFFF, s2, o);
    }
    if (lane == 0) {
        float mu  = s1 * (1.0f / CCH);
        float var = s2 * (1.0f / CCH) - mu * mu;
        mu_o[m] = mu;
        rs_o[m] = rsqrtf(var + 1e-3f);
    }
}

// ----------------- winograd input transform (LN2 fused) ---------------------
__device__ __forceinline__ void bt6(const float d[6], float t[6]) {
    t[0] = 4.f * d[0] - 5.f * d[2] + d[4];
    t[1] = -4.f * d[1] - 4.f * d[2] + d[3] + d[4];
    t[2] = 4.f * d[1] - 4.f * d[2] - d[3] + d[4];
    t[3] = -2.f * d[1] - d[2] + 2.f * d[3] + d[4];
    t[4] = 2.f * d[1] - d[2] - 2.f * d[3] + d[4];
    t[5] = 4.f * d[1] - 5.f * d[3] + d[5];
}

__global__ __launch_bounds__(256)
void wino_in(const __half* __restrict__ x,
             const float* __restrict__ mu,
             const float* __restrict__ rs,
             const float* __restrict__ gamma,
             const float* __restrict__ beta,
             __nv_bfloat16* __restrict__ Vh,
             __nv_bfloat16* __restrict__ Vl)
{
    int i = blockIdx.x * 256 + threadIdx.x;
    if (i >= NT4 * CCH) return;
    int tile = i / CCH, c = i % CCH;
    int b = tile / 196, r = tile % 196, ty = r / 14, tx = r % 14;
    float gm = gamma[c], bt = beta[c];

    float d[6][6];
    #pragma unroll
    for (int ii = 0; ii < 6; ii++) {
        int h = 4 * ty - 1 + ii;
        #pragma unroll
        for (int jj = 0; jj < 6; jj++) {
            int w = 4 * tx - 1 + jj;
            bool ok = (h >= 0) && (h < HH) && (w >= 0) && (w < WW_);
            if (ok) {
                size_t row = (size_t)(b * HH + h) * WW_ + w;
                d[ii][jj] = (__half2float(x[row * CCH + c]) - mu[row]) * rs[row] * gm + bt;
            } else d[ii][jj] = 0.f;
        }
    }
    float t[6][6];
    #pragma unroll
    for (int jj = 0; jj < 6; jj++) {
        float col[6], tc[6];
        #pragma unroll
        for (int ii = 0; ii < 6; ii++) col[ii] = d[ii][jj];
        bt6(col, tc);
        #pragma unroll
        for (int ii = 0; ii < 6; ii++) t[ii][jj] = tc[ii];
    }
    #pragma unroll
    for (int ii = 0; ii < 6; ii++) {
        float V6[6];
        bt6(t[ii], V6);
        #pragma unroll
        for (int jj = 0; jj < 6; jj++) {
            int p = ii * 6 + jj;
            __nv_bfloat16 hi, lo;
            split_bf16(V6[jj], hi, lo);
            size_t idx = ((size_t)p * NTP + tile) * CCH + c;
            Vh[idx] = hi; Vl[idx] = lo;
        }
    }
}

// ----------------------- winograd output transform --------------------------
__device__ __forceinline__ void at6(const float m[6], float s[4]) {
    s[0] = m[0] + m[1] + m[2] + m[3] + m[4];
    s[1] = m[1] - m[2] + 2.f * m[3] - 2.f * m[4];
    s[2] = m[1] + m[2] + 4.f * m[3] + 4.f * m[4];
    s[3] = m[1] - m[2] + 8.f * m[3] - 8.f * m[4] + m[5];
}

__global__ __launch_bounds__(256)
void wino_out(const float* __restrict__ M,
              const float* __restrict__ scale,
              const float* __restrict__ shiftv,
              __half* __restrict__ h116)
{
    int i = blockIdx.x * 256 + threadIdx.x;
    if (i >= NT4 * HIDDEN) return;
    int tile = i / HIDDEN, co = i % HIDDEN;
    int b = tile / 196, r = tile % 196, ty = r / 14, tx = r % 14;

    float m[6][6];
    #pragma unroll
    for (int p = 0; p < 36; p++)
        m[p / 6][p % 6] = M[((size_t)p * NTP + tile) * HIDDEN + co];

    float s[4][6];
    #pragma unroll
    for (int jj = 0; jj < 6; jj++) {
        float col[6], sc4[4];
        #pragma unroll
        for (int ii = 0; ii < 6; ii++) col[ii] = m[ii][jj];
        at6(col, sc4);
        #pragma unroll
        for (int ii = 0; ii < 4; ii++) s[ii][jj] = sc4[ii];
    }
    float sc = scale[co], sh = shiftv[co];
    #pragma unroll
    for (int ii = 0; ii < 4; ii++) {
        float Y4[4];
        at6(s[ii], Y4);
        #pragma unroll
        for (int jj = 0; jj < 4; jj++) {
            float v = Y4[jj] * sc + sh;
            v = 0.5f * v * (1.0f + erff(v * 0.70710678118654752f));
            size_t px = (size_t)b * 3136 + (size_t)(4 * ty + ii) * 56 + (4 * tx + jj);
            h116[px * HIDDEN + co] = __float2half(v);
        }
    }
}

// ------------------------------- LayerNorm (LN1) ----------------------------
__global__ __launch_bounds__(256)
void ln_kernel(const float* __restrict__ x,
               const float* __restrict__ gamma,
               const float* __restrict__ beta,
               __half* __restrict__ out16)
{
    int m = blockIdx.x * 8 + (threadIdx.x >> 5);
    int lane = threadIdx.x & 31;

    int win = m / NTOK, tok = m % NTOK;
    int b  = win >> 6, wi = win & 63;
    int hs = (wi >> 3) * WS + tok / WS;
    int ws = (wi & 7)  * WS + tok % WS;
    int h = hs + SHIFT; if (h >= HH)  h -= HH;
    int w = ws + SHIFT; if (w >= WW_) w -= WW_;
    int src_p = (b * HH + h) * WW_ + w;

    const float* src = x + (size_t)src_p * CCH;
    float v[6];
    float s1 = 0.f, s2 = 0.f;
    #pragma unroll
    for (int q = 0; q < 6; q++) {
        v[q] = src[lane + 32 * q];
        s1 += v[q]; s2 += v[q] * v[q];
    }
    #pragma unroll
    for (int o = 16; o > 0; o >>= 1) {
        s1 += __shfl_xor_sync(0xFFFFFFFF, s1, o);
        s2 += __shfl_xor_sync(0xFFFFFFFF, s2, o);
    }
    float mu  = s1 * (1.0f / CCH);
    float var = s2 * (1.0f / CCH) - mu * mu;
    float rsg = rsqrtf(var + 1e-3f);

    #pragma unroll
    for (int q = 0; q < 6; q++) {
        int c = lane + 32 * q;
        float yv = (v[q] - mu) * rsg * gamma[c] + beta[c];
        out16[(size_t)m * CCH + c] = __float2half(yv);
    }
}

// ------------------------------- Attention ---------------------------------
// q/k/v stay fp16 in smem as __half2 (2 taps per 4B crossbar access).
// qs2/ks2 rows padded to 17 half2 (odd stride -> conflict-free lane-varying mm).
#define QKP2 17
__global__ void attn_kernel(const __half* __restrict__ qkv,
                            const float* __restrict__ table,
                            __half* __restrict__ o16)
{
    int blk = blockIdx.x;
    int win = blk / HEADS;
    int head = blk % HEADS;
    int tid = threadIdx.x;

    __shared__ __half2 qs2[NTOK * QKP2], ks2[NTOK * QKP2], vs2[NTOK * 16];
    __shared__ float S[NTOK * 50];

    const __half2 scale2 = __floats2half2_rn(QKSCALE, QKSCALE);
    for (int t = tid; t < NTOK * 16; t += 128) {
        int n = t >> 4, dp = t & 15;
        const __half2* base = reinterpret_cast<const __half2*>(
            qkv + (size_t)(win * NTOK + n) * (3 * CCH) + head * HD) + dp;
        qs2[n * QKP2 + dp] = __hmul2(base[0], scale2);
        ks2[n * QKP2 + dp] = base[CCH / 2];
        vs2[t] = base[CCH];
    }
    __syncthreads();

    int wi = win & 63;
    int wh = wi >> 3, wwn = wi & 7;

    for (int t = tid; t < NTOK * NTOK; t += 128) {
        int n = t / NTOK, mm = t % NTOK;
        float s = 0.f;
        #pragma unroll
        for (int dp = 0; dp < 16; dp++) {
            float2 a = __half22float2(qs2[n * QKP2 + dp]);
            float2 b = __half22float2(ks2[mm * QKP2 + dp]);
            s += a.x * b.x + a.y * b.y;
        }
        int rn = n / WS, cn = n % WS, rm = mm / WS, cm = mm % WS;
        int idx = (rn - rm + WS - 1) * (2 * WS - 1) + (cn - cm + WS - 1);
        s += table[idx * HEADS + head];
        int hn = wh * WS + rn, wn = wwn * WS + cn;
        int hm = wh * WS + rm, wm = wwn * WS + cm;
        int reg_n = (hn < 49 ? 0 : (hn < 53 ? 1 : 2)) * 3 + (wn < 49 ? 0 : (wn < 53 ? 1 : 2));
        int reg_m = (hm < 49 ? 0 : (hm < 53 ? 1 : 2)) * 3 + (wm < 49 ? 0 : (wm < 53 ? 1 : 2));
        if (reg_n != reg_m) s -= 100.0f;
        S[n * 50 + mm] = s;
    }
    __syncthreads();

    // warp-per-row softmax
    {
        int w4 = tid >> 5, lane = tid & 31;
        for (int row = w4; row < NTOK; row += 4) {
            float* Sr = S + row * 50;
            float mx = -1e30f;
            for (int c = lane; c < NTOK; c += 32) mx = fmaxf(mx, Sr[c]);
            #pragma unroll
            for (int o = 16; o > 0; o >>= 1)
                mx = fmaxf(mx, __shfl_xor_sync(0xFFFFFFFF, mx, o));
            float sum = 0.f;
            for (int c = lane; c < NTOK; c += 32) {
                float e = __expf(Sr[c] - mx);
                Sr[c] = e; sum += e;
            }
            #pragma unroll
            for (int o = 16; o > 0; o >>= 1)
                sum += __shfl_xor_sync(0xFFFFFFFF, sum, o);
            float inv = 1.0f / sum;
            for (int c = lane; c < NTOK; c += 32) Sr[c] *= inv;
        }
    }
    __syncthreads();

    for (int t = tid; t < NTOK * 16; t += 128) {
        int n = t >> 4, dp = t & 15;
        float2 acc = make_float2(0.f, 0.f);
        #pragma unroll 7
        for (int m2 = 0; m2 < NTOK; m2++) {
            float p = S[n * 50 + m2];
            float2 v = __half22float2(vs2[m2 * 16 + dp]);
            acc.x += p * v.x;
            acc.y += p * v.y;
        }
        size_t idx = (size_t)(win * NTOK + n) * CCH + head * HD + 2 * dp;
        *reinterpret_cast<__half2*>(o16 + idx) = __floats2half2_rn(acc.x, acc.y);
    }
}

// ---------------------------- HMMA GEMM ------------------------------------
// SPLIT=1 (fp16): C = A[M,K] x B[K,N] plain.
// SPLIT=3 (bf16): C = A'[M,3K] x B'[3K,N], A' = [Ah|Al|Ah].
// STG: pipeline depth (3 for short-K, 4 for long-K).
// epi: 2=+bias,remap,+addF(f32) -> f16   4=BN,+addH(f16) -> f32
//      5=raw -> f32                       6=+bias -> f16
template<int WN, int MINCTA, int SPLIT, int STG, typename T>
__global__ __launch_bounds__(256, MINCTA)
void gemm_tc(const T* __restrict__ Ah,
             const T* __restrict__ Al,
             const T* __restrict__ Bs,
             const float* __restrict__ bias,
             float* __restrict__ Cf,
             __half* __restrict__ C16,
             const float* __restrict__ scale,
             const float* __restrict__ shiftv,
             const float* __restrict__ addF,
             const __half* __restrict__ addH,
             int N, int K1, int epi,
             size_t zsA, size_t zsB, size_t zsC)
{
    constexpr int TN   = 2 * WN;
    constexpr int NB   = WN / 16;
    constexpr int NI   = WN / 8;
    constexpr int B_STG = TN * ROWB;
    constexpr int BPASS = TN / 64;

    Ah += blockIdx.z * zsA;
    Al += blockIdx.z * zsA;
    Bs += blockIdx.z * zsB;
    if (Cf) Cf += blockIdx.z * zsC;

    extern __shared__ char smem[];
    uint32_t sA0 = (uint32_t)__cvta_generic_to_shared(smem);
    uint32_t sB0 = sA0 + STG * A_STG;

    int tid = threadIdx.x;
    int wid = tid >> 5, lid = tid & 31;
    int wr = wid >> 1, wc = wid & 1;
    int m0 = blockIdx.y * TM, n0 = blockIdx.x * TN;
    int KS = SPLIT * K1;
    int nk = KS / TKB;

    int arow = tid >> 2;
    int aj = tid & 3;
    size_t arowoff[4];
    #pragma unroll
    for (int p = 0; p < 4; p++) arowoff[p] = (size_t)(m0 + arow + p * 64) * K1;
    size_t browoff[BPASS];
    #pragma unroll
    for (int p = 0; p < BPASS; p++)
        browoff[p] = (size_t)(n0 + arow + p * 64) * KS;

    float acc[4][NI][4];
    #pragma unroll
    for (int i = 0; i < 4; i++)
        #pragma unroll
        for (int j = 0; j < NI; j++)
            #pragma unroll
            for (int q = 0; q < 4; q++) acc[i][j][q] = 0.f;

    auto load_stage = [&](int kt) {
        int s = kt % STG;
        int k3 = kt * TKB;
        int seg = k3 / K1;
        int kk = k3 - seg * K1;
        const T* Asrc = (SPLIT == 3 && seg == 1) ? Al : Ah;
        #pragma unroll
        for (int p = 0; p < 4; p++) {
            uint32_t dst = sA0 + s * A_STG + (arow + p * 64) * ROWB + aj * 16;
            cp_async16(dst, Asrc + arowoff[p] + kk + aj * 8, true);
        }
        #pragma unroll
        for (int p = 0; p < BPASS; p++) {
            uint32_t dst = sB0 + s * B_STG + (arow + p * 64) * ROWB + aj * 16;
            cp_async16(dst, Bs + browoff[p] + k3 + aj * 8, true);
        }
    };

    auto compute = [&](int s) {
        uint32_t aBase = sA0 + s * A_STG + (wr * 64 + (lid & 15)) * ROWB + (lid >> 4) * 16;
        uint32_t bBase = sB0 + s * B_STG
                       + (wc * WN + (lid & 7) + ((lid >> 4) << 3)) * ROWB
                       + ((lid >> 3) & 1) * 16;
        #pragma unroll
        for (int ks = 0; ks < 2; ks++) {
            uint32_t a[4][4], b[NB][4];
            #pragma unroll
            for (int mi = 0; mi < 4; mi++)
                ldsm_x4(aBase + mi * 16 * ROWB + ks * 32, a[mi]);
            #pragma unroll
            for (int bi = 0; bi < NB; bi++)
                ldsm_x4(bBase + bi * 16 * ROWB + ks * 32, b[bi]);
            #pragma unroll
            for (int mi = 0; mi < 4; mi++)
                #pragma unroll
                for (int ni = 0; ni < NI; ni++)
                    mma_any<T>(acc[mi][ni], a[mi],
                               b[ni >> 1][(ni & 1) * 2], b[ni >> 1][(ni & 1) * 2 + 1]);
        }
    };

    #pragma unroll
    for (int p = 0; p < STG - 1; p++) { if (p < nk) load_stage(p); CP_COMMIT(); }

    for (int kt = 0; kt < nk; kt++) {
        CP_WAIT(STG - 2);
        __syncthreads();
        if (kt + STG - 1 < nk) load_stage(kt + STG - 1);
        CP_COMMIT();
        compute(kt % STG);
    }

    // ------------------------------ epilogue -------------------------------
    int g = lid >> 2, t2 = (lid & 3) * 2;
    #pragma unroll
    for (int mi = 0; mi < 4; mi++) {
        #pragma unroll
        for (int rr = 0; rr < 2; rr++) {
            int m = m0 + wr * 64 + mi * 16 + g + rr * 8;
            size_t orow;
            if (epi == 2) {
                int win = m / NTOK, tok = m % NTOK;
                int b = win >> 6, wi2 = win & 63;
                int hs = (wi2 >> 3) * WS + tok / WS;
                int ws = (wi2 & 7)  * WS + tok % WS;
                int h = hs + SHIFT; if (h >= HH)  h -= HH;
                int w = ws + SHIFT; if (w >= WW_) w -= WW_;
                orow = (size_t)(b * HH + h) * WW_ + w;
            } else {
                orow = (size_t)m;
            }
            #pragma unroll
            for (int ni = 0; ni < NI; ni++) {
                int n = n0 + wc * WN + ni * 8 + t2;
                float v0 = acc[mi][ni][rr * 2 + 0];
                float v1 = acc[mi][ni][rr * 2 + 1];
                if (epi == 6) {
                    __half2 o;
                    o.x = __float2half(v0 + bias[n]);
                    o.y = __float2half(v1 + bias[n + 1]);
                    *reinterpret_cast<__half2*>(C16 + (size_t)m * N + n) = o;
                } else if (epi == 2) {
                    size_t oi = orow * CCH + n;
                    float2 a4 = *reinterpret_cast<const float2*>(addF + oi);
                    __half2 o;
                    o.x = __float2half(v0 + bias[n] + a4.x);
                    o.y = __float2half(v1 + bias[n + 1] + a4.y);
                    *reinterpret_cast<__half2*>(C16 + oi) = o;
                } else if (epi == 4) {
                    size_t oi = (size_t)m * CCH + n;
                    float2 a4 = __half22float2(
                        *reinterpret_cast<const __half2*>(addH + oi));
                    float2 o = { v0 * scale[n] + shiftv[n] + a4.x,
                                 v1 * scale[n + 1] + shiftv[n + 1] + a4.y };
                    *reinterpret_cast<float2*>(Cf + oi) = o;
                } else {  // epi == 5: raw fp32
                    float2 o = { v0, v1 };
                    *reinterpret_cast<float2*>(Cf + (size_t)m * N + n) = o;
                }
            }
        }
    }
}

// ------------------------------- launcher -----------------------------------
extern "C" void kernel_launch(void* const* d_in, const int* in_sizes, int n_in,
                              void* d_out, int out_size)
{
    const float* x         = (const float*)d_in[0];
    const float* ln1_g     = (const float*)d_in[1];
    const float* ln1_b     = (const float*)d_in[2];
    const float* w_qkv     = (const float*)d_in[3];
    const float* b_qkv     = (const float*)d_in[4];
    const float* bias_tbl  = (const float*)d_in[5];
    const float* w_proj    = (const float*)d_in[6];
    const float* b_proj    = (const float*)d_in[7];
    const float* ln2_g     = (const float*)d_in[8];
    const float* ln2_b     = (const float*)d_in[9];
    const float* w_ffn1    = (const float*)d_in[10];
    const float* bn1_scale = (const float*)d_in[11];
    const float* bn1_shift = (const float*)d_in[12];
    const float* w_ffn2    = (const float*)d_in[13];
    const float* bn2_scale = (const float*)d_in[14];
    const float* bn2_shift = (const float*)d_in[15];
    float* out = (float*)d_out;

    __half *xw16, *qkv16, *o16, *xmid16, *h116, *wq16, *wp16, *w216;
    __nv_bfloat16 *U, *Vh, *Vl;
    float *mu, *rs, *Mbuf;
    cudaGetSymbolAddress((void**)&xw16,   g_xw16);
    cudaGetSymbolAddress((void**)&qkv16,  g_qkv16);
    cudaGetSymbolAddress((void**)&o16,    g_o16);
    cudaGetSymbolAddress((void**)&xmid16, g_xmid);
    cudaGetSymbolAddress((void**)&mu,     g_mu);
    cudaGetSymbolAddress((void**)&rs,     g_rs);
    cudaGetSymbolAddress((void**)&h116,   g_h116);
    cudaGetSymbolAddress((void**)&wq16,   g_wq16);
    cudaGetSymbolAddress((void**)&wp16,   g_wp16);
    cudaGetSymbolAddress((void**)&w216,   g_w216);
    cudaGetSymbolAddress((void**)&U,  g_U);
    cudaGetSymbolAddress((void**)&Vh, g_Vh); cudaGetSymbolAddress((void**)&Vl, g_Vl);
    cudaGetSymbolAddress((void**)&Mbuf, g_M);

    constexpr int SM3 = 3 * (A_STG + 64 * ROWB);   // 76800
    constexpr int SM4 = 4 * (A_STG + 64 * ROWB);   // 102400
    cudaFuncSetAttribute((const void*)gemm_tc<32,2,1,3,__half>,
                         cudaFuncAttributeMaxDynamicSharedMemorySize, SM3);
    cudaFuncSetAttribute((const void*)gemm_tc<32,2,1,4,__half>,
                         cudaFuncAttributeMaxDynamicSharedMemorySize, SM4);
    cudaFuncSetAttribute((const void*)gemm_tc<32,2,3,4,__nv_bfloat16>,
                         cudaFuncAttributeMaxDynamicSharedMemorySize, SM4);

    // weight preps
    prep_w16<<<(192 * 576 + 255) / 256, 256>>>(w_qkv, wq16, 192, 576);
    prep_w16<<<(192 * 192 + 255) / 256, 256>>>(w_proj, wp16, 192, 192);
    prep_w16<<<(768 * 192 + 255) / 256, 256>>>(w_ffn2, w216, 768, 192);
    wino_wt<<<(CCH * HIDDEN + 255) / 256, 256>>>(w_ffn1, U);

    // LN1 + roll + window partition -> fp16
    ln_kernel<<<MROWS / 8, 256>>>(x, ln1_g, ln1_b, xw16);

    // QKV GEMM [M,192]x[192,576] fp16 -> fp16  (short K: STAGES=3)
    gemm_tc<32,2,1,3,__half><<<dim3(576 / 64, MROWS / TM), 256, SM3>>>(
        xw16, xw16, wq16, b_qkv, nullptr, qkv16, nullptr, nullptr, nullptr, nullptr,
        576, 192, 6, 0, 0, 0);

    // attention -> fp16
    attn_kernel<<<(MROWS / NTOK) * HEADS, 128>>>(qkv16, bias_tbl, o16);

    // proj GEMM + window reverse + roll + shortcut(x fp32) -> fp16 trunk (STAGES=3)
    gemm_tc<32,2,1,3,__half><<<dim3(192 / 64, MROWS / TM), 256, SM3>>>(
        o16, o16, wp16, b_proj, nullptr, xmid16, nullptr, nullptr, x, nullptr,
        192, 192, 2, 0, 0, 0);

    // LN2 row stats (fp16 trunk)
    ln_stats<<<MROWS / 8, 256>>>(xmid16, mu, rs);

    // winograd F(4,3) input transform with fused LN2 -> bf16 hi/lo
    wino_in<<<(NT4 * CCH + 255) / 256, 256>>>(xmid16, mu, rs, ln2_g, ln2_b, Vh, Vl);

    // 36 batched transform GEMMs [6400,192]x[192,768] -> fp32 M (nk=18: STAGES=4)
    gemm_tc<32,2,3,4,__nv_bfloat16><<<dim3(HIDDEN / 64, NTP / TM, 36), 256, SM4>>>(
        Vh, Vl, U, nullptr, Mbuf, nullptr, nullptr, nullptr, nullptr, nullptr,
        HIDDEN, 192, 5,
        (size_t)NTP * CCH, (size_t)HIDDEN * 576, (size_t)NTP * HIDDEN);

    // winograd output transform + BN + GELU -> h1 fp16
    wino_out<<<(NT4 * HIDDEN + 255) / 256, 256>>>(Mbuf, bn1_scale, bn1_shift, h116);

    // conv1x1 GEMM + BN + residual(fp16 trunk) -> out fp32 (nk=24: STAGES=4)
    gemm_tc<32,2,1,4,__half><<<dim3(CCH / 64, MROWS / TM), 256, SM4>>>(
        h116, h116, w216, nullptr, out, nullptr, bn2_scale, bn2_shift, nullptr, xmid16,
        CCH, 768, 4, 0, 0, 0);
}

// round 16
// speedup vs baseline: 5.8361x; 1.0163x over previous
#include <cuda_runtime.h>
#include <cuda_bf16.h>
#include <cuda_fp16.h>
#include <cstdint>
#include <math.h>

// ---------------------------------------------------------------------------
// SwinTransformerLayer on GB300, mma.sync tensor cores.
// - QKV / proj / conv1x1 GEMMs: plain fp16 (residual-diluted error ~1e-4 each)
// - conv3x3: Winograd F(4x4,3x3); transform GEMMs bf16 3-term split, fp32 M
//   (16-bit anywhere in the winograd chain amplified ~6-10x — locked, R11).
// - fp16 residual trunk; half2 attention smem (R15); padded QK rows (R13).
// Round 16: vectorized winograd transforms + ln1 (2 channels/thread), merged
// weight-prep launches.
// ---------------------------------------------------------------------------

#define BATCH   32
#define HH      56
#define WW_     56
#define CCH     192
#define WS      7
#define SHIFT   3
#define HEADS   6
#define HD      32
#define NTOK    49
#define MROWS   (BATCH*HH*WW_)   // 100352
#define HIDDEN  768
#define QKSCALE 0.17677669529663687f
#define NT4     6272             // 32 * 14 * 14 winograd F(4,3) tiles
#define NTP     6400             // padded to multiple of 256

#define TM      256
#define TKB     32               // K elements per stage
#define ROWB    80               // padded row bytes (40 elems) — conflict-free ldmatrix
#define A_STG   (TM*ROWB)        // 20480

// ------------------------- scratch (device globals) ------------------------
__device__ __align__(16) __half        g_xw16 [(size_t)MROWS * CCH];
__device__ __align__(16) __half        g_qkv16[(size_t)MROWS * 3 * CCH];
__device__ __align__(16) __half        g_o16  [(size_t)MROWS * CCH];
__device__ __align__(16) __half        g_xmid [(size_t)MROWS * CCH];   // fp16 trunk
__device__ __align__(16) float         g_mu   [(size_t)MROWS];
__device__ __align__(16) float         g_rs   [(size_t)MROWS];
__device__ __align__(16) __half        g_h116 [(size_t)MROWS * HIDDEN];
// fp16 1-term weights, [N,K]
__device__ __align__(16) __half        g_wq16 [(size_t)576 * 192];
__device__ __align__(16) __half        g_wp16 [(size_t)192 * 192];
__device__ __align__(16) __half        g_w216 [(size_t)192 * 768];
// winograd F(4,3): 36 planes, bf16 3-term
__device__ __align__(16) __nv_bfloat16 g_U  [(size_t)36 * HIDDEN * 576];   // [p][co][3K]
__device__ __align__(16) __nv_bfloat16 g_Vh [(size_t)36 * NTP * CCH];
__device__ __align__(16) __nv_bfloat16 g_Vl [(size_t)36 * NTP * CCH];
__device__ __align__(16) float         g_M  [(size_t)36 * NTP * HIDDEN];   // fp32

// ------------------------------ PTX helpers --------------------------------
__device__ __forceinline__ void cp_async16(uint32_t dst, const void* src, bool full) {
    int sz = full ? 16 : 0;
    asm volatile("cp.async.cg.shared.global [%0], [%1], 16, %2;"
                 :: "r"(dst), "l"(src), "r"(sz) : "memory");
}
#define CP_COMMIT() asm volatile("cp.async.commit_group;" ::: "memory")
#define CP_WAIT(n)  asm volatile("cp.async.wait_group %0;" :: "n"(n) : "memory")

__device__ __forceinline__ void ldsm_x4(uint32_t addr, uint32_t r[4]) {
    asm volatile("ldmatrix.sync.aligned.m8n8.x4.shared.b16 {%0,%1,%2,%3}, [%4];"
                 : "=r"(r[0]), "=r"(r[1]), "=r"(r[2]), "=r"(r[3]) : "r"(addr));
}
template<typename T>
__device__ __forceinline__ void mma_any(float c[4], const uint32_t a[4],
                                        uint32_t b0, uint32_t b1);
template<>
__device__ __forceinline__ void mma_any<__nv_bfloat16>(float c[4], const uint32_t a[4],
                                                       uint32_t b0, uint32_t b1) {
    asm volatile("mma.sync.aligned.m16n8k16.row.col.f32.bf16.bf16.f32 "
                 "{%0,%1,%2,%3}, {%4,%5,%6,%7}, {%8,%9}, {%0,%1,%2,%3};"
                 : "+f"(c[0]), "+f"(c[1]), "+f"(c[2]), "+f"(c[3])
                 : "r"(a[0]), "r"(a[1]), "r"(a[2]), "r"(a[3]), "r"(b0), "r"(b1));
}
template<>
__device__ __forceinline__ void mma_any<__half>(float c[4], const uint32_t a[4],
                                                uint32_t b0, uint32_t b1) {
    asm volatile("mma.sync.aligned.m16n8k16.row.col.f32.f16.f16.f32 "
                 "{%0,%1,%2,%3}, {%4,%5,%6,%7}, {%8,%9}, {%0,%1,%2,%3};"
                 : "+f"(c[0]), "+f"(c[1]), "+f"(c[2]), "+f"(c[3])
                 : "r"(a[0]), "r"(a[1]), "r"(a[2]), "r"(a[3]), "r"(b0), "r"(b1));
}

__device__ __forceinline__ void split_bf16(float v, __nv_bfloat16& hi, __nv_bfloat16& lo) {
    hi = __float2bfloat16(v);
    lo = __float2bfloat16(v - __bfloat162float(hi));
}

// float2 componentwise ops for vectorized transforms
__device__ __forceinline__ float2 f2add(float2 a, float2 b) { return make_float2(a.x + b.x, a.y + b.y); }
__device__ __forceinline__ float2 f2sub(float2 a, float2 b) { return make_float2(a.x - b.x, a.y - b.y); }
__device__ __forceinline__ float2 f2scl(float s, float2 a)  { return make_float2(s * a.x, s * a.y); }

// ----------------------------- weight prep ---------------------------------
// single kernel for all three fp16 1-term weight transposes.
#define NQ (192*576)
#define NP (192*192)
#define N2 (768*192)
__global__ void prep_all(const float* __restrict__ Wq, const float* __restrict__ Wp,
                         const float* __restrict__ W2,
                         __half* __restrict__ Dq, __half* __restrict__ Dp,
                         __half* __restrict__ D2)
{
    int i = blockIdx.x * 256 + threadIdx.x;
    if (i < NQ) {
        int k = i / 576, n = i % 576;
        Dq[(size_t)n * 192 + k] = __float2half(Wq[i]);
    } else if (i < NQ + NP) {
        int j = i - NQ;
        int k = j / 192, n = j % 192;
        Dp[(size_t)n * 192 + k] = __float2half(Wp[j]);
    } else if (i < NQ + NP + N2) {
        int j = i - NQ - NP;
        int k = j / 192, n = j % 192;
        D2[(size_t)n * 768 + k] = __float2half(W2[j]);
    }
}

// ----------------------- winograd weight transform --------------------------
__global__ void wino_wt(const float* __restrict__ W, __nv_bfloat16* __restrict__ U)
{
    int i = blockIdx.x * 256 + threadIdx.x;
    if (i >= CCH * HIDDEN) return;
    int ci = i % CCH, co = i / CCH;

    float g[3][3];
    #pragma unroll
    for (int ky = 0; ky < 3; ky++)
        #pragma unroll
        for (int kx = 0; kx < 3; kx++)
            g[ky][kx] = W[((size_t)(ky * 3 + kx) * CCH + ci) * HIDDEN + co];

    float u[6][3];
    #pragma unroll
    for (int c = 0; c < 3; c++) {
        float g0 = g[0][c], g1 = g[1][c], g2 = g[2][c];
        u[0][c] = 0.25f * g0;
        u[1][c] = -(g0 + g1 + g2) * (1.0f / 6.0f);
        u[2][c] = (-g0 + g1 - g2) * (1.0f / 6.0f);
        u[3][c] = g0 * (1.0f / 24.0f) + g1 * (1.0f / 12.0f) + g2 * (1.0f / 6.0f);
        u[4][c] = g0 * (1.0f / 24.0f) - g1 * (1.0f / 12.0f) + g2 * (1.0f / 6.0f);
        u[5][c] = g2;
    }
    #pragma unroll
    for (int r = 0; r < 6; r++) {
        float a0 = u[r][0], a1 = u[r][1], a2 = u[r][2];
        float U6[6];
        U6[0] = 0.25f * a0;
        U6[1] = -(a0 + a1 + a2) * (1.0f / 6.0f);
        U6[2] = (-a0 + a1 - a2) * (1.0f / 6.0f);
        U6[3] = a0 * (1.0f / 24.0f) + a1 * (1.0f / 12.0f) + a2 * (1.0f / 6.0f);
        U6[4] = a0 * (1.0f / 24.0f) - a1 * (1.0f / 12.0f) + a2 * (1.0f / 6.0f);
        U6[5] = a2;
        #pragma unroll
        for (int c = 0; c < 6; c++) {
            int p = r * 6 + c;
            __nv_bfloat16 hi, lo;
            split_bf16(U6[c], hi, lo);
            size_t base = ((size_t)p * HIDDEN + co) * 576;
            U[base + ci]       = hi;
            U[base + 192 + ci] = hi;
            U[base + 384 + ci] = lo;
        }
    }
}

// ------------------------ LN row statistics (for LN2) -----------------------
__global__ __launch_bounds__(256)
void ln_stats(const __half* __restrict__ x, float* __restrict__ mu_o,
              float* __restrict__ rs_o)
{
    int m = blockIdx.x * 8 + (threadIdx.x >> 5);
    int lane = threadIdx.x & 31;
    const __half2* src = reinterpret_cast<const __half2*>(x + (size_t)m * CCH);
    float s1 = 0.f, s2 = 0.f;
    #pragma unroll
    for (int q = 0; q < 3; q++) {
        float2 v = __half22float2(src[lane + 32 * q]);
        s1 += v.x + v.y; s2 += v.x * v.x + v.y * v.y;
    }
    #pragma unroll
    for (int o = 16; o > 0; o >>= 1) {
        s1 += __shfl_xor_sync(0xFFFFFFFF, s1, o);
        s2 += __shfl_xor_sync(0xFFFFFFFF, s2, o);
    }
    if (lane == 0) {
        float mu  = s1 * (1.0f / CCH);
        float var = s2 * (1.0f / CCH) - mu * mu;
        mu_o[m] = mu;
        rs_o[m] = rsqrtf(var + 1e-3f);
    }
}

// ----------------- winograd input transform (LN2 fused) ---------------------
// 2 channels per thread: half2 loads, bf16x2 stores, in-place float2 transform.
__device__ __forceinline__ void bt6_2(const float2 d[6], float2 t[6]) {
    t[0] = f2add(f2sub(f2scl(4.f, d[0]), f2scl(5.f, d[2])), d[4]);
    t[1] = f2add(f2add(f2sub(f2scl(-4.f, d[1]), f2scl(4.f, d[2])), d[3]), d[4]);
    t[2] = f2add(f2sub(f2sub(f2scl(4.f, d[1]), f2scl(4.f, d[2])), d[3]), d[4]);
    t[3] = f2add(f2add(f2sub(f2scl(-2.f, d[1]), d[2]), f2scl(2.f, d[3])), d[4]);
    t[4] = f2add(f2sub(f2sub(f2scl(2.f, d[1]), d[2]), f2scl(2.f, d[3])), d[4]);
    t[5] = f2add(f2sub(f2scl(4.f, d[1]), f2scl(5.f, d[3])), d[5]);
}

__global__ __launch_bounds__(256)
void wino_in(const __half* __restrict__ x,
             const float* __restrict__ mu,
             const float* __restrict__ rs,
             const float* __restrict__ gamma,
             const float* __restrict__ beta,
             __nv_bfloat16* __restrict__ Vh,
             __nv_bfloat16* __restrict__ Vl)
{
    int i = blockIdx.x * 256 + threadIdx.x;
    if (i >= NT4 * (CCH / 2)) return;
    int tile = i / (CCH / 2), cp = i % (CCH / 2);
    int b = tile / 196, r = tile % 196, ty = r / 14, tx = r % 14;
    float2 gm = *reinterpret_cast<const float2*>(gamma + 2 * cp);
    float2 bt = *reinterpret_cast<const float2*>(beta + 2 * cp);

    float2 d[6][6];
    #pragma unroll
    for (int ii = 0; ii < 6; ii++) {
        int h = 4 * ty - 1 + ii;
        #pragma unroll
        for (int jj = 0; jj < 6; jj++) {
            int w = 4 * tx - 1 + jj;
            bool ok = (h >= 0) && (h < HH) && (w >= 0) && (w < WW_);
            if (ok) {
                size_t row = (size_t)(b * HH + h) * WW_ + w;
                float2 v = __half22float2(
                    *reinterpret_cast<const __half2*>(x + row * CCH + 2 * cp));
                float mr = mu[row], rr2 = rs[row];
                d[ii][jj].x = (v.x - mr) * rr2 * gm.x + bt.x;
                d[ii][jj].y = (v.y - mr) * rr2 * gm.y + bt.y;
            } else d[ii][jj] = make_float2(0.f, 0.f);
        }
    }
    // in-place column transform
    #pragma unroll
    for (int jj = 0; jj < 6; jj++) {
        float2 col[6], tc[6];
        #pragma unroll
        for (int ii = 0; ii < 6; ii++) col[ii] = d[ii][jj];
        bt6_2(col, tc);
        #pragma unroll
        for (int ii = 0; ii < 6; ii++) d[ii][jj] = tc[ii];
    }
    #pragma unroll
    for (int ii = 0; ii < 6; ii++) {
        float2 V6[6];
        bt6_2(d[ii], V6);
        #pragma unroll
        for (int jj = 0; jj < 6; jj++) {
            int p = ii * 6 + jj;
            __nv_bfloat16 hx, lx, hy, ly;
            split_bf16(V6[jj].x, hx, lx);
            split_bf16(V6[jj].y, hy, ly);
            size_t idx = ((size_t)p * NTP + tile) * CCH + 2 * cp;
            __nv_bfloat162 hv; hv.x = hx; hv.y = hy;
            __nv_bfloat162 lv; lv.x = lx; lv.y = ly;
            *reinterpret_cast<__nv_bfloat162*>(Vh + idx) = hv;
            *reinterpret_cast<__nv_bfloat162*>(Vl + idx) = lv;
        }
    }
}

// ----------------------- winograd output transform --------------------------
// 2 output channels per thread: float2 M loads, half2 stores.
__device__ __forceinline__ void at6_2(const float2 m[6], float2 s[4]) {
    s[0] = f2add(f2add(f2add(f2add(m[0], m[1]), m[2]), m[3]), m[4]);
    s[1] = f2sub(f2add(f2sub(m[1], m[2]), f2scl(2.f, m[3])), f2scl(2.f, m[4]));
    s[2] = f2add(f2add(f2add(m[1], m[2]), f2scl(4.f, m[3])), f2scl(4.f, m[4]));
    s[3] = f2add(f2add(f2sub(f2sub(m[1], m[2]), f2scl(8.f, m[4])), f2scl(8.f, m[3])), m[5]);
}

__global__ __launch_bounds__(256)
void wino_out(const float* __restrict__ M,
              const float* __restrict__ scale,
              const float* __restrict__ shiftv,
              __half* __restrict__ h116)
{
    int i = blockIdx.x * 256 + threadIdx.x;
    if (i >= NT4 * (HIDDEN / 2)) return;
    int tile = i / (HIDDEN / 2), cop = i % (HIDDEN / 2);
    int b = tile / 196, r = tile % 196, ty = r / 14, tx = r % 14;

    float2 m[6][6];
    #pragma unroll
    for (int p = 0; p < 36; p++)
        m[p / 6][p % 6] = *reinterpret_cast<const float2*>(
            M + ((size_t)p * NTP + tile) * HIDDEN + 2 * cop);

    float2 s[4][6];
    #pragma unroll
    for (int jj = 0; jj < 6; jj++) {
        float2 col[6], sc4[4];
        #pragma unroll
        for (int ii = 0; ii < 6; ii++) col[ii] = m[ii][jj];
        at6_2(col, sc4);
        #pragma unroll
        for (int ii = 0; ii < 4; ii++) s[ii][jj] = sc4[ii];
    }
    float2 sc = *reinterpret_cast<const float2*>(scale + 2 * cop);
    float2 sh = *reinterpret_cast<const float2*>(shiftv + 2 * cop);
    #pragma unroll
    for (int ii = 0; ii < 4; ii++) {
        float2 Y4[4];
        at6_2(s[ii], Y4);
        #pragma unroll
        for (int jj = 0; jj < 4; jj++) {
            float vx = Y4[jj].x * sc.x + sh.x;
            float vy = Y4[jj].y * sc.y + sh.y;
            vx = 0.5f * vx * (1.0f + erff(vx * 0.70710678118654752f));
            vy = 0.5f * vy * (1.0f + erff(vy * 0.70710678118654752f));
            size_t px = (size_t)b * 3136 + (size_t)(4 * ty + ii) * 56 + (4 * tx + jj);
            *reinterpret_cast<__half2*>(h116 + px * HIDDEN + 2 * cop) =
                __floats2half2_rn(vx, vy);
        }
    }
}

// ------------------------------- LayerNorm (LN1) ----------------------------
__global__ __launch_bounds__(256)
void ln_kernel(const float* __restrict__ x,
               const float* __restrict__ gamma,
               const float* __restrict__ beta,
               __half* __restrict__ out16)
{
    int m = blockIdx.x * 8 + (threadIdx.x >> 5);
    int lane = threadIdx.x & 31;

    int win = m / NTOK, tok = m % NTOK;
    int b  = win >> 6, wi = win & 63;
    int hs = (wi >> 3) * WS + tok / WS;
    int ws = (wi & 7)  * WS + tok % WS;
    int h = hs + SHIFT; if (h >= HH)  h -= HH;
    int w = ws + SHIFT; if (w >= WW_) w -= WW_;
    int src_p = (b * HH + h) * WW_ + w;

    const float2* src = reinterpret_cast<const float2*>(x + (size_t)src_p * CCH);
    float2 v[3];
    float s1 = 0.f, s2 = 0.f;
    #pragma unroll
    for (int q = 0; q < 3; q++) {
        v[q] = src[lane + 32 * q];
        s1 += v[q].x + v[q].y;
        s2 += v[q].x * v[q].x + v[q].y * v[q].y;
    }
    #pragma unroll
    for (int o = 16; o > 0; o >>= 1) {
        s1 += __shfl_xor_sync(0xFFFFFFFF, s1, o);
        s2 += __shfl_xor_sync(0xFFFFFFFF, s2, o);
    }
    float mu  = s1 * (1.0f / CCH);
    float var = s2 * (1.0f / CCH) - mu * mu;
    float rsg = rsqrtf(var + 1e-3f);

    #pragma unroll
    for (int q = 0; q < 3; q++) {
        int cp = lane + 32 * q;
        float2 gm = *reinterpret_cast<const float2*>(gamma + 2 * cp);
        float2 bt = *reinterpret_cast<const float2*>(beta + 2 * cp);
        float yx = (v[q].x - mu) * rsg * gm.x + bt.x;
        float yy = (v[q].y - mu) * rsg * gm.y + bt.y;
        *reinterpret_cast<__half2*>(out16 + (size_t)m * CCH + 2 * cp) =
            __floats2half2_rn(yx, yy);
    }
}

// ------------------------------- Attention ---------------------------------
#define QKP2 17
__global__ void attn_kernel(const __half* __restrict__ qkv,
                            const float* __restrict__ table,
                            __half* __restrict__ o16)
{
    int blk = blockIdx.x;
    int win = blk / HEADS;
    int head = blk % HEADS;
    int tid = threadIdx.x;

    __shared__ __half2 qs2[NTOK * QKP2], ks2[NTOK * QKP2], vs2[NTOK * 16];
    __shared__ float S[NTOK * 50];

    const __half2 scale2 = __floats2half2_rn(QKSCALE, QKSCALE);
    for (int t = tid; t < NTOK * 16; t += 128) {
        int n = t >> 4, dp = t & 15;
        const __half2* base = reinterpret_cast<const __half2*>(
            qkv + (size_t)(win * NTOK + n) * (3 * CCH) + head * HD) + dp;
        qs2[n * QKP2 + dp] = __hmul2(base[0], scale2);
        ks2[n * QKP2 + dp] = base[CCH / 2];
        vs2[t] = base[CCH];
    }
    __syncthreads();

    int wi = win & 63;
    int wh = wi >> 3, wwn = wi & 7;

    for (int t = tid; t < NTOK * NTOK; t += 128) {
        int n = t / NTOK, mm = t % NTOK;
        float s = 0.f;
        #pragma unroll
        for (int dp = 0; dp < 16; dp++) {
            float2 a = __half22float2(qs2[n * QKP2 + dp]);
            float2 b = __half22float2(ks2[mm * QKP2 + dp]);
            s += a.x * b.x + a.y * b.y;
        }
        int rn = n / WS, cn = n % WS, rm = mm / WS, cm = mm % WS;
        int idx = (rn - rm + WS - 1) * (2 * WS - 1) + (cn - cm + WS - 1);
        s += table[idx * HEADS + head];
        int hn = wh * WS + rn, wn = wwn * WS + cn;
        int hm = wh * WS + rm, wm = wwn * WS + cm;
        int reg_n = (hn < 49 ? 0 : (hn < 53 ? 1 : 2)) * 3 + (wn < 49 ? 0 : (wn < 53 ? 1 : 2));
        int reg_m = (hm < 49 ? 0 : (hm < 53 ? 1 : 2)) * 3 + (wm < 49 ? 0 : (wm < 53 ? 1 : 2));
        if (reg_n != reg_m) s -= 100.0f;
        S[n * 50 + mm] = s;
    }
    __syncthreads();

    // warp-per-row softmax
    {
        int w4 = tid >> 5, lane = tid & 31;
        for (int row = w4; row < NTOK; row += 4) {
            float* Sr = S + row * 50;
            float mx = -1e30f;
            for (int c = lane; c < NTOK; c += 32) mx = fmaxf(mx, Sr[c]);
            #pragma unroll
            for (int o = 16; o > 0; o >>= 1)
                mx = fmaxf(mx, __shfl_xor_sync(0xFFFFFFFF, mx, o));
            float sum = 0.f;
            for (int c = lane; c < NTOK; c += 32) {
                float e = __expf(Sr[c] - mx);
                Sr[c] = e; sum += e;
            }
            #pragma unroll
            for (int o = 16; o > 0; o >>= 1)
                sum += __shfl_xor_sync(0xFFFFFFFF, sum, o);
            float inv = 1.0f / sum;
            for (int c = lane; c < NTOK; c += 32) Sr[c] *= inv;
        }
    }
    __syncthreads();

    for (int t = tid; t < NTOK * 16; t += 128) {
        int n = t >> 4, dp = t & 15;
        float2 acc = make_float2(0.f, 0.f);
        #pragma unroll 7
        for (int m2 = 0; m2 < NTOK; m2++) {
            float p = S[n * 50 + m2];
            float2 v = __half22float2(vs2[m2 * 16 + dp]);
            acc.x += p * v.x;
            acc.y += p * v.y;
        }
        size_t idx = (size_t)(win * NTOK + n) * CCH + head * HD + 2 * dp;
        *reinterpret_cast<__half2*>(o16 + idx) = __floats2half2_rn(acc.x, acc.y);
    }
}

// ---------------------------- HMMA GEMM ------------------------------------
// SPLIT=1 (fp16): C = A[M,K] x B[K,N] plain.
// SPLIT=3 (bf16): C = A'[M,3K] x B'[3K,N], A' = [Ah|Al|Ah].
// STG: pipeline depth (3 for short-K, 4 for long-K).
// epi: 2=+bias,remap,+addF(f32) -> f16   4=BN,+addH(f16) -> f32
//      5=raw -> f32                       6=+bias -> f16
template<int WN, int MINCTA, int SPLIT, int STG, typename T>
__global__ __launch_bounds__(256, MINCTA)
void gemm_tc(const T* __restrict__ Ah,
             const T* __restrict__ Al,
             const T* __restrict__ Bs,
             const float* __restrict__ bias,
             float* __restrict__ Cf,
             __half* __restrict__ C16,
             const float* __restrict__ scale,
             const float* __restrict__ shiftv,
             const float* __restrict__ addF,
             const __half* __restrict__ addH,
             int N, int K1, int epi,
             size_t zsA, size_t zsB, size_t zsC)
{
    constexpr int TN   = 2 * WN;
    constexpr int NB   = WN / 16;
    constexpr int NI   = WN / 8;
    constexpr int B_STG = TN * ROWB;
    constexpr int BPASS = TN / 64;

    Ah += blockIdx.z * zsA;
    Al += blockIdx.z * zsA;
    Bs += blockIdx.z * zsB;
    if (Cf) Cf += blockIdx.z * zsC;

    extern __shared__ char smem[];
    uint32_t sA0 = (uint32_t)__cvta_generic_to_shared(smem);
    uint32_t sB0 = sA0 + STG * A_STG;

    int tid = threadIdx.x;
    int wid = tid >> 5, lid = tid & 31;
    int wr = wid >> 1, wc = wid & 1;
    int m0 = blockIdx.y * TM, n0 = blockIdx.x * TN;
    int KS = SPLIT * K1;
    int nk = KS / TKB;

    int arow = tid >> 2;
    int aj = tid & 3;
    size_t arowoff[4];
    #pragma unroll
    for (int p = 0; p < 4; p++) arowoff[p] = (size_t)(m0 + arow + p * 64) * K1;
    size_t browoff[BPASS];
    #pragma unroll
    for (int p = 0; p < BPASS; p++)
        browoff[p] = (size_t)(n0 + arow + p * 64) * KS;

    float acc[4][NI][4];
    #pragma unroll
    for (int i = 0; i < 4; i++)
        #pragma unroll
        for (int j = 0; j < NI; j++)
            #pragma unroll
            for (int q = 0; q < 4; q++) acc[i][j][q] = 0.f;

    auto load_stage = [&](int kt) {
        int s = kt % STG;
        int k3 = kt * TKB;
        int seg = k3 / K1;
        int kk = k3 - seg * K1;
        const T* Asrc = (SPLIT == 3 && seg == 1) ? Al : Ah;
        #pragma unroll
        for (int p = 0; p < 4; p++) {
            uint32_t dst = sA0 + s * A_STG + (arow + p * 64) * ROWB + aj * 16;
            cp_async16(dst, Asrc + arowoff[p] + kk + aj * 8, true);
        }
        #pragma unroll
        for (int p = 0; p < BPASS; p++) {
            uint32_t dst = sB0 + s * B_STG + (arow + p * 64) * ROWB + aj * 16;
            cp_async16(dst, Bs + browoff[p] + k3 + aj * 8, true);
        }
    };

    auto compute = [&](int s) {
        uint32_t aBase = sA0 + s * A_STG + (wr * 64 + (lid & 15)) * ROWB + (lid >> 4) * 16;
        uint32_t bBase = sB0 + s * B_STG
                       + (wc * WN + (lid & 7) + ((lid >> 4) << 3)) * ROWB
                       + ((lid >> 3) & 1) * 16;
        #pragma unroll
        for (int ks = 0; ks < 2; ks++) {
            uint32_t a[4][4], b[NB][4];
            #pragma unroll
            for (int mi = 0; mi < 4; mi++)
                ldsm_x4(aBase + mi * 16 * ROWB + ks * 32, a[mi]);
            #pragma unroll
            for (int bi = 0; bi < NB; bi++)
                ldsm_x4(bBase + bi * 16 * ROWB + ks * 32, b[bi]);
            #pragma unroll
            for (int mi = 0; mi < 4; mi++)
                #pragma unroll
                for (int ni = 0; ni < NI; ni++)
                    mma_any<T>(acc[mi][ni], a[mi],
                               b[ni >> 1][(ni & 1) * 2], b[ni >> 1][(ni & 1) * 2 + 1]);
        }
    };

    #pragma unroll
    for (int p = 0; p < STG - 1; p++) { if (p < nk) load_stage(p); CP_COMMIT(); }

    for (int kt = 0; kt < nk; kt++) {
        CP_WAIT(STG - 2);
        __syncthreads();
        if (kt + STG - 1 < nk) load_stage(kt + STG - 1);
        CP_COMMIT();
        compute(kt % STG);
    }

    // ------------------------------ epilogue -------------------------------
    int g = lid >> 2, t2 = (lid & 3) * 2;
    #pragma unroll
    for (int mi = 0; mi < 4; mi++) {
        #pragma unroll
        for (int rr = 0; rr < 2; rr++) {
            int m = m0 + wr * 64 + mi * 16 + g + rr * 8;
            size_t orow;
            if (epi == 2) {
                int win = m / NTOK, tok = m % NTOK;
                int b = win >> 6, wi2 = win & 63;
                int hs = (wi2 >> 3) * WS + tok / WS;
                int ws = (wi2 & 7)  * WS + tok % WS;
                int h = hs + SHIFT; if (h >= HH)  h -= HH;
                int w = ws + SHIFT; if (w >= WW_) w -= WW_;
                orow = (size_t)(b * HH + h) * WW_ + w;
            } else {
                orow = (size_t)m;
            }
            #pragma unroll
            for (int ni = 0; ni < NI; ni++) {
                int n = n0 + wc * WN + ni * 8 + t2;
                float v0 = acc[mi][ni][rr * 2 + 0];
                float v1 = acc[mi][ni][rr * 2 + 1];
                if (epi == 6) {
                    __half2 o;
                    o.x = __float2half(v0 + bias[n]);
                    o.y = __float2half(v1 + bias[n + 1]);
                    *reinterpret_cast<__half2*>(C16 + (size_t)m * N + n) = o;
                } else if (epi == 2) {
                    size_t oi = orow * CCH + n;
                    float2 a4 = *reinterpret_cast<const float2*>(addF + oi);
                    __half2 o;
                    o.x = __float2half(v0 + bias[n] + a4.x);
                    o.y = __float2half(v1 + bias[n + 1] + a4.y);
                    *reinterpret_cast<__half2*>(C16 + oi) = o;
                } else if (epi == 4) {
                    size_t oi = (size_t)m * CCH + n;
                    float2 a4 = __half22float2(
                        *reinterpret_cast<const __half2*>(addH + oi));
                    float2 o = { v0 * scale[n] + shiftv[n] + a4.x,
                                 v1 * scale[n + 1] + shiftv[n + 1] + a4.y };
                    *reinterpret_cast<float2*>(Cf + oi) = o;
                } else {  // epi == 5: raw fp32
                    float2 o = { v0, v1 };
                    *reinterpret_cast<float2*>(Cf + (size_t)m * N + n) = o;
                }
            }
        }
    }
}

// ------------------------------- launcher -----------------------------------
extern "C" void kernel_launch(void* const* d_in, const int* in_sizes, int n_in,
                              void* d_out, int out_size)
{
    const float* x         = (const float*)d_in[0];
    const float* ln1_g     = (const float*)d_in[1];
    const float* ln1_b     = (const float*)d_in[2];
    const float* w_qkv     = (const float*)d_in[3];
    const float* b_qkv     = (const float*)d_in[4];
    const float* bias_tbl  = (const float*)d_in[5];
    const float* w_proj    = (const float*)d_in[6];
    const float* b_proj    = (const float*)d_in[7];
    const float* ln2_g     = (const float*)d_in[8];
    const float* ln2_b     = (const float*)d_in[9];
    const float* w_ffn1    = (const float*)d_in[10];
    const float* bn1_scale = (const float*)d_in[11];
    const float* bn1_shift = (const float*)d_in[12];
    const float* w_ffn2    = (const float*)d_in[13];
    const float* bn2_scale = (const float*)d_in[14];
    const float* bn2_shift = (const float*)d_in[15];
    float* out = (float*)d_out;

    __half *xw16, *qkv16, *o16, *xmid16, *h116, *wq16, *wp16, *w216;
    __nv_bfloat16 *U, *Vh, *Vl;
    float *mu, *rs, *Mbuf;
    cudaGetSymbolAddress((void**)&xw16,   g_xw16);
    cudaGetSymbolAddress((void**)&qkv16,  g_qkv16);
    cudaGetSymbolAddress((void**)&o16,    g_o16);
    cudaGetSymbolAddress((void**)&xmid16, g_xmid);
    cudaGetSymbolAddress((void**)&mu,     g_mu);
    cudaGetSymbolAddress((void**)&rs,     g_rs);
    cudaGetSymbolAddress((void**)&h116,   g_h116);
    cudaGetSymbolAddress((void**)&wq16,   g_wq16);
    cudaGetSymbolAddress((void**)&wp16,   g_wp16);
    cudaGetSymbolAddress((void**)&w216,   g_w216);
    cudaGetSymbolAddress((void**)&U,  g_U);
    cudaGetSymbolAddress((void**)&Vh, g_Vh); cudaGetSymbolAddress((void**)&Vl, g_Vl);
    cudaGetSymbolAddress((void**)&Mbuf, g_M);

    constexpr int SM3 = 3 * (A_STG + 64 * ROWB);   // 76800
    constexpr int SM4 = 4 * (A_STG + 64 * ROWB);   // 102400
    cudaFuncSetAttribute((const void*)gemm_tc<32,2,1,3,__half>,
                         cudaFuncAttributeMaxDynamicSharedMemorySize, SM3);
    cudaFuncSetAttribute((const void*)gemm_tc<32,2,1,4,__half>,
                         cudaFuncAttributeMaxDynamicSharedMemorySize, SM4);
    cudaFuncSetAttribute((const void*)gemm_tc<32,2,3,4,__nv_bfloat16>,
                         cudaFuncAttributeMaxDynamicSharedMemorySize, SM4);

    // weight preps (one merged launch + winograd weight transform)
    prep_all<<<(NQ + NP + N2 + 255) / 256, 256>>>(w_qkv, w_proj, w_ffn2,
                                                  wq16, wp16, w216);
    wino_wt<<<(CCH * HIDDEN + 255) / 256, 256>>>(w_ffn1, U);

    // LN1 + roll + window partition -> fp16
    ln_kernel<<<MROWS / 8, 256>>>(x, ln1_g, ln1_b, xw16);

    // QKV GEMM [M,192]x[192,576] fp16 -> fp16  (short K: STAGES=3)
    gemm_tc<32,2,1,3,__half><<<dim3(576 / 64, MROWS / TM), 256, SM3>>>(
        xw16, xw16, wq16, b_qkv, nullptr, qkv16, nullptr, nullptr, nullptr, nullptr,
        576, 192, 6, 0, 0, 0);

    // attention -> fp16
    attn_kernel<<<(MROWS / NTOK) * HEADS, 128>>>(qkv16, bias_tbl, o16);

    // proj GEMM + window reverse + roll + shortcut(x fp32) -> fp16 trunk (STAGES=3)
    gemm_tc<32,2,1,3,__half><<<dim3(192 / 64, MROWS / TM), 256, SM3>>>(
        o16, o16, wp16, b_proj, nullptr, xmid16, nullptr, nullptr, x, nullptr,
        192, 192, 2, 0, 0, 0);

    // LN2 row stats (fp16 trunk)
    ln_stats<<<MROWS / 8, 256>>>(xmid16, mu, rs);

    // winograd F(4,3) input transform with fused LN2 -> bf16 hi/lo (2 ch/thread)
    wino_in<<<(NT4 * (CCH / 2) + 255) / 256, 256>>>(xmid16, mu, rs, ln2_g, ln2_b, Vh, Vl);

    // 36 batched transform GEMMs [6400,192]x[192,768] -> fp32 M (nk=18: STAGES=4)
    gemm_tc<32,2,3,4,__nv_bfloat16><<<dim3(HIDDEN / 64, NTP / TM, 36), 256, SM4>>>(
        Vh, Vl, U, nullptr, Mbuf, nullptr, nullptr, nullptr, nullptr, nullptr,
        HIDDEN, 192, 5,
        (size_t)NTP * CCH, (size_t)HIDDEN * 576, (size_t)NTP * HIDDEN);

    // winograd output transform + BN + GELU -> h1 fp16 (2 ch/thread)
    wino_out<<<(NT4 * (HIDDEN / 2) + 255) / 256, 256>>>(Mbuf, bn1_scale, bn1_shift, h116);

    // conv1x1 GEMM + BN + residual(fp16 trunk) -> out fp32 (nk=24: STAGES=4)
    gemm_tc<32,2,1,4,__half><<<dim3(CCH / 64, MROWS / TM), 256, SM4>>>(
        h116, h116, w216, nullptr, out, nullptr, bn2_scale, bn2_shift, nullptr, xmid16,
        CCH, 768, 4, 0, 0, 0);
}